// round 1
// baseline (speedup 1.0000x reference)
#include <cuda_runtime.h>
#include <math.h>

// ---------------- problem constants ----------------
#define CB   64      // batch
#define CS   512     // seq
#define CD   768     // model dim
#define CE   32      // entities
#define CL   16      // span len
#define CTQ  128     // Tq
#define CH   3       // heads
#define CDK  128     // head dim
#define CHDK 384     // H*DK
#define CDFF 3072
#define CNH  1024
#define CNL  3
#define NROWS (CB*CE*CL)     // 32768
#define NENT  (CB*CE)        // 2048

// ---------------- device scratch (no allocations allowed) ----------------
__device__ float g_x  [NROWS*CD];     // activations
__device__ float g_qb [NROWS*CHDK];
__device__ float g_kb [NROWS*CHDK];
__device__ float g_vb [NROWS*CHDK];
__device__ float g_ob [NROWS*CHDK];
__device__ float g_t  [NROWS*CD];     // temp (Wo out / FFN2 out)
__device__ float g_f  [NROWS*CDFF];   // FFN hidden
__device__ float g_ent [NENT*CD];     // enc_ent
__device__ float g_entp[NENT*770];    // ent_proj (D+2)
__device__ float g_attnw[CB*CTQ*CE];  // pooling attention weights
__device__ float g_wa  [CB*CD];
__device__ float g_feat[CB*2*CD];
__device__ float g_h   [CB*CNH];

// ---------------- helpers ----------------
__device__ __forceinline__ float blockReduceSum(float val) {
    __shared__ float sh[32];
    int lane = threadIdx.x & 31, wid = threadIdx.x >> 5;
    #pragma unroll
    for (int o = 16; o > 0; o >>= 1) val += __shfl_xor_sync(0xffffffffu, val, o);
    if (lane == 0) sh[wid] = val;
    __syncthreads();
    int nw = (blockDim.x + 31) >> 5;
    val = (threadIdx.x < nw) ? sh[lane] : 0.f;
    if (wid == 0) {
        #pragma unroll
        for (int o = 16; o > 0; o >>= 1) val += __shfl_xor_sync(0xffffffffu, val, o);
    }
    return val;  // valid in warp 0
}

// ---------------- gather spans into g_x ----------------
__global__ void gather_kernel(const float* __restrict__ q_enc,
                              const int* __restrict__ ranges) {
    int row = blockIdx.x;              // 0..32767
    int be = row >> 4, l = row & 15;
    int b = be >> 5, e = be & 31;
    int st = ranges[(b * CE + e) * 2];
    int en = ranges[(b * CE + e) * 2 + 1];
    int src = min(max(st + l, 0), CS - 1);
    bool m = l < (en - st);
    const float* s = q_enc + ((size_t)b * CS + src) * CD;
    float* d = g_x + (size_t)row * CD;
    for (int i = threadIdx.x; i < CD; i += 256) d[i] = m ? s[i] : 0.f;
}

// ---------------- tiled SGEMM: C[M,N] = A[M,K] @ W[K,N] + bias, opt ReLU ----
// BM=BN=64, BK=16, 16x16 threads, 4x4 per thread. K must be mult of 16.
__global__ void gemm_bias_kernel(const float* __restrict__ A,
                                 const float* __restrict__ W,
                                 const float* __restrict__ bias,
                                 float* __restrict__ C,
                                 int M, int N, int K, int relu) {
    __shared__ float As[16][65];
    __shared__ float Bs[16][68];
    int tx = threadIdx.x, ty = threadIdx.y;
    int tid = ty * 16 + tx;
    int m0 = blockIdx.y * 64, n0 = blockIdx.x * 64;

    int a_row = tid >> 2;          // 0..63
    int a_col = (tid & 3) << 2;    // 0,4,8,12
    int b_row = tid >> 4;          // 0..15
    int b_col = (tid & 15) << 2;   // 0..60

    float acc[4][4] = {};
    for (int k0 = 0; k0 < K; k0 += 16) {
        int m = m0 + a_row;
        #pragma unroll
        for (int i = 0; i < 4; i++) {
            float v = 0.f;
            if (m < M) v = A[(size_t)m * K + k0 + a_col + i];
            As[a_col + i][a_row] = v;
        }
        #pragma unroll
        for (int i = 0; i < 4; i++) {
            int n = n0 + b_col + i;
            float v = 0.f;
            if (n < N) v = W[(size_t)(k0 + b_row) * N + n];
            Bs[b_row][b_col + i] = v;
        }
        __syncthreads();
        #pragma unroll
        for (int kk = 0; kk < 16; kk++) {
            float ra[4], rb[4];
            #pragma unroll
            for (int i = 0; i < 4; i++) ra[i] = As[kk][ty * 4 + i];
            #pragma unroll
            for (int j = 0; j < 4; j++) rb[j] = Bs[kk][tx * 4 + j];
            #pragma unroll
            for (int i = 0; i < 4; i++)
                #pragma unroll
                for (int j = 0; j < 4; j++)
                    acc[i][j] += ra[i] * rb[j];
        }
        __syncthreads();
    }
    #pragma unroll
    for (int i = 0; i < 4; i++) {
        int m = m0 + ty * 4 + i;
        if (m >= M) continue;
        #pragma unroll
        for (int j = 0; j < 4; j++) {
            int n = n0 + tx * 4 + j;
            if (n >= N) continue;
            float v = acc[i][j] + bias[n];
            if (relu) v = fmaxf(v, 0.f);
            C[(size_t)m * N + n] = v;
        }
    }
}

// ---------------- per-(span,head) attention, L=16, DK=128 -----------------
__global__ void attn_kernel() {
    int nh = blockIdx.x;
    int n = nh / CH, h = nh % CH;
    __shared__ float qs[16][129], ks[16][129], vs[16][129];
    __shared__ float sc[16][17];
    int tid = threadIdx.x;  // 128
    for (int idx = tid; idx < 16 * 128; idx += 128) {
        int l = idx >> 7, d = idx & 127;
        size_t base = ((size_t)(n * CL + l)) * CHDK + h * CDK + d;
        qs[l][d] = g_qb[base];
        ks[l][d] = g_kb[base];
        vs[l][d] = g_vb[base];
    }
    __syncthreads();
    const float scale = 0.088388347648318447f;  // 1/sqrt(128)
    for (int p = tid; p < 256; p += 128) {
        int qi = p >> 4, ki = p & 15;
        float s = 0.f;
        #pragma unroll
        for (int d = 0; d < 128; d++) s += qs[qi][d] * ks[ki][d];
        sc[qi][ki] = s * scale;
    }
    __syncthreads();
    if (tid < 16) {
        float m = -1e30f;
        #pragma unroll
        for (int k = 0; k < 16; k++) m = fmaxf(m, sc[tid][k]);
        float sum = 0.f;
        #pragma unroll
        for (int k = 0; k < 16; k++) { float e = __expf(sc[tid][k] - m); sc[tid][k] = e; sum += e; }
        float inv = 1.f / sum;
        #pragma unroll
        for (int k = 0; k < 16; k++) sc[tid][k] *= inv;
    }
    __syncthreads();
    int d = tid;  // 0..127
    #pragma unroll
    for (int qi = 0; qi < 16; qi++) {
        float acc = 0.f;
        #pragma unroll
        for (int k = 0; k < 16; k++) acc += sc[qi][k] * vs[k][d];
        g_ob[((size_t)(n * CL + qi)) * CHDK + h * CDK + d] = acc;
    }
}

// ---------------- x = LN(x + t) ----------------
__global__ void add_ln_kernel(const float* __restrict__ gamma,
                              const float* __restrict__ beta) {
    int row = blockIdx.x;
    int tid = threadIdx.x;  // 256, 3 elems per thread
    float v[3];
    float s = 0.f;
    #pragma unroll
    for (int j = 0; j < 3; j++) {
        size_t idx = (size_t)row * CD + tid + j * 256;
        v[j] = g_x[idx] + g_t[idx];
        s += v[j];
    }
    s = blockReduceSum(s);
    __shared__ float mean_s, rstd_s;
    if (tid == 0) mean_s = s * (1.f / CD);
    __syncthreads();
    float m = mean_s;
    float vv = 0.f;
    #pragma unroll
    for (int j = 0; j < 3; j++) { float d = v[j] - m; vv += d * d; }
    vv = blockReduceSum(vv);
    if (tid == 0) rstd_s = rsqrtf(vv * (1.f / CD) + 1e-5f);
    __syncthreads();
    float r = rstd_s;
    #pragma unroll
    for (int j = 0; j < 3; j++) {
        int c = tid + j * 256;
        g_x[(size_t)row * CD + c] = (v[j] - m) * r * gamma[c] + beta[c];
    }
}

// ---------------- enc_ent = x[:, :, 0, :] ----------------
__global__ void copy_ent_kernel() {
    int r = blockIdx.x;  // 0..2047
    for (int d = threadIdx.x; d < CD; d += 256)
        g_ent[(size_t)r * CD + d] = g_x[(size_t)r * CL * CD + d];
}

// ---------------- pooling attention weights (softmax over E) --------------
__global__ void pool_attn_kernel(const float* __restrict__ q_enc,
                                 const float* __restrict__ hint) {
    int t = blockIdx.x, b = blockIdx.y;
    __shared__ float qv[770];
    __shared__ float lg[32];
    int tid = threadIdx.x;  // 256
    for (int i = tid; i < 770; i += 256)
        qv[i] = (i < CD) ? q_enc[((size_t)b * CS + t) * CD + i]
                         : hint[((size_t)b * CTQ + t) * 2 + (i - CD)];
    __syncthreads();
    int e = tid >> 3, sub = tid & 7;
    const float* ep = g_entp + ((size_t)b * CE + e) * 770;
    float p = 0.f;
    for (int d = sub; d < 770; d += 8) p += qv[d] * ep[d];
    p += __shfl_down_sync(0xffffffffu, p, 4, 8);
    p += __shfl_down_sync(0xffffffffu, p, 2, 8);
    p += __shfl_down_sync(0xffffffffu, p, 1, 8);
    if (sub == 0) lg[e] = p;
    __syncthreads();
    if (tid < 32) {
        float v = lg[tid];
        float m = v;
        #pragma unroll
        for (int o = 16; o > 0; o >>= 1) m = fmaxf(m, __shfl_xor_sync(0xffffffffu, m, o));
        float ex = __expf(v - m);
        float sm = ex;
        #pragma unroll
        for (int o = 16; o > 0; o >>= 1) sm += __shfl_xor_sync(0xffffffffu, sm, o);
        g_attnw[((size_t)b * CTQ + t) * CE + tid] = ex / sm;
    }
}

// wa[b,d] = sum_e (sum_{t<qlen} attn[b,t,e]) * ent[b,e,d]
__global__ void pool_wa_kernel(const int* __restrict__ qlen) {
    int b = blockIdx.x;
    int tid = threadIdx.x;  // 256
    __shared__ float A[32];
    int n = qlen[b];
    if (tid < 32) {
        float s = 0.f;
        for (int t = 0; t < n; t++) s += g_attnw[((size_t)b * CTQ + t) * CE + tid];
        A[tid] = s;
    }
    __syncthreads();
    #pragma unroll
    for (int j = 0; j < 3; j++) {
        int d = tid + j * 256;
        float s = 0.f;
        #pragma unroll
        for (int e = 0; e < 32; e++) s += A[e] * g_ent[((size_t)b * CE + e) * CD + d];
        g_wa[(size_t)b * CD + d] = s;
    }
}

// feat = [q_enc[b,0,:], wa[b,:]]
__global__ void feat_kernel(const float* __restrict__ q_enc) {
    int b = blockIdx.x;
    for (int i = threadIdx.x; i < 2 * CD; i += 256)
        g_feat[(size_t)b * 2 * CD + i] =
            (i < CD) ? q_enc[(size_t)b * CS * CD + i] : g_wa[(size_t)b * CD + (i - CD)];
}

// out[b] = dot(h[b], W2) + b2
__global__ void head_out_kernel(const float* __restrict__ W2,
                                const float* __restrict__ b2,
                                float* __restrict__ out) {
    int b = blockIdx.x, tid = threadIdx.x;  // 256
    float s = 0.f;
    for (int n = tid; n < CNH; n += 256) s += g_h[(size_t)b * CNH + n] * W2[n];
    s = blockReduceSum(s);
    if (tid == 0) out[b] = s + b2[0];
}

// ---------------- host launch ----------------
static float* dsymf(const void* symbol) {
    void* p = nullptr;
    cudaGetSymbolAddress(&p, symbol);
    return (float*)p;
}

extern "C" void kernel_launch(void* const* d_in, const int* in_sizes, int n_in,
                              void* d_out, int out_size) {
    const float* q_enc  = (const float*)d_in[0];
    const int*   q_qlen = (const int*)  d_in[1];
    const float* hint   = (const float*)d_in[2];
    const int*   ranges = (const int*)  d_in[3];
    const float* Wq  = (const float*)d_in[4];
    const float* bq  = (const float*)d_in[5];
    const float* Wk  = (const float*)d_in[6];
    const float* bk  = (const float*)d_in[7];
    const float* Wv  = (const float*)d_in[8];
    const float* bv  = (const float*)d_in[9];
    const float* Wo  = (const float*)d_in[10];
    const float* bo  = (const float*)d_in[11];
    const float* ln1g = (const float*)d_in[12];
    const float* ln1b = (const float*)d_in[13];
    const float* Wf1 = (const float*)d_in[14];
    const float* bf1 = (const float*)d_in[15];
    const float* Wf2 = (const float*)d_in[16];
    const float* bf2 = (const float*)d_in[17];
    const float* ln2g = (const float*)d_in[18];
    const float* ln2b = (const float*)d_in[19];
    const float* W_ea = (const float*)d_in[20];
    const float* b_ea = (const float*)d_in[21];
    const float* W1  = (const float*)d_in[22];
    const float* b1  = (const float*)d_in[23];
    const float* W2  = (const float*)d_in[24];
    const float* b2  = (const float*)d_in[25];
    float* out = (float*)d_out;

    float* x   = dsymf(g_x);
    float* qb_ = dsymf(g_qb);
    float* kb_ = dsymf(g_kb);
    float* vb_ = dsymf(g_vb);
    float* ob_ = dsymf(g_ob);
    float* t_  = dsymf(g_t);
    float* f_  = dsymf(g_f);
    float* ent = dsymf(g_ent);
    float* entp = dsymf(g_entp);
    float* feat = dsymf(g_feat);
    float* h_  = dsymf(g_h);

    dim3 blk(16, 16);

    gather_kernel<<<NROWS, 256>>>(q_enc, ranges);

    for (int i = 0; i < CNL; i++) {
        const float* wq = Wq + (size_t)i * CD * CHDK;
        const float* wk = Wk + (size_t)i * CD * CHDK;
        const float* wv = Wv + (size_t)i * CD * CHDK;
        const float* wo = Wo + (size_t)i * CHDK * CD;
        const float* w1 = Wf1 + (size_t)i * CD * CDFF;
        const float* w2 = Wf2 + (size_t)i * CDFF * CD;

        gemm_bias_kernel<<<dim3(CHDK / 64, NROWS / 64), blk>>>(x, wq, bq + i * CHDK, qb_, NROWS, CHDK, CD, 0);
        gemm_bias_kernel<<<dim3(CHDK / 64, NROWS / 64), blk>>>(x, wk, bk + i * CHDK, kb_, NROWS, CHDK, CD, 0);
        gemm_bias_kernel<<<dim3(CHDK / 64, NROWS / 64), blk>>>(x, wv, bv + i * CHDK, vb_, NROWS, CHDK, CD, 0);

        attn_kernel<<<NENT * CH, 128>>>();

        gemm_bias_kernel<<<dim3(CD / 64, NROWS / 64), blk>>>(ob_, wo, bo + i * CD, t_, NROWS, CD, CHDK, 0);
        add_ln_kernel<<<NROWS, 256>>>(ln1g + i * CD, ln1b + i * CD);

        gemm_bias_kernel<<<dim3(CDFF / 64, NROWS / 64), blk>>>(x, w1, bf1 + i * CDFF, f_, NROWS, CDFF, CD, 1);
        gemm_bias_kernel<<<dim3(CD / 64, NROWS / 64), blk>>>(f_, w2, bf2 + i * CD, t_, NROWS, CD, CDFF, 0);
        add_ln_kernel<<<NROWS, 256>>>(ln2g + i * CD, ln2b + i * CD);
    }

    copy_ent_kernel<<<NENT, 256>>>();
    gemm_bias_kernel<<<dim3((770 + 63) / 64, NENT / 64), blk>>>(ent, W_ea, b_ea, entp, NENT, 770, CD, 0);

    pool_attn_kernel<<<dim3(CTQ, CB), 256>>>(q_enc, hint);
    pool_wa_kernel<<<CB, 256>>>(q_qlen);

    feat_kernel<<<CB, 256>>>(q_enc);
    gemm_bias_kernel<<<dim3(CNH / 64, 1), blk>>>(feat, W1, b1, h_, CB, CNH, 2 * CD, 1);
    head_out_kernel<<<CB, 256>>>(W2, b2, out);
}

// round 4
// speedup vs baseline: 3.2359x; 3.2359x over previous
#include <cuda_runtime.h>
#include <cuda_bf16.h>
#include <math.h>
#include <stdint.h>

// ---------------- problem constants ----------------
#define CB   64
#define CS   512
#define CD   768
#define CE   32
#define CL   16
#define CTQ  128
#define CH   3
#define CDK  128
#define CHDK 384
#define CQKV 1152
#define CDFF 3072
#define CNH  1024
#define CNL  3
#define NROWS (CB*CE*CL)     // 32768
#define NENT  (CB*CE)        // 2048

// ---------------- device scratch ----------------
__device__ float          g_x  [NROWS*CD];
__device__ __nv_bfloat16  g_xh [NROWS*CD];
__device__ __nv_bfloat16  g_xl [NROWS*CD];
__device__ float          g_qkv[NROWS*CQKV];
__device__ __nv_bfloat16  g_oh [NROWS*CHDK];
__device__ __nv_bfloat16  g_ol [NROWS*CHDK];
__device__ __nv_bfloat16  g_fh [NROWS*CDFF];
__device__ __nv_bfloat16  g_fl [NROWS*CDFF];
__device__ float          g_t  [NROWS*CD];

__device__ __nv_bfloat16  g_wqkvh[CNL*CQKV*CD], g_wqkvl[CNL*CQKV*CD];
__device__ __nv_bfloat16  g_woh [CNL*CD*CHDK],  g_wol [CNL*CD*CHDK];
__device__ __nv_bfloat16  g_wf1h[CNL*CDFF*CD],  g_wf1l[CNL*CDFF*CD];
__device__ __nv_bfloat16  g_wf2h[CNL*CD*CDFF],  g_wf2l[CNL*CD*CDFF];
__device__ float          g_bqkv[CNL*CQKV];

__device__ float g_ent [NENT*CD];
__device__ float g_entp[NENT*770];
__device__ float g_attnw[CB*CTQ*CE];
__device__ float g_wa  [CB*CD];
__device__ float g_feat[CB*2*CD];
__device__ float g_h   [CB*CNH];

// ---------------- helpers ----------------
__device__ __forceinline__ uint32_t smem_u32(const void* p) {
    uint32_t a;
    asm("{ .reg .u64 t; cvta.to.shared.u64 t, %1; cvt.u32.u64 %0, t; }" : "=r"(a) : "l"(p));
    return a;
}

__device__ __forceinline__ void split_bf16(float v, __nv_bfloat16& h, __nv_bfloat16& l) {
    h = __float2bfloat16_rn(v);
    l = __float2bfloat16_rn(v - __bfloat162float(h));
}

__device__ __forceinline__ void ldmatrix_x4(uint32_t* r, uint32_t addr) {
    asm volatile("ldmatrix.sync.aligned.m8n8.x4.shared.b16 {%0,%1,%2,%3}, [%4];"
        : "=r"(r[0]), "=r"(r[1]), "=r"(r[2]), "=r"(r[3]) : "r"(addr));
}

__device__ __forceinline__ void mma16816(float* c, const uint32_t* a,
                                         uint32_t b0, uint32_t b1) {
    asm volatile("mma.sync.aligned.m16n8k16.row.col.f32.bf16.bf16.f32 "
        "{%0,%1,%2,%3}, {%4,%5,%6,%7}, {%8,%9}, {%0,%1,%2,%3};"
        : "+f"(c[0]), "+f"(c[1]), "+f"(c[2]), "+f"(c[3])
        : "r"(a[0]), "r"(a[1]), "r"(a[2]), "r"(a[3]), "r"(b0), "r"(b1));
}

// ---------------- tensor-core GEMM (mma.sync bf16, bf16-split x3) ---------
// C[M,N] = (Ah+Al)[M,K] @ (Wh+Wl)^T + bias   (W stored [N,K] K-major)
// chain: Ah*Wh, Al*Wh, Ah*Wl as one K-extended loop.
#define BK      32
#define ROWB    80                  // 32 bf16 = 64B data, padded to 80B
#define ATILE   (128*ROWB)          // 10240
#define STAGE_BYTES (2*ATILE)       // 20480
#define STAGES  4
#define SMEM_DYN (STAGES*STAGE_BYTES + 128)

__global__ __launch_bounds__(256, 1) void gemm_mma(
    const __nv_bfloat16* __restrict__ Ah, const __nv_bfloat16* __restrict__ Al,
    const __nv_bfloat16* __restrict__ Wh, const __nv_bfloat16* __restrict__ Wl,
    const float* __restrict__ bias,
    float* __restrict__ Cf,
    __nv_bfloat16* __restrict__ Chi, __nv_bfloat16* __restrict__ Clo,
    int K, int Nld, int relu)
{
    extern __shared__ char dynsmem[];
    uint32_t sbase = (smem_u32(dynsmem) + 127u) & ~127u;

    int tid  = threadIdx.x;
    int wid  = tid >> 5, lane = tid & 31;
    int wm   = wid & 3, wn = wid >> 2;           // 4 x 2 warp grid
    int m0   = blockIdx.y * 128, n0 = blockIdx.x * 128;

    const int KC = K >> 5;       // 32-elem chunks per pass
    const int NC = 3 * KC;

    auto load_chunk = [&](int cc, int buf) {
        int p = cc / KC, kc = cc - p * KC;
        const __nv_bfloat16* Ab = (p == 1) ? Al : Ah;
        const __nv_bfloat16* Wb = (p == 2) ? Wl : Wh;
        uint32_t tb = sbase + buf * STAGE_BYTES;
        #pragma unroll
        for (int i = 0; i < 2; i++) {
            int seg = tid + i * 256;             // 0..511
            int row = seg >> 2, c = seg & 3;
            uint32_t da = tb + row * ROWB + c * 16;
            const __nv_bfloat16* sa = Ab + (size_t)(m0 + row) * K + kc * 32 + c * 8;
            asm volatile("cp.async.cg.shared.global [%0], [%1], 16;" :: "r"(da), "l"(sa));
            uint32_t db = tb + ATILE + row * ROWB + c * 16;
            const __nv_bfloat16* sb = Wb + (size_t)(n0 + row) * K + kc * 32 + c * 8;
            asm volatile("cp.async.cg.shared.global [%0], [%1], 16;" :: "r"(db), "l"(sb));
        }
        asm volatile("cp.async.commit_group;" ::: "memory");
    };

    float acc[2][8][4];
    #pragma unroll
    for (int i = 0; i < 2; i++)
        #pragma unroll
        for (int j = 0; j < 8; j++)
            #pragma unroll
            for (int q = 0; q < 4; q++) acc[i][j][q] = 0.f;

    // prologue: 3 chunks in flight
    load_chunk(0, 0);
    load_chunk(1, 1);
    load_chunk(2, 2);

    // per-thread ldmatrix address components
    int lrow = lane & 15;               // smem row within 16-row group
    int lcol = (lane >> 4) << 4;        // +16B for k8..15 matrices

    for (int c = 0; c < NC; c++) {
        asm volatile("cp.async.wait_group 2;" ::: "memory");
        __syncthreads();

        uint32_t sb = sbase + (c & (STAGES - 1)) * STAGE_BYTES;

        if (c + 3 < NC) load_chunk(c + 3, (c + 3) & (STAGES - 1));
        else            asm volatile("cp.async.commit_group;" ::: "memory");

        uint32_t aAddr = sb + (uint32_t)(wm * 32 + lrow) * ROWB + lcol;
        uint32_t bAddr = sb + ATILE + (uint32_t)(wn * 64 + lrow) * ROWB + lcol;

        #pragma unroll
        for (int ks = 0; ks < 2; ks++) {
            uint32_t a[2][4], b[4][4];
            #pragma unroll
            for (int i = 0; i < 2; i++)
                ldmatrix_x4(a[i], aAddr + i * (16 * ROWB) + ks * 32);
            #pragma unroll
            for (int jj = 0; jj < 4; jj++)
                ldmatrix_x4(b[jj], bAddr + jj * (16 * ROWB) + ks * 32);
            #pragma unroll
            for (int i = 0; i < 2; i++) {
                #pragma unroll
                for (int jj = 0; jj < 4; jj++) {
                    mma16816(acc[i][2 * jj],     a[i], b[jj][0], b[jj][2]);
                    mma16816(acc[i][2 * jj + 1], a[i], b[jj][1], b[jj][3]);
                }
            }
        }
    }

    // ---------------- epilogue ----------------
    const float2* bp = (const float2*)(bias + n0 + wn * 64);
    float2 bv[8];
    #pragma unroll
    for (int j = 0; j < 8; j++) bv[j] = bp[j * 4 + (lane & 3)];

    #pragma unroll
    for (int i = 0; i < 2; i++) {
        int m_lo = m0 + wm * 32 + i * 16 + (lane >> 2);
        #pragma unroll
        for (int j = 0; j < 8; j++) {
            int n = n0 + wn * 64 + j * 8 + (lane & 3) * 2;
            float v0 = acc[i][j][0] + bv[j].x;
            float v1 = acc[i][j][1] + bv[j].y;
            float v2 = acc[i][j][2] + bv[j].x;
            float v3 = acc[i][j][3] + bv[j].y;
            if (relu) {
                v0 = fmaxf(v0, 0.f); v1 = fmaxf(v1, 0.f);
                v2 = fmaxf(v2, 0.f); v3 = fmaxf(v3, 0.f);
            }
            if (Cf) {
                *(float2*)(Cf + (size_t)m_lo * Nld + n)        = make_float2(v0, v1);
                *(float2*)(Cf + (size_t)(m_lo + 8) * Nld + n)  = make_float2(v2, v3);
            }
            if (Chi) {
                __nv_bfloat16 h0, l0, h1, l1;
                split_bf16(v0, h0, l0); split_bf16(v1, h1, l1);
                __nv_bfloat162 ph = __nv_bfloat162(h0, h1);
                __nv_bfloat162 pl = __nv_bfloat162(l0, l1);
                *(uint32_t*)(Chi + (size_t)m_lo * Nld + n) = *(uint32_t*)&ph;
                *(uint32_t*)(Clo + (size_t)m_lo * Nld + n) = *(uint32_t*)&pl;
                split_bf16(v2, h0, l0); split_bf16(v3, h1, l1);
                ph = __nv_bfloat162(h0, h1);
                pl = __nv_bfloat162(l0, l1);
                *(uint32_t*)(Chi + (size_t)(m_lo + 8) * Nld + n) = *(uint32_t*)&ph;
                *(uint32_t*)(Clo + (size_t)(m_lo + 8) * Nld + n) = *(uint32_t*)&pl;
            }
        }
    }
}

// ---------------- weight transpose + bf16 split ----------------
__global__ void wconv_kernel(const float* __restrict__ src,
                             __nv_bfloat16* __restrict__ dh,
                             __nv_bfloat16* __restrict__ dl,
                             int K, int N, int rowOff, int dstLd) {
    __shared__ float ts[32][33];
    int n0 = blockIdx.x * 32, k0 = blockIdx.y * 32;
    int tx = threadIdx.x, ty = threadIdx.y;  // 32x8
    #pragma unroll
    for (int j = 0; j < 4; j++)
        ts[ty + 8 * j][tx] = src[(size_t)(k0 + ty + 8 * j) * N + n0 + tx];
    __syncthreads();
    #pragma unroll
    for (int j = 0; j < 4; j++) {
        float v = ts[tx][ty + 8 * j];
        size_t di = (size_t)(rowOff + n0 + ty + 8 * j) * dstLd + k0 + tx;
        __nv_bfloat16 h, l;
        split_bf16(v, h, l);
        dh[di] = h; dl[di] = l;
    }
}

__global__ void bqkv_kernel(const float* __restrict__ bq,
                            const float* __restrict__ bk,
                            const float* __restrict__ bv) {
    int i = blockIdx.x;
    for (int j = threadIdx.x; j < CQKV; j += 256)
        g_bqkv[i * CQKV + j] =
            (j < CHDK) ? bq[i * CHDK + j] :
            (j < 2 * CHDK) ? bk[i * CHDK + j - CHDK] : bv[i * CHDK + j - 2 * CHDK];
}

// ---------------- gather spans into g_x (+ bf16 split) ----------------
__global__ void gather_kernel(const float* __restrict__ q_enc,
                              const int* __restrict__ ranges) {
    int row = blockIdx.x;
    int be = row >> 4, l = row & 15;
    int b = be >> 5, e = be & 31;
    int st = ranges[(b * CE + e) * 2];
    int en = ranges[(b * CE + e) * 2 + 1];
    int src = min(max(st + l, 0), CS - 1);
    bool m = l < (en - st);
    const float* s = q_enc + ((size_t)b * CS + src) * CD;
    size_t base = (size_t)row * CD;
    for (int i = threadIdx.x; i < CD; i += 256) {
        float v = m ? s[i] : 0.f;
        g_x[base + i] = v;
        __nv_bfloat16 h, lo; split_bf16(v, h, lo);
        g_xh[base + i] = h; g_xl[base + i] = lo;
    }
}

// ---------------- fp32 SIMT GEMM (small tail matrices) ----------------
__global__ void gemm_bias_kernel(const float* __restrict__ A,
                                 const float* __restrict__ W,
                                 const float* __restrict__ bias,
                                 float* __restrict__ C,
                                 int M, int N, int K, int relu) {
    __shared__ float As[16][65];
    __shared__ float Bs[16][68];
    int tx = threadIdx.x, ty = threadIdx.y;
    int tid = ty * 16 + tx;
    int m0 = blockIdx.y * 64, n0 = blockIdx.x * 64;
    int a_row = tid >> 2, a_col = (tid & 3) << 2;
    int b_row = tid >> 4, b_col = (tid & 15) << 2;
    float acc[4][4] = {};
    for (int k0 = 0; k0 < K; k0 += 16) {
        int m = m0 + a_row;
        #pragma unroll
        for (int i = 0; i < 4; i++) {
            float v = 0.f;
            if (m < M) v = A[(size_t)m * K + k0 + a_col + i];
            As[a_col + i][a_row] = v;
        }
        #pragma unroll
        for (int i = 0; i < 4; i++) {
            int n = n0 + b_col + i;
            float v = 0.f;
            if (n < N) v = W[(size_t)(k0 + b_row) * N + n];
            Bs[b_row][b_col + i] = v;
        }
        __syncthreads();
        #pragma unroll
        for (int kk = 0; kk < 16; kk++) {
            float ra[4], rb[4];
            #pragma unroll
            for (int i = 0; i < 4; i++) ra[i] = As[kk][ty * 4 + i];
            #pragma unroll
            for (int j = 0; j < 4; j++) rb[j] = Bs[kk][tx * 4 + j];
            #pragma unroll
            for (int i = 0; i < 4; i++)
                #pragma unroll
                for (int j = 0; j < 4; j++)
                    acc[i][j] += ra[i] * rb[j];
        }
        __syncthreads();
    }
    #pragma unroll
    for (int i = 0; i < 4; i++) {
        int m = m0 + ty * 4 + i;
        if (m >= M) continue;
        #pragma unroll
        for (int j = 0; j < 4; j++) {
            int n = n0 + tx * 4 + j;
            if (n >= N) continue;
            float v = acc[i][j] + bias[n];
            if (relu) v = fmaxf(v, 0.f);
            C[(size_t)m * N + n] = v;
        }
    }
}

// ---------------- per-(span,head) attention ----------------
__global__ void attn_kernel() {
    int nh = blockIdx.x;
    int n = nh / CH, h = nh % CH;
    __shared__ float qs[16][129], ks[16][129], vs[16][129];
    __shared__ float sc[16][17];
    int tid = threadIdx.x;  // 128
    for (int idx = tid; idx < 16 * 128; idx += 128) {
        int l = idx >> 7, d = idx & 127;
        size_t base = ((size_t)(n * CL + l)) * CQKV + h * CDK + d;
        qs[l][d] = g_qkv[base];
        ks[l][d] = g_qkv[base + CHDK];
        vs[l][d] = g_qkv[base + 2 * CHDK];
    }
    __syncthreads();
    const float scale = 0.088388347648318447f;
    for (int p = tid; p < 256; p += 128) {
        int qi = p >> 4, ki = p & 15;
        float s = 0.f;
        #pragma unroll
        for (int d = 0; d < 128; d++) s += qs[qi][d] * ks[ki][d];
        sc[qi][ki] = s * scale;
    }
    __syncthreads();
    if (tid < 16) {
        float m = -1e30f;
        #pragma unroll
        for (int k = 0; k < 16; k++) m = fmaxf(m, sc[tid][k]);
        float sum = 0.f;
        #pragma unroll
        for (int k = 0; k < 16; k++) { float e = __expf(sc[tid][k] - m); sc[tid][k] = e; sum += e; }
        float inv = 1.f / sum;
        #pragma unroll
        for (int k = 0; k < 16; k++) sc[tid][k] *= inv;
    }
    __syncthreads();
    int d = tid;
    #pragma unroll
    for (int qi = 0; qi < 16; qi++) {
        float acc = 0.f;
        #pragma unroll
        for (int k = 0; k < 16; k++) acc += sc[qi][k] * vs[k][d];
        size_t oi = ((size_t)(n * CL + qi)) * CHDK + h * CDK + d;
        __nv_bfloat16 hh, ll; split_bf16(acc, hh, ll);
        g_oh[oi] = hh; g_ol[oi] = ll;
    }
}

// ---------------- x = LN(x + t) (+ bf16 split) ----------------
__device__ __forceinline__ float blockReduceSum(float val) {
    __shared__ float sh[32];
    int lane = threadIdx.x & 31, wid = threadIdx.x >> 5;
    #pragma unroll
    for (int o = 16; o > 0; o >>= 1) val += __shfl_xor_sync(0xffffffffu, val, o);
    if (lane == 0) sh[wid] = val;
    __syncthreads();
    int nw = (blockDim.x + 31) >> 5;
    val = (threadIdx.x < nw) ? sh[lane] : 0.f;
    if (wid == 0) {
        #pragma unroll
        for (int o = 16; o > 0; o >>= 1) val += __shfl_xor_sync(0xffffffffu, val, o);
    }
    return val;
}

__global__ void add_ln_kernel(const float* __restrict__ gamma,
                              const float* __restrict__ beta) {
    int row = blockIdx.x;
    int tid = threadIdx.x;
    float v[3];
    float s = 0.f;
    #pragma unroll
    for (int j = 0; j < 3; j++) {
        size_t idx = (size_t)row * CD + tid + j * 256;
        v[j] = g_x[idx] + g_t[idx];
        s += v[j];
    }
    s = blockReduceSum(s);
    __shared__ float mean_s, rstd_s;
    if (tid == 0) mean_s = s * (1.f / CD);
    __syncthreads();
    float m = mean_s;
    float vv = 0.f;
    #pragma unroll
    for (int j = 0; j < 3; j++) { float d = v[j] - m; vv += d * d; }
    vv = blockReduceSum(vv);
    if (tid == 0) rstd_s = rsqrtf(vv * (1.f / CD) + 1e-5f);
    __syncthreads();
    float r = rstd_s;
    #pragma unroll
    for (int j = 0; j < 3; j++) {
        int c = tid + j * 256;
        float o = (v[j] - m) * r * gamma[c] + beta[c];
        size_t idx = (size_t)row * CD + c;
        g_x[idx] = o;
        __nv_bfloat16 h, l; split_bf16(o, h, l);
        g_xh[idx] = h; g_xl[idx] = l;
    }
}

// ---------------- tail kernels ----------------
__global__ void copy_ent_kernel() {
    int r = blockIdx.x;
    for (int d = threadIdx.x; d < CD; d += 256)
        g_ent[(size_t)r * CD + d] = g_x[(size_t)r * CL * CD + d];
}

__global__ void pool_attn_kernel(const float* __restrict__ q_enc,
                                 const float* __restrict__ hint) {
    int t = blockIdx.x, b = blockIdx.y;
    __shared__ float qv[770];
    __shared__ float lg[32];
    int tid = threadIdx.x;
    for (int i = tid; i < 770; i += 256)
        qv[i] = (i < CD) ? q_enc[((size_t)b * CS + t) * CD + i]
                         : hint[((size_t)b * CTQ + t) * 2 + (i - CD)];
    __syncthreads();
    int e = tid >> 3, sub = tid & 7;
    const float* ep = g_entp + ((size_t)b * CE + e) * 770;
    float p = 0.f;
    for (int d = sub; d < 770; d += 8) p += qv[d] * ep[d];
    p += __shfl_down_sync(0xffffffffu, p, 4, 8);
    p += __shfl_down_sync(0xffffffffu, p, 2, 8);
    p += __shfl_down_sync(0xffffffffu, p, 1, 8);
    if (sub == 0) lg[e] = p;
    __syncthreads();
    if (tid < 32) {
        float v = lg[tid];
        float m = v;
        #pragma unroll
        for (int o = 16; o > 0; o >>= 1) m = fmaxf(m, __shfl_xor_sync(0xffffffffu, m, o));
        float ex = __expf(v - m);
        float sm = ex;
        #pragma unroll
        for (int o = 16; o > 0; o >>= 1) sm += __shfl_xor_sync(0xffffffffu, sm, o);
        g_attnw[((size_t)b * CTQ + t) * CE + tid] = ex / sm;
    }
}

__global__ void pool_wa_kernel(const int* __restrict__ qlen) {
    int b = blockIdx.x;
    int tid = threadIdx.x;
    __shared__ float A[32];
    int n = qlen[b];
    if (tid < 32) {
        float s = 0.f;
        for (int t = 0; t < n; t++) s += g_attnw[((size_t)b * CTQ + t) * CE + tid];
        A[tid] = s;
    }
    __syncthreads();
    #pragma unroll
    for (int j = 0; j < 3; j++) {
        int d = tid + j * 256;
        float s = 0.f;
        #pragma unroll
        for (int e = 0; e < 32; e++) s += A[e] * g_ent[((size_t)b * CE + e) * CD + d];
        g_wa[(size_t)b * CD + d] = s;
    }
}

__global__ void feat_kernel(const float* __restrict__ q_enc) {
    int b = blockIdx.x;
    for (int i = threadIdx.x; i < 2 * CD; i += 256)
        g_feat[(size_t)b * 2 * CD + i] =
            (i < CD) ? q_enc[(size_t)b * CS * CD + i] : g_wa[(size_t)b * CD + (i - CD)];
}

__global__ void head_out_kernel(const float* __restrict__ W2,
                                const float* __restrict__ b2,
                                float* __restrict__ out) {
    int b = blockIdx.x, tid = threadIdx.x;
    float s = 0.f;
    for (int n = tid; n < CNH; n += 256) s += g_h[(size_t)b * CNH + n] * W2[n];
    s = blockReduceSum(s);
    if (tid == 0) out[b] = s + b2[0];
}

// ---------------- host ----------------
template <typename T>
static T* dsym(const void* symbol) {
    void* p = nullptr;
    cudaGetSymbolAddress(&p, symbol);
    return (T*)p;
}

extern "C" void kernel_launch(void* const* d_in, const int* in_sizes, int n_in,
                              void* d_out, int out_size) {
    const float* q_enc  = (const float*)d_in[0];
    const int*   q_qlen = (const int*)  d_in[1];
    const float* hint   = (const float*)d_in[2];
    const int*   ranges = (const int*)  d_in[3];
    const float* Wq  = (const float*)d_in[4];
    const float* bq  = (const float*)d_in[5];
    const float* Wk  = (const float*)d_in[6];
    const float* bk  = (const float*)d_in[7];
    const float* Wv  = (const float*)d_in[8];
    const float* bv  = (const float*)d_in[9];
    const float* Wo  = (const float*)d_in[10];
    const float* bo  = (const float*)d_in[11];
    const float* ln1g = (const float*)d_in[12];
    const float* ln1b = (const float*)d_in[13];
    const float* Wf1 = (const float*)d_in[14];
    const float* bf1 = (const float*)d_in[15];
    const float* Wf2 = (const float*)d_in[16];
    const float* bf2 = (const float*)d_in[17];
    const float* ln2g = (const float*)d_in[18];
    const float* ln2b = (const float*)d_in[19];
    const float* W_ea = (const float*)d_in[20];
    const float* b_ea = (const float*)d_in[21];
    const float* W1  = (const float*)d_in[22];
    const float* b1  = (const float*)d_in[23];
    const float* W2  = (const float*)d_in[24];
    const float* b2  = (const float*)d_in[25];
    float* out = (float*)d_out;

    cudaFuncSetAttribute(gemm_mma, cudaFuncAttributeMaxDynamicSharedMemorySize, SMEM_DYN);

    __nv_bfloat16* xh  = dsym<__nv_bfloat16>(g_xh);
    __nv_bfloat16* xl  = dsym<__nv_bfloat16>(g_xl);
    __nv_bfloat16* oh  = dsym<__nv_bfloat16>(g_oh);
    __nv_bfloat16* ol  = dsym<__nv_bfloat16>(g_ol);
    __nv_bfloat16* fh  = dsym<__nv_bfloat16>(g_fh);
    __nv_bfloat16* fl  = dsym<__nv_bfloat16>(g_fl);
    float* qkv = dsym<float>(g_qkv);
    float* t_  = dsym<float>(g_t);
    __nv_bfloat16* wqkvh = dsym<__nv_bfloat16>(g_wqkvh);
    __nv_bfloat16* wqkvl = dsym<__nv_bfloat16>(g_wqkvl);
    __nv_bfloat16* woh   = dsym<__nv_bfloat16>(g_woh);
    __nv_bfloat16* wol   = dsym<__nv_bfloat16>(g_wol);
    __nv_bfloat16* wf1h  = dsym<__nv_bfloat16>(g_wf1h);
    __nv_bfloat16* wf1l  = dsym<__nv_bfloat16>(g_wf1l);
    __nv_bfloat16* wf2h  = dsym<__nv_bfloat16>(g_wf2h);
    __nv_bfloat16* wf2l  = dsym<__nv_bfloat16>(g_wf2l);
    float* bqkv = dsym<float>(g_bqkv);
    float* x    = dsym<float>(g_x);
    float* ent  = dsym<float>(g_ent);
    float* entp = dsym<float>(g_entp);
    float* feat = dsym<float>(g_feat);
    float* h_   = dsym<float>(g_h);

    dim3 wblk(32, 8);
    for (int i = 0; i < CNL; i++) {
        size_t oQ = (size_t)i * CQKV * CD;
        wconv_kernel<<<dim3(CHDK/32, CD/32), wblk>>>(Wq + (size_t)i*CD*CHDK, wqkvh + oQ, wqkvl + oQ, CD, CHDK, 0,      CD);
        wconv_kernel<<<dim3(CHDK/32, CD/32), wblk>>>(Wk + (size_t)i*CD*CHDK, wqkvh + oQ, wqkvl + oQ, CD, CHDK, CHDK,   CD);
        wconv_kernel<<<dim3(CHDK/32, CD/32), wblk>>>(Wv + (size_t)i*CD*CHDK, wqkvh + oQ, wqkvl + oQ, CD, CHDK, 2*CHDK, CD);
        size_t oO = (size_t)i * CD * CHDK;
        wconv_kernel<<<dim3(CD/32, CHDK/32), wblk>>>(Wo + (size_t)i*CHDK*CD, woh + oO, wol + oO, CHDK, CD, 0, CHDK);
        size_t oF1 = (size_t)i * CDFF * CD;
        wconv_kernel<<<dim3(CDFF/32, CD/32), wblk>>>(Wf1 + (size_t)i*CD*CDFF, wf1h + oF1, wf1l + oF1, CD, CDFF, 0, CD);
        size_t oF2 = (size_t)i * CD * CDFF;
        wconv_kernel<<<dim3(CD/32, CDFF/32), wblk>>>(Wf2 + (size_t)i*CDFF*CD, wf2h + oF2, wf2l + oF2, CDFF, CD, 0, CDFF);
    }
    bqkv_kernel<<<CNL, 256>>>(bq, bk, bv);

    gather_kernel<<<NROWS, 256>>>(q_enc, ranges);

    for (int i = 0; i < CNL; i++) {
        size_t oQ  = (size_t)i * CQKV * CD;
        size_t oO  = (size_t)i * CD * CHDK;
        size_t oF1 = (size_t)i * CDFF * CD;
        size_t oF2 = (size_t)i * CD * CDFF;

        gemm_mma<<<dim3(CQKV/128, NROWS/128), 256, SMEM_DYN>>>(
            xh, xl, wqkvh + oQ, wqkvl + oQ, bqkv + i*CQKV,
            qkv, nullptr, nullptr, CD, CQKV, 0);

        attn_kernel<<<NENT * CH, 128>>>();

        gemm_mma<<<dim3(CD/128, NROWS/128), 256, SMEM_DYN>>>(
            oh, ol, woh + oO, wol + oO, bo + i*CD,
            t_, nullptr, nullptr, CHDK, CD, 0);

        add_ln_kernel<<<NROWS, 256>>>(ln1g + i*CD, ln1b + i*CD);

        gemm_mma<<<dim3(CDFF/128, NROWS/128), 256, SMEM_DYN>>>(
            xh, xl, wf1h + oF1, wf1l + oF1, bf1 + i*CDFF,
            nullptr, fh, fl, CD, CDFF, 1);

        gemm_mma<<<dim3(CD/128, NROWS/128), 256, SMEM_DYN>>>(
            fh, fl, wf2h + oF2, wf2l + oF2, bf2 + i*CD,
            t_, nullptr, nullptr, CDFF, CD, 0);

        add_ln_kernel<<<NROWS, 256>>>(ln2g + i*CD, ln2b + i*CD);
    }

    dim3 blk(16, 16);
    copy_ent_kernel<<<NENT, 256>>>();
    gemm_bias_kernel<<<dim3((770 + 63) / 64, NENT / 64), blk>>>(ent, W_ea, b_ea, entp, NENT, 770, CD, 0);
    pool_attn_kernel<<<dim3(CTQ, CB), 256>>>(q_enc, hint);
    pool_wa_kernel<<<CB, 256>>>(q_qlen);
    feat_kernel<<<CB, 256>>>(q_enc);
    gemm_bias_kernel<<<dim3(CNH / 64, 1), blk>>>(feat, W1, b1, h_, CB, CNH, 2 * CD, 1);
    head_out_kernel<<<CB, 256>>>(W2, b2, out);
}

// round 5
// speedup vs baseline: 3.2962x; 1.0187x over previous
#include <cuda_runtime.h>
#include <cuda_bf16.h>
#include <math.h>
#include <stdint.h>

// ---------------- problem constants ----------------
#define CB   64
#define CS   512
#define CD   768
#define CE   32
#define CL   16
#define CTQ  128
#define CH   3
#define CDK  128
#define CHDK 384
#define CQKV 1152
#define CDFF 3072
#define CNH  1024
#define CNL  3
#define NROWS (CB*CE*CL)     // 32768
#define NENT  (CB*CE)        // 2048

// ---------------- device scratch ----------------
__device__ float          g_x  [NROWS*CD];
__device__ __nv_bfloat16  g_xh [NROWS*CD];
__device__ __nv_bfloat16  g_xl [NROWS*CD];
__device__ float          g_qkv[NROWS*CQKV];
__device__ __nv_bfloat16  g_oh [NROWS*CHDK];
__device__ __nv_bfloat16  g_ol [NROWS*CHDK];
__device__ __nv_bfloat16  g_fh [NROWS*CDFF];
__device__ __nv_bfloat16  g_fl [NROWS*CDFF];
__device__ float          g_t  [NROWS*CD];

__device__ __nv_bfloat16  g_wqkvh[CNL*CQKV*CD], g_wqkvl[CNL*CQKV*CD];
__device__ __nv_bfloat16  g_woh [CNL*CD*CHDK],  g_wol [CNL*CD*CHDK];
__device__ __nv_bfloat16  g_wf1h[CNL*CDFF*CD],  g_wf1l[CNL*CDFF*CD];
__device__ __nv_bfloat16  g_wf2h[CNL*CD*CDFF],  g_wf2l[CNL*CD*CDFF];
__device__ float          g_bqkv[CNL*CQKV];

__device__ float g_ent [NENT*CD];
__device__ float g_entp[NENT*770];
__device__ float g_attnw[CB*CTQ*CE];
__device__ float g_wa  [CB*CD];
__device__ float g_feat[CB*2*CD];
__device__ float g_h   [CB*CNH];

// ---------------- helpers ----------------
__device__ __forceinline__ uint32_t smem_u32(const void* p) {
    uint32_t a;
    asm("{ .reg .u64 t; cvta.to.shared.u64 t, %1; cvt.u32.u64 %0, t; }" : "=r"(a) : "l"(p));
    return a;
}

__device__ __forceinline__ void split_bf16(float v, __nv_bfloat16& h, __nv_bfloat16& l) {
    h = __float2bfloat16_rn(v);
    l = __float2bfloat16_rn(v - __bfloat162float(h));
}

__device__ __forceinline__ void ldmatrix_x4(uint32_t* r, uint32_t addr) {
    asm volatile("ldmatrix.sync.aligned.m8n8.x4.shared.b16 {%0,%1,%2,%3}, [%4];"
        : "=r"(r[0]), "=r"(r[1]), "=r"(r[2]), "=r"(r[3]) : "r"(addr));
}

__device__ __forceinline__ void mma16816(float* c, const uint32_t* a,
                                         uint32_t b0, uint32_t b1) {
    asm volatile("mma.sync.aligned.m16n8k16.row.col.f32.bf16.bf16.f32 "
        "{%0,%1,%2,%3}, {%4,%5,%6,%7}, {%8,%9}, {%0,%1,%2,%3};"
        : "+f"(c[0]), "+f"(c[1]), "+f"(c[2]), "+f"(c[3])
        : "r"(a[0]), "r"(a[1]), "r"(a[2]), "r"(a[3]), "r"(b0), "r"(b1));
}

// ---------------- tensor-core GEMM (mma.sync bf16, fused 3-term split) ----
// C[M,N] = (Ah+Al)[M,K] @ (Wh+Wl)^T + bias   (W stored [N,K] K-major)
// Per K-chunk (32): load Ah,Al,Wh,Wl once; acc += AhWh + AlWh + AhWl.
#define ROWB    80                  // 32 bf16 = 64B data, padded to 80B
#define TTILE   (128*ROWB)          // 10240 per tile
#define STAGE_BYTES (4*TTILE)       // 40960: Ah|Al|Wh|Wl
#define STAGES  3
#define SMEM_DYN (STAGES*STAGE_BYTES + 128)

__global__ __launch_bounds__(256, 1) void gemm_mma(
    const __nv_bfloat16* __restrict__ Ah, const __nv_bfloat16* __restrict__ Al,
    const __nv_bfloat16* __restrict__ Wh, const __nv_bfloat16* __restrict__ Wl,
    const float* __restrict__ bias,
    float* __restrict__ Cf,
    __nv_bfloat16* __restrict__ Chi, __nv_bfloat16* __restrict__ Clo,
    int K, int Nld, int relu)
{
    extern __shared__ char dynsmem[];
    uint32_t sbase = (smem_u32(dynsmem) + 127u) & ~127u;

    int tid  = threadIdx.x;
    int wid  = tid >> 5, lane = tid & 31;
    int wm   = wid & 3, wn = wid >> 2;           // 4 x 2 warp grid
    int m0   = blockIdx.y * 128, n0 = blockIdx.x * 128;

    const int NC = K >> 5;       // 32-elem chunks

    auto load_chunk = [&](int kc, int buf) {
        uint32_t tb = sbase + buf * STAGE_BYTES;
        #pragma unroll
        for (int i = 0; i < 8; i++) {
            int seg  = tid + i * 256;            // 0..2047
            int tile = seg >> 9;                 // 0:Ah 1:Al 2:Wh 3:Wl
            int row  = (seg >> 2) & 127;
            int c    = seg & 3;
            uint32_t dst = tb + tile * TTILE + row * ROWB + c * 16;
            const __nv_bfloat16* src;
            if (tile == 0)      src = Ah + (size_t)(m0 + row) * K + kc * 32 + c * 8;
            else if (tile == 1) src = Al + (size_t)(m0 + row) * K + kc * 32 + c * 8;
            else if (tile == 2) src = Wh + (size_t)(n0 + row) * K + kc * 32 + c * 8;
            else                src = Wl + (size_t)(n0 + row) * K + kc * 32 + c * 8;
            asm volatile("cp.async.cg.shared.global [%0], [%1], 16;" :: "r"(dst), "l"(src));
        }
        asm volatile("cp.async.commit_group;" ::: "memory");
    };

    float acc[2][8][4];
    #pragma unroll
    for (int i = 0; i < 2; i++)
        #pragma unroll
        for (int j = 0; j < 8; j++)
            #pragma unroll
            for (int q = 0; q < 4; q++) acc[i][j][q] = 0.f;

    // prologue: 2 chunks in flight
    load_chunk(0, 0);
    if (NC > 1) load_chunk(1, 1);

    int lrow = lane & 15;               // smem row within 16-row group
    int lcol = (lane >> 4) << 4;        // +16B for k8..15 matrices

    for (int c = 0; c < NC; c++) {
        if (c < NC - 1) asm volatile("cp.async.wait_group 1;" ::: "memory");
        else            asm volatile("cp.async.wait_group 0;" ::: "memory");
        __syncthreads();

        uint32_t sb = sbase + (c % STAGES) * STAGE_BYTES;

        if (c + 2 < NC) load_chunk(c + 2, (c + 2) % STAGES);

        uint32_t aAddr = sb + (uint32_t)(wm * 32 + lrow) * ROWB + lcol;
        uint32_t bAddr = sb + 2 * TTILE + (uint32_t)(wn * 64 + lrow) * ROWB + lcol;

        #pragma unroll
        for (int ks = 0; ks < 2; ks++) {
            uint32_t ah[2][4], al[2][4], bh[4][4], bl[4][4];
            #pragma unroll
            for (int i = 0; i < 2; i++) {
                ldmatrix_x4(ah[i], aAddr + i * (16 * ROWB) + ks * 32);
                ldmatrix_x4(al[i], aAddr + TTILE + i * (16 * ROWB) + ks * 32);
            }
            #pragma unroll
            for (int jj = 0; jj < 4; jj++) {
                ldmatrix_x4(bh[jj], bAddr + jj * (16 * ROWB) + ks * 32);
                ldmatrix_x4(bl[jj], bAddr + TTILE + jj * (16 * ROWB) + ks * 32);
            }
            #pragma unroll
            for (int i = 0; i < 2; i++) {
                #pragma unroll
                for (int jj = 0; jj < 4; jj++) {
                    mma16816(acc[i][2 * jj],     ah[i], bh[jj][0], bh[jj][2]);
                    mma16816(acc[i][2 * jj + 1], ah[i], bh[jj][1], bh[jj][3]);
                    mma16816(acc[i][2 * jj],     al[i], bh[jj][0], bh[jj][2]);
                    mma16816(acc[i][2 * jj + 1], al[i], bh[jj][1], bh[jj][3]);
                    mma16816(acc[i][2 * jj],     ah[i], bl[jj][0], bl[jj][2]);
                    mma16816(acc[i][2 * jj + 1], ah[i], bl[jj][1], bl[jj][3]);
                }
            }
        }
    }

    // ---------------- epilogue ----------------
    const float2* bp = (const float2*)(bias + n0 + wn * 64);
    float2 bv[8];
    #pragma unroll
    for (int j = 0; j < 8; j++) bv[j] = bp[j * 4 + (lane & 3)];

    #pragma unroll
    for (int i = 0; i < 2; i++) {
        int m_lo = m0 + wm * 32 + i * 16 + (lane >> 2);
        #pragma unroll
        for (int j = 0; j < 8; j++) {
            int n = n0 + wn * 64 + j * 8 + (lane & 3) * 2;
            float v0 = acc[i][j][0] + bv[j].x;
            float v1 = acc[i][j][1] + bv[j].y;
            float v2 = acc[i][j][2] + bv[j].x;
            float v3 = acc[i][j][3] + bv[j].y;
            if (relu) {
                v0 = fmaxf(v0, 0.f); v1 = fmaxf(v1, 0.f);
                v2 = fmaxf(v2, 0.f); v3 = fmaxf(v3, 0.f);
            }
            if (Cf) {
                *(float2*)(Cf + (size_t)m_lo * Nld + n)        = make_float2(v0, v1);
                *(float2*)(Cf + (size_t)(m_lo + 8) * Nld + n)  = make_float2(v2, v3);
            }
            if (Chi) {
                __nv_bfloat16 h0, l0, h1, l1;
                split_bf16(v0, h0, l0); split_bf16(v1, h1, l1);
                __nv_bfloat162 ph = __nv_bfloat162(h0, h1);
                __nv_bfloat162 pl = __nv_bfloat162(l0, l1);
                *(uint32_t*)(Chi + (size_t)m_lo * Nld + n) = *(uint32_t*)&ph;
                *(uint32_t*)(Clo + (size_t)m_lo * Nld + n) = *(uint32_t*)&pl;
                split_bf16(v2, h0, l0); split_bf16(v3, h1, l1);
                ph = __nv_bfloat162(h0, h1);
                pl = __nv_bfloat162(l0, l1);
                *(uint32_t*)(Chi + (size_t)(m_lo + 8) * Nld + n) = *(uint32_t*)&ph;
                *(uint32_t*)(Clo + (size_t)(m_lo + 8) * Nld + n) = *(uint32_t*)&pl;
            }
        }
    }
}

// ---------------- weight transpose + bf16 split ----------------
__global__ void wconv_kernel(const float* __restrict__ src,
                             __nv_bfloat16* __restrict__ dh,
                             __nv_bfloat16* __restrict__ dl,
                             int K, int N, int rowOff, int dstLd) {
    __shared__ float ts[32][33];
    int n0 = blockIdx.x * 32, k0 = blockIdx.y * 32;
    int tx = threadIdx.x, ty = threadIdx.y;  // 32x8
    #pragma unroll
    for (int j = 0; j < 4; j++)
        ts[ty + 8 * j][tx] = src[(size_t)(k0 + ty + 8 * j) * N + n0 + tx];
    __syncthreads();
    #pragma unroll
    for (int j = 0; j < 4; j++) {
        float v = ts[tx][ty + 8 * j];
        size_t di = (size_t)(rowOff + n0 + ty + 8 * j) * dstLd + k0 + tx;
        __nv_bfloat16 h, l;
        split_bf16(v, h, l);
        dh[di] = h; dl[di] = l;
    }
}

__global__ void bqkv_kernel(const float* __restrict__ bq,
                            const float* __restrict__ bk,
                            const float* __restrict__ bv) {
    int i = blockIdx.x;
    for (int j = threadIdx.x; j < CQKV; j += 256)
        g_bqkv[i * CQKV + j] =
            (j < CHDK) ? bq[i * CHDK + j] :
            (j < 2 * CHDK) ? bk[i * CHDK + j - CHDK] : bv[i * CHDK + j - 2 * CHDK];
}

// ---------------- gather spans into g_x (+ bf16 split) ----------------
__global__ void gather_kernel(const float* __restrict__ q_enc,
                              const int* __restrict__ ranges) {
    int row = blockIdx.x;
    int be = row >> 4, l = row & 15;
    int b = be >> 5, e = be & 31;
    int st = ranges[(b * CE + e) * 2];
    int en = ranges[(b * CE + e) * 2 + 1];
    int src = min(max(st + l, 0), CS - 1);
    bool m = l < (en - st);
    const float* s = q_enc + ((size_t)b * CS + src) * CD;
    size_t base = (size_t)row * CD;
    for (int i = threadIdx.x; i < CD; i += 256) {
        float v = m ? s[i] : 0.f;
        g_x[base + i] = v;
        __nv_bfloat16 h, lo; split_bf16(v, h, lo);
        g_xh[base + i] = h; g_xl[base + i] = lo;
    }
}

// ---------------- fp32 SIMT GEMM (small tail matrices) ----------------
__global__ void gemm_bias_kernel(const float* __restrict__ A,
                                 const float* __restrict__ W,
                                 const float* __restrict__ bias,
                                 float* __restrict__ C,
                                 int M, int N, int K, int relu) {
    __shared__ float As[16][65];
    __shared__ float Bs[16][68];
    int tx = threadIdx.x, ty = threadIdx.y;
    int tid = ty * 16 + tx;
    int m0 = blockIdx.y * 64, n0 = blockIdx.x * 64;
    int a_row = tid >> 2, a_col = (tid & 3) << 2;
    int b_row = tid >> 4, b_col = (tid & 15) << 2;
    float acc[4][4] = {};
    for (int k0 = 0; k0 < K; k0 += 16) {
        int m = m0 + a_row;
        #pragma unroll
        for (int i = 0; i < 4; i++) {
            float v = 0.f;
            if (m < M) v = A[(size_t)m * K + k0 + a_col + i];
            As[a_col + i][a_row] = v;
        }
        #pragma unroll
        for (int i = 0; i < 4; i++) {
            int n = n0 + b_col + i;
            float v = 0.f;
            if (n < N) v = W[(size_t)(k0 + b_row) * N + n];
            Bs[b_row][b_col + i] = v;
        }
        __syncthreads();
        #pragma unroll
        for (int kk = 0; kk < 16; kk++) {
            float ra[4], rb[4];
            #pragma unroll
            for (int i = 0; i < 4; i++) ra[i] = As[kk][ty * 4 + i];
            #pragma unroll
            for (int j = 0; j < 4; j++) rb[j] = Bs[kk][tx * 4 + j];
            #pragma unroll
            for (int i = 0; i < 4; i++)
                #pragma unroll
                for (int j = 0; j < 4; j++)
                    acc[i][j] += ra[i] * rb[j];
        }
        __syncthreads();
    }
    #pragma unroll
    for (int i = 0; i < 4; i++) {
        int m = m0 + ty * 4 + i;
        if (m >= M) continue;
        #pragma unroll
        for (int j = 0; j < 4; j++) {
            int n = n0 + tx * 4 + j;
            if (n >= N) continue;
            float v = acc[i][j] + bias[n];
            if (relu) v = fmaxf(v, 0.f);
            C[(size_t)m * N + n] = v;
        }
    }
}

// ---------------- per-(span,head) attention ----------------
__global__ void attn_kernel() {
    int nh = blockIdx.x;
    int n = nh / CH, h = nh % CH;
    __shared__ float qs[16][129], ks[16][129], vs[16][129];
    __shared__ float sc[16][17];
    int tid = threadIdx.x;  // 128
    for (int idx = tid; idx < 16 * 128; idx += 128) {
        int l = idx >> 7, d = idx & 127;
        size_t base = ((size_t)(n * CL + l)) * CQKV + h * CDK + d;
        qs[l][d] = g_qkv[base];
        ks[l][d] = g_qkv[base + CHDK];
        vs[l][d] = g_qkv[base + 2 * CHDK];
    }
    __syncthreads();
    const float scale = 0.088388347648318447f;
    for (int p = tid; p < 256; p += 128) {
        int qi = p >> 4, ki = p & 15;
        float s = 0.f;
        #pragma unroll
        for (int d = 0; d < 128; d++) s += qs[qi][d] * ks[ki][d];
        sc[qi][ki] = s * scale;
    }
    __syncthreads();
    if (tid < 16) {
        float m = -1e30f;
        #pragma unroll
        for (int k = 0; k < 16; k++) m = fmaxf(m, sc[tid][k]);
        float sum = 0.f;
        #pragma unroll
        for (int k = 0; k < 16; k++) { float e = __expf(sc[tid][k] - m); sc[tid][k] = e; sum += e; }
        float inv = 1.f / sum;
        #pragma unroll
        for (int k = 0; k < 16; k++) sc[tid][k] *= inv;
    }
    __syncthreads();
    int d = tid;
    #pragma unroll
    for (int qi = 0; qi < 16; qi++) {
        float acc = 0.f;
        #pragma unroll
        for (int k = 0; k < 16; k++) acc += sc[qi][k] * vs[k][d];
        size_t oi = ((size_t)(n * CL + qi)) * CHDK + h * CDK + d;
        __nv_bfloat16 hh, ll; split_bf16(acc, hh, ll);
        g_oh[oi] = hh; g_ol[oi] = ll;
    }
}

// ---------------- x = LN(x + t) (+ bf16 split) ----------------
__device__ __forceinline__ float blockReduceSum(float val) {
    __shared__ float sh[32];
    int lane = threadIdx.x & 31, wid = threadIdx.x >> 5;
    #pragma unroll
    for (int o = 16; o > 0; o >>= 1) val += __shfl_xor_sync(0xffffffffu, val, o);
    if (lane == 0) sh[wid] = val;
    __syncthreads();
    int nw = (blockDim.x + 31) >> 5;
    val = (threadIdx.x < nw) ? sh[lane] : 0.f;
    if (wid == 0) {
        #pragma unroll
        for (int o = 16; o > 0; o >>= 1) val += __shfl_xor_sync(0xffffffffu, val, o);
    }
    return val;
}

__global__ void add_ln_kernel(const float* __restrict__ gamma,
                              const float* __restrict__ beta) {
    int row = blockIdx.x;
    int tid = threadIdx.x;
    float v[3];
    float s = 0.f;
    #pragma unroll
    for (int j = 0; j < 3; j++) {
        size_t idx = (size_t)row * CD + tid + j * 256;
        v[j] = g_x[idx] + g_t[idx];
        s += v[j];
    }
    s = blockReduceSum(s);
    __shared__ float mean_s, rstd_s;
    if (tid == 0) mean_s = s * (1.f / CD);
    __syncthreads();
    float m = mean_s;
    float vv = 0.f;
    #pragma unroll
    for (int j = 0; j < 3; j++) { float d = v[j] - m; vv += d * d; }
    vv = blockReduceSum(vv);
    if (tid == 0) rstd_s = rsqrtf(vv * (1.f / CD) + 1e-5f);
    __syncthreads();
    float r = rstd_s;
    #pragma unroll
    for (int j = 0; j < 3; j++) {
        int c = tid + j * 256;
        float o = (v[j] - m) * r * gamma[c] + beta[c];
        size_t idx = (size_t)row * CD + c;
        g_x[idx] = o;
        __nv_bfloat16 h, l; split_bf16(o, h, l);
        g_xh[idx] = h; g_xl[idx] = l;
    }
}

// ---------------- tail kernels ----------------
__global__ void copy_ent_kernel() {
    int r = blockIdx.x;
    for (int d = threadIdx.x; d < CD; d += 256)
        g_ent[(size_t)r * CD + d] = g_x[(size_t)r * CL * CD + d];
}

__global__ void pool_attn_kernel(const float* __restrict__ q_enc,
                                 const float* __restrict__ hint) {
    int t = blockIdx.x, b = blockIdx.y;
    __shared__ float qv[770];
    __shared__ float lg[32];
    int tid = threadIdx.x;
    for (int i = tid; i < 770; i += 256)
        qv[i] = (i < CD) ? q_enc[((size_t)b * CS + t) * CD + i]
                         : hint[((size_t)b * CTQ + t) * 2 + (i - CD)];
    __syncthreads();
    int e = tid >> 3, sub = tid & 7;
    const float* ep = g_entp + ((size_t)b * CE + e) * 770;
    float p = 0.f;
    for (int d = sub; d < 770; d += 8) p += qv[d] * ep[d];
    p += __shfl_down_sync(0xffffffffu, p, 4, 8);
    p += __shfl_down_sync(0xffffffffu, p, 2, 8);
    p += __shfl_down_sync(0xffffffffu, p, 1, 8);
    if (sub == 0) lg[e] = p;
    __syncthreads();
    if (tid < 32) {
        float v = lg[tid];
        float m = v;
        #pragma unroll
        for (int o = 16; o > 0; o >>= 1) m = fmaxf(m, __shfl_xor_sync(0xffffffffu, m, o));
        float ex = __expf(v - m);
        float sm = ex;
        #pragma unroll
        for (int o = 16; o > 0; o >>= 1) sm += __shfl_xor_sync(0xffffffffu, sm, o);
        g_attnw[((size_t)b * CTQ + t) * CE + tid] = ex / sm;
    }
}

__global__ void pool_wa_kernel(const int* __restrict__ qlen) {
    int b = blockIdx.x;
    int tid = threadIdx.x;
    __shared__ float A[32];
    int n = qlen[b];
    if (tid < 32) {
        float s = 0.f;
        for (int t = 0; t < n; t++) s += g_attnw[((size_t)b * CTQ + t) * CE + tid];
        A[tid] = s;
    }
    __syncthreads();
    #pragma unroll
    for (int j = 0; j < 3; j++) {
        int d = tid + j * 256;
        float s = 0.f;
        #pragma unroll
        for (int e = 0; e < 32; e++) s += A[e] * g_ent[((size_t)b * CE + e) * CD + d];
        g_wa[(size_t)b * CD + d] = s;
    }
}

__global__ void feat_kernel(const float* __restrict__ q_enc) {
    int b = blockIdx.x;
    for (int i = threadIdx.x; i < 2 * CD; i += 256)
        g_feat[(size_t)b * 2 * CD + i] =
            (i < CD) ? q_enc[(size_t)b * CS * CD + i] : g_wa[(size_t)b * CD + (i - CD)];
}

__global__ void head_out_kernel(const float* __restrict__ W2,
                                const float* __restrict__ b2,
                                float* __restrict__ out) {
    int b = blockIdx.x, tid = threadIdx.x;
    float s = 0.f;
    for (int n = tid; n < CNH; n += 256) s += g_h[(size_t)b * CNH + n] * W2[n];
    s = blockReduceSum(s);
    if (tid == 0) out[b] = s + b2[0];
}

// ---------------- host ----------------
template <typename T>
static T* dsym(const void* symbol) {
    void* p = nullptr;
    cudaGetSymbolAddress(&p, symbol);
    return (T*)p;
}

extern "C" void kernel_launch(void* const* d_in, const int* in_sizes, int n_in,
                              void* d_out, int out_size) {
    const float* q_enc  = (const float*)d_in[0];
    const int*   q_qlen = (const int*)  d_in[1];
    const float* hint   = (const float*)d_in[2];
    const int*   ranges = (const int*)  d_in[3];
    const float* Wq  = (const float*)d_in[4];
    const float* bq  = (const float*)d_in[5];
    const float* Wk  = (const float*)d_in[6];
    const float* bk  = (const float*)d_in[7];
    const float* Wv  = (const float*)d_in[8];
    const float* bv  = (const float*)d_in[9];
    const float* Wo  = (const float*)d_in[10];
    const float* bo  = (const float*)d_in[11];
    const float* ln1g = (const float*)d_in[12];
    const float* ln1b = (const float*)d_in[13];
    const float* Wf1 = (const float*)d_in[14];
    const float* bf1 = (const float*)d_in[15];
    const float* Wf2 = (const float*)d_in[16];
    const float* bf2 = (const float*)d_in[17];
    const float* ln2g = (const float*)d_in[18];
    const float* ln2b = (const float*)d_in[19];
    const float* W_ea = (const float*)d_in[20];
    const float* b_ea = (const float*)d_in[21];
    const float* W1  = (const float*)d_in[22];
    const float* b1  = (const float*)d_in[23];
    const float* W2  = (const float*)d_in[24];
    const float* b2  = (const float*)d_in[25];
    float* out = (float*)d_out;

    cudaFuncSetAttribute(gemm_mma, cudaFuncAttributeMaxDynamicSharedMemorySize, SMEM_DYN);

    __nv_bfloat16* xh  = dsym<__nv_bfloat16>(g_xh);
    __nv_bfloat16* xl  = dsym<__nv_bfloat16>(g_xl);
    __nv_bfloat16* oh  = dsym<__nv_bfloat16>(g_oh);
    __nv_bfloat16* ol  = dsym<__nv_bfloat16>(g_ol);
    __nv_bfloat16* fh  = dsym<__nv_bfloat16>(g_fh);
    __nv_bfloat16* fl  = dsym<__nv_bfloat16>(g_fl);
    float* qkv = dsym<float>(g_qkv);
    float* t_  = dsym<float>(g_t);
    __nv_bfloat16* wqkvh = dsym<__nv_bfloat16>(g_wqkvh);
    __nv_bfloat16* wqkvl = dsym<__nv_bfloat16>(g_wqkvl);
    __nv_bfloat16* woh   = dsym<__nv_bfloat16>(g_woh);
    __nv_bfloat16* wol   = dsym<__nv_bfloat16>(g_wol);
    __nv_bfloat16* wf1h  = dsym<__nv_bfloat16>(g_wf1h);
    __nv_bfloat16* wf1l  = dsym<__nv_bfloat16>(g_wf1l);
    __nv_bfloat16* wf2h  = dsym<__nv_bfloat16>(g_wf2h);
    __nv_bfloat16* wf2l  = dsym<__nv_bfloat16>(g_wf2l);
    float* bqkv = dsym<float>(g_bqkv);
    float* x    = dsym<float>(g_x);
    float* ent  = dsym<float>(g_ent);
    float* entp = dsym<float>(g_entp);
    float* feat = dsym<float>(g_feat);
    float* h_   = dsym<float>(g_h);

    dim3 wblk(32, 8);

    // layer-0 QKV weight conversions + bias + gather FIRST, so that the
    // first gemm_mma is launch index 5 (ncu -s 5 -c 1 lands on it).
    {
        size_t oQ = 0;
        wconv_kernel<<<dim3(CHDK/32, CD/32), wblk>>>(Wq, wqkvh + oQ, wqkvl + oQ, CD, CHDK, 0,      CD);
        wconv_kernel<<<dim3(CHDK/32, CD/32), wblk>>>(Wk, wqkvh + oQ, wqkvl + oQ, CD, CHDK, CHDK,   CD);
        wconv_kernel<<<dim3(CHDK/32, CD/32), wblk>>>(Wv, wqkvh + oQ, wqkvl + oQ, CD, CHDK, 2*CHDK, CD);
    }
    bqkv_kernel<<<CNL, 256>>>(bq, bk, bv);
    gather_kernel<<<NROWS, 256>>>(q_enc, ranges);

    // launch #5: the big QKV GEMM (layer 0)
    gemm_mma<<<dim3(CQKV/128, NROWS/128), 256, SMEM_DYN>>>(
        xh, xl, wqkvh, wqkvl, bqkv,
        qkv, nullptr, nullptr, CD, CQKV, 0);

    // remaining weight conversions (stream-ordered before their gemms)
    for (int i = 0; i < CNL; i++) {
        if (i > 0) {
            size_t oQ = (size_t)i * CQKV * CD;
            wconv_kernel<<<dim3(CHDK/32, CD/32), wblk>>>(Wq + (size_t)i*CD*CHDK, wqkvh + oQ, wqkvl + oQ, CD, CHDK, 0,      CD);
            wconv_kernel<<<dim3(CHDK/32, CD/32), wblk>>>(Wk + (size_t)i*CD*CHDK, wqkvh + oQ, wqkvl + oQ, CD, CHDK, CHDK,   CD);
            wconv_kernel<<<dim3(CHDK/32, CD/32), wblk>>>(Wv + (size_t)i*CD*CHDK, wqkvh + oQ, wqkvl + oQ, CD, CHDK, 2*CHDK, CD);
        }
        size_t oO = (size_t)i * CD * CHDK;
        wconv_kernel<<<dim3(CD/32, CHDK/32), wblk>>>(Wo + (size_t)i*CHDK*CD, woh + oO, wol + oO, CHDK, CD, 0, CHDK);
        size_t oF1 = (size_t)i * CDFF * CD;
        wconv_kernel<<<dim3(CDFF/32, CD/32), wblk>>>(Wf1 + (size_t)i*CD*CDFF, wf1h + oF1, wf1l + oF1, CD, CDFF, 0, CD);
        size_t oF2 = (size_t)i * CD * CDFF;
        wconv_kernel<<<dim3(CD/32, CDFF/32), wblk>>>(Wf2 + (size_t)i*CDFF*CD, wf2h + oF2, wf2l + oF2, CDFF, CD, 0, CDFF);
    }

    for (int i = 0; i < CNL; i++) {
        size_t oQ  = (size_t)i * CQKV * CD;
        size_t oO  = (size_t)i * CD * CHDK;
        size_t oF1 = (size_t)i * CDFF * CD;
        size_t oF2 = (size_t)i * CD * CDFF;

        if (i > 0) {
            gemm_mma<<<dim3(CQKV/128, NROWS/128), 256, SMEM_DYN>>>(
                xh, xl, wqkvh + oQ, wqkvl + oQ, bqkv + i*CQKV,
                qkv, nullptr, nullptr, CD, CQKV, 0);
        }

        attn_kernel<<<NENT * CH, 128>>>();

        gemm_mma<<<dim3(CD/128, NROWS/128), 256, SMEM_DYN>>>(
            oh, ol, woh + oO, wol + oO, bo + i*CD,
            t_, nullptr, nullptr, CHDK, CD, 0);

        add_ln_kernel<<<NROWS, 256>>>(ln1g + i*CD, ln1b + i*CD);

        gemm_mma<<<dim3(CDFF/128, NROWS/128), 256, SMEM_DYN>>>(
            xh, xl, wf1h + oF1, wf1l + oF1, bf1 + i*CDFF,
            nullptr, fh, fl, CD, CDFF, 1);

        gemm_mma<<<dim3(CD/128, NROWS/128), 256, SMEM_DYN>>>(
            fh, fl, wf2h + oF2, wf2l + oF2, bf2 + i*CD,
            t_, nullptr, nullptr, CDFF, CD, 0);

        add_ln_kernel<<<NROWS, 256>>>(ln2g + i*CD, ln2b + i*CD);
    }

    dim3 blk(16, 16);
    copy_ent_kernel<<<NENT, 256>>>();
    gemm_bias_kernel<<<dim3((770 + 63) / 64, NENT / 64), blk>>>(ent, W_ea, b_ea, entp, NENT, 770, CD, 0);
    pool_attn_kernel<<<dim3(CTQ, CB), 256>>>(q_enc, hint);
    pool_wa_kernel<<<CB, 256>>>(q_qlen);
    feat_kernel<<<CB, 256>>>(q_enc);
    gemm_bias_kernel<<<dim3(CNH / 64, 1), blk>>>(feat, W1, b1, h_, CB, CNH, 2 * CD, 1);
    head_out_kernel<<<CB, 256>>>(W2, b2, out);
}

// round 6
// speedup vs baseline: 3.3108x; 1.0044x over previous
#include <cuda_runtime.h>
#include <cuda_bf16.h>
#include <math.h>
#include <stdint.h>

// ---------------- problem constants ----------------
#define CB   64
#define CS   512
#define CD   768
#define CE   32
#define CL   16
#define CTQ  128
#define CH   3
#define CDK  128
#define CHDK 384
#define CQKV 1152
#define CDFF 3072
#define CNH  1024
#define CNL  3
#define NROWS (CB*CE*CL)     // 32768
#define NENT  (CB*CE)        // 2048

// ---------------- device scratch ----------------
__device__ float          g_x  [NROWS*CD];
__device__ __nv_bfloat16  g_xh [NROWS*CD];
__device__ __nv_bfloat16  g_xl [NROWS*CD];
__device__ float          g_qkv[NROWS*CQKV];
__device__ __nv_bfloat16  g_oh [NROWS*CHDK];
__device__ __nv_bfloat16  g_ol [NROWS*CHDK];
__device__ __nv_bfloat16  g_fh [NROWS*CDFF];
__device__ __nv_bfloat16  g_fl [NROWS*CDFF];
__device__ float          g_t  [NROWS*CD];

__device__ __nv_bfloat16  g_wqkvh[CNL*CQKV*CD], g_wqkvl[CNL*CQKV*CD];
__device__ __nv_bfloat16  g_woh [CNL*CD*CHDK],  g_wol [CNL*CD*CHDK];
__device__ __nv_bfloat16  g_wf1h[CNL*CDFF*CD],  g_wf1l[CNL*CDFF*CD];
__device__ __nv_bfloat16  g_wf2h[CNL*CD*CDFF],  g_wf2l[CNL*CD*CDFF];
__device__ float          g_bqkv[CNL*CQKV];

__device__ float g_ent [NENT*CD];
__device__ float g_entp[NENT*770];
__device__ float g_attnw[CB*CTQ*CE];
__device__ float g_wa  [CB*CD];
__device__ float g_feat[CB*2*CD];
__device__ float g_h   [CB*CNH];

// ---------------- helpers ----------------
__device__ __forceinline__ uint32_t smem_u32(const void* p) {
    uint32_t a;
    asm("{ .reg .u64 t; cvta.to.shared.u64 t, %1; cvt.u32.u64 %0, t; }" : "=r"(a) : "l"(p));
    return a;
}

__device__ __forceinline__ void split_bf16(float v, __nv_bfloat16& h, __nv_bfloat16& l) {
    h = __float2bfloat16_rn(v);
    l = __float2bfloat16_rn(v - __bfloat162float(h));
}

__device__ __forceinline__ void ldmatrix_x4(uint32_t* r, uint32_t addr) {
    asm volatile("ldmatrix.sync.aligned.m8n8.x4.shared.b16 {%0,%1,%2,%3}, [%4];"
        : "=r"(r[0]), "=r"(r[1]), "=r"(r[2]), "=r"(r[3]) : "r"(addr));
}

__device__ __forceinline__ void mma16816(float* c, const uint32_t* a,
                                         uint32_t b0, uint32_t b1) {
    asm volatile("mma.sync.aligned.m16n8k16.row.col.f32.bf16.bf16.f32 "
        "{%0,%1,%2,%3}, {%4,%5,%6,%7}, {%8,%9}, {%0,%1,%2,%3};"
        : "+f"(c[0]), "+f"(c[1]), "+f"(c[2]), "+f"(c[3])
        : "r"(a[0]), "r"(a[1]), "r"(a[2]), "r"(a[3]), "r"(b0), "r"(b1));
}

// ---------------- tensor-core GEMM (mma.sync bf16, fused 3-term split) ----
// C[M,N] = (Ah+Al)[M,K] @ (Wh+Wl)^T + bias   (W stored [N,K] K-major)
// Per K-chunk (32): load Ah,Al,Wh,Wl once; acc += AhWh + AlWh + AhWl,
// issued TERM-MAJOR so same-accumulator HMMAs are 16 apart (RAW hiding).
#define ROWB    80                  // 32 bf16 = 64B data, padded to 80B
#define TTILE   (128*ROWB)          // 10240 per tile
#define STAGE_BYTES (4*TTILE)       // 40960: Ah|Al|Wh|Wl
#define STAGES  3
#define SMEM_DYN (STAGES*STAGE_BYTES + 128)

__global__ __launch_bounds__(256, 1) void gemm_mma(
    const __nv_bfloat16* __restrict__ Ah, const __nv_bfloat16* __restrict__ Al,
    const __nv_bfloat16* __restrict__ Wh, const __nv_bfloat16* __restrict__ Wl,
    const float* __restrict__ bias,
    float* __restrict__ Cf,
    __nv_bfloat16* __restrict__ Chi, __nv_bfloat16* __restrict__ Clo,
    int K, int Nld, int relu)
{
    extern __shared__ char dynsmem[];
    uint32_t sbase = (smem_u32(dynsmem) + 127u) & ~127u;

    int tid  = threadIdx.x;
    int wid  = tid >> 5, lane = tid & 31;
    int wm   = wid & 3, wn = wid >> 2;           // 4 x 2 warp grid
    int m0   = blockIdx.y * 128, n0 = blockIdx.x * 128;

    const int NC = K >> 5;       // 32-elem chunks

    auto load_chunk = [&](int kc, int buf) {
        uint32_t tb = sbase + buf * STAGE_BYTES;
        #pragma unroll
        for (int i = 0; i < 8; i++) {
            int seg  = tid + i * 256;            // 0..2047
            int tile = seg >> 9;                 // 0:Ah 1:Al 2:Wh 3:Wl
            int row  = (seg >> 2) & 127;
            int c    = seg & 3;
            uint32_t dst = tb + tile * TTILE + row * ROWB + c * 16;
            const __nv_bfloat16* src;
            if (tile == 0)      src = Ah + (size_t)(m0 + row) * K + kc * 32 + c * 8;
            else if (tile == 1) src = Al + (size_t)(m0 + row) * K + kc * 32 + c * 8;
            else if (tile == 2) src = Wh + (size_t)(n0 + row) * K + kc * 32 + c * 8;
            else                src = Wl + (size_t)(n0 + row) * K + kc * 32 + c * 8;
            asm volatile("cp.async.cg.shared.global [%0], [%1], 16;" :: "r"(dst), "l"(src));
        }
        asm volatile("cp.async.commit_group;" ::: "memory");
    };

    float acc[2][8][4];
    #pragma unroll
    for (int i = 0; i < 2; i++)
        #pragma unroll
        for (int j = 0; j < 8; j++)
            #pragma unroll
            for (int q = 0; q < 4; q++) acc[i][j][q] = 0.f;

    // prologue: 2 chunks in flight
    load_chunk(0, 0);
    if (NC > 1) load_chunk(1, 1);

    int lrow = lane & 15;               // smem row within 16-row group
    int lcol = (lane >> 4) << 4;        // +16B for k8..15 matrices

    for (int c = 0; c < NC; c++) {
        if (c < NC - 1) asm volatile("cp.async.wait_group 1;" ::: "memory");
        else            asm volatile("cp.async.wait_group 0;" ::: "memory");
        __syncthreads();

        uint32_t sb = sbase + (c % STAGES) * STAGE_BYTES;

        if (c + 2 < NC) load_chunk(c + 2, (c + 2) % STAGES);

        uint32_t aAddr = sb + (uint32_t)(wm * 32 + lrow) * ROWB + lcol;
        uint32_t bAddr = sb + 2 * TTILE + (uint32_t)(wn * 64 + lrow) * ROWB + lcol;

        #pragma unroll
        for (int ks = 0; ks < 2; ks++) {
            uint32_t ah[2][4], al[2][4], bh[4][4], bl[4][4];
            #pragma unroll
            for (int i = 0; i < 2; i++) {
                ldmatrix_x4(ah[i], aAddr + i * (16 * ROWB) + ks * 32);
                ldmatrix_x4(al[i], aAddr + TTILE + i * (16 * ROWB) + ks * 32);
            }
            #pragma unroll
            for (int jj = 0; jj < 4; jj++) {
                ldmatrix_x4(bh[jj], bAddr + jj * (16 * ROWB) + ks * 32);
                ldmatrix_x4(bl[jj], bAddr + TTILE + jj * (16 * ROWB) + ks * 32);
            }
            // term 1: Ah*Wh (16 independent MMAs)
            #pragma unroll
            for (int i = 0; i < 2; i++)
                #pragma unroll
                for (int jj = 0; jj < 4; jj++) {
                    mma16816(acc[i][2 * jj],     ah[i], bh[jj][0], bh[jj][2]);
                    mma16816(acc[i][2 * jj + 1], ah[i], bh[jj][1], bh[jj][3]);
                }
            // term 2: Al*Wh
            #pragma unroll
            for (int i = 0; i < 2; i++)
                #pragma unroll
                for (int jj = 0; jj < 4; jj++) {
                    mma16816(acc[i][2 * jj],     al[i], bh[jj][0], bh[jj][2]);
                    mma16816(acc[i][2 * jj + 1], al[i], bh[jj][1], bh[jj][3]);
                }
            // term 3: Ah*Wl
            #pragma unroll
            for (int i = 0; i < 2; i++)
                #pragma unroll
                for (int jj = 0; jj < 4; jj++) {
                    mma16816(acc[i][2 * jj],     ah[i], bl[jj][0], bl[jj][2]);
                    mma16816(acc[i][2 * jj + 1], ah[i], bl[jj][1], bl[jj][3]);
                }
        }
    }

    // ---------------- epilogue ----------------
    const float2* bp = (const float2*)(bias + n0 + wn * 64);
    float2 bv[8];
    #pragma unroll
    for (int j = 0; j < 8; j++) bv[j] = bp[j * 4 + (lane & 3)];

    #pragma unroll
    for (int i = 0; i < 2; i++) {
        int m_lo = m0 + wm * 32 + i * 16 + (lane >> 2);
        #pragma unroll
        for (int j = 0; j < 8; j++) {
            int n = n0 + wn * 64 + j * 8 + (lane & 3) * 2;
            float v0 = acc[i][j][0] + bv[j].x;
            float v1 = acc[i][j][1] + bv[j].y;
            float v2 = acc[i][j][2] + bv[j].x;
            float v3 = acc[i][j][3] + bv[j].y;
            if (relu) {
                v0 = fmaxf(v0, 0.f); v1 = fmaxf(v1, 0.f);
                v2 = fmaxf(v2, 0.f); v3 = fmaxf(v3, 0.f);
            }
            if (Cf) {
                *(float2*)(Cf + (size_t)m_lo * Nld + n)        = make_float2(v0, v1);
                *(float2*)(Cf + (size_t)(m_lo + 8) * Nld + n)  = make_float2(v2, v3);
            }
            if (Chi) {
                __nv_bfloat16 h0, l0, h1, l1;
                split_bf16(v0, h0, l0); split_bf16(v1, h1, l1);
                __nv_bfloat162 ph = __nv_bfloat162(h0, h1);
                __nv_bfloat162 pl = __nv_bfloat162(l0, l1);
                *(uint32_t*)(Chi + (size_t)m_lo * Nld + n) = *(uint32_t*)&ph;
                *(uint32_t*)(Clo + (size_t)m_lo * Nld + n) = *(uint32_t*)&pl;
                split_bf16(v2, h0, l0); split_bf16(v3, h1, l1);
                ph = __nv_bfloat162(h0, h1);
                pl = __nv_bfloat162(l0, l1);
                *(uint32_t*)(Chi + (size_t)(m_lo + 8) * Nld + n) = *(uint32_t*)&ph;
                *(uint32_t*)(Clo + (size_t)(m_lo + 8) * Nld + n) = *(uint32_t*)&pl;
            }
        }
    }
}

// ---------------- weight transpose + bf16 split ----------------
__global__ void wconv_kernel(const float* __restrict__ src,
                             __nv_bfloat16* __restrict__ dh,
                             __nv_bfloat16* __restrict__ dl,
                             int K, int N, int rowOff, int dstLd) {
    __shared__ float ts[32][33];
    int n0 = blockIdx.x * 32, k0 = blockIdx.y * 32;
    int tx = threadIdx.x, ty = threadIdx.y;  // 32x8
    #pragma unroll
    for (int j = 0; j < 4; j++)
        ts[ty + 8 * j][tx] = src[(size_t)(k0 + ty + 8 * j) * N + n0 + tx];
    __syncthreads();
    #pragma unroll
    for (int j = 0; j < 4; j++) {
        float v = ts[tx][ty + 8 * j];
        size_t di = (size_t)(rowOff + n0 + ty + 8 * j) * dstLd + k0 + tx;
        __nv_bfloat16 h, l;
        split_bf16(v, h, l);
        dh[di] = h; dl[di] = l;
    }
}

// fused Q/K/V weight conversion: blockIdx.z picks the source matrix.
__global__ void wconv3_kernel(const float* __restrict__ srcQ,
                              const float* __restrict__ srcK,
                              const float* __restrict__ srcV,
                              __nv_bfloat16* __restrict__ dh,
                              __nv_bfloat16* __restrict__ dl) {
    __shared__ float ts[32][33];
    int z = blockIdx.z;
    const float* src = (z == 0) ? srcQ : (z == 1) ? srcK : srcV;
    int rowOff = z * CHDK;
    int n0 = blockIdx.x * 32, k0 = blockIdx.y * 32;
    int tx = threadIdx.x, ty = threadIdx.y;  // 32x8
    #pragma unroll
    for (int j = 0; j < 4; j++)
        ts[ty + 8 * j][tx] = src[(size_t)(k0 + ty + 8 * j) * CHDK + n0 + tx];
    __syncthreads();
    #pragma unroll
    for (int j = 0; j < 4; j++) {
        float v = ts[tx][ty + 8 * j];
        size_t di = (size_t)(rowOff + n0 + ty + 8 * j) * CD + k0 + tx;
        __nv_bfloat16 h, l;
        split_bf16(v, h, l);
        dh[di] = h; dl[di] = l;
    }
}

__global__ void bqkv_kernel(const float* __restrict__ bq,
                            const float* __restrict__ bk,
                            const float* __restrict__ bv) {
    int i = blockIdx.x;
    for (int j = threadIdx.x; j < CQKV; j += 256)
        g_bqkv[i * CQKV + j] =
            (j < CHDK) ? bq[i * CHDK + j] :
            (j < 2 * CHDK) ? bk[i * CHDK + j - CHDK] : bv[i * CHDK + j - 2 * CHDK];
}

// ---------------- gather spans into g_x (+ bf16 split) ----------------
__global__ void gather_kernel(const float* __restrict__ q_enc,
                              const int* __restrict__ ranges) {
    int row = blockIdx.x;
    int be = row >> 4, l = row & 15;
    int b = be >> 5, e = be & 31;
    int st = ranges[(b * CE + e) * 2];
    int en = ranges[(b * CE + e) * 2 + 1];
    int src = min(max(st + l, 0), CS - 1);
    bool m = l < (en - st);
    const float* s = q_enc + ((size_t)b * CS + src) * CD;
    size_t base = (size_t)row * CD;
    for (int i = threadIdx.x; i < CD; i += 256) {
        float v = m ? s[i] : 0.f;
        g_x[base + i] = v;
        __nv_bfloat16 h, lo; split_bf16(v, h, lo);
        g_xh[base + i] = h; g_xl[base + i] = lo;
    }
}

// ---------------- fp32 SIMT GEMM (small tail matrices) ----------------
__global__ void gemm_bias_kernel(const float* __restrict__ A,
                                 const float* __restrict__ W,
                                 const float* __restrict__ bias,
                                 float* __restrict__ C,
                                 int M, int N, int K, int relu) {
    __shared__ float As[16][65];
    __shared__ float Bs[16][68];
    int tx = threadIdx.x, ty = threadIdx.y;
    int tid = ty * 16 + tx;
    int m0 = blockIdx.y * 64, n0 = blockIdx.x * 64;
    int a_row = tid >> 2, a_col = (tid & 3) << 2;
    int b_row = tid >> 4, b_col = (tid & 15) << 2;
    float acc[4][4] = {};
    for (int k0 = 0; k0 < K; k0 += 16) {
        int m = m0 + a_row;
        #pragma unroll
        for (int i = 0; i < 4; i++) {
            float v = 0.f;
            if (m < M) v = A[(size_t)m * K + k0 + a_col + i];
            As[a_col + i][a_row] = v;
        }
        #pragma unroll
        for (int i = 0; i < 4; i++) {
            int n = n0 + b_col + i;
            float v = 0.f;
            if (n < N) v = W[(size_t)(k0 + b_row) * N + n];
            Bs[b_row][b_col + i] = v;
        }
        __syncthreads();
        #pragma unroll
        for (int kk = 0; kk < 16; kk++) {
            float ra[4], rb[4];
            #pragma unroll
            for (int i = 0; i < 4; i++) ra[i] = As[kk][ty * 4 + i];
            #pragma unroll
            for (int j = 0; j < 4; j++) rb[j] = Bs[kk][tx * 4 + j];
            #pragma unroll
            for (int i = 0; i < 4; i++)
                #pragma unroll
                for (int j = 0; j < 4; j++)
                    acc[i][j] += ra[i] * rb[j];
        }
        __syncthreads();
    }
    #pragma unroll
    for (int i = 0; i < 4; i++) {
        int m = m0 + ty * 4 + i;
        if (m >= M) continue;
        #pragma unroll
        for (int j = 0; j < 4; j++) {
            int n = n0 + tx * 4 + j;
            if (n >= N) continue;
            float v = acc[i][j] + bias[n];
            if (relu) v = fmaxf(v, 0.f);
            C[(size_t)m * N + n] = v;
        }
    }
}

// ---------------- per-(span,head) attention ----------------
__global__ void attn_kernel() {
    int nh = blockIdx.x;
    int n = nh / CH, h = nh % CH;
    __shared__ float qs[16][129], ks[16][129], vs[16][129];
    __shared__ float sc[16][17];
    int tid = threadIdx.x;  // 128
    for (int idx = tid; idx < 16 * 128; idx += 128) {
        int l = idx >> 7, d = idx & 127;
        size_t base = ((size_t)(n * CL + l)) * CQKV + h * CDK + d;
        qs[l][d] = g_qkv[base];
        ks[l][d] = g_qkv[base + CHDK];
        vs[l][d] = g_qkv[base + 2 * CHDK];
    }
    __syncthreads();
    const float scale = 0.088388347648318447f;
    for (int p = tid; p < 256; p += 128) {
        int qi = p >> 4, ki = p & 15;
        float s = 0.f;
        #pragma unroll
        for (int d = 0; d < 128; d++) s += qs[qi][d] * ks[ki][d];
        sc[qi][ki] = s * scale;
    }
    __syncthreads();
    if (tid < 16) {
        float m = -1e30f;
        #pragma unroll
        for (int k = 0; k < 16; k++) m = fmaxf(m, sc[tid][k]);
        float sum = 0.f;
        #pragma unroll
        for (int k = 0; k < 16; k++) { float e = __expf(sc[tid][k] - m); sc[tid][k] = e; sum += e; }
        float inv = 1.f / sum;
        #pragma unroll
        for (int k = 0; k < 16; k++) sc[tid][k] *= inv;
    }
    __syncthreads();
    int d = tid;
    #pragma unroll
    for (int qi = 0; qi < 16; qi++) {
        float acc = 0.f;
        #pragma unroll
        for (int k = 0; k < 16; k++) acc += sc[qi][k] * vs[k][d];
        size_t oi = ((size_t)(n * CL + qi)) * CHDK + h * CDK + d;
        __nv_bfloat16 hh, ll; split_bf16(acc, hh, ll);
        g_oh[oi] = hh; g_ol[oi] = ll;
    }
}

// ---------------- x = LN(x + t) (+ bf16 split) ----------------
__device__ __forceinline__ float blockReduceSum(float val) {
    __shared__ float sh[32];
    int lane = threadIdx.x & 31, wid = threadIdx.x >> 5;
    #pragma unroll
    for (int o = 16; o > 0; o >>= 1) val += __shfl_xor_sync(0xffffffffu, val, o);
    if (lane == 0) sh[wid] = val;
    __syncthreads();
    int nw = (blockDim.x + 31) >> 5;
    val = (threadIdx.x < nw) ? sh[lane] : 0.f;
    if (wid == 0) {
        #pragma unroll
        for (int o = 16; o > 0; o >>= 1) val += __shfl_xor_sync(0xffffffffu, val, o);
    }
    return val;
}

__global__ void add_ln_kernel(const float* __restrict__ gamma,
                              const float* __restrict__ beta) {
    int row = blockIdx.x;
    int tid = threadIdx.x;
    float v[3];
    float s = 0.f;
    #pragma unroll
    for (int j = 0; j < 3; j++) {
        size_t idx = (size_t)row * CD + tid + j * 256;
        v[j] = g_x[idx] + g_t[idx];
        s += v[j];
    }
    s = blockReduceSum(s);
    __shared__ float mean_s, rstd_s;
    if (tid == 0) mean_s = s * (1.f / CD);
    __syncthreads();
    float m = mean_s;
    float vv = 0.f;
    #pragma unroll
    for (int j = 0; j < 3; j++) { float d = v[j] - m; vv += d * d; }
    vv = blockReduceSum(vv);
    if (tid == 0) rstd_s = rsqrtf(vv * (1.f / CD) + 1e-5f);
    __syncthreads();
    float r = rstd_s;
    #pragma unroll
    for (int j = 0; j < 3; j++) {
        int c = tid + j * 256;
        float o = (v[j] - m) * r * gamma[c] + beta[c];
        size_t idx = (size_t)row * CD + c;
        g_x[idx] = o;
        __nv_bfloat16 h, l; split_bf16(o, h, l);
        g_xh[idx] = h; g_xl[idx] = l;
    }
}

// ---------------- tail kernels ----------------
__global__ void copy_ent_kernel() {
    int r = blockIdx.x;
    for (int d = threadIdx.x; d < CD; d += 256)
        g_ent[(size_t)r * CD + d] = g_x[(size_t)r * CL * CD + d];
}

__global__ void pool_attn_kernel(const float* __restrict__ q_enc,
                                 const float* __restrict__ hint) {
    int t = blockIdx.x, b = blockIdx.y;
    __shared__ float qv[770];
    __shared__ float lg[32];
    int tid = threadIdx.x;
    for (int i = tid; i < 770; i += 256)
        qv[i] = (i < CD) ? q_enc[((size_t)b * CS + t) * CD + i]
                         : hint[((size_t)b * CTQ + t) * 2 + (i - CD)];
    __syncthreads();
    int e = tid >> 3, sub = tid & 7;
    const float* ep = g_entp + ((size_t)b * CE + e) * 770;
    float p = 0.f;
    for (int d = sub; d < 770; d += 8) p += qv[d] * ep[d];
    p += __shfl_down_sync(0xffffffffu, p, 4, 8);
    p += __shfl_down_sync(0xffffffffu, p, 2, 8);
    p += __shfl_down_sync(0xffffffffu, p, 1, 8);
    if (sub == 0) lg[e] = p;
    __syncthreads();
    if (tid < 32) {
        float v = lg[tid];
        float m = v;
        #pragma unroll
        for (int o = 16; o > 0; o >>= 1) m = fmaxf(m, __shfl_xor_sync(0xffffffffu, m, o));
        float ex = __expf(v - m);
        float sm = ex;
        #pragma unroll
        for (int o = 16; o > 0; o >>= 1) sm += __shfl_xor_sync(0xffffffffu, sm, o);
        g_attnw[((size_t)b * CTQ + t) * CE + tid] = ex / sm;
    }
}

__global__ void pool_wa_kernel(const int* __restrict__ qlen) {
    int b = blockIdx.x;
    int tid = threadIdx.x;
    __shared__ float A[32];
    int n = qlen[b];
    if (tid < 32) {
        float s = 0.f;
        for (int t = 0; t < n; t++) s += g_attnw[((size_t)b * CTQ + t) * CE + tid];
        A[tid] = s;
    }
    __syncthreads();
    #pragma unroll
    for (int j = 0; j < 3; j++) {
        int d = tid + j * 256;
        float s = 0.f;
        #pragma unroll
        for (int e = 0; e < 32; e++) s += A[e] * g_ent[((size_t)b * CE + e) * CD + d];
        g_wa[(size_t)b * CD + d] = s;
    }
}

__global__ void feat_kernel(const float* __restrict__ q_enc) {
    int b = blockIdx.x;
    for (int i = threadIdx.x; i < 2 * CD; i += 256)
        g_feat[(size_t)b * 2 * CD + i] =
            (i < CD) ? q_enc[(size_t)b * CS * CD + i] : g_wa[(size_t)b * CD + (i - CD)];
}

__global__ void head_out_kernel(const float* __restrict__ W2,
                                const float* __restrict__ b2,
                                float* __restrict__ out) {
    int b = blockIdx.x, tid = threadIdx.x;
    float s = 0.f;
    for (int n = tid; n < CNH; n += 256) s += g_h[(size_t)b * CNH + n] * W2[n];
    s = blockReduceSum(s);
    if (tid == 0) out[b] = s + b2[0];
}

// ---------------- host ----------------
template <typename T>
static T* dsym(const void* symbol) {
    void* p = nullptr;
    cudaGetSymbolAddress(&p, symbol);
    return (T*)p;
}

extern "C" void kernel_launch(void* const* d_in, const int* in_sizes, int n_in,
                              void* d_out, int out_size) {
    const float* q_enc  = (const float*)d_in[0];
    const int*   q_qlen = (const int*)  d_in[1];
    const float* hint   = (const float*)d_in[2];
    const int*   ranges = (const int*)  d_in[3];
    const float* Wq  = (const float*)d_in[4];
    const float* bq  = (const float*)d_in[5];
    const float* Wk  = (const float*)d_in[6];
    const float* bk  = (const float*)d_in[7];
    const float* Wv  = (const float*)d_in[8];
    const float* bv  = (const float*)d_in[9];
    const float* Wo  = (const float*)d_in[10];
    const float* bo  = (const float*)d_in[11];
    const float* ln1g = (const float*)d_in[12];
    const float* ln1b = (const float*)d_in[13];
    const float* Wf1 = (const float*)d_in[14];
    const float* bf1 = (const float*)d_in[15];
    const float* Wf2 = (const float*)d_in[16];
    const float* bf2 = (const float*)d_in[17];
    const float* ln2g = (const float*)d_in[18];
    const float* ln2b = (const float*)d_in[19];
    const float* W_ea = (const float*)d_in[20];
    const float* b_ea = (const float*)d_in[21];
    const float* W1  = (const float*)d_in[22];
    const float* b1  = (const float*)d_in[23];
    const float* W2  = (const float*)d_in[24];
    const float* b2  = (const float*)d_in[25];
    float* out = (float*)d_out;

    cudaFuncSetAttribute(gemm_mma, cudaFuncAttributeMaxDynamicSharedMemorySize, SMEM_DYN);

    __nv_bfloat16* xh  = dsym<__nv_bfloat16>(g_xh);
    __nv_bfloat16* xl  = dsym<__nv_bfloat16>(g_xl);
    __nv_bfloat16* oh  = dsym<__nv_bfloat16>(g_oh);
    __nv_bfloat16* ol  = dsym<__nv_bfloat16>(g_ol);
    __nv_bfloat16* fh  = dsym<__nv_bfloat16>(g_fh);
    __nv_bfloat16* fl  = dsym<__nv_bfloat16>(g_fl);
    float* qkv = dsym<float>(g_qkv);
    float* t_  = dsym<float>(g_t);
    __nv_bfloat16* wqkvh = dsym<__nv_bfloat16>(g_wqkvh);
    __nv_bfloat16* wqkvl = dsym<__nv_bfloat16>(g_wqkvl);
    __nv_bfloat16* woh   = dsym<__nv_bfloat16>(g_woh);
    __nv_bfloat16* wol   = dsym<__nv_bfloat16>(g_wol);
    __nv_bfloat16* wf1h  = dsym<__nv_bfloat16>(g_wf1h);
    __nv_bfloat16* wf1l  = dsym<__nv_bfloat16>(g_wf1l);
    __nv_bfloat16* wf2h  = dsym<__nv_bfloat16>(g_wf2h);
    __nv_bfloat16* wf2l  = dsym<__nv_bfloat16>(g_wf2l);
    float* bqkv = dsym<float>(g_bqkv);
    float* x    = dsym<float>(g_x);
    float* ent  = dsym<float>(g_ent);
    float* entp = dsym<float>(g_entp);
    float* feat = dsym<float>(g_feat);
    float* h_   = dsym<float>(g_h);

    dim3 wblk(32, 8);

    // launch 0: fused layer-0 QKV weight conversion (grid.z = 3)
    wconv3_kernel<<<dim3(CHDK/32, CD/32, 3), wblk>>>(Wq, Wk, Wv, wqkvh, wqkvl);
    // launch 1: bias concat, launch 2: gather
    bqkv_kernel<<<CNL, 256>>>(bq, bk, bv);
    gather_kernel<<<NROWS, 256>>>(q_enc, ranges);

    // launch 3: the big QKV GEMM (layer 0) — ncu window target
    gemm_mma<<<dim3(CQKV/128, NROWS/128), 256, SMEM_DYN>>>(
        xh, xl, wqkvh, wqkvl, bqkv,
        qkv, nullptr, nullptr, CD, CQKV, 0);

    // remaining weight conversions (stream-ordered before their gemms)
    for (int i = 0; i < CNL; i++) {
        if (i > 0) {
            size_t oQ = (size_t)i * CQKV * CD;
            wconv3_kernel<<<dim3(CHDK/32, CD/32, 3), wblk>>>(
                Wq + (size_t)i*CD*CHDK, Wk + (size_t)i*CD*CHDK, Wv + (size_t)i*CD*CHDK,
                wqkvh + oQ, wqkvl + oQ);
        }
        size_t oO = (size_t)i * CD * CHDK;
        wconv_kernel<<<dim3(CD/32, CHDK/32), wblk>>>(Wo + (size_t)i*CHDK*CD, woh + oO, wol + oO, CHDK, CD, 0, CHDK);
        size_t oF1 = (size_t)i * CDFF * CD;
        wconv_kernel<<<dim3(CDFF/32, CD/32), wblk>>>(Wf1 + (size_t)i*CD*CDFF, wf1h + oF1, wf1l + oF1, CD, CDFF, 0, CD);
        size_t oF2 = (size_t)i * CD * CDFF;
        wconv_kernel<<<dim3(CD/32, CDFF/32), wblk>>>(Wf2 + (size_t)i*CDFF*CD, wf2h + oF2, wf2l + oF2, CDFF, CD, 0, CDFF);
    }

    for (int i = 0; i < CNL; i++) {
        size_t oQ  = (size_t)i * CQKV * CD;
        size_t oO  = (size_t)i * CD * CHDK;
        size_t oF1 = (size_t)i * CDFF * CD;
        size_t oF2 = (size_t)i * CD * CDFF;

        if (i > 0) {
            gemm_mma<<<dim3(CQKV/128, NROWS/128), 256, SMEM_DYN>>>(
                xh, xl, wqkvh + oQ, wqkvl + oQ, bqkv + i*CQKV,
                qkv, nullptr, nullptr, CD, CQKV, 0);
        }

        attn_kernel<<<NENT * CH, 128>>>();

        gemm_mma<<<dim3(CD/128, NROWS/128), 256, SMEM_DYN>>>(
            oh, ol, woh + oO, wol + oO, bo + i*CD,
            t_, nullptr, nullptr, CHDK, CD, 0);

        add_ln_kernel<<<NROWS, 256>>>(ln1g + i*CD, ln1b + i*CD);

        gemm_mma<<<dim3(CDFF/128, NROWS/128), 256, SMEM_DYN>>>(
            xh, xl, wf1h + oF1, wf1l + oF1, bf1 + i*CDFF,
            nullptr, fh, fl, CD, CDFF, 1);

        gemm_mma<<<dim3(CD/128, NROWS/128), 256, SMEM_DYN>>>(
            fh, fl, wf2h + oF2, wf2l + oF2, bf2 + i*CD,
            t_, nullptr, nullptr, CDFF, CD, 0);

        add_ln_kernel<<<NROWS, 256>>>(ln2g + i*CD, ln2b + i*CD);
    }

    dim3 blk(16, 16);
    copy_ent_kernel<<<NENT, 256>>>();
    gemm_bias_kernel<<<dim3((770 + 63) / 64, NENT / 64), blk>>>(ent, W_ea, b_ea, entp, NENT, 770, CD, 0);
    pool_attn_kernel<<<dim3(CTQ, CB), 256>>>(q_enc, hint);
    pool_wa_kernel<<<CB, 256>>>(q_qlen);
    feat_kernel<<<CB, 256>>>(q_enc);
    gemm_bias_kernel<<<dim3(CNH / 64, 1), blk>>>(feat, W1, b1, h_, CB, CNH, 2 * CD, 1);
    head_out_kernel<<<CB, 256>>>(W2, b2, out);
}

// round 7
// speedup vs baseline: 3.3766x; 1.0199x over previous
#include <cuda_runtime.h>
#include <cuda_bf16.h>
#include <math.h>
#include <stdint.h>

// ---------------- problem constants ----------------
#define CB   64
#define CS   512
#define CD   768
#define CE   32
#define CL   16
#define CTQ  128
#define CH   3
#define CDK  128
#define CHDK 384
#define CQKV 1152
#define CDFF 3072
#define CNH  1024
#define CNL  3
#define NROWS (CB*CE*CL)     // 32768
#define NENT  (CB*CE)        // 2048

// ---------------- device scratch ----------------
__device__ float          g_x  [NROWS*CD];
__device__ __nv_bfloat16  g_xh [NROWS*CD];
__device__ __nv_bfloat16  g_xl [NROWS*CD];
__device__ float          g_qkv[NROWS*CQKV];
__device__ __nv_bfloat16  g_oh [NROWS*CHDK];
__device__ __nv_bfloat16  g_ol [NROWS*CHDK];
__device__ __nv_bfloat16  g_fh [NROWS*CDFF];
__device__ __nv_bfloat16  g_fl [NROWS*CDFF];
__device__ float          g_t  [NROWS*CD];

__device__ __nv_bfloat16  g_wqkvh[CNL*CQKV*CD], g_wqkvl[CNL*CQKV*CD];
__device__ __nv_bfloat16  g_woh [CNL*CD*CHDK],  g_wol [CNL*CD*CHDK];
__device__ __nv_bfloat16  g_wf1h[CNL*CDFF*CD],  g_wf1l[CNL*CDFF*CD];
__device__ __nv_bfloat16  g_wf2h[CNL*CD*CDFF],  g_wf2l[CNL*CD*CDFF];
__device__ float          g_bqkv[CNL*CQKV];

__device__ float g_ent [NENT*CD];
__device__ float g_entp[NENT*770];
__device__ float g_attnw[CB*CTQ*CE];
__device__ float g_wa  [CB*CD];
__device__ float g_feat[CB*2*CD];
__device__ float g_h   [CB*CNH];

// ---------------- helpers ----------------
__device__ __forceinline__ uint32_t smem_u32(const void* p) {
    uint32_t a;
    asm("{ .reg .u64 t; cvta.to.shared.u64 t, %1; cvt.u32.u64 %0, t; }" : "=r"(a) : "l"(p));
    return a;
}

__device__ __forceinline__ void split_bf16(float v, __nv_bfloat16& h, __nv_bfloat16& l) {
    h = __float2bfloat16_rn(v);
    l = __float2bfloat16_rn(v - __bfloat162float(h));
}

__device__ __forceinline__ void ldmatrix_x4(uint32_t* r, uint32_t addr) {
    asm volatile("ldmatrix.sync.aligned.m8n8.x4.shared.b16 {%0,%1,%2,%3}, [%4];"
        : "=r"(r[0]), "=r"(r[1]), "=r"(r[2]), "=r"(r[3]) : "r"(addr));
}

__device__ __forceinline__ void mma16816(float* c, const uint32_t* a,
                                         uint32_t b0, uint32_t b1) {
    asm volatile("mma.sync.aligned.m16n8k16.row.col.f32.bf16.bf16.f32 "
        "{%0,%1,%2,%3}, {%4,%5,%6,%7}, {%8,%9}, {%0,%1,%2,%3};"
        : "+f"(c[0]), "+f"(c[1]), "+f"(c[2]), "+f"(c[3])
        : "r"(a[0]), "r"(a[1]), "r"(a[2]), "r"(a[3]), "r"(b0), "r"(b1));
}

// ---------------- tensor-core GEMM (mma.sync bf16, fused 3-term split) ----
// C[M,N] = (Ah+Al)[M,K] @ (Wh+Wl)^T + bias   (W stored [N,K] K-major)
// CTA tile 256x128, 512 threads (16 warps = 8m x 2n, each 32x64).
// Per K-chunk (32): load Ah,Al,Wh,Wl once; acc += AhWh + AlWh + AhWl.
#define ROWB    80                  // 32 bf16 = 64B data, padded to 80B
#define AT_BYTES (256*ROWB)         // 20480
#define WT_BYTES (128*ROWB)         // 10240
#define STAGE_BYTES (2*AT_BYTES + 2*WT_BYTES)  // 61440
#define STAGES  3
#define SMEM_DYN (STAGES*STAGE_BYTES + 128)

__global__ __launch_bounds__(512, 1) void gemm_mma(
    const __nv_bfloat16* __restrict__ Ah, const __nv_bfloat16* __restrict__ Al,
    const __nv_bfloat16* __restrict__ Wh, const __nv_bfloat16* __restrict__ Wl,
    const float* __restrict__ bias,
    float* __restrict__ Cf,
    __nv_bfloat16* __restrict__ Chi, __nv_bfloat16* __restrict__ Clo,
    int K, int Nld, int relu)
{
    extern __shared__ char dynsmem[];
    uint32_t sbase = (smem_u32(dynsmem) + 127u) & ~127u;

    int tid  = threadIdx.x;
    int wid  = tid >> 5, lane = tid & 31;
    int wm   = wid & 7, wn = wid >> 3;           // 8 x 2 warp grid
    int m0   = blockIdx.y * 256, n0 = blockIdx.x * 128;

    const int NC = K >> 5;       // 32-elem chunks

    auto load_chunk = [&](int kc, int buf) {
        uint32_t tb = sbase + buf * STAGE_BYTES;
        #pragma unroll
        for (int i = 0; i < 6; i++) {
            int seg = tid + i * 512;             // 0..3071
            uint32_t dst;
            const __nv_bfloat16* src;
            if (seg < 2048) {                    // A tiles: 256 rows x 4 segs
                int row = (seg & 1023) >> 2;
                int c   = seg & 3;
                const __nv_bfloat16* base = (seg < 1024) ? Ah : Al;
                dst = tb + ((seg < 1024) ? 0u : (uint32_t)AT_BYTES)
                         + row * ROWB + c * 16;
                src = base + (size_t)(m0 + row) * K + kc * 32 + c * 8;
            } else {                             // W tiles: 128 rows x 4 segs
                int s2  = seg - 2048;
                int row = (s2 & 511) >> 2;
                int c   = s2 & 3;
                const __nv_bfloat16* base = (s2 < 512) ? Wh : Wl;
                dst = tb + 2 * AT_BYTES + ((s2 < 512) ? 0u : (uint32_t)WT_BYTES)
                         + row * ROWB + c * 16;
                src = base + (size_t)(n0 + row) * K + kc * 32 + c * 8;
            }
            asm volatile("cp.async.cg.shared.global [%0], [%1], 16;" :: "r"(dst), "l"(src));
        }
        asm volatile("cp.async.commit_group;" ::: "memory");
    };

    float acc[2][8][4];
    #pragma unroll
    for (int i = 0; i < 2; i++)
        #pragma unroll
        for (int j = 0; j < 8; j++)
            #pragma unroll
            for (int q = 0; q < 4; q++) acc[i][j][q] = 0.f;

    // prologue: 2 chunks in flight
    load_chunk(0, 0);
    if (NC > 1) load_chunk(1, 1);

    int lrow = lane & 15;               // smem row within 16-row group
    int lcol = (lane >> 4) << 4;        // +16B for k8..15 matrices

    for (int c = 0; c < NC; c++) {
        if (c < NC - 1) asm volatile("cp.async.wait_group 1;" ::: "memory");
        else            asm volatile("cp.async.wait_group 0;" ::: "memory");
        __syncthreads();

        uint32_t sb = sbase + (c % STAGES) * STAGE_BYTES;

        if (c + 2 < NC) load_chunk(c + 2, (c + 2) % STAGES);

        uint32_t aAddr = sb + (uint32_t)(wm * 32 + lrow) * ROWB + lcol;
        uint32_t bAddr = sb + 2 * AT_BYTES + (uint32_t)(wn * 64 + lrow) * ROWB + lcol;

        #pragma unroll
        for (int ks = 0; ks < 2; ks++) {
            uint32_t ah[2][4], al[2][4], b[4][4];
            #pragma unroll
            for (int i = 0; i < 2; i++) {
                ldmatrix_x4(ah[i], aAddr + i * (16 * ROWB) + ks * 32);
                ldmatrix_x4(al[i], aAddr + AT_BYTES + i * (16 * ROWB) + ks * 32);
            }
            // phase 1: b <- Wh fragments; terms Ah*Wh and Al*Wh
            #pragma unroll
            for (int jj = 0; jj < 4; jj++)
                ldmatrix_x4(b[jj], bAddr + jj * (16 * ROWB) + ks * 32);
            #pragma unroll
            for (int i = 0; i < 2; i++)
                #pragma unroll
                for (int jj = 0; jj < 4; jj++) {
                    mma16816(acc[i][2 * jj],     ah[i], b[jj][0], b[jj][2]);
                    mma16816(acc[i][2 * jj + 1], ah[i], b[jj][1], b[jj][3]);
                }
            #pragma unroll
            for (int i = 0; i < 2; i++)
                #pragma unroll
                for (int jj = 0; jj < 4; jj++) {
                    mma16816(acc[i][2 * jj],     al[i], b[jj][0], b[jj][2]);
                    mma16816(acc[i][2 * jj + 1], al[i], b[jj][1], b[jj][3]);
                }
            // phase 2: b <- Wl fragments; term Ah*Wl
            #pragma unroll
            for (int jj = 0; jj < 4; jj++)
                ldmatrix_x4(b[jj], bAddr + WT_BYTES + jj * (16 * ROWB) + ks * 32);
            #pragma unroll
            for (int i = 0; i < 2; i++)
                #pragma unroll
                for (int jj = 0; jj < 4; jj++) {
                    mma16816(acc[i][2 * jj],     ah[i], b[jj][0], b[jj][2]);
                    mma16816(acc[i][2 * jj + 1], ah[i], b[jj][1], b[jj][3]);
                }
        }
    }

    // ---------------- epilogue ----------------
    const float2* bp = (const float2*)(bias + n0 + wn * 64);
    float2 bv[8];
    #pragma unroll
    for (int j = 0; j < 8; j++) bv[j] = bp[j * 4 + (lane & 3)];

    #pragma unroll
    for (int i = 0; i < 2; i++) {
        int m_lo = m0 + wm * 32 + i * 16 + (lane >> 2);
        #pragma unroll
        for (int j = 0; j < 8; j++) {
            int n = n0 + wn * 64 + j * 8 + (lane & 3) * 2;
            float v0 = acc[i][j][0] + bv[j].x;
            float v1 = acc[i][j][1] + bv[j].y;
            float v2 = acc[i][j][2] + bv[j].x;
            float v3 = acc[i][j][3] + bv[j].y;
            if (relu) {
                v0 = fmaxf(v0, 0.f); v1 = fmaxf(v1, 0.f);
                v2 = fmaxf(v2, 0.f); v3 = fmaxf(v3, 0.f);
            }
            if (Cf) {
                *(float2*)(Cf + (size_t)m_lo * Nld + n)        = make_float2(v0, v1);
                *(float2*)(Cf + (size_t)(m_lo + 8) * Nld + n)  = make_float2(v2, v3);
            }
            if (Chi) {
                __nv_bfloat16 h0, l0, h1, l1;
                split_bf16(v0, h0, l0); split_bf16(v1, h1, l1);
                __nv_bfloat162 ph = __nv_bfloat162(h0, h1);
                __nv_bfloat162 pl = __nv_bfloat162(l0, l1);
                *(uint32_t*)(Chi + (size_t)m_lo * Nld + n) = *(uint32_t*)&ph;
                *(uint32_t*)(Clo + (size_t)m_lo * Nld + n) = *(uint32_t*)&pl;
                split_bf16(v2, h0, l0); split_bf16(v3, h1, l1);
                ph = __nv_bfloat162(h0, h1);
                pl = __nv_bfloat162(l0, l1);
                *(uint32_t*)(Chi + (size_t)(m_lo + 8) * Nld + n) = *(uint32_t*)&ph;
                *(uint32_t*)(Clo + (size_t)(m_lo + 8) * Nld + n) = *(uint32_t*)&pl;
            }
        }
    }
}

// ---------------- weight transpose + bf16 split ----------------
__global__ void wconv_kernel(const float* __restrict__ src,
                             __nv_bfloat16* __restrict__ dh,
                             __nv_bfloat16* __restrict__ dl,
                             int K, int N, int rowOff, int dstLd) {
    __shared__ float ts[32][33];
    int n0 = blockIdx.x * 32, k0 = blockIdx.y * 32;
    int tx = threadIdx.x, ty = threadIdx.y;  // 32x8
    #pragma unroll
    for (int j = 0; j < 4; j++)
        ts[ty + 8 * j][tx] = src[(size_t)(k0 + ty + 8 * j) * N + n0 + tx];
    __syncthreads();
    #pragma unroll
    for (int j = 0; j < 4; j++) {
        float v = ts[tx][ty + 8 * j];
        size_t di = (size_t)(rowOff + n0 + ty + 8 * j) * dstLd + k0 + tx;
        __nv_bfloat16 h, l;
        split_bf16(v, h, l);
        dh[di] = h; dl[di] = l;
    }
}

// fused Q/K/V weight conversion: blockIdx.z picks the source matrix.
__global__ void wconv3_kernel(const float* __restrict__ srcQ,
                              const float* __restrict__ srcK,
                              const float* __restrict__ srcV,
                              __nv_bfloat16* __restrict__ dh,
                              __nv_bfloat16* __restrict__ dl) {
    __shared__ float ts[32][33];
    int z = blockIdx.z;
    const float* src = (z == 0) ? srcQ : (z == 1) ? srcK : srcV;
    int rowOff = z * CHDK;
    int n0 = blockIdx.x * 32, k0 = blockIdx.y * 32;
    int tx = threadIdx.x, ty = threadIdx.y;  // 32x8
    #pragma unroll
    for (int j = 0; j < 4; j++)
        ts[ty + 8 * j][tx] = src[(size_t)(k0 + ty + 8 * j) * CHDK + n0 + tx];
    __syncthreads();
    #pragma unroll
    for (int j = 0; j < 4; j++) {
        float v = ts[tx][ty + 8 * j];
        size_t di = (size_t)(rowOff + n0 + ty + 8 * j) * CD + k0 + tx;
        __nv_bfloat16 h, l;
        split_bf16(v, h, l);
        dh[di] = h; dl[di] = l;
    }
}

__global__ void bqkv_kernel(const float* __restrict__ bq,
                            const float* __restrict__ bk,
                            const float* __restrict__ bv) {
    int i = blockIdx.x;
    for (int j = threadIdx.x; j < CQKV; j += 256)
        g_bqkv[i * CQKV + j] =
            (j < CHDK) ? bq[i * CHDK + j] :
            (j < 2 * CHDK) ? bk[i * CHDK + j - CHDK] : bv[i * CHDK + j - 2 * CHDK];
}

// ---------------- gather spans into g_x (+ bf16 split) ----------------
__global__ void gather_kernel(const float* __restrict__ q_enc,
                              const int* __restrict__ ranges) {
    int row = blockIdx.x;
    int be = row >> 4, l = row & 15;
    int b = be >> 5, e = be & 31;
    int st = ranges[(b * CE + e) * 2];
    int en = ranges[(b * CE + e) * 2 + 1];
    int src = min(max(st + l, 0), CS - 1);
    bool m = l < (en - st);
    const float* s = q_enc + ((size_t)b * CS + src) * CD;
    size_t base = (size_t)row * CD;
    for (int i = threadIdx.x; i < CD; i += 256) {
        float v = m ? s[i] : 0.f;
        g_x[base + i] = v;
        __nv_bfloat16 h, lo; split_bf16(v, h, lo);
        g_xh[base + i] = h; g_xl[base + i] = lo;
    }
}

// ---------------- fp32 SIMT GEMM (small tail matrices) ----------------
__global__ void gemm_bias_kernel(const float* __restrict__ A,
                                 const float* __restrict__ W,
                                 const float* __restrict__ bias,
                                 float* __restrict__ C,
                                 int M, int N, int K, int relu) {
    __shared__ float As[16][65];
    __shared__ float Bs[16][68];
    int tx = threadIdx.x, ty = threadIdx.y;
    int tid = ty * 16 + tx;
    int m0 = blockIdx.y * 64, n0 = blockIdx.x * 64;
    int a_row = tid >> 2, a_col = (tid & 3) << 2;
    int b_row = tid >> 4, b_col = (tid & 15) << 2;
    float acc[4][4] = {};
    for (int k0 = 0; k0 < K; k0 += 16) {
        int m = m0 + a_row;
        #pragma unroll
        for (int i = 0; i < 4; i++) {
            float v = 0.f;
            if (m < M) v = A[(size_t)m * K + k0 + a_col + i];
            As[a_col + i][a_row] = v;
        }
        #pragma unroll
        for (int i = 0; i < 4; i++) {
            int n = n0 + b_col + i;
            float v = 0.f;
            if (n < N) v = W[(size_t)(k0 + b_row) * N + n];
            Bs[b_row][b_col + i] = v;
        }
        __syncthreads();
        #pragma unroll
        for (int kk = 0; kk < 16; kk++) {
            float ra[4], rb[4];
            #pragma unroll
            for (int i = 0; i < 4; i++) ra[i] = As[kk][ty * 4 + i];
            #pragma unroll
            for (int j = 0; j < 4; j++) rb[j] = Bs[kk][tx * 4 + j];
            #pragma unroll
            for (int i = 0; i < 4; i++)
                #pragma unroll
                for (int j = 0; j < 4; j++)
                    acc[i][j] += ra[i] * rb[j];
        }
        __syncthreads();
    }
    #pragma unroll
    for (int i = 0; i < 4; i++) {
        int m = m0 + ty * 4 + i;
        if (m >= M) continue;
        #pragma unroll
        for (int j = 0; j < 4; j++) {
            int n = n0 + tx * 4 + j;
            if (n >= N) continue;
            float v = acc[i][j] + bias[n];
            if (relu) v = fmaxf(v, 0.f);
            C[(size_t)m * N + n] = v;
        }
    }
}

// ---------------- per-(span,head) attention ----------------
__global__ void attn_kernel() {
    int nh = blockIdx.x;
    int n = nh / CH, h = nh % CH;
    __shared__ float qs[16][129], ks[16][129], vs[16][129];
    __shared__ float sc[16][17];
    int tid = threadIdx.x;  // 128
    for (int idx = tid; idx < 16 * 128; idx += 128) {
        int l = idx >> 7, d = idx & 127;
        size_t base = ((size_t)(n * CL + l)) * CQKV + h * CDK + d;
        qs[l][d] = g_qkv[base];
        ks[l][d] = g_qkv[base + CHDK];
        vs[l][d] = g_qkv[base + 2 * CHDK];
    }
    __syncthreads();
    const float scale = 0.088388347648318447f;
    for (int p = tid; p < 256; p += 128) {
        int qi = p >> 4, ki = p & 15;
        float s = 0.f;
        #pragma unroll
        for (int d = 0; d < 128; d++) s += qs[qi][d] * ks[ki][d];
        sc[qi][ki] = s * scale;
    }
    __syncthreads();
    if (tid < 16) {
        float m = -1e30f;
        #pragma unroll
        for (int k = 0; k < 16; k++) m = fmaxf(m, sc[tid][k]);
        float sum = 0.f;
        #pragma unroll
        for (int k = 0; k < 16; k++) { float e = __expf(sc[tid][k] - m); sc[tid][k] = e; sum += e; }
        float inv = 1.f / sum;
        #pragma unroll
        for (int k = 0; k < 16; k++) sc[tid][k] *= inv;
    }
    __syncthreads();
    int d = tid;
    #pragma unroll
    for (int qi = 0; qi < 16; qi++) {
        float acc = 0.f;
        #pragma unroll
        for (int k = 0; k < 16; k++) acc += sc[qi][k] * vs[k][d];
        size_t oi = ((size_t)(n * CL + qi)) * CHDK + h * CDK + d;
        __nv_bfloat16 hh, ll; split_bf16(acc, hh, ll);
        g_oh[oi] = hh; g_ol[oi] = ll;
    }
}

// ---------------- x = LN(x + t) (+ bf16 split) ----------------
__device__ __forceinline__ float blockReduceSum(float val) {
    __shared__ float sh[32];
    int lane = threadIdx.x & 31, wid = threadIdx.x >> 5;
    #pragma unroll
    for (int o = 16; o > 0; o >>= 1) val += __shfl_xor_sync(0xffffffffu, val, o);
    if (lane == 0) sh[wid] = val;
    __syncthreads();
    int nw = (blockDim.x + 31) >> 5;
    val = (threadIdx.x < nw) ? sh[lane] : 0.f;
    if (wid == 0) {
        #pragma unroll
        for (int o = 16; o > 0; o >>= 1) val += __shfl_xor_sync(0xffffffffu, val, o);
    }
    return val;
}

__global__ void add_ln_kernel(const float* __restrict__ gamma,
                              const float* __restrict__ beta) {
    int row = blockIdx.x;
    int tid = threadIdx.x;
    float v[3];
    float s = 0.f;
    #pragma unroll
    for (int j = 0; j < 3; j++) {
        size_t idx = (size_t)row * CD + tid + j * 256;
        v[j] = g_x[idx] + g_t[idx];
        s += v[j];
    }
    s = blockReduceSum(s);
    __shared__ float mean_s, rstd_s;
    if (tid == 0) mean_s = s * (1.f / CD);
    __syncthreads();
    float m = mean_s;
    float vv = 0.f;
    #pragma unroll
    for (int j = 0; j < 3; j++) { float d = v[j] - m; vv += d * d; }
    vv = blockReduceSum(vv);
    if (tid == 0) rstd_s = rsqrtf(vv * (1.f / CD) + 1e-5f);
    __syncthreads();
    float r = rstd_s;
    #pragma unroll
    for (int j = 0; j < 3; j++) {
        int c = tid + j * 256;
        float o = (v[j] - m) * r * gamma[c] + beta[c];
        size_t idx = (size_t)row * CD + c;
        g_x[idx] = o;
        __nv_bfloat16 h, l; split_bf16(o, h, l);
        g_xh[idx] = h; g_xl[idx] = l;
    }
}

// ---------------- tail kernels ----------------
__global__ void copy_ent_kernel() {
    int r = blockIdx.x;
    for (int d = threadIdx.x; d < CD; d += 256)
        g_ent[(size_t)r * CD + d] = g_x[(size_t)r * CL * CD + d];
}

__global__ void pool_attn_kernel(const float* __restrict__ q_enc,
                                 const float* __restrict__ hint) {
    int t = blockIdx.x, b = blockIdx.y;
    __shared__ float qv[770];
    __shared__ float lg[32];
    int tid = threadIdx.x;
    for (int i = tid; i < 770; i += 256)
        qv[i] = (i < CD) ? q_enc[((size_t)b * CS + t) * CD + i]
                         : hint[((size_t)b * CTQ + t) * 2 + (i - CD)];
    __syncthreads();
    int e = tid >> 3, sub = tid & 7;
    const float* ep = g_entp + ((size_t)b * CE + e) * 770;
    float p = 0.f;
    for (int d = sub; d < 770; d += 8) p += qv[d] * ep[d];
    p += __shfl_down_sync(0xffffffffu, p, 4, 8);
    p += __shfl_down_sync(0xffffffffu, p, 2, 8);
    p += __shfl_down_sync(0xffffffffu, p, 1, 8);
    if (sub == 0) lg[e] = p;
    __syncthreads();
    if (tid < 32) {
        float v = lg[tid];
        float m = v;
        #pragma unroll
        for (int o = 16; o > 0; o >>= 1) m = fmaxf(m, __shfl_xor_sync(0xffffffffu, m, o));
        float ex = __expf(v - m);
        float sm = ex;
        #pragma unroll
        for (int o = 16; o > 0; o >>= 1) sm += __shfl_xor_sync(0xffffffffu, sm, o);
        g_attnw[((size_t)b * CTQ + t) * CE + tid] = ex / sm;
    }
}

__global__ void pool_wa_kernel(const int* __restrict__ qlen) {
    int b = blockIdx.x;
    int tid = threadIdx.x;
    __shared__ float A[32];
    int n = qlen[b];
    if (tid < 32) {
        float s = 0.f;
        for (int t = 0; t < n; t++) s += g_attnw[((size_t)b * CTQ + t) * CE + tid];
        A[tid] = s;
    }
    __syncthreads();
    #pragma unroll
    for (int j = 0; j < 3; j++) {
        int d = tid + j * 256;
        float s = 0.f;
        #pragma unroll
        for (int e = 0; e < 32; e++) s += A[e] * g_ent[((size_t)b * CE + e) * CD + d];
        g_wa[(size_t)b * CD + d] = s;
    }
}

__global__ void feat_kernel(const float* __restrict__ q_enc) {
    int b = blockIdx.x;
    for (int i = threadIdx.x; i < 2 * CD; i += 256)
        g_feat[(size_t)b * 2 * CD + i] =
            (i < CD) ? q_enc[(size_t)b * CS * CD + i] : g_wa[(size_t)b * CD + (i - CD)];
}

__global__ void head_out_kernel(const float* __restrict__ W2,
                                const float* __restrict__ b2,
                                float* __restrict__ out) {
    int b = blockIdx.x, tid = threadIdx.x;
    float s = 0.f;
    for (int n = tid; n < CNH; n += 256) s += g_h[(size_t)b * CNH + n] * W2[n];
    s = blockReduceSum(s);
    if (tid == 0) out[b] = s + b2[0];
}

// ---------------- host ----------------
template <typename T>
static T* dsym(const void* symbol) {
    void* p = nullptr;
    cudaGetSymbolAddress(&p, symbol);
    return (T*)p;
}

extern "C" void kernel_launch(void* const* d_in, const int* in_sizes, int n_in,
                              void* d_out, int out_size) {
    const float* q_enc  = (const float*)d_in[0];
    const int*   q_qlen = (const int*)  d_in[1];
    const float* hint   = (const float*)d_in[2];
    const int*   ranges = (const int*)  d_in[3];
    const float* Wq  = (const float*)d_in[4];
    const float* bq  = (const float*)d_in[5];
    const float* Wk  = (const float*)d_in[6];
    const float* bk  = (const float*)d_in[7];
    const float* Wv  = (const float*)d_in[8];
    const float* bv  = (const float*)d_in[9];
    const float* Wo  = (const float*)d_in[10];
    const float* bo  = (const float*)d_in[11];
    const float* ln1g = (const float*)d_in[12];
    const float* ln1b = (const float*)d_in[13];
    const float* Wf1 = (const float*)d_in[14];
    const float* bf1 = (const float*)d_in[15];
    const float* Wf2 = (const float*)d_in[16];
    const float* bf2 = (const float*)d_in[17];
    const float* ln2g = (const float*)d_in[18];
    const float* ln2b = (const float*)d_in[19];
    const float* W_ea = (const float*)d_in[20];
    const float* b_ea = (const float*)d_in[21];
    const float* W1  = (const float*)d_in[22];
    const float* b1  = (const float*)d_in[23];
    const float* W2  = (const float*)d_in[24];
    const float* b2  = (const float*)d_in[25];
    float* out = (float*)d_out;

    cudaFuncSetAttribute(gemm_mma, cudaFuncAttributeMaxDynamicSharedMemorySize, SMEM_DYN);

    __nv_bfloat16* xh  = dsym<__nv_bfloat16>(g_xh);
    __nv_bfloat16* xl  = dsym<__nv_bfloat16>(g_xl);
    __nv_bfloat16* oh  = dsym<__nv_bfloat16>(g_oh);
    __nv_bfloat16* ol  = dsym<__nv_bfloat16>(g_ol);
    __nv_bfloat16* fh  = dsym<__nv_bfloat16>(g_fh);
    __nv_bfloat16* fl  = dsym<__nv_bfloat16>(g_fl);
    float* qkv = dsym<float>(g_qkv);
    float* t_  = dsym<float>(g_t);
    __nv_bfloat16* wqkvh = dsym<__nv_bfloat16>(g_wqkvh);
    __nv_bfloat16* wqkvl = dsym<__nv_bfloat16>(g_wqkvl);
    __nv_bfloat16* woh   = dsym<__nv_bfloat16>(g_woh);
    __nv_bfloat16* wol   = dsym<__nv_bfloat16>(g_wol);
    __nv_bfloat16* wf1h  = dsym<__nv_bfloat16>(g_wf1h);
    __nv_bfloat16* wf1l  = dsym<__nv_bfloat16>(g_wf1l);
    __nv_bfloat16* wf2h  = dsym<__nv_bfloat16>(g_wf2h);
    __nv_bfloat16* wf2l  = dsym<__nv_bfloat16>(g_wf2l);
    float* bqkv = dsym<float>(g_bqkv);
    float* x    = dsym<float>(g_x);
    float* ent  = dsym<float>(g_ent);
    float* entp = dsym<float>(g_entp);
    float* feat = dsym<float>(g_feat);
    float* h_   = dsym<float>(g_h);

    dim3 wblk(32, 8);

    // launch 0: fused layer-0 QKV weight conversion (grid.z = 3)
    wconv3_kernel<<<dim3(CHDK/32, CD/32, 3), wblk>>>(Wq, Wk, Wv, wqkvh, wqkvl);
    // launch 1: bias concat, launch 2: gather
    bqkv_kernel<<<CNL, 256>>>(bq, bk, bv);
    gather_kernel<<<NROWS, 256>>>(q_enc, ranges);

    // launch 3: the big QKV GEMM (layer 0) — ncu window target
    gemm_mma<<<dim3(CQKV/128, NROWS/256), 512, SMEM_DYN>>>(
        xh, xl, wqkvh, wqkvl, bqkv,
        qkv, nullptr, nullptr, CD, CQKV, 0);

    // remaining weight conversions (stream-ordered before their gemms)
    for (int i = 0; i < CNL; i++) {
        if (i > 0) {
            size_t oQ = (size_t)i * CQKV * CD;
            wconv3_kernel<<<dim3(CHDK/32, CD/32, 3), wblk>>>(
                Wq + (size_t)i*CD*CHDK, Wk + (size_t)i*CD*CHDK, Wv + (size_t)i*CD*CHDK,
                wqkvh + oQ, wqkvl + oQ);
        }
        size_t oO = (size_t)i * CD * CHDK;
        wconv_kernel<<<dim3(CD/32, CHDK/32), wblk>>>(Wo + (size_t)i*CHDK*CD, woh + oO, wol + oO, CHDK, CD, 0, CHDK);
        size_t oF1 = (size_t)i * CDFF * CD;
        wconv_kernel<<<dim3(CDFF/32, CD/32), wblk>>>(Wf1 + (size_t)i*CD*CDFF, wf1h + oF1, wf1l + oF1, CD, CDFF, 0, CD);
        size_t oF2 = (size_t)i * CD * CDFF;
        wconv_kernel<<<dim3(CD/32, CDFF/32), wblk>>>(Wf2 + (size_t)i*CDFF*CD, wf2h + oF2, wf2l + oF2, CDFF, CD, 0, CDFF);
    }

    for (int i = 0; i < CNL; i++) {
        size_t oQ  = (size_t)i * CQKV * CD;
        size_t oO  = (size_t)i * CD * CHDK;
        size_t oF1 = (size_t)i * CDFF * CD;
        size_t oF2 = (size_t)i * CD * CDFF;

        if (i > 0) {
            gemm_mma<<<dim3(CQKV/128, NROWS/256), 512, SMEM_DYN>>>(
                xh, xl, wqkvh + oQ, wqkvl + oQ, bqkv + i*CQKV,
                qkv, nullptr, nullptr, CD, CQKV, 0);
        }

        attn_kernel<<<NENT * CH, 128>>>();

        gemm_mma<<<dim3(CD/128, NROWS/256), 512, SMEM_DYN>>>(
            oh, ol, woh + oO, wol + oO, bo + i*CD,
            t_, nullptr, nullptr, CHDK, CD, 0);

        add_ln_kernel<<<NROWS, 256>>>(ln1g + i*CD, ln1b + i*CD);

        gemm_mma<<<dim3(CDFF/128, NROWS/256), 512, SMEM_DYN>>>(
            xh, xl, wf1h + oF1, wf1l + oF1, bf1 + i*CDFF,
            nullptr, fh, fl, CD, CDFF, 1);

        gemm_mma<<<dim3(CD/128, NROWS/256), 512, SMEM_DYN>>>(
            fh, fl, wf2h + oF2, wf2l + oF2, bf2 + i*CD,
            t_, nullptr, nullptr, CDFF, CD, 0);

        add_ln_kernel<<<NROWS, 256>>>(ln2g + i*CD, ln2b + i*CD);
    }

    dim3 blk(16, 16);
    copy_ent_kernel<<<NENT, 256>>>();
    gemm_bias_kernel<<<dim3((770 + 63) / 64, NENT / 64), blk>>>(ent, W_ea, b_ea, entp, NENT, 770, CD, 0);
    pool_attn_kernel<<<dim3(CTQ, CB), 256>>>(q_enc, hint);
    pool_wa_kernel<<<CB, 256>>>(q_qlen);
    feat_kernel<<<CB, 256>>>(q_enc);
    gemm_bias_kernel<<<dim3(CNH / 64, 1), blk>>>(feat, W1, b1, h_, CB, CNH, 2 * CD, 1);
    head_out_kernel<<<CB, 256>>>(W2, b2, out);
}

// round 8
// speedup vs baseline: 4.4549x; 1.3193x over previous
#include <cuda_runtime.h>
#include <cuda_bf16.h>
#include <math.h>
#include <stdint.h>

// ---------------- problem constants ----------------
#define CB   64
#define CS   512
#define CD   768
#define CE   32
#define CL   16
#define CTQ  128
#define CH   3
#define CDK  128
#define CHDK 384
#define CQKV 1152
#define CDFF 3072
#define CNH  1024
#define CNL  3
#define NROWS (CB*CE*CL)     // 32768
#define NENT  (CB*CE)        // 2048

// ---------------- device scratch ----------------
__device__ float          g_x  [NROWS*CD];
__device__ __nv_bfloat16  g_xh [NROWS*CD];
__device__ __nv_bfloat16  g_xl [NROWS*CD];
__device__ float          g_qkv[NROWS*CQKV];
__device__ __nv_bfloat16  g_oh [NROWS*CHDK];
__device__ __nv_bfloat16  g_ol [NROWS*CHDK];
__device__ __nv_bfloat16  g_fh [NROWS*CDFF];
__device__ __nv_bfloat16  g_fl [NROWS*CDFF];
__device__ float          g_t  [NROWS*CD];

// compact (last-layer) buffers: 2048 rows
__device__ float          g_xc [NENT*CD];
__device__ __nv_bfloat16  g_xch[NENT*CD];
__device__ __nv_bfloat16  g_xcl[NENT*CD];

__device__ __nv_bfloat16  g_wqkvh[CNL*CQKV*CD], g_wqkvl[CNL*CQKV*CD];
__device__ __nv_bfloat16  g_woh [CNL*CD*CHDK],  g_wol [CNL*CD*CHDK];
__device__ __nv_bfloat16  g_wf1h[CNL*CDFF*CD],  g_wf1l[CNL*CDFF*CD];
__device__ __nv_bfloat16  g_wf2h[CNL*CD*CDFF],  g_wf2l[CNL*CD*CDFF];
__device__ float          g_bqkv[CNL*CQKV];

__device__ float g_ent [NENT*CD];
__device__ float g_entp[NENT*770];
__device__ float g_attnw[CB*CTQ*CE];
__device__ float g_wa  [CB*CD];
__device__ float g_feat[CB*2*CD];
__device__ float g_h   [CB*CNH];

// ---------------- helpers ----------------
__device__ __forceinline__ uint32_t smem_u32(const void* p) {
    uint32_t a;
    asm("{ .reg .u64 t; cvta.to.shared.u64 t, %1; cvt.u32.u64 %0, t; }" : "=r"(a) : "l"(p));
    return a;
}

__device__ __forceinline__ void split_bf16(float v, __nv_bfloat16& h, __nv_bfloat16& l) {
    h = __float2bfloat16_rn(v);
    l = __float2bfloat16_rn(v - __bfloat162float(h));
}

__device__ __forceinline__ void ldmatrix_x4(uint32_t* r, uint32_t addr) {
    asm volatile("ldmatrix.sync.aligned.m8n8.x4.shared.b16 {%0,%1,%2,%3}, [%4];"
        : "=r"(r[0]), "=r"(r[1]), "=r"(r[2]), "=r"(r[3]) : "r"(addr));
}

__device__ __forceinline__ void mma16816(float* c, const uint32_t* a,
                                         uint32_t b0, uint32_t b1) {
    asm volatile("mma.sync.aligned.m16n8k16.row.col.f32.bf16.bf16.f32 "
        "{%0,%1,%2,%3}, {%4,%5,%6,%7}, {%8,%9}, {%0,%1,%2,%3};"
        : "+f"(c[0]), "+f"(c[1]), "+f"(c[2]), "+f"(c[3])
        : "r"(a[0]), "r"(a[1]), "r"(a[2]), "r"(a[3]), "r"(b0), "r"(b1));
}

// ---------------- tensor-core GEMM (mma.sync bf16, fused 3-term split) ----
// C[M,N] = (Ah+Al)[M,K] @ (Wh+Wl)^T + bias   (W stored [N,K] K-major)
// CTA tile 256x128, 512 threads (16 warps = 8m x 2n, each 32x64).
#define ROWB    80                  // 32 bf16 = 64B data, padded to 80B
#define AT_BYTES (256*ROWB)         // 20480
#define WT_BYTES (128*ROWB)         // 10240
#define STAGE_BYTES (2*AT_BYTES + 2*WT_BYTES)  // 61440
#define STAGES  3
#define SMEM_DYN (STAGES*STAGE_BYTES + 128)

__global__ __launch_bounds__(512, 1) void gemm_mma(
    const __nv_bfloat16* __restrict__ Ah, const __nv_bfloat16* __restrict__ Al,
    const __nv_bfloat16* __restrict__ Wh, const __nv_bfloat16* __restrict__ Wl,
    const float* __restrict__ bias,
    float* __restrict__ Cf,
    __nv_bfloat16* __restrict__ Chi, __nv_bfloat16* __restrict__ Clo,
    int K, int Nld, int relu)
{
    extern __shared__ char dynsmem[];
    uint32_t sbase = (smem_u32(dynsmem) + 127u) & ~127u;

    int tid  = threadIdx.x;
    int wid  = tid >> 5, lane = tid & 31;
    int wm   = wid & 7, wn = wid >> 3;           // 8 x 2 warp grid
    int m0   = blockIdx.y * 256, n0 = blockIdx.x * 128;

    const int NC = K >> 5;       // 32-elem chunks

    auto load_chunk = [&](int kc, int buf) {
        uint32_t tb = sbase + buf * STAGE_BYTES;
        #pragma unroll
        for (int i = 0; i < 6; i++) {
            int seg = tid + i * 512;             // 0..3071
            uint32_t dst;
            const __nv_bfloat16* src;
            if (seg < 2048) {                    // A tiles: 256 rows x 4 segs
                int row = (seg & 1023) >> 2;
                int c   = seg & 3;
                const __nv_bfloat16* base = (seg < 1024) ? Ah : Al;
                dst = tb + ((seg < 1024) ? 0u : (uint32_t)AT_BYTES)
                         + row * ROWB + c * 16;
                src = base + (size_t)(m0 + row) * K + kc * 32 + c * 8;
            } else {                             // W tiles: 128 rows x 4 segs
                int s2  = seg - 2048;
                int row = (s2 & 511) >> 2;
                int c   = s2 & 3;
                const __nv_bfloat16* base = (s2 < 512) ? Wh : Wl;
                dst = tb + 2 * AT_BYTES + ((s2 < 512) ? 0u : (uint32_t)WT_BYTES)
                         + row * ROWB + c * 16;
                src = base + (size_t)(n0 + row) * K + kc * 32 + c * 8;
            }
            asm volatile("cp.async.cg.shared.global [%0], [%1], 16;" :: "r"(dst), "l"(src));
        }
        asm volatile("cp.async.commit_group;" ::: "memory");
    };

    float acc[2][8][4];
    #pragma unroll
    for (int i = 0; i < 2; i++)
        #pragma unroll
        for (int j = 0; j < 8; j++)
            #pragma unroll
            for (int q = 0; q < 4; q++) acc[i][j][q] = 0.f;

    // prologue: 2 chunks in flight
    load_chunk(0, 0);
    if (NC > 1) load_chunk(1, 1);

    int lrow = lane & 15;               // smem row within 16-row group
    int lcol = (lane >> 4) << 4;        // +16B for k8..15 matrices

    for (int c = 0; c < NC; c++) {
        if (c < NC - 1) asm volatile("cp.async.wait_group 1;" ::: "memory");
        else            asm volatile("cp.async.wait_group 0;" ::: "memory");
        __syncthreads();

        uint32_t sb = sbase + (c % STAGES) * STAGE_BYTES;

        if (c + 2 < NC) load_chunk(c + 2, (c + 2) % STAGES);

        uint32_t aAddr = sb + (uint32_t)(wm * 32 + lrow) * ROWB + lcol;
        uint32_t bAddr = sb + 2 * AT_BYTES + (uint32_t)(wn * 64 + lrow) * ROWB + lcol;

        #pragma unroll
        for (int ks = 0; ks < 2; ks++) {
            uint32_t ah[2][4], al[2][4], b[4][4];
            #pragma unroll
            for (int i = 0; i < 2; i++) {
                ldmatrix_x4(ah[i], aAddr + i * (16 * ROWB) + ks * 32);
                ldmatrix_x4(al[i], aAddr + AT_BYTES + i * (16 * ROWB) + ks * 32);
            }
            // phase 1: b <- Wh fragments; terms Ah*Wh and Al*Wh
            #pragma unroll
            for (int jj = 0; jj < 4; jj++)
                ldmatrix_x4(b[jj], bAddr + jj * (16 * ROWB) + ks * 32);
            #pragma unroll
            for (int i = 0; i < 2; i++)
                #pragma unroll
                for (int jj = 0; jj < 4; jj++) {
                    mma16816(acc[i][2 * jj],     ah[i], b[jj][0], b[jj][2]);
                    mma16816(acc[i][2 * jj + 1], ah[i], b[jj][1], b[jj][3]);
                }
            #pragma unroll
            for (int i = 0; i < 2; i++)
                #pragma unroll
                for (int jj = 0; jj < 4; jj++) {
                    mma16816(acc[i][2 * jj],     al[i], b[jj][0], b[jj][2]);
                    mma16816(acc[i][2 * jj + 1], al[i], b[jj][1], b[jj][3]);
                }
            // phase 2: b <- Wl fragments; term Ah*Wl
            #pragma unroll
            for (int jj = 0; jj < 4; jj++)
                ldmatrix_x4(b[jj], bAddr + WT_BYTES + jj * (16 * ROWB) + ks * 32);
            #pragma unroll
            for (int i = 0; i < 2; i++)
                #pragma unroll
                for (int jj = 0; jj < 4; jj++) {
                    mma16816(acc[i][2 * jj],     ah[i], b[jj][0], b[jj][2]);
                    mma16816(acc[i][2 * jj + 1], ah[i], b[jj][1], b[jj][3]);
                }
        }
    }

    // ---------------- epilogue ----------------
    const float2* bp = (const float2*)(bias + n0 + wn * 64);
    float2 bv[8];
    #pragma unroll
    for (int j = 0; j < 8; j++) bv[j] = bp[j * 4 + (lane & 3)];

    #pragma unroll
    for (int i = 0; i < 2; i++) {
        int m_lo = m0 + wm * 32 + i * 16 + (lane >> 2);
        #pragma unroll
        for (int j = 0; j < 8; j++) {
            int n = n0 + wn * 64 + j * 8 + (lane & 3) * 2;
            float v0 = acc[i][j][0] + bv[j].x;
            float v1 = acc[i][j][1] + bv[j].y;
            float v2 = acc[i][j][2] + bv[j].x;
            float v3 = acc[i][j][3] + bv[j].y;
            if (relu) {
                v0 = fmaxf(v0, 0.f); v1 = fmaxf(v1, 0.f);
                v2 = fmaxf(v2, 0.f); v3 = fmaxf(v3, 0.f);
            }
            if (Cf) {
                *(float2*)(Cf + (size_t)m_lo * Nld + n)        = make_float2(v0, v1);
                *(float2*)(Cf + (size_t)(m_lo + 8) * Nld + n)  = make_float2(v2, v3);
            }
            if (Chi) {
                __nv_bfloat16 h0, l0, h1, l1;
                split_bf16(v0, h0, l0); split_bf16(v1, h1, l1);
                __nv_bfloat162 ph = __nv_bfloat162(h0, h1);
                __nv_bfloat162 pl = __nv_bfloat162(l0, l1);
                *(uint32_t*)(Chi + (size_t)m_lo * Nld + n) = *(uint32_t*)&ph;
                *(uint32_t*)(Clo + (size_t)m_lo * Nld + n) = *(uint32_t*)&pl;
                split_bf16(v2, h0, l0); split_bf16(v3, h1, l1);
                ph = __nv_bfloat162(h0, h1);
                pl = __nv_bfloat162(l0, l1);
                *(uint32_t*)(Chi + (size_t)(m_lo + 8) * Nld + n) = *(uint32_t*)&ph;
                *(uint32_t*)(Clo + (size_t)(m_lo + 8) * Nld + n) = *(uint32_t*)&pl;
            }
        }
    }
}

// ---------------- weight transpose + bf16 split ----------------
__global__ void wconv_kernel(const float* __restrict__ src,
                             __nv_bfloat16* __restrict__ dh,
                             __nv_bfloat16* __restrict__ dl,
                             int K, int N, int rowOff, int dstLd) {
    __shared__ float ts[32][33];
    int n0 = blockIdx.x * 32, k0 = blockIdx.y * 32;
    int tx = threadIdx.x, ty = threadIdx.y;  // 32x8
    #pragma unroll
    for (int j = 0; j < 4; j++)
        ts[ty + 8 * j][tx] = src[(size_t)(k0 + ty + 8 * j) * N + n0 + tx];
    __syncthreads();
    #pragma unroll
    for (int j = 0; j < 4; j++) {
        float v = ts[tx][ty + 8 * j];
        size_t di = (size_t)(rowOff + n0 + ty + 8 * j) * dstLd + k0 + tx;
        __nv_bfloat16 h, l;
        split_bf16(v, h, l);
        dh[di] = h; dl[di] = l;
    }
}

// fused Q/K/V weight conversion: blockIdx.z picks the source matrix.
__global__ void wconv3_kernel(const float* __restrict__ srcQ,
                              const float* __restrict__ srcK,
                              const float* __restrict__ srcV,
                              __nv_bfloat16* __restrict__ dh,
                              __nv_bfloat16* __restrict__ dl) {
    __shared__ float ts[32][33];
    int z = blockIdx.z;
    const float* src = (z == 0) ? srcQ : (z == 1) ? srcK : srcV;
    int rowOff = z * CHDK;
    int n0 = blockIdx.x * 32, k0 = blockIdx.y * 32;
    int tx = threadIdx.x, ty = threadIdx.y;  // 32x8
    #pragma unroll
    for (int j = 0; j < 4; j++)
        ts[ty + 8 * j][tx] = src[(size_t)(k0 + ty + 8 * j) * CHDK + n0 + tx];
    __syncthreads();
    #pragma unroll
    for (int j = 0; j < 4; j++) {
        float v = ts[tx][ty + 8 * j];
        size_t di = (size_t)(rowOff + n0 + ty + 8 * j) * CD + k0 + tx;
        __nv_bfloat16 h, l;
        split_bf16(v, h, l);
        dh[di] = h; dl[di] = l;
    }
}

__global__ void bqkv_kernel(const float* __restrict__ bq,
                            const float* __restrict__ bk,
                            const float* __restrict__ bv) {
    int i = blockIdx.x;
    for (int j = threadIdx.x; j < CQKV; j += 256)
        g_bqkv[i * CQKV + j] =
            (j < CHDK) ? bq[i * CHDK + j] :
            (j < 2 * CHDK) ? bk[i * CHDK + j - CHDK] : bv[i * CHDK + j - 2 * CHDK];
}

// ---------------- gather spans into g_x (+ bf16 split) ----------------
__global__ void gather_kernel(const float* __restrict__ q_enc,
                              const int* __restrict__ ranges) {
    int row = blockIdx.x;
    int be = row >> 4, l = row & 15;
    int b = be >> 5, e = be & 31;
    int st = ranges[(b * CE + e) * 2];
    int en = ranges[(b * CE + e) * 2 + 1];
    int src = min(max(st + l, 0), CS - 1);
    bool m = l < (en - st);
    const float* s = q_enc + ((size_t)b * CS + src) * CD;
    size_t base = (size_t)row * CD;
    for (int i = threadIdx.x; i < CD; i += 256) {
        float v = m ? s[i] : 0.f;
        g_x[base + i] = v;
        __nv_bfloat16 h, lo; split_bf16(v, h, lo);
        g_xh[base + i] = h; g_xl[base + i] = lo;
    }
}

// ---------------- fp32 SIMT GEMM (small tail matrices) ----------------
__global__ void gemm_bias_kernel(const float* __restrict__ A,
                                 const float* __restrict__ W,
                                 const float* __restrict__ bias,
                                 float* __restrict__ C,
                                 int M, int N, int K, int relu) {
    __shared__ float As[16][65];
    __shared__ float Bs[16][68];
    int tx = threadIdx.x, ty = threadIdx.y;
    int tid = ty * 16 + tx;
    int m0 = blockIdx.y * 64, n0 = blockIdx.x * 64;
    int a_row = tid >> 2, a_col = (tid & 3) << 2;
    int b_row = tid >> 4, b_col = (tid & 15) << 2;
    float acc[4][4] = {};
    for (int k0 = 0; k0 < K; k0 += 16) {
        int m = m0 + a_row;
        #pragma unroll
        for (int i = 0; i < 4; i++) {
            float v = 0.f;
            if (m < M) v = A[(size_t)m * K + k0 + a_col + i];
            As[a_col + i][a_row] = v;
        }
        #pragma unroll
        for (int i = 0; i < 4; i++) {
            int n = n0 + b_col + i;
            float v = 0.f;
            if (n < N) v = W[(size_t)(k0 + b_row) * N + n];
            Bs[b_row][b_col + i] = v;
        }
        __syncthreads();
        #pragma unroll
        for (int kk = 0; kk < 16; kk++) {
            float ra[4], rb[4];
            #pragma unroll
            for (int i = 0; i < 4; i++) ra[i] = As[kk][ty * 4 + i];
            #pragma unroll
            for (int j = 0; j < 4; j++) rb[j] = Bs[kk][tx * 4 + j];
            #pragma unroll
            for (int i = 0; i < 4; i++)
                #pragma unroll
                for (int j = 0; j < 4; j++)
                    acc[i][j] += ra[i] * rb[j];
        }
        __syncthreads();
    }
    #pragma unroll
    for (int i = 0; i < 4; i++) {
        int m = m0 + ty * 4 + i;
        if (m >= M) continue;
        #pragma unroll
        for (int j = 0; j < 4; j++) {
            int n = n0 + tx * 4 + j;
            if (n >= N) continue;
            float v = acc[i][j] + bias[n];
            if (relu) v = fmaxf(v, 0.f);
            C[(size_t)m * N + n] = v;
        }
    }
}

// ---------------- per-(span,head) attention (full, layers 0..NL-2) -------
__global__ void attn_kernel() {
    int nh = blockIdx.x;
    int n = nh / CH, h = nh % CH;
    __shared__ float qs[16][129], ks[16][129], vs[16][129];
    __shared__ float sc[16][17];
    int tid = threadIdx.x;  // 128
    for (int idx = tid; idx < 16 * 128; idx += 128) {
        int l = idx >> 7, d = idx & 127;
        size_t base = ((size_t)(n * CL + l)) * CQKV + h * CDK + d;
        qs[l][d] = g_qkv[base];
        ks[l][d] = g_qkv[base + CHDK];
        vs[l][d] = g_qkv[base + 2 * CHDK];
    }
    __syncthreads();
    const float scale = 0.088388347648318447f;
    for (int p = tid; p < 256; p += 128) {
        int qi = p >> 4, ki = p & 15;
        float s = 0.f;
        #pragma unroll
        for (int d = 0; d < 128; d++) s += qs[qi][d] * ks[ki][d];
        sc[qi][ki] = s * scale;
    }
    __syncthreads();
    if (tid < 16) {
        float m = -1e30f;
        #pragma unroll
        for (int k = 0; k < 16; k++) m = fmaxf(m, sc[tid][k]);
        float sum = 0.f;
        #pragma unroll
        for (int k = 0; k < 16; k++) { float e = __expf(sc[tid][k] - m); sc[tid][k] = e; sum += e; }
        float inv = 1.f / sum;
        #pragma unroll
        for (int k = 0; k < 16; k++) sc[tid][k] *= inv;
    }
    __syncthreads();
    int d = tid;
    #pragma unroll
    for (int qi = 0; qi < 16; qi++) {
        float acc = 0.f;
        #pragma unroll
        for (int k = 0; k < 16; k++) acc += sc[qi][k] * vs[k][d];
        size_t oi = ((size_t)(n * CL + qi)) * CHDK + h * CDK + d;
        __nv_bfloat16 hh, ll; split_bf16(acc, hh, ll);
        g_oh[oi] = hh; g_ol[oi] = ll;
    }
}

// last layer: only query position 0 is needed; writes COMPACT rows (2048).
__global__ void attn0_kernel() {
    int nh = blockIdx.x;
    int n = nh / CH, h = nh % CH;
    __shared__ float ks[16][129], vs[16][129];
    __shared__ float q0[128];
    __shared__ float p[16];
    int tid = threadIdx.x;  // 128
    for (int idx = tid; idx < 16 * 128; idx += 128) {
        int l = idx >> 7, d = idx & 127;
        size_t base = ((size_t)(n * CL + l)) * CQKV + h * CDK + d;
        ks[l][d] = g_qkv[base + CHDK];
        vs[l][d] = g_qkv[base + 2 * CHDK];
    }
    q0[tid] = g_qkv[((size_t)(n * CL)) * CQKV + h * CDK + tid];
    __syncthreads();
    const float scale = 0.088388347648318447f;
    if (tid < 16) {
        float s = 0.f;
        #pragma unroll
        for (int d = 0; d < 128; d++) s += q0[d] * ks[tid][d];
        p[tid] = s * scale;
    }
    __syncthreads();
    if (tid == 0) {
        float m = -1e30f;
        #pragma unroll
        for (int k = 0; k < 16; k++) m = fmaxf(m, p[k]);
        float sum = 0.f;
        #pragma unroll
        for (int k = 0; k < 16; k++) { float e = __expf(p[k] - m); p[k] = e; sum += e; }
        float inv = 1.f / sum;
        #pragma unroll
        for (int k = 0; k < 16; k++) p[k] *= inv;
    }
    __syncthreads();
    float acc = 0.f;
    #pragma unroll
    for (int k = 0; k < 16; k++) acc += p[k] * vs[k][tid];
    size_t oi = (size_t)n * CHDK + h * CDK + tid;   // compact row n
    __nv_bfloat16 hh, ll; split_bf16(acc, hh, ll);
    g_oh[oi] = hh; g_ol[oi] = ll;
}

// ---------------- LayerNorm kernels ----------------
__device__ __forceinline__ float blockReduceSum(float val) {
    __shared__ float sh[32];
    int lane = threadIdx.x & 31, wid = threadIdx.x >> 5;
    #pragma unroll
    for (int o = 16; o > 0; o >>= 1) val += __shfl_xor_sync(0xffffffffu, val, o);
    if (lane == 0) sh[wid] = val;
    __syncthreads();
    int nw = (blockDim.x + 31) >> 5;
    val = (threadIdx.x < nw) ? sh[lane] : 0.f;
    if (wid == 0) {
        #pragma unroll
        for (int o = 16; o > 0; o >>= 1) val += __shfl_xor_sync(0xffffffffu, val, o);
    }
    return val;
}

__global__ void add_ln_kernel(const float* __restrict__ gamma,
                              const float* __restrict__ beta) {
    int row = blockIdx.x;
    int tid = threadIdx.x;
    float v[3];
    float s = 0.f;
    #pragma unroll
    for (int j = 0; j < 3; j++) {
        size_t idx = (size_t)row * CD + tid + j * 256;
        v[j] = g_x[idx] + g_t[idx];
        s += v[j];
    }
    s = blockReduceSum(s);
    __shared__ float mean_s, rstd_s;
    if (tid == 0) mean_s = s * (1.f / CD);
    __syncthreads();
    float m = mean_s;
    float vv = 0.f;
    #pragma unroll
    for (int j = 0; j < 3; j++) { float d = v[j] - m; vv += d * d; }
    vv = blockReduceSum(vv);
    if (tid == 0) rstd_s = rsqrtf(vv * (1.f / CD) + 1e-5f);
    __syncthreads();
    float r = rstd_s;
    #pragma unroll
    for (int j = 0; j < 3; j++) {
        int c = tid + j * 256;
        float o = (v[j] - m) * r * gamma[c] + beta[c];
        size_t idx = (size_t)row * CD + c;
        g_x[idx] = o;
        __nv_bfloat16 h, l; split_bf16(o, h, l);
        g_xh[idx] = h; g_xl[idx] = l;
    }
}

// last-layer LN1: residual = g_x row (r*16), t = g_t compact row r.
// writes g_xc (fp32) + g_xch/g_xcl splits (compact).
__global__ void ln1_last_kernel(const float* __restrict__ gamma,
                                const float* __restrict__ beta) {
    int r = blockIdx.x;  // 0..2047
    int tid = threadIdx.x;
    float v[3];
    float s = 0.f;
    #pragma unroll
    for (int j = 0; j < 3; j++) {
        int c = tid + j * 256;
        v[j] = g_x[((size_t)r * CL) * CD + c] + g_t[(size_t)r * CD + c];
        s += v[j];
    }
    s = blockReduceSum(s);
    __shared__ float mean_s, rstd_s;
    if (tid == 0) mean_s = s * (1.f / CD);
    __syncthreads();
    float m = mean_s;
    float vv = 0.f;
    #pragma unroll
    for (int j = 0; j < 3; j++) { float d = v[j] - m; vv += d * d; }
    vv = blockReduceSum(vv);
    if (tid == 0) rstd_s = rsqrtf(vv * (1.f / CD) + 1e-5f);
    __syncthreads();
    float rr = rstd_s;
    #pragma unroll
    for (int j = 0; j < 3; j++) {
        int c = tid + j * 256;
        float o = (v[j] - m) * rr * gamma[c] + beta[c];
        size_t idx = (size_t)r * CD + c;
        g_xc[idx] = o;
        __nv_bfloat16 h, l; split_bf16(o, h, l);
        g_xch[idx] = h; g_xcl[idx] = l;
    }
}

// last-layer LN2: residual = g_xc, t = g_t compact; writes g_ent (fp32).
__global__ void ln2_last_kernel(const float* __restrict__ gamma,
                                const float* __restrict__ beta) {
    int r = blockIdx.x;  // 0..2047
    int tid = threadIdx.x;
    float v[3];
    float s = 0.f;
    #pragma unroll
    for (int j = 0; j < 3; j++) {
        size_t idx = (size_t)r * CD + tid + j * 256;
        v[j] = g_xc[idx] + g_t[idx];
        s += v[j];
    }
    s = blockReduceSum(s);
    __shared__ float mean_s, rstd_s;
    if (tid == 0) mean_s = s * (1.f / CD);
    __syncthreads();
    float m = mean_s;
    float vv = 0.f;
    #pragma unroll
    for (int j = 0; j < 3; j++) { float d = v[j] - m; vv += d * d; }
    vv = blockReduceSum(vv);
    if (tid == 0) rstd_s = rsqrtf(vv * (1.f / CD) + 1e-5f);
    __syncthreads();
    float rr = rstd_s;
    #pragma unroll
    for (int j = 0; j < 3; j++) {
        int c = tid + j * 256;
        g_ent[(size_t)r * CD + c] = (v[j] - m) * rr * gamma[c] + beta[c];
    }
}

// ---------------- tail kernels ----------------
__global__ void pool_attn_kernel(const float* __restrict__ q_enc,
                                 const float* __restrict__ hint) {
    int t = blockIdx.x, b = blockIdx.y;
    __shared__ float qv[770];
    __shared__ float lg[32];
    int tid = threadIdx.x;
    for (int i = tid; i < 770; i += 256)
        qv[i] = (i < CD) ? q_enc[((size_t)b * CS + t) * CD + i]
                         : hint[((size_t)b * CTQ + t) * 2 + (i - CD)];
    __syncthreads();
    int e = tid >> 3, sub = tid & 7;
    const float* ep = g_entp + ((size_t)b * CE + e) * 770;
    float p = 0.f;
    for (int d = sub; d < 770; d += 8) p += qv[d] * ep[d];
    p += __shfl_down_sync(0xffffffffu, p, 4, 8);
    p += __shfl_down_sync(0xffffffffu, p, 2, 8);
    p += __shfl_down_sync(0xffffffffu, p, 1, 8);
    if (sub == 0) lg[e] = p;
    __syncthreads();
    if (tid < 32) {
        float v = lg[tid];
        float m = v;
        #pragma unroll
        for (int o = 16; o > 0; o >>= 1) m = fmaxf(m, __shfl_xor_sync(0xffffffffu, m, o));
        float ex = __expf(v - m);
        float sm = ex;
        #pragma unroll
        for (int o = 16; o > 0; o >>= 1) sm += __shfl_xor_sync(0xffffffffu, sm, o);
        g_attnw[((size_t)b * CTQ + t) * CE + tid] = ex / sm;
    }
}

__global__ void pool_wa_kernel(const int* __restrict__ qlen) {
    int b = blockIdx.x;
    int tid = threadIdx.x;
    __shared__ float A[32];
    int n = qlen[b];
    if (tid < 32) {
        float s = 0.f;
        for (int t = 0; t < n; t++) s += g_attnw[((size_t)b * CTQ + t) * CE + tid];
        A[tid] = s;
    }
    __syncthreads();
    #pragma unroll
    for (int j = 0; j < 3; j++) {
        int d = tid + j * 256;
        float s = 0.f;
        #pragma unroll
        for (int e = 0; e < 32; e++) s += A[e] * g_ent[((size_t)b * CE + e) * CD + d];
        g_wa[(size_t)b * CD + d] = s;
    }
}

__global__ void feat_kernel(const float* __restrict__ q_enc) {
    int b = blockIdx.x;
    for (int i = threadIdx.x; i < 2 * CD; i += 256)
        g_feat[(size_t)b * 2 * CD + i] =
            (i < CD) ? q_enc[(size_t)b * CS * CD + i] : g_wa[(size_t)b * CD + (i - CD)];
}

__global__ void head_out_kernel(const float* __restrict__ W2,
                                const float* __restrict__ b2,
                                float* __restrict__ out) {
    int b = blockIdx.x, tid = threadIdx.x;
    float s = 0.f;
    for (int n = tid; n < CNH; n += 256) s += g_h[(size_t)b * CNH + n] * W2[n];
    s = blockReduceSum(s);
    if (tid == 0) out[b] = s + b2[0];
}

// ---------------- host ----------------
template <typename T>
static T* dsym(const void* symbol) {
    void* p = nullptr;
    cudaGetSymbolAddress(&p, symbol);
    return (T*)p;
}

extern "C" void kernel_launch(void* const* d_in, const int* in_sizes, int n_in,
                              void* d_out, int out_size) {
    const float* q_enc  = (const float*)d_in[0];
    const int*   q_qlen = (const int*)  d_in[1];
    const float* hint   = (const float*)d_in[2];
    const int*   ranges = (const int*)  d_in[3];
    const float* Wq  = (const float*)d_in[4];
    const float* bq  = (const float*)d_in[5];
    const float* Wk  = (const float*)d_in[6];
    const float* bk  = (const float*)d_in[7];
    const float* Wv  = (const float*)d_in[8];
    const float* bv  = (const float*)d_in[9];
    const float* Wo  = (const float*)d_in[10];
    const float* bo  = (const float*)d_in[11];
    const float* ln1g = (const float*)d_in[12];
    const float* ln1b = (const float*)d_in[13];
    const float* Wf1 = (const float*)d_in[14];
    const float* bf1 = (const float*)d_in[15];
    const float* Wf2 = (const float*)d_in[16];
    const float* bf2 = (const float*)d_in[17];
    const float* ln2g = (const float*)d_in[18];
    const float* ln2b = (const float*)d_in[19];
    const float* W_ea = (const float*)d_in[20];
    const float* b_ea = (const float*)d_in[21];
    const float* W1  = (const float*)d_in[22];
    const float* b1  = (const float*)d_in[23];
    const float* W2  = (const float*)d_in[24];
    const float* b2  = (const float*)d_in[25];
    float* out = (float*)d_out;

    cudaFuncSetAttribute(gemm_mma, cudaFuncAttributeMaxDynamicSharedMemorySize, SMEM_DYN);

    __nv_bfloat16* xh  = dsym<__nv_bfloat16>(g_xh);
    __nv_bfloat16* xl  = dsym<__nv_bfloat16>(g_xl);
    __nv_bfloat16* oh  = dsym<__nv_bfloat16>(g_oh);
    __nv_bfloat16* ol  = dsym<__nv_bfloat16>(g_ol);
    __nv_bfloat16* fh  = dsym<__nv_bfloat16>(g_fh);
    __nv_bfloat16* fl  = dsym<__nv_bfloat16>(g_fl);
    __nv_bfloat16* xch = dsym<__nv_bfloat16>(g_xch);
    __nv_bfloat16* xcl = dsym<__nv_bfloat16>(g_xcl);
    float* qkv = dsym<float>(g_qkv);
    float* t_  = dsym<float>(g_t);
    __nv_bfloat16* wqkvh = dsym<__nv_bfloat16>(g_wqkvh);
    __nv_bfloat16* wqkvl = dsym<__nv_bfloat16>(g_wqkvl);
    __nv_bfloat16* woh   = dsym<__nv_bfloat16>(g_woh);
    __nv_bfloat16* wol   = dsym<__nv_bfloat16>(g_wol);
    __nv_bfloat16* wf1h  = dsym<__nv_bfloat16>(g_wf1h);
    __nv_bfloat16* wf1l  = dsym<__nv_bfloat16>(g_wf1l);
    __nv_bfloat16* wf2h  = dsym<__nv_bfloat16>(g_wf2h);
    __nv_bfloat16* wf2l  = dsym<__nv_bfloat16>(g_wf2l);
    float* bqkv = dsym<float>(g_bqkv);
    float* ent  = dsym<float>(g_ent);
    float* entp = dsym<float>(g_entp);
    float* feat = dsym<float>(g_feat);
    float* h_   = dsym<float>(g_h);

    dim3 wblk(32, 8);

    // launch 0: fused layer-0 QKV weight conversion; 1: bias concat; 2: gather
    wconv3_kernel<<<dim3(CHDK/32, CD/32, 3), wblk>>>(Wq, Wk, Wv, wqkvh, wqkvl);
    bqkv_kernel<<<CNL, 256>>>(bq, bk, bv);
    gather_kernel<<<NROWS, 256>>>(q_enc, ranges);

    // launch 3: layer-0 QKV GEMM — ncu window target
    gemm_mma<<<dim3(CQKV/128, NROWS/256), 512, SMEM_DYN>>>(
        xh, xl, wqkvh, wqkvl, bqkv,
        qkv, nullptr, nullptr, CD, CQKV, 0);

    // remaining weight conversions
    for (int i = 0; i < CNL; i++) {
        if (i > 0) {
            size_t oQ = (size_t)i * CQKV * CD;
            wconv3_kernel<<<dim3(CHDK/32, CD/32, 3), wblk>>>(
                Wq + (size_t)i*CD*CHDK, Wk + (size_t)i*CD*CHDK, Wv + (size_t)i*CD*CHDK,
                wqkvh + oQ, wqkvl + oQ);
        }
        size_t oO = (size_t)i * CD * CHDK;
        wconv_kernel<<<dim3(CD/32, CHDK/32), wblk>>>(Wo + (size_t)i*CHDK*CD, woh + oO, wol + oO, CHDK, CD, 0, CHDK);
        size_t oF1 = (size_t)i * CDFF * CD;
        wconv_kernel<<<dim3(CDFF/32, CD/32), wblk>>>(Wf1 + (size_t)i*CD*CDFF, wf1h + oF1, wf1l + oF1, CD, CDFF, 0, CD);
        size_t oF2 = (size_t)i * CD * CDFF;
        wconv_kernel<<<dim3(CD/32, CDFF/32), wblk>>>(Wf2 + (size_t)i*CDFF*CD, wf2h + oF2, wf2l + oF2, CDFF, CD, 0, CDFF);
    }

    // ---- layers 0 .. NL-2: full-width pipeline ----
    for (int i = 0; i < CNL - 1; i++) {
        size_t oQ  = (size_t)i * CQKV * CD;
        size_t oO  = (size_t)i * CD * CHDK;
        size_t oF1 = (size_t)i * CDFF * CD;
        size_t oF2 = (size_t)i * CD * CDFF;

        if (i > 0) {
            gemm_mma<<<dim3(CQKV/128, NROWS/256), 512, SMEM_DYN>>>(
                xh, xl, wqkvh + oQ, wqkvl + oQ, bqkv + i*CQKV,
                qkv, nullptr, nullptr, CD, CQKV, 0);
        }

        attn_kernel<<<NENT * CH, 128>>>();

        gemm_mma<<<dim3(CD/128, NROWS/256), 512, SMEM_DYN>>>(
            oh, ol, woh + oO, wol + oO, bo + i*CD,
            t_, nullptr, nullptr, CHDK, CD, 0);

        add_ln_kernel<<<NROWS, 256>>>(ln1g + i*CD, ln1b + i*CD);

        gemm_mma<<<dim3(CDFF/128, NROWS/256), 512, SMEM_DYN>>>(
            xh, xl, wf1h + oF1, wf1l + oF1, bf1 + i*CDFF,
            nullptr, fh, fl, CD, CDFF, 1);

        gemm_mma<<<dim3(CD/128, NROWS/256), 512, SMEM_DYN>>>(
            fh, fl, wf2h + oF2, wf2l + oF2, bf2 + i*CD,
            t_, nullptr, nullptr, CDFF, CD, 0);

        add_ln_kernel<<<NROWS, 256>>>(ln2g + i*CD, ln2b + i*CD);
    }

    // ---- layer NL-1 (last): only span-row 0 needed post-attention ----
    {
        const int i = CNL - 1;
        size_t oQ  = (size_t)i * CQKV * CD;
        size_t oO  = (size_t)i * CD * CHDK;
        size_t oF1 = (size_t)i * CDFF * CD;
        size_t oF2 = (size_t)i * CD * CDFF;

        // full QKV (K/V needed for all positions)
        gemm_mma<<<dim3(CQKV/128, NROWS/256), 512, SMEM_DYN>>>(
            xh, xl, wqkvh + oQ, wqkvl + oQ, bqkv + i*CQKV,
            qkv, nullptr, nullptr, CD, CQKV, 0);

        // attention for q=0 only; compact output rows (2048 x 384)
        attn0_kernel<<<NENT * CH, 128>>>();

        // Wo GEMM compact (M = 2048)
        gemm_mma<<<dim3(CD/128, NENT/256), 512, SMEM_DYN>>>(
            oh, ol, woh + oO, wol + oO, bo + i*CD,
            t_, nullptr, nullptr, CHDK, CD, 0);

        ln1_last_kernel<<<NENT, 256>>>(ln1g + i*CD, ln1b + i*CD);

        // FFN1 compact
        gemm_mma<<<dim3(CDFF/128, NENT/256), 512, SMEM_DYN>>>(
            xch, xcl, wf1h + oF1, wf1l + oF1, bf1 + i*CDFF,
            nullptr, fh, fl, CD, CDFF, 1);

        // FFN2 compact
        gemm_mma<<<dim3(CD/128, NENT/256), 512, SMEM_DYN>>>(
            fh, fl, wf2h + oF2, wf2l + oF2, bf2 + i*CD,
            t_, nullptr, nullptr, CDFF, CD, 0);

        ln2_last_kernel<<<NENT, 256>>>(ln2g + i*CD, ln2b + i*CD);
    }

    dim3 blk(16, 16);
    gemm_bias_kernel<<<dim3((770 + 63) / 64, NENT / 64), blk>>>(ent, W_ea, b_ea, entp, NENT, 770, CD, 0);
    pool_attn_kernel<<<dim3(CTQ, CB), 256>>>(q_enc, hint);
    pool_wa_kernel<<<CB, 256>>>(q_qlen);
    feat_kernel<<<CB, 256>>>(q_enc);
    gemm_bias_kernel<<<dim3(CNH / 64, 1), blk>>>(feat, W1, b1, h_, CB, CNH, 2 * CD, 1);
    head_out_kernel<<<CB, 256>>>(W2, b2, out);
}

// round 9
// speedup vs baseline: 5.7212x; 1.2842x over previous
#include <cuda_runtime.h>
#include <cuda_fp16.h>
#include <math.h>
#include <stdint.h>

// ---------------- problem constants ----------------
#define CB   64
#define CS   512
#define CD   768
#define CE   32
#define CL   16
#define CTQ  128
#define CH   3
#define CDK  128
#define CHDK 384
#define CQKV 1152
#define CDFF 3072
#define CNH  1024
#define CNL  3
#define NROWS (CB*CE*CL)     // 32768
#define NENT  (CB*CE)        // 2048

// ---------------- device scratch ----------------
__device__ float   g_x  [NROWS*CD];
__device__ __half  g_xh [NROWS*CD];
__device__ __half  g_xl [NROWS*CD];
__device__ float   g_qkv[NROWS*CQKV];
__device__ __half  g_oh [NROWS*CHDK];
__device__ __half  g_ol [NROWS*CHDK];
__device__ __half  g_fh [NROWS*CDFF];
__device__ __half  g_fl [NROWS*CDFF];
__device__ float   g_t  [NROWS*CD];

// compact (last-layer) buffers: 2048 rows
__device__ float   g_xc [NENT*CD];
__device__ __half  g_xch[NENT*CD];
__device__ __half  g_xcl[NENT*CD];

// fp16 weights (single precision term each)
__device__ __half  g_wqkvh[CNL*CQKV*CD];
__device__ __half  g_woh [CNL*CD*CHDK];
__device__ __half  g_wf1h[CNL*CDFF*CD];
__device__ __half  g_wf2h[CNL*CD*CDFF];
__device__ float   g_bqkv[CNL*CQKV];

__device__ float g_ent [NENT*CD];
__device__ float g_entp[NENT*770];
__device__ float g_attnw[CB*CTQ*CE];
__device__ float g_wa  [CB*CD];
__device__ float g_feat[CB*2*CD];
__device__ float g_h   [CB*CNH];

// ---------------- helpers ----------------
__device__ __forceinline__ uint32_t smem_u32(const void* p) {
    uint32_t a;
    asm("{ .reg .u64 t; cvta.to.shared.u64 t, %1; cvt.u32.u64 %0, t; }" : "=r"(a) : "l"(p));
    return a;
}

__device__ __forceinline__ void split_fp16(float v, __half& h, __half& l) {
    h = __float2half_rn(v);
    l = __float2half_rn(v - __half2float(h));
}

__device__ __forceinline__ void ldmatrix_x4(uint32_t* r, uint32_t addr) {
    asm volatile("ldmatrix.sync.aligned.m8n8.x4.shared.b16 {%0,%1,%2,%3}, [%4];"
        : "=r"(r[0]), "=r"(r[1]), "=r"(r[2]), "=r"(r[3]) : "r"(addr));
}

__device__ __forceinline__ void mma16816(float* c, const uint32_t* a,
                                         uint32_t b0, uint32_t b1) {
    asm volatile("mma.sync.aligned.m16n8k16.row.col.f32.f16.f16.f32 "
        "{%0,%1,%2,%3}, {%4,%5,%6,%7}, {%8,%9}, {%0,%1,%2,%3};"
        : "+f"(c[0]), "+f"(c[1]), "+f"(c[2]), "+f"(c[3])
        : "r"(a[0]), "r"(a[1]), "r"(a[2]), "r"(a[3]), "r"(b0), "r"(b1));
}

// ---------------- tensor-core GEMM (mma.sync fp16, 2-term split) ----------
// C[M,N] = (Ah+Al)[M,K] @ Wh^T + bias   (W stored [N,K] K-major, fp16)
// CTA tile 256x128, 512 threads (16 warps = 8m x 2n, each 32x64).
#define ROWB    80                  // 32 fp16 = 64B data, padded to 80B
#define AT_BYTES (256*ROWB)         // 20480
#define WT_BYTES (128*ROWB)         // 10240
#define STAGE_BYTES (2*AT_BYTES + WT_BYTES)  // 51200: Ah|Al|Wh
#define STAGES  3
#define SMEM_DYN (STAGES*STAGE_BYTES + 128)

__global__ __launch_bounds__(512, 1) void gemm_mma(
    const __half* __restrict__ Ah, const __half* __restrict__ Al,
    const __half* __restrict__ Wh,
    const float* __restrict__ bias,
    float* __restrict__ Cf,
    __half* __restrict__ Chi, __half* __restrict__ Clo,
    int K, int Nld, int relu)
{
    extern __shared__ char dynsmem[];
    uint32_t sbase = (smem_u32(dynsmem) + 127u) & ~127u;

    int tid  = threadIdx.x;
    int wid  = tid >> 5, lane = tid & 31;
    int wm   = wid & 7, wn = wid >> 3;           // 8 x 2 warp grid
    int m0   = blockIdx.y * 256, n0 = blockIdx.x * 128;

    const int NC = K >> 5;       // 32-elem chunks

    auto load_chunk = [&](int kc, int buf) {
        uint32_t tb = sbase + buf * STAGE_BYTES;
        #pragma unroll
        for (int i = 0; i < 5; i++) {
            int seg = tid + i * 512;             // 0..2559
            uint32_t dst;
            const __half* src;
            if (seg < 2048) {                    // A tiles: 256 rows x 4 segs x2
                int row = (seg & 1023) >> 2;
                int c   = seg & 3;
                const __half* base = (seg < 1024) ? Ah : Al;
                dst = tb + ((seg < 1024) ? 0u : (uint32_t)AT_BYTES)
                         + row * ROWB + c * 16;
                src = base + (size_t)(m0 + row) * K + kc * 32 + c * 8;
            } else {                             // W tile: 128 rows x 4 segs
                int s2  = seg - 2048;            // 0..511
                int row = s2 >> 2;
                int c   = s2 & 3;
                dst = tb + 2 * AT_BYTES + row * ROWB + c * 16;
                src = Wh + (size_t)(n0 + row) * K + kc * 32 + c * 8;
            }
            asm volatile("cp.async.cg.shared.global [%0], [%1], 16;" :: "r"(dst), "l"(src));
        }
        asm volatile("cp.async.commit_group;" ::: "memory");
    };

    float acc[2][8][4];
    #pragma unroll
    for (int i = 0; i < 2; i++)
        #pragma unroll
        for (int j = 0; j < 8; j++)
            #pragma unroll
            for (int q = 0; q < 4; q++) acc[i][j][q] = 0.f;

    // prologue: 2 chunks in flight
    load_chunk(0, 0);
    if (NC > 1) load_chunk(1, 1);

    int lrow = lane & 15;               // smem row within 16-row group
    int lcol = (lane >> 4) << 4;        // +16B for k8..15 matrices

    for (int c = 0; c < NC; c++) {
        if (c < NC - 1) asm volatile("cp.async.wait_group 1;" ::: "memory");
        else            asm volatile("cp.async.wait_group 0;" ::: "memory");
        __syncthreads();

        uint32_t sb = sbase + (c % STAGES) * STAGE_BYTES;

        if (c + 2 < NC) load_chunk(c + 2, (c + 2) % STAGES);

        uint32_t aAddr = sb + (uint32_t)(wm * 32 + lrow) * ROWB + lcol;
        uint32_t bAddr = sb + 2 * AT_BYTES + (uint32_t)(wn * 64 + lrow) * ROWB + lcol;

        #pragma unroll
        for (int ks = 0; ks < 2; ks++) {
            uint32_t ah[2][4], al[2][4], b[4][4];
            #pragma unroll
            for (int i = 0; i < 2; i++) {
                ldmatrix_x4(ah[i], aAddr + i * (16 * ROWB) + ks * 32);
                ldmatrix_x4(al[i], aAddr + AT_BYTES + i * (16 * ROWB) + ks * 32);
            }
            #pragma unroll
            for (int jj = 0; jj < 4; jj++)
                ldmatrix_x4(b[jj], bAddr + jj * (16 * ROWB) + ks * 32);
            // term 1: Ah*Wh
            #pragma unroll
            for (int i = 0; i < 2; i++)
                #pragma unroll
                for (int jj = 0; jj < 4; jj++) {
                    mma16816(acc[i][2 * jj],     ah[i], b[jj][0], b[jj][2]);
                    mma16816(acc[i][2 * jj + 1], ah[i], b[jj][1], b[jj][3]);
                }
            // term 2: Al*Wh
            #pragma unroll
            for (int i = 0; i < 2; i++)
                #pragma unroll
                for (int jj = 0; jj < 4; jj++) {
                    mma16816(acc[i][2 * jj],     al[i], b[jj][0], b[jj][2]);
                    mma16816(acc[i][2 * jj + 1], al[i], b[jj][1], b[jj][3]);
                }
        }
    }

    // ---------------- epilogue ----------------
    const float2* bp = (const float2*)(bias + n0 + wn * 64);
    float2 bv[8];
    #pragma unroll
    for (int j = 0; j < 8; j++) bv[j] = bp[j * 4 + (lane & 3)];

    #pragma unroll
    for (int i = 0; i < 2; i++) {
        int m_lo = m0 + wm * 32 + i * 16 + (lane >> 2);
        #pragma unroll
        for (int j = 0; j < 8; j++) {
            int n = n0 + wn * 64 + j * 8 + (lane & 3) * 2;
            float v0 = acc[i][j][0] + bv[j].x;
            float v1 = acc[i][j][1] + bv[j].y;
            float v2 = acc[i][j][2] + bv[j].x;
            float v3 = acc[i][j][3] + bv[j].y;
            if (relu) {
                v0 = fmaxf(v0, 0.f); v1 = fmaxf(v1, 0.f);
                v2 = fmaxf(v2, 0.f); v3 = fmaxf(v3, 0.f);
            }
            if (Cf) {
                *(float2*)(Cf + (size_t)m_lo * Nld + n)        = make_float2(v0, v1);
                *(float2*)(Cf + (size_t)(m_lo + 8) * Nld + n)  = make_float2(v2, v3);
            }
            if (Chi) {
                __half h0, l0, h1, l1;
                split_fp16(v0, h0, l0); split_fp16(v1, h1, l1);
                __half2 ph = __halves2half2(h0, h1);
                __half2 pl = __halves2half2(l0, l1);
                *(uint32_t*)(Chi + (size_t)m_lo * Nld + n) = *(uint32_t*)&ph;
                *(uint32_t*)(Clo + (size_t)m_lo * Nld + n) = *(uint32_t*)&pl;
                split_fp16(v2, h0, l0); split_fp16(v3, h1, l1);
                ph = __halves2half2(h0, h1);
                pl = __halves2half2(l0, l1);
                *(uint32_t*)(Chi + (size_t)(m_lo + 8) * Nld + n) = *(uint32_t*)&ph;
                *(uint32_t*)(Clo + (size_t)(m_lo + 8) * Nld + n) = *(uint32_t*)&pl;
            }
        }
    }
}

// ---------------- weight transpose + fp16 convert ----------------
__global__ void wconv_kernel(const float* __restrict__ src,
                             __half* __restrict__ dh,
                             int K, int N, int rowOff, int dstLd) {
    __shared__ float ts[32][33];
    int n0 = blockIdx.x * 32, k0 = blockIdx.y * 32;
    int tx = threadIdx.x, ty = threadIdx.y;  // 32x8
    #pragma unroll
    for (int j = 0; j < 4; j++)
        ts[ty + 8 * j][tx] = src[(size_t)(k0 + ty + 8 * j) * N + n0 + tx];
    __syncthreads();
    #pragma unroll
    for (int j = 0; j < 4; j++) {
        float v = ts[tx][ty + 8 * j];
        size_t di = (size_t)(rowOff + n0 + ty + 8 * j) * dstLd + k0 + tx;
        dh[di] = __float2half_rn(v);
    }
}

// fused Q/K/V weight conversion: blockIdx.z picks the source matrix.
__global__ void wconv3_kernel(const float* __restrict__ srcQ,
                              const float* __restrict__ srcK,
                              const float* __restrict__ srcV,
                              __half* __restrict__ dh) {
    __shared__ float ts[32][33];
    int z = blockIdx.z;
    const float* src = (z == 0) ? srcQ : (z == 1) ? srcK : srcV;
    int rowOff = z * CHDK;
    int n0 = blockIdx.x * 32, k0 = blockIdx.y * 32;
    int tx = threadIdx.x, ty = threadIdx.y;  // 32x8
    #pragma unroll
    for (int j = 0; j < 4; j++)
        ts[ty + 8 * j][tx] = src[(size_t)(k0 + ty + 8 * j) * CHDK + n0 + tx];
    __syncthreads();
    #pragma unroll
    for (int j = 0; j < 4; j++) {
        float v = ts[tx][ty + 8 * j];
        size_t di = (size_t)(rowOff + n0 + ty + 8 * j) * CD + k0 + tx;
        dh[di] = __float2half_rn(v);
    }
}

__global__ void bqkv_kernel(const float* __restrict__ bq,
                            const float* __restrict__ bk,
                            const float* __restrict__ bv) {
    int i = blockIdx.x;
    for (int j = threadIdx.x; j < CQKV; j += 256)
        g_bqkv[i * CQKV + j] =
            (j < CHDK) ? bq[i * CHDK + j] :
            (j < 2 * CHDK) ? bk[i * CHDK + j - CHDK] : bv[i * CHDK + j - 2 * CHDK];
}

// ---------------- gather spans into g_x (+ fp16 split) ----------------
__global__ void gather_kernel(const float* __restrict__ q_enc,
                              const int* __restrict__ ranges) {
    int row = blockIdx.x;
    int be = row >> 4, l = row & 15;
    int b = be >> 5, e = be & 31;
    int st = ranges[(b * CE + e) * 2];
    int en = ranges[(b * CE + e) * 2 + 1];
    int src = min(max(st + l, 0), CS - 1);
    bool m = l < (en - st);
    const float* s = q_enc + ((size_t)b * CS + src) * CD;
    size_t base = (size_t)row * CD;
    for (int i = threadIdx.x; i < CD; i += 256) {
        float v = m ? s[i] : 0.f;
        g_x[base + i] = v;
        __half h, lo; split_fp16(v, h, lo);
        g_xh[base + i] = h; g_xl[base + i] = lo;
    }
}

// ---------------- fp32 SIMT GEMM (small tail matrices) ----------------
__global__ void gemm_bias_kernel(const float* __restrict__ A,
                                 const float* __restrict__ W,
                                 const float* __restrict__ bias,
                                 float* __restrict__ C,
                                 int M, int N, int K, int relu) {
    __shared__ float As[16][65];
    __shared__ float Bs[16][68];
    int tx = threadIdx.x, ty = threadIdx.y;
    int tid = ty * 16 + tx;
    int m0 = blockIdx.y * 64, n0 = blockIdx.x * 64;
    int a_row = tid >> 2, a_col = (tid & 3) << 2;
    int b_row = tid >> 4, b_col = (tid & 15) << 2;
    float acc[4][4] = {};
    for (int k0 = 0; k0 < K; k0 += 16) {
        int m = m0 + a_row;
        #pragma unroll
        for (int i = 0; i < 4; i++) {
            float v = 0.f;
            if (m < M) v = A[(size_t)m * K + k0 + a_col + i];
            As[a_col + i][a_row] = v;
        }
        #pragma unroll
        for (int i = 0; i < 4; i++) {
            int n = n0 + b_col + i;
            float v = 0.f;
            if (n < N) v = W[(size_t)(k0 + b_row) * N + n];
            Bs[b_row][b_col + i] = v;
        }
        __syncthreads();
        #pragma unroll
        for (int kk = 0; kk < 16; kk++) {
            float ra[4], rb[4];
            #pragma unroll
            for (int i = 0; i < 4; i++) ra[i] = As[kk][ty * 4 + i];
            #pragma unroll
            for (int j = 0; j < 4; j++) rb[j] = Bs[kk][tx * 4 + j];
            #pragma unroll
            for (int i = 0; i < 4; i++)
                #pragma unroll
                for (int j = 0; j < 4; j++)
                    acc[i][j] += ra[i] * rb[j];
        }
        __syncthreads();
    }
    #pragma unroll
    for (int i = 0; i < 4; i++) {
        int m = m0 + ty * 4 + i;
        if (m >= M) continue;
        #pragma unroll
        for (int j = 0; j < 4; j++) {
            int n = n0 + tx * 4 + j;
            if (n >= N) continue;
            float v = acc[i][j] + bias[n];
            if (relu) v = fmaxf(v, 0.f);
            C[(size_t)m * N + n] = v;
        }
    }
}

// ---------------- per-(span,head) attention (full, layers 0..NL-2) -------
__global__ void attn_kernel() {
    int nh = blockIdx.x;
    int n = nh / CH, h = nh % CH;
    __shared__ float qs[16][129], ks[16][129], vs[16][129];
    __shared__ float sc[16][17];
    int tid = threadIdx.x;  // 128
    for (int idx = tid; idx < 16 * 128; idx += 128) {
        int l = idx >> 7, d = idx & 127;
        size_t base = ((size_t)(n * CL + l)) * CQKV + h * CDK + d;
        qs[l][d] = g_qkv[base];
        ks[l][d] = g_qkv[base + CHDK];
        vs[l][d] = g_qkv[base + 2 * CHDK];
    }
    __syncthreads();
    const float scale = 0.088388347648318447f;
    for (int p = tid; p < 256; p += 128) {
        int qi = p >> 4, ki = p & 15;
        float s = 0.f;
        #pragma unroll
        for (int d = 0; d < 128; d++) s += qs[qi][d] * ks[ki][d];
        sc[qi][ki] = s * scale;
    }
    __syncthreads();
    if (tid < 16) {
        float m = -1e30f;
        #pragma unroll
        for (int k = 0; k < 16; k++) m = fmaxf(m, sc[tid][k]);
        float sum = 0.f;
        #pragma unroll
        for (int k = 0; k < 16; k++) { float e = __expf(sc[tid][k] - m); sc[tid][k] = e; sum += e; }
        float inv = 1.f / sum;
        #pragma unroll
        for (int k = 0; k < 16; k++) sc[tid][k] *= inv;
    }
    __syncthreads();
    int d = tid;
    #pragma unroll
    for (int qi = 0; qi < 16; qi++) {
        float acc = 0.f;
        #pragma unroll
        for (int k = 0; k < 16; k++) acc += sc[qi][k] * vs[k][d];
        size_t oi = ((size_t)(n * CL + qi)) * CHDK + h * CDK + d;
        __half hh, ll; split_fp16(acc, hh, ll);
        g_oh[oi] = hh; g_ol[oi] = ll;
    }
}

// last layer: only query position 0 is needed; writes COMPACT rows (2048).
__global__ void attn0_kernel() {
    int nh = blockIdx.x;
    int n = nh / CH, h = nh % CH;
    __shared__ float ks[16][129], vs[16][129];
    __shared__ float q0[128];
    __shared__ float p[16];
    int tid = threadIdx.x;  // 128
    for (int idx = tid; idx < 16 * 128; idx += 128) {
        int l = idx >> 7, d = idx & 127;
        size_t base = ((size_t)(n * CL + l)) * CQKV + h * CDK + d;
        ks[l][d] = g_qkv[base + CHDK];
        vs[l][d] = g_qkv[base + 2 * CHDK];
    }
    q0[tid] = g_qkv[((size_t)(n * CL)) * CQKV + h * CDK + tid];
    __syncthreads();
    const float scale = 0.088388347648318447f;
    if (tid < 16) {
        float s = 0.f;
        #pragma unroll
        for (int d = 0; d < 128; d++) s += q0[d] * ks[tid][d];
        p[tid] = s * scale;
    }
    __syncthreads();
    if (tid == 0) {
        float m = -1e30f;
        #pragma unroll
        for (int k = 0; k < 16; k++) m = fmaxf(m, p[k]);
        float sum = 0.f;
        #pragma unroll
        for (int k = 0; k < 16; k++) { float e = __expf(p[k] - m); p[k] = e; sum += e; }
        float inv = 1.f / sum;
        #pragma unroll
        for (int k = 0; k < 16; k++) p[k] *= inv;
    }
    __syncthreads();
    float acc = 0.f;
    #pragma unroll
    for (int k = 0; k < 16; k++) acc += p[k] * vs[k][tid];
    size_t oi = (size_t)n * CHDK + h * CDK + tid;   // compact row n
    __half hh, ll; split_fp16(acc, hh, ll);
    g_oh[oi] = hh; g_ol[oi] = ll;
}

// ---------------- LayerNorm kernels ----------------
__device__ __forceinline__ float blockReduceSum(float val) {
    __shared__ float sh[32];
    int lane = threadIdx.x & 31, wid = threadIdx.x >> 5;
    #pragma unroll
    for (int o = 16; o > 0; o >>= 1) val += __shfl_xor_sync(0xffffffffu, val, o);
    if (lane == 0) sh[wid] = val;
    __syncthreads();
    int nw = (blockDim.x + 31) >> 5;
    val = (threadIdx.x < nw) ? sh[lane] : 0.f;
    if (wid == 0) {
        #pragma unroll
        for (int o = 16; o > 0; o >>= 1) val += __shfl_xor_sync(0xffffffffu, val, o);
    }
    return val;
}

__global__ void add_ln_kernel(const float* __restrict__ gamma,
                              const float* __restrict__ beta) {
    int row = blockIdx.x;
    int tid = threadIdx.x;
    float v[3];
    float s = 0.f;
    #pragma unroll
    for (int j = 0; j < 3; j++) {
        size_t idx = (size_t)row * CD + tid + j * 256;
        v[j] = g_x[idx] + g_t[idx];
        s += v[j];
    }
    s = blockReduceSum(s);
    __shared__ float mean_s, rstd_s;
    if (tid == 0) mean_s = s * (1.f / CD);
    __syncthreads();
    float m = mean_s;
    float vv = 0.f;
    #pragma unroll
    for (int j = 0; j < 3; j++) { float d = v[j] - m; vv += d * d; }
    vv = blockReduceSum(vv);
    if (tid == 0) rstd_s = rsqrtf(vv * (1.f / CD) + 1e-5f);
    __syncthreads();
    float r = rstd_s;
    #pragma unroll
    for (int j = 0; j < 3; j++) {
        int c = tid + j * 256;
        float o = (v[j] - m) * r * gamma[c] + beta[c];
        size_t idx = (size_t)row * CD + c;
        g_x[idx] = o;
        __half h, l; split_fp16(o, h, l);
        g_xh[idx] = h; g_xl[idx] = l;
    }
}

// last-layer LN1: residual = g_x row (r*16), t = g_t compact row r.
__global__ void ln1_last_kernel(const float* __restrict__ gamma,
                                const float* __restrict__ beta) {
    int r = blockIdx.x;  // 0..2047
    int tid = threadIdx.x;
    float v[3];
    float s = 0.f;
    #pragma unroll
    for (int j = 0; j < 3; j++) {
        int c = tid + j * 256;
        v[j] = g_x[((size_t)r * CL) * CD + c] + g_t[(size_t)r * CD + c];
        s += v[j];
    }
    s = blockReduceSum(s);
    __shared__ float mean_s, rstd_s;
    if (tid == 0) mean_s = s * (1.f / CD);
    __syncthreads();
    float m = mean_s;
    float vv = 0.f;
    #pragma unroll
    for (int j = 0; j < 3; j++) { float d = v[j] - m; vv += d * d; }
    vv = blockReduceSum(vv);
    if (tid == 0) rstd_s = rsqrtf(vv * (1.f / CD) + 1e-5f);
    __syncthreads();
    float rr = rstd_s;
    #pragma unroll
    for (int j = 0; j < 3; j++) {
        int c = tid + j * 256;
        float o = (v[j] - m) * rr * gamma[c] + beta[c];
        size_t idx = (size_t)r * CD + c;
        g_xc[idx] = o;
        __half h, l; split_fp16(o, h, l);
        g_xch[idx] = h; g_xcl[idx] = l;
    }
}

// last-layer LN2: residual = g_xc, t = g_t compact; writes g_ent (fp32).
__global__ void ln2_last_kernel(const float* __restrict__ gamma,
                                const float* __restrict__ beta) {
    int r = blockIdx.x;  // 0..2047
    int tid = threadIdx.x;
    float v[3];
    float s = 0.f;
    #pragma unroll
    for (int j = 0; j < 3; j++) {
        size_t idx = (size_t)r * CD + tid + j * 256;
        v[j] = g_xc[idx] + g_t[idx];
        s += v[j];
    }
    s = blockReduceSum(s);
    __shared__ float mean_s, rstd_s;
    if (tid == 0) mean_s = s * (1.f / CD);
    __syncthreads();
    float m = mean_s;
    float vv = 0.f;
    #pragma unroll
    for (int j = 0; j < 3; j++) { float d = v[j] - m; vv += d * d; }
    vv = blockReduceSum(vv);
    if (tid == 0) rstd_s = rsqrtf(vv * (1.f / CD) + 1e-5f);
    __syncthreads();
    float rr = rstd_s;
    #pragma unroll
    for (int j = 0; j < 3; j++) {
        int c = tid + j * 256;
        g_ent[(size_t)r * CD + c] = (v[j] - m) * rr * gamma[c] + beta[c];
    }
}

// ---------------- tail kernels ----------------
__global__ void pool_attn_kernel(const float* __restrict__ q_enc,
                                 const float* __restrict__ hint) {
    int t = blockIdx.x, b = blockIdx.y;
    __shared__ float qv[770];
    __shared__ float lg[32];
    int tid = threadIdx.x;
    for (int i = tid; i < 770; i += 256)
        qv[i] = (i < CD) ? q_enc[((size_t)b * CS + t) * CD + i]
                         : hint[((size_t)b * CTQ + t) * 2 + (i - CD)];
    __syncthreads();
    int e = tid >> 3, sub = tid & 7;
    const float* ep = g_entp + ((size_t)b * CE + e) * 770;
    float p = 0.f;
    for (int d = sub; d < 770; d += 8) p += qv[d] * ep[d];
    p += __shfl_down_sync(0xffffffffu, p, 4, 8);
    p += __shfl_down_sync(0xffffffffu, p, 2, 8);
    p += __shfl_down_sync(0xffffffffu, p, 1, 8);
    if (sub == 0) lg[e] = p;
    __syncthreads();
    if (tid < 32) {
        float v = lg[tid];
        float m = v;
        #pragma unroll
        for (int o = 16; o > 0; o >>= 1) m = fmaxf(m, __shfl_xor_sync(0xffffffffu, m, o));
        float ex = __expf(v - m);
        float sm = ex;
        #pragma unroll
        for (int o = 16; o > 0; o >>= 1) sm += __shfl_xor_sync(0xffffffffu, sm, o);
        g_attnw[((size_t)b * CTQ + t) * CE + tid] = ex / sm;
    }
}

__global__ void pool_wa_kernel(const int* __restrict__ qlen) {
    int b = blockIdx.x;
    int tid = threadIdx.x;
    __shared__ float A[32];
    int n = qlen[b];
    if (tid < 32) {
        float s = 0.f;
        for (int t = 0; t < n; t++) s += g_attnw[((size_t)b * CTQ + t) * CE + tid];
        A[tid] = s;
    }
    __syncthreads();
    #pragma unroll
    for (int j = 0; j < 3; j++) {
        int d = tid + j * 256;
        float s = 0.f;
        #pragma unroll
        for (int e = 0; e < 32; e++) s += A[e] * g_ent[((size_t)b * CE + e) * CD + d];
        g_wa[(size_t)b * CD + d] = s;
    }
}

__global__ void feat_kernel(const float* __restrict__ q_enc) {
    int b = blockIdx.x;
    for (int i = threadIdx.x; i < 2 * CD; i += 256)
        g_feat[(size_t)b * 2 * CD + i] =
            (i < CD) ? q_enc[(size_t)b * CS * CD + i] : g_wa[(size_t)b * CD + (i - CD)];
}

__global__ void head_out_kernel(const float* __restrict__ W2,
                                const float* __restrict__ b2,
                                float* __restrict__ out) {
    int b = blockIdx.x, tid = threadIdx.x;
    float s = 0.f;
    for (int n = tid; n < CNH; n += 256) s += g_h[(size_t)b * CNH + n] * W2[n];
    s = blockReduceSum(s);
    if (tid == 0) out[b] = s + b2[0];
}

// ---------------- host ----------------
template <typename T>
static T* dsym(const void* symbol) {
    void* p = nullptr;
    cudaGetSymbolAddress(&p, symbol);
    return (T*)p;
}

extern "C" void kernel_launch(void* const* d_in, const int* in_sizes, int n_in,
                              void* d_out, int out_size) {
    const float* q_enc  = (const float*)d_in[0];
    const int*   q_qlen = (const int*)  d_in[1];
    const float* hint   = (const float*)d_in[2];
    const int*   ranges = (const int*)  d_in[3];
    const float* Wq  = (const float*)d_in[4];
    const float* bq  = (const float*)d_in[5];
    const float* Wk  = (const float*)d_in[6];
    const float* bk  = (const float*)d_in[7];
    const float* Wv  = (const float*)d_in[8];
    const float* bv  = (const float*)d_in[9];
    const float* Wo  = (const float*)d_in[10];
    const float* bo  = (const float*)d_in[11];
    const float* ln1g = (const float*)d_in[12];
    const float* ln1b = (const float*)d_in[13];
    const float* Wf1 = (const float*)d_in[14];
    const float* bf1 = (const float*)d_in[15];
    const float* Wf2 = (const float*)d_in[16];
    const float* bf2 = (const float*)d_in[17];
    const float* ln2g = (const float*)d_in[18];
    const float* ln2b = (const float*)d_in[19];
    const float* W_ea = (const float*)d_in[20];
    const float* b_ea = (const float*)d_in[21];
    const float* W1  = (const float*)d_in[22];
    const float* b1  = (const float*)d_in[23];
    const float* W2  = (const float*)d_in[24];
    const float* b2  = (const float*)d_in[25];
    float* out = (float*)d_out;

    cudaFuncSetAttribute(gemm_mma, cudaFuncAttributeMaxDynamicSharedMemorySize, SMEM_DYN);

    __half* xh  = dsym<__half>(g_xh);
    __half* xl  = dsym<__half>(g_xl);
    __half* oh  = dsym<__half>(g_oh);
    __half* ol  = dsym<__half>(g_ol);
    __half* fh  = dsym<__half>(g_fh);
    __half* fl  = dsym<__half>(g_fl);
    __half* xch = dsym<__half>(g_xch);
    __half* xcl = dsym<__half>(g_xcl);
    float* qkv = dsym<float>(g_qkv);
    float* t_  = dsym<float>(g_t);
    __half* wqkvh = dsym<__half>(g_wqkvh);
    __half* woh   = dsym<__half>(g_woh);
    __half* wf1h  = dsym<__half>(g_wf1h);
    __half* wf2h  = dsym<__half>(g_wf2h);
    float* bqkv = dsym<float>(g_bqkv);
    float* ent  = dsym<float>(g_ent);
    float* entp = dsym<float>(g_entp);
    float* feat = dsym<float>(g_feat);
    float* h_   = dsym<float>(g_h);

    dim3 wblk(32, 8);

    // launch 0: fused layer-0 QKV weight conversion; 1: bias concat; 2: gather
    wconv3_kernel<<<dim3(CHDK/32, CD/32, 3), wblk>>>(Wq, Wk, Wv, wqkvh);
    bqkv_kernel<<<CNL, 256>>>(bq, bk, bv);
    gather_kernel<<<NROWS, 256>>>(q_enc, ranges);

    // launch 3: layer-0 QKV GEMM — ncu window target
    gemm_mma<<<dim3(CQKV/128, NROWS/256), 512, SMEM_DYN>>>(
        xh, xl, wqkvh, bqkv,
        qkv, nullptr, nullptr, CD, CQKV, 0);

    // remaining weight conversions
    for (int i = 0; i < CNL; i++) {
        if (i > 0) {
            size_t oQ = (size_t)i * CQKV * CD;
            wconv3_kernel<<<dim3(CHDK/32, CD/32, 3), wblk>>>(
                Wq + (size_t)i*CD*CHDK, Wk + (size_t)i*CD*CHDK, Wv + (size_t)i*CD*CHDK,
                wqkvh + oQ);
        }
        size_t oO = (size_t)i * CD * CHDK;
        wconv_kernel<<<dim3(CD/32, CHDK/32), wblk>>>(Wo + (size_t)i*CHDK*CD, woh + oO, CHDK, CD, 0, CHDK);
        size_t oF1 = (size_t)i * CDFF * CD;
        wconv_kernel<<<dim3(CDFF/32, CD/32), wblk>>>(Wf1 + (size_t)i*CD*CDFF, wf1h + oF1, CD, CDFF, 0, CD);
        size_t oF2 = (size_t)i * CD * CDFF;
        wconv_kernel<<<dim3(CD/32, CDFF/32), wblk>>>(Wf2 + (size_t)i*CDFF*CD, wf2h + oF2, CDFF, CD, 0, CDFF);
    }

    // ---- layers 0 .. NL-2: full-width pipeline ----
    for (int i = 0; i < CNL - 1; i++) {
        size_t oQ  = (size_t)i * CQKV * CD;
        size_t oO  = (size_t)i * CD * CHDK;
        size_t oF1 = (size_t)i * CDFF * CD;
        size_t oF2 = (size_t)i * CD * CDFF;

        if (i > 0) {
            gemm_mma<<<dim3(CQKV/128, NROWS/256), 512, SMEM_DYN>>>(
                xh, xl, wqkvh + oQ, bqkv + i*CQKV,
                qkv, nullptr, nullptr, CD, CQKV, 0);
        }

        attn_kernel<<<NENT * CH, 128>>>();

        gemm_mma<<<dim3(CD/128, NROWS/256), 512, SMEM_DYN>>>(
            oh, ol, woh + oO, bo + i*CD,
            t_, nullptr, nullptr, CHDK, CD, 0);

        add_ln_kernel<<<NROWS, 256>>>(ln1g + i*CD, ln1b + i*CD);

        gemm_mma<<<dim3(CDFF/128, NROWS/256), 512, SMEM_DYN>>>(
            xh, xl, wf1h + oF1, bf1 + i*CDFF,
            nullptr, fh, fl, CD, CDFF, 1);

        gemm_mma<<<dim3(CD/128, NROWS/256), 512, SMEM_DYN>>>(
            fh, fl, wf2h + oF2, bf2 + i*CD,
            t_, nullptr, nullptr, CDFF, CD, 0);

        add_ln_kernel<<<NROWS, 256>>>(ln2g + i*CD, ln2b + i*CD);
    }

    // ---- layer NL-1 (last): only span-row 0 needed post-attention ----
    {
        const int i = CNL - 1;
        size_t oQ  = (size_t)i * CQKV * CD;
        size_t oO  = (size_t)i * CD * CHDK;
        size_t oF1 = (size_t)i * CDFF * CD;
        size_t oF2 = (size_t)i * CD * CDFF;

        // full QKV (K/V needed for all positions)
        gemm_mma<<<dim3(CQKV/128, NROWS/256), 512, SMEM_DYN>>>(
            xh, xl, wqkvh + oQ, bqkv + i*CQKV,
            qkv, nullptr, nullptr, CD, CQKV, 0);

        // attention for q=0 only; compact output rows (2048 x 384)
        attn0_kernel<<<NENT * CH, 128>>>();

        // Wo GEMM compact (M = 2048)
        gemm_mma<<<dim3(CD/128, NENT/256), 512, SMEM_DYN>>>(
            oh, ol, woh + oO, bo + i*CD,
            t_, nullptr, nullptr, CHDK, CD, 0);

        ln1_last_kernel<<<NENT, 256>>>(ln1g + i*CD, ln1b + i*CD);

        // FFN1 compact
        gemm_mma<<<dim3(CDFF/128, NENT/256), 512, SMEM_DYN>>>(
            xch, xcl, wf1h + oF1, bf1 + i*CDFF,
            nullptr, fh, fl, CD, CDFF, 1);

        // FFN2 compact
        gemm_mma<<<dim3(CD/128, NENT/256), 512, SMEM_DYN>>>(
            fh, fl, wf2h + oF2, bf2 + i*CD,
            t_, nullptr, nullptr, CDFF, CD, 0);

        ln2_last_kernel<<<NENT, 256>>>(ln2g + i*CD, ln2b + i*CD);
    }

    dim3 blk(16, 16);
    gemm_bias_kernel<<<dim3((770 + 63) / 64, NENT / 64), blk>>>(ent, W_ea, b_ea, entp, NENT, 770, CD, 0);
    pool_attn_kernel<<<dim3(CTQ, CB), 256>>>(q_enc, hint);
    pool_wa_kernel<<<CB, 256>>>(q_qlen);
    feat_kernel<<<CB, 256>>>(q_enc);
    gemm_bias_kernel<<<dim3(CNH / 64, 1), blk>>>(feat, W1, b1, h_, CB, CNH, 2 * CD, 1);
    head_out_kernel<<<CB, 256>>>(W2, b2, out);
}

// round 10
// speedup vs baseline: 6.5546x; 1.1457x over previous
#include <cuda_runtime.h>
#include <cuda_fp16.h>
#include <math.h>
#include <stdint.h>

// ---------------- problem constants ----------------
#define CB   64
#define CS   512
#define CD   768
#define CE   32
#define CL   16
#define CTQ  128
#define CH   3
#define CDK  128
#define CHDK 384
#define CQKV 1152
#define CDFF 3072
#define CNH  1024
#define CNL  3
#define NROWS (CB*CE*CL)     // 32768
#define NENT  (CB*CE)        // 2048

// ---------------- device scratch ----------------
__device__ float   g_x  [NROWS*CD];
__device__ __half  g_xh [NROWS*CD];
__device__ __half  g_xl [NROWS*CD];
__device__ float   g_qkv[NROWS*CQKV];
__device__ __half  g_oh [NROWS*CHDK];
__device__ __half  g_ol [NROWS*CHDK];
__device__ __half  g_fh [NROWS*CDFF];
__device__ __half  g_fl [NROWS*CDFF];
__device__ float   g_t  [NROWS*CD];

// compact (last-layer) buffers: 2048 rows
__device__ float   g_xc [NENT*CD];
__device__ __half  g_xch[NENT*CD];
__device__ __half  g_xcl[NENT*CD];

// fp16 weights (single precision term each)
__device__ __half  g_wqkvh[CNL*CQKV*CD];
__device__ __half  g_woh [CNL*CD*CHDK];
__device__ __half  g_wf1h[CNL*CDFF*CD];
__device__ __half  g_wf2h[CNL*CD*CDFF];
__device__ float   g_bqkv[CNL*CQKV];

__device__ float g_ent [NENT*CD];
__device__ float g_entp[NENT*770];
__device__ float g_attnw[CB*CTQ*CE];
__device__ float g_wa  [CB*CD];
__device__ float g_feat[CB*2*CD];
__device__ float g_h   [CB*CNH];

// ---------------- helpers ----------------
__device__ __forceinline__ uint32_t smem_u32(const void* p) {
    uint32_t a;
    asm("{ .reg .u64 t; cvta.to.shared.u64 t, %1; cvt.u32.u64 %0, t; }" : "=r"(a) : "l"(p));
    return a;
}

__device__ __forceinline__ void split_fp16(float v, __half& h, __half& l) {
    h = __float2half_rn(v);
    l = __float2half_rn(v - __half2float(h));
}

__device__ __forceinline__ void ldmatrix_x4(uint32_t* r, uint32_t addr) {
    asm volatile("ldmatrix.sync.aligned.m8n8.x4.shared.b16 {%0,%1,%2,%3}, [%4];"
        : "=r"(r[0]), "=r"(r[1]), "=r"(r[2]), "=r"(r[3]) : "r"(addr));
}

__device__ __forceinline__ void mma16816(float* c, const uint32_t* a,
                                         uint32_t b0, uint32_t b1) {
    asm volatile("mma.sync.aligned.m16n8k16.row.col.f32.f16.f16.f32 "
        "{%0,%1,%2,%3}, {%4,%5,%6,%7}, {%8,%9}, {%0,%1,%2,%3};"
        : "+f"(c[0]), "+f"(c[1]), "+f"(c[2]), "+f"(c[3])
        : "r"(a[0]), "r"(a[1]), "r"(a[2]), "r"(a[3]), "r"(b0), "r"(b1));
}

// ---------------- tensor-core GEMM (mma.sync fp16, 2-term split) ----------
// C[M,N] = (Ah+Al)[M,K] @ Wh^T + bias   (W stored [N,K] K-major, fp16)
// CTA tile 128x128, 256 threads (8 warps = 4m x 2n, each 32x64).
// 2 CTAs co-resident per SM (independent barrier domains hide sync/load).
#define ROWB    80                  // 32 fp16 = 64B data, padded to 80B
#define TTILE   (128*ROWB)          // 10240
#define STAGE_BYTES (3*TTILE)       // 30720: Ah|Al|Wh
#define STAGES  3
#define SMEM_DYN (STAGES*STAGE_BYTES + 128)

__global__ __launch_bounds__(256, 2) void gemm_mma(
    const __half* __restrict__ Ah, const __half* __restrict__ Al,
    const __half* __restrict__ Wh,
    const float* __restrict__ bias,
    float* __restrict__ Cf,
    __half* __restrict__ Chi, __half* __restrict__ Clo,
    int K, int Nld, int relu)
{
    extern __shared__ char dynsmem[];
    uint32_t sbase = (smem_u32(dynsmem) + 127u) & ~127u;

    int tid  = threadIdx.x;
    int wid  = tid >> 5, lane = tid & 31;
    int wm   = wid & 3, wn = wid >> 2;           // 4 x 2 warp grid
    int m0   = blockIdx.y * 128, n0 = blockIdx.x * 128;

    const int NC = K >> 5;       // 32-elem chunks

    auto load_chunk = [&](int kc, int buf) {
        uint32_t tb = sbase + buf * STAGE_BYTES;
        #pragma unroll
        for (int i = 0; i < 6; i++) {
            int seg = tid + i * 256;             // 0..1535
            int tile = seg >> 9;                 // 0:Ah 1:Al 2:Wh
            int row  = (seg & 511) >> 2;
            int c    = seg & 3;
            uint32_t dst = tb + tile * TTILE + row * ROWB + c * 16;
            const __half* src;
            if (tile == 0)      src = Ah + (size_t)(m0 + row) * K + kc * 32 + c * 8;
            else if (tile == 1) src = Al + (size_t)(m0 + row) * K + kc * 32 + c * 8;
            else                src = Wh + (size_t)(n0 + row) * K + kc * 32 + c * 8;
            asm volatile("cp.async.cg.shared.global [%0], [%1], 16;" :: "r"(dst), "l"(src));
        }
        asm volatile("cp.async.commit_group;" ::: "memory");
    };

    float acc[2][8][4];
    #pragma unroll
    for (int i = 0; i < 2; i++)
        #pragma unroll
        for (int j = 0; j < 8; j++)
            #pragma unroll
            for (int q = 0; q < 4; q++) acc[i][j][q] = 0.f;

    // prologue: 2 chunks in flight
    load_chunk(0, 0);
    if (NC > 1) load_chunk(1, 1);

    int lrow = lane & 15;               // smem row within 16-row group
    int lcol = (lane >> 4) << 4;        // +16B for k8..15 matrices

    for (int c = 0; c < NC; c++) {
        if (c < NC - 1) asm volatile("cp.async.wait_group 1;" ::: "memory");
        else            asm volatile("cp.async.wait_group 0;" ::: "memory");
        __syncthreads();

        uint32_t sb = sbase + (c % STAGES) * STAGE_BYTES;

        if (c + 2 < NC) load_chunk(c + 2, (c + 2) % STAGES);

        uint32_t aAddr = sb + (uint32_t)(wm * 32 + lrow) * ROWB + lcol;
        uint32_t bAddr = sb + 2 * TTILE + (uint32_t)(wn * 64 + lrow) * ROWB + lcol;

        #pragma unroll
        for (int ks = 0; ks < 2; ks++) {
            uint32_t ah[2][4], al[2][4], b[4][4];
            #pragma unroll
            for (int i = 0; i < 2; i++) {
                ldmatrix_x4(ah[i], aAddr + i * (16 * ROWB) + ks * 32);
                ldmatrix_x4(al[i], aAddr + TTILE + i * (16 * ROWB) + ks * 32);
            }
            #pragma unroll
            for (int jj = 0; jj < 4; jj++)
                ldmatrix_x4(b[jj], bAddr + jj * (16 * ROWB) + ks * 32);
            // term 1: Ah*Wh
            #pragma unroll
            for (int i = 0; i < 2; i++)
                #pragma unroll
                for (int jj = 0; jj < 4; jj++) {
                    mma16816(acc[i][2 * jj],     ah[i], b[jj][0], b[jj][2]);
                    mma16816(acc[i][2 * jj + 1], ah[i], b[jj][1], b[jj][3]);
                }
            // term 2: Al*Wh
            #pragma unroll
            for (int i = 0; i < 2; i++)
                #pragma unroll
                for (int jj = 0; jj < 4; jj++) {
                    mma16816(acc[i][2 * jj],     al[i], b[jj][0], b[jj][2]);
                    mma16816(acc[i][2 * jj + 1], al[i], b[jj][1], b[jj][3]);
                }
        }
    }

    // ---------------- epilogue ----------------
    const float2* bp = (const float2*)(bias + n0 + wn * 64);
    float2 bv[8];
    #pragma unroll
    for (int j = 0; j < 8; j++) bv[j] = bp[j * 4 + (lane & 3)];

    #pragma unroll
    for (int i = 0; i < 2; i++) {
        int m_lo = m0 + wm * 32 + i * 16 + (lane >> 2);
        #pragma unroll
        for (int j = 0; j < 8; j++) {
            int n = n0 + wn * 64 + j * 8 + (lane & 3) * 2;
            float v0 = acc[i][j][0] + bv[j].x;
            float v1 = acc[i][j][1] + bv[j].y;
            float v2 = acc[i][j][2] + bv[j].x;
            float v3 = acc[i][j][3] + bv[j].y;
            if (relu) {
                v0 = fmaxf(v0, 0.f); v1 = fmaxf(v1, 0.f);
                v2 = fmaxf(v2, 0.f); v3 = fmaxf(v3, 0.f);
            }
            if (Cf) {
                *(float2*)(Cf + (size_t)m_lo * Nld + n)        = make_float2(v0, v1);
                *(float2*)(Cf + (size_t)(m_lo + 8) * Nld + n)  = make_float2(v2, v3);
            }
            if (Chi) {
                __half h0, l0, h1, l1;
                split_fp16(v0, h0, l0); split_fp16(v1, h1, l1);
                __half2 ph = __halves2half2(h0, h1);
                __half2 pl = __halves2half2(l0, l1);
                *(uint32_t*)(Chi + (size_t)m_lo * Nld + n) = *(uint32_t*)&ph;
                *(uint32_t*)(Clo + (size_t)m_lo * Nld + n) = *(uint32_t*)&pl;
                split_fp16(v2, h0, l0); split_fp16(v3, h1, l1);
                ph = __halves2half2(h0, h1);
                pl = __halves2half2(l0, l1);
                *(uint32_t*)(Chi + (size_t)(m_lo + 8) * Nld + n) = *(uint32_t*)&ph;
                *(uint32_t*)(Clo + (size_t)(m_lo + 8) * Nld + n) = *(uint32_t*)&pl;
            }
        }
    }
}

// ---------------- weight transpose + fp16 convert ----------------
__global__ void wconv_kernel(const float* __restrict__ src,
                             __half* __restrict__ dh,
                             int K, int N, int rowOff, int dstLd) {
    __shared__ float ts[32][33];
    int n0 = blockIdx.x * 32, k0 = blockIdx.y * 32;
    int tx = threadIdx.x, ty = threadIdx.y;  // 32x8
    #pragma unroll
    for (int j = 0; j < 4; j++)
        ts[ty + 8 * j][tx] = src[(size_t)(k0 + ty + 8 * j) * N + n0 + tx];
    __syncthreads();
    #pragma unroll
    for (int j = 0; j < 4; j++) {
        float v = ts[tx][ty + 8 * j];
        size_t di = (size_t)(rowOff + n0 + ty + 8 * j) * dstLd + k0 + tx;
        dh[di] = __float2half_rn(v);
    }
}

// fused Q/K/V weight conversion: blockIdx.z picks the source matrix.
__global__ void wconv3_kernel(const float* __restrict__ srcQ,
                              const float* __restrict__ srcK,
                              const float* __restrict__ srcV,
                              __half* __restrict__ dh) {
    __shared__ float ts[32][33];
    int z = blockIdx.z;
    const float* src = (z == 0) ? srcQ : (z == 1) ? srcK : srcV;
    int rowOff = z * CHDK;
    int n0 = blockIdx.x * 32, k0 = blockIdx.y * 32;
    int tx = threadIdx.x, ty = threadIdx.y;  // 32x8
    #pragma unroll
    for (int j = 0; j < 4; j++)
        ts[ty + 8 * j][tx] = src[(size_t)(k0 + ty + 8 * j) * CHDK + n0 + tx];
    __syncthreads();
    #pragma unroll
    for (int j = 0; j < 4; j++) {
        float v = ts[tx][ty + 8 * j];
        size_t di = (size_t)(rowOff + n0 + ty + 8 * j) * CD + k0 + tx;
        dh[di] = __float2half_rn(v);
    }
}

__global__ void bqkv_kernel(const float* __restrict__ bq,
                            const float* __restrict__ bk,
                            const float* __restrict__ bv) {
    int i = blockIdx.x;
    for (int j = threadIdx.x; j < CQKV; j += 256)
        g_bqkv[i * CQKV + j] =
            (j < CHDK) ? bq[i * CHDK + j] :
            (j < 2 * CHDK) ? bk[i * CHDK + j - CHDK] : bv[i * CHDK + j - 2 * CHDK];
}

// ---------------- gather spans into g_x (+ fp16 split) ----------------
__global__ void gather_kernel(const float* __restrict__ q_enc,
                              const int* __restrict__ ranges) {
    int row = blockIdx.x;
    int be = row >> 4, l = row & 15;
    int b = be >> 5, e = be & 31;
    int st = ranges[(b * CE + e) * 2];
    int en = ranges[(b * CE + e) * 2 + 1];
    int src = min(max(st + l, 0), CS - 1);
    bool m = l < (en - st);
    const float* s = q_enc + ((size_t)b * CS + src) * CD;
    size_t base = (size_t)row * CD;
    for (int i = threadIdx.x; i < CD; i += 256) {
        float v = m ? s[i] : 0.f;
        g_x[base + i] = v;
        __half h, lo; split_fp16(v, h, lo);
        g_xh[base + i] = h; g_xl[base + i] = lo;
    }
}

// ---------------- fp32 SIMT GEMM (small tail matrices) ----------------
__global__ void gemm_bias_kernel(const float* __restrict__ A,
                                 const float* __restrict__ W,
                                 const float* __restrict__ bias,
                                 float* __restrict__ C,
                                 int M, int N, int K, int relu) {
    __shared__ float As[16][65];
    __shared__ float Bs[16][68];
    int tx = threadIdx.x, ty = threadIdx.y;
    int tid = ty * 16 + tx;
    int m0 = blockIdx.y * 64, n0 = blockIdx.x * 64;
    int a_row = tid >> 2, a_col = (tid & 3) << 2;
    int b_row = tid >> 4, b_col = (tid & 15) << 2;
    float acc[4][4] = {};
    for (int k0 = 0; k0 < K; k0 += 16) {
        int m = m0 + a_row;
        #pragma unroll
        for (int i = 0; i < 4; i++) {
            float v = 0.f;
            if (m < M) v = A[(size_t)m * K + k0 + a_col + i];
            As[a_col + i][a_row] = v;
        }
        #pragma unroll
        for (int i = 0; i < 4; i++) {
            int n = n0 + b_col + i;
            float v = 0.f;
            if (n < N) v = W[(size_t)(k0 + b_row) * N + n];
            Bs[b_row][b_col + i] = v;
        }
        __syncthreads();
        #pragma unroll
        for (int kk = 0; kk < 16; kk++) {
            float ra[4], rb[4];
            #pragma unroll
            for (int i = 0; i < 4; i++) ra[i] = As[kk][ty * 4 + i];
            #pragma unroll
            for (int j = 0; j < 4; j++) rb[j] = Bs[kk][tx * 4 + j];
            #pragma unroll
            for (int i = 0; i < 4; i++)
                #pragma unroll
                for (int j = 0; j < 4; j++)
                    acc[i][j] += ra[i] * rb[j];
        }
        __syncthreads();
    }
    #pragma unroll
    for (int i = 0; i < 4; i++) {
        int m = m0 + ty * 4 + i;
        if (m >= M) continue;
        #pragma unroll
        for (int j = 0; j < 4; j++) {
            int n = n0 + tx * 4 + j;
            if (n >= N) continue;
            float v = acc[i][j] + bias[n];
            if (relu) v = fmaxf(v, 0.f);
            C[(size_t)m * N + n] = v;
        }
    }
}

// ---------------- per-(span,head) attention (full, layers 0..NL-2) -------
__global__ void attn_kernel() {
    int nh = blockIdx.x;
    int n = nh / CH, h = nh % CH;
    __shared__ float qs[16][129], ks[16][129], vs[16][129];
    __shared__ float sc[16][17];
    int tid = threadIdx.x;  // 128
    for (int idx = tid; idx < 16 * 128; idx += 128) {
        int l = idx >> 7, d = idx & 127;
        size_t base = ((size_t)(n * CL + l)) * CQKV + h * CDK + d;
        qs[l][d] = g_qkv[base];
        ks[l][d] = g_qkv[base + CHDK];
        vs[l][d] = g_qkv[base + 2 * CHDK];
    }
    __syncthreads();
    const float scale = 0.088388347648318447f;
    for (int p = tid; p < 256; p += 128) {
        int qi = p >> 4, ki = p & 15;
        float s = 0.f;
        #pragma unroll
        for (int d = 0; d < 128; d++) s += qs[qi][d] * ks[ki][d];
        sc[qi][ki] = s * scale;
    }
    __syncthreads();
    if (tid < 16) {
        float m = -1e30f;
        #pragma unroll
        for (int k = 0; k < 16; k++) m = fmaxf(m, sc[tid][k]);
        float sum = 0.f;
        #pragma unroll
        for (int k = 0; k < 16; k++) { float e = __expf(sc[tid][k] - m); sc[tid][k] = e; sum += e; }
        float inv = 1.f / sum;
        #pragma unroll
        for (int k = 0; k < 16; k++) sc[tid][k] *= inv;
    }
    __syncthreads();
    int d = tid;
    #pragma unroll
    for (int qi = 0; qi < 16; qi++) {
        float acc = 0.f;
        #pragma unroll
        for (int k = 0; k < 16; k++) acc += sc[qi][k] * vs[k][d];
        size_t oi = ((size_t)(n * CL + qi)) * CHDK + h * CDK + d;
        __half hh, ll; split_fp16(acc, hh, ll);
        g_oh[oi] = hh; g_ol[oi] = ll;
    }
}

// last layer: only query position 0 is needed; writes COMPACT rows (2048).
__global__ void attn0_kernel() {
    int nh = blockIdx.x;
    int n = nh / CH, h = nh % CH;
    __shared__ float ks[16][129], vs[16][129];
    __shared__ float q0[128];
    __shared__ float p[16];
    int tid = threadIdx.x;  // 128
    for (int idx = tid; idx < 16 * 128; idx += 128) {
        int l = idx >> 7, d = idx & 127;
        size_t base = ((size_t)(n * CL + l)) * CQKV + h * CDK + d;
        ks[l][d] = g_qkv[base + CHDK];
        vs[l][d] = g_qkv[base + 2 * CHDK];
    }
    q0[tid] = g_qkv[((size_t)(n * CL)) * CQKV + h * CDK + tid];
    __syncthreads();
    const float scale = 0.088388347648318447f;
    if (tid < 16) {
        float s = 0.f;
        #pragma unroll
        for (int d = 0; d < 128; d++) s += q0[d] * ks[tid][d];
        p[tid] = s * scale;
    }
    __syncthreads();
    if (tid == 0) {
        float m = -1e30f;
        #pragma unroll
        for (int k = 0; k < 16; k++) m = fmaxf(m, p[k]);
        float sum = 0.f;
        #pragma unroll
        for (int k = 0; k < 16; k++) { float e = __expf(p[k] - m); p[k] = e; sum += e; }
        float inv = 1.f / sum;
        #pragma unroll
        for (int k = 0; k < 16; k++) p[k] *= inv;
    }
    __syncthreads();
    float acc = 0.f;
    #pragma unroll
    for (int k = 0; k < 16; k++) acc += p[k] * vs[k][tid];
    size_t oi = (size_t)n * CHDK + h * CDK + tid;   // compact row n
    __half hh, ll; split_fp16(acc, hh, ll);
    g_oh[oi] = hh; g_ol[oi] = ll;
}

// ---------------- LayerNorm kernels ----------------
__device__ __forceinline__ float blockReduceSum(float val) {
    __shared__ float sh[32];
    int lane = threadIdx.x & 31, wid = threadIdx.x >> 5;
    #pragma unroll
    for (int o = 16; o > 0; o >>= 1) val += __shfl_xor_sync(0xffffffffu, val, o);
    if (lane == 0) sh[wid] = val;
    __syncthreads();
    int nw = (blockDim.x + 31) >> 5;
    val = (threadIdx.x < nw) ? sh[lane] : 0.f;
    if (wid == 0) {
        #pragma unroll
        for (int o = 16; o > 0; o >>= 1) val += __shfl_xor_sync(0xffffffffu, val, o);
    }
    return val;
}

__global__ void add_ln_kernel(const float* __restrict__ gamma,
                              const float* __restrict__ beta) {
    int row = blockIdx.x;
    int tid = threadIdx.x;
    float v[3];
    float s = 0.f;
    #pragma unroll
    for (int j = 0; j < 3; j++) {
        size_t idx = (size_t)row * CD + tid + j * 256;
        v[j] = g_x[idx] + g_t[idx];
        s += v[j];
    }
    s = blockReduceSum(s);
    __shared__ float mean_s, rstd_s;
    if (tid == 0) mean_s = s * (1.f / CD);
    __syncthreads();
    float m = mean_s;
    float vv = 0.f;
    #pragma unroll
    for (int j = 0; j < 3; j++) { float d = v[j] - m; vv += d * d; }
    vv = blockReduceSum(vv);
    if (tid == 0) rstd_s = rsqrtf(vv * (1.f / CD) + 1e-5f);
    __syncthreads();
    float r = rstd_s;
    #pragma unroll
    for (int j = 0; j < 3; j++) {
        int c = tid + j * 256;
        float o = (v[j] - m) * r * gamma[c] + beta[c];
        size_t idx = (size_t)row * CD + c;
        g_x[idx] = o;
        __half h, l; split_fp16(o, h, l);
        g_xh[idx] = h; g_xl[idx] = l;
    }
}

// last-layer LN1: residual = g_x row (r*16), t = g_t compact row r.
__global__ void ln1_last_kernel(const float* __restrict__ gamma,
                                const float* __restrict__ beta) {
    int r = blockIdx.x;  // 0..2047
    int tid = threadIdx.x;
    float v[3];
    float s = 0.f;
    #pragma unroll
    for (int j = 0; j < 3; j++) {
        int c = tid + j * 256;
        v[j] = g_x[((size_t)r * CL) * CD + c] + g_t[(size_t)r * CD + c];
        s += v[j];
    }
    s = blockReduceSum(s);
    __shared__ float mean_s, rstd_s;
    if (tid == 0) mean_s = s * (1.f / CD);
    __syncthreads();
    float m = mean_s;
    float vv = 0.f;
    #pragma unroll
    for (int j = 0; j < 3; j++) { float d = v[j] - m; vv += d * d; }
    vv = blockReduceSum(vv);
    if (tid == 0) rstd_s = rsqrtf(vv * (1.f / CD) + 1e-5f);
    __syncthreads();
    float rr = rstd_s;
    #pragma unroll
    for (int j = 0; j < 3; j++) {
        int c = tid + j * 256;
        float o = (v[j] - m) * rr * gamma[c] + beta[c];
        size_t idx = (size_t)r * CD + c;
        g_xc[idx] = o;
        __half h, l; split_fp16(o, h, l);
        g_xch[idx] = h; g_xcl[idx] = l;
    }
}

// last-layer LN2: residual = g_xc, t = g_t compact; writes g_ent (fp32).
__global__ void ln2_last_kernel(const float* __restrict__ gamma,
                                const float* __restrict__ beta) {
    int r = blockIdx.x;  // 0..2047
    int tid = threadIdx.x;
    float v[3];
    float s = 0.f;
    #pragma unroll
    for (int j = 0; j < 3; j++) {
        size_t idx = (size_t)r * CD + tid + j * 256;
        v[j] = g_xc[idx] + g_t[idx];
        s += v[j];
    }
    s = blockReduceSum(s);
    __shared__ float mean_s, rstd_s;
    if (tid == 0) mean_s = s * (1.f / CD);
    __syncthreads();
    float m = mean_s;
    float vv = 0.f;
    #pragma unroll
    for (int j = 0; j < 3; j++) { float d = v[j] - m; vv += d * d; }
    vv = blockReduceSum(vv);
    if (tid == 0) rstd_s = rsqrtf(vv * (1.f / CD) + 1e-5f);
    __syncthreads();
    float rr = rstd_s;
    #pragma unroll
    for (int j = 0; j < 3; j++) {
        int c = tid + j * 256;
        g_ent[(size_t)r * CD + c] = (v[j] - m) * rr * gamma[c] + beta[c];
    }
}

// ---------------- tail kernels ----------------
__global__ void pool_attn_kernel(const float* __restrict__ q_enc,
                                 const float* __restrict__ hint) {
    int t = blockIdx.x, b = blockIdx.y;
    __shared__ float qv[770];
    __shared__ float lg[32];
    int tid = threadIdx.x;
    for (int i = tid; i < 770; i += 256)
        qv[i] = (i < CD) ? q_enc[((size_t)b * CS + t) * CD + i]
                         : hint[((size_t)b * CTQ + t) * 2 + (i - CD)];
    __syncthreads();
    int e = tid >> 3, sub = tid & 7;
    const float* ep = g_entp + ((size_t)b * CE + e) * 770;
    float p = 0.f;
    for (int d = sub; d < 770; d += 8) p += qv[d] * ep[d];
    p += __shfl_down_sync(0xffffffffu, p, 4, 8);
    p += __shfl_down_sync(0xffffffffu, p, 2, 8);
    p += __shfl_down_sync(0xffffffffu, p, 1, 8);
    if (sub == 0) lg[e] = p;
    __syncthreads();
    if (tid < 32) {
        float v = lg[tid];
        float m = v;
        #pragma unroll
        for (int o = 16; o > 0; o >>= 1) m = fmaxf(m, __shfl_xor_sync(0xffffffffu, m, o));
        float ex = __expf(v - m);
        float sm = ex;
        #pragma unroll
        for (int o = 16; o > 0; o >>= 1) sm += __shfl_xor_sync(0xffffffffu, sm, o);
        g_attnw[((size_t)b * CTQ + t) * CE + tid] = ex / sm;
    }
}

__global__ void pool_wa_kernel(const int* __restrict__ qlen) {
    int b = blockIdx.x;
    int tid = threadIdx.x;
    __shared__ float A[32];
    int n = qlen[b];
    if (tid < 32) {
        float s = 0.f;
        for (int t = 0; t < n; t++) s += g_attnw[((size_t)b * CTQ + t) * CE + tid];
        A[tid] = s;
    }
    __syncthreads();
    #pragma unroll
    for (int j = 0; j < 3; j++) {
        int d = tid + j * 256;
        float s = 0.f;
        #pragma unroll
        for (int e = 0; e < 32; e++) s += A[e] * g_ent[((size_t)b * CE + e) * CD + d];
        g_wa[(size_t)b * CD + d] = s;
    }
}

__global__ void feat_kernel(const float* __restrict__ q_enc) {
    int b = blockIdx.x;
    for (int i = threadIdx.x; i < 2 * CD; i += 256)
        g_feat[(size_t)b * 2 * CD + i] =
            (i < CD) ? q_enc[(size_t)b * CS * CD + i] : g_wa[(size_t)b * CD + (i - CD)];
}

__global__ void head_out_kernel(const float* __restrict__ W2,
                                const float* __restrict__ b2,
                                float* __restrict__ out) {
    int b = blockIdx.x, tid = threadIdx.x;
    float s = 0.f;
    for (int n = tid; n < CNH; n += 256) s += g_h[(size_t)b * CNH + n] * W2[n];
    s = blockReduceSum(s);
    if (tid == 0) out[b] = s + b2[0];
}

// ---------------- host ----------------
template <typename T>
static T* dsym(const void* symbol) {
    void* p = nullptr;
    cudaGetSymbolAddress(&p, symbol);
    return (T*)p;
}

extern "C" void kernel_launch(void* const* d_in, const int* in_sizes, int n_in,
                              void* d_out, int out_size) {
    const float* q_enc  = (const float*)d_in[0];
    const int*   q_qlen = (const int*)  d_in[1];
    const float* hint   = (const float*)d_in[2];
    const int*   ranges = (const int*)  d_in[3];
    const float* Wq  = (const float*)d_in[4];
    const float* bq  = (const float*)d_in[5];
    const float* Wk  = (const float*)d_in[6];
    const float* bk  = (const float*)d_in[7];
    const float* Wv  = (const float*)d_in[8];
    const float* bv  = (const float*)d_in[9];
    const float* Wo  = (const float*)d_in[10];
    const float* bo  = (const float*)d_in[11];
    const float* ln1g = (const float*)d_in[12];
    const float* ln1b = (const float*)d_in[13];
    const float* Wf1 = (const float*)d_in[14];
    const float* bf1 = (const float*)d_in[15];
    const float* Wf2 = (const float*)d_in[16];
    const float* bf2 = (const float*)d_in[17];
    const float* ln2g = (const float*)d_in[18];
    const float* ln2b = (const float*)d_in[19];
    const float* W_ea = (const float*)d_in[20];
    const float* b_ea = (const float*)d_in[21];
    const float* W1  = (const float*)d_in[22];
    const float* b1  = (const float*)d_in[23];
    const float* W2  = (const float*)d_in[24];
    const float* b2  = (const float*)d_in[25];
    float* out = (float*)d_out;

    cudaFuncSetAttribute(gemm_mma, cudaFuncAttributeMaxDynamicSharedMemorySize, SMEM_DYN);

    __half* xh  = dsym<__half>(g_xh);
    __half* xl  = dsym<__half>(g_xl);
    __half* oh  = dsym<__half>(g_oh);
    __half* ol  = dsym<__half>(g_ol);
    __half* fh  = dsym<__half>(g_fh);
    __half* fl  = dsym<__half>(g_fl);
    __half* xch = dsym<__half>(g_xch);
    __half* xcl = dsym<__half>(g_xcl);
    float* qkv = dsym<float>(g_qkv);
    float* t_  = dsym<float>(g_t);
    __half* wqkvh = dsym<__half>(g_wqkvh);
    __half* woh   = dsym<__half>(g_woh);
    __half* wf1h  = dsym<__half>(g_wf1h);
    __half* wf2h  = dsym<__half>(g_wf2h);
    float* bqkv = dsym<float>(g_bqkv);
    float* ent  = dsym<float>(g_ent);
    float* entp = dsym<float>(g_entp);
    float* feat = dsym<float>(g_feat);
    float* h_   = dsym<float>(g_h);

    dim3 wblk(32, 8);

    // launch 0: fused layer-0 QKV weight conversion; 1: bias concat; 2: gather
    wconv3_kernel<<<dim3(CHDK/32, CD/32, 3), wblk>>>(Wq, Wk, Wv, wqkvh);
    bqkv_kernel<<<CNL, 256>>>(bq, bk, bv);
    gather_kernel<<<NROWS, 256>>>(q_enc, ranges);

    // launch 3: layer-0 QKV GEMM — ncu window target
    gemm_mma<<<dim3(CQKV/128, NROWS/128), 256, SMEM_DYN>>>(
        xh, xl, wqkvh, bqkv,
        qkv, nullptr, nullptr, CD, CQKV, 0);

    // remaining weight conversions
    for (int i = 0; i < CNL; i++) {
        if (i > 0) {
            size_t oQ = (size_t)i * CQKV * CD;
            wconv3_kernel<<<dim3(CHDK/32, CD/32, 3), wblk>>>(
                Wq + (size_t)i*CD*CHDK, Wk + (size_t)i*CD*CHDK, Wv + (size_t)i*CD*CHDK,
                wqkvh + oQ);
        }
        size_t oO = (size_t)i * CD * CHDK;
        wconv_kernel<<<dim3(CD/32, CHDK/32), wblk>>>(Wo + (size_t)i*CHDK*CD, woh + oO, CHDK, CD, 0, CHDK);
        size_t oF1 = (size_t)i * CDFF * CD;
        wconv_kernel<<<dim3(CDFF/32, CD/32), wblk>>>(Wf1 + (size_t)i*CD*CDFF, wf1h + oF1, CD, CDFF, 0, CD);
        size_t oF2 = (size_t)i * CD * CDFF;
        wconv_kernel<<<dim3(CD/32, CDFF/32), wblk>>>(Wf2 + (size_t)i*CDFF*CD, wf2h + oF2, CDFF, CD, 0, CDFF);
    }

    // ---- layers 0 .. NL-2: full-width pipeline ----
    for (int i = 0; i < CNL - 1; i++) {
        size_t oQ  = (size_t)i * CQKV * CD;
        size_t oO  = (size_t)i * CD * CHDK;
        size_t oF1 = (size_t)i * CDFF * CD;
        size_t oF2 = (size_t)i * CD * CDFF;

        if (i > 0) {
            gemm_mma<<<dim3(CQKV/128, NROWS/128), 256, SMEM_DYN>>>(
                xh, xl, wqkvh + oQ, bqkv + i*CQKV,
                qkv, nullptr, nullptr, CD, CQKV, 0);
        }

        attn_kernel<<<NENT * CH, 128>>>();

        gemm_mma<<<dim3(CD/128, NROWS/128), 256, SMEM_DYN>>>(
            oh, ol, woh + oO, bo + i*CD,
            t_, nullptr, nullptr, CHDK, CD, 0);

        add_ln_kernel<<<NROWS, 256>>>(ln1g + i*CD, ln1b + i*CD);

        gemm_mma<<<dim3(CDFF/128, NROWS/128), 256, SMEM_DYN>>>(
            xh, xl, wf1h + oF1, bf1 + i*CDFF,
            nullptr, fh, fl, CD, CDFF, 1);

        gemm_mma<<<dim3(CD/128, NROWS/128), 256, SMEM_DYN>>>(
            fh, fl, wf2h + oF2, bf2 + i*CD,
            t_, nullptr, nullptr, CDFF, CD, 0);

        add_ln_kernel<<<NROWS, 256>>>(ln2g + i*CD, ln2b + i*CD);
    }

    // ---- layer NL-1 (last): only span-row 0 needed post-attention ----
    {
        const int i = CNL - 1;
        size_t oQ  = (size_t)i * CQKV * CD;
        size_t oO  = (size_t)i * CD * CHDK;
        size_t oF1 = (size_t)i * CDFF * CD;
        size_t oF2 = (size_t)i * CD * CDFF;

        // full QKV (K/V needed for all positions)
        gemm_mma<<<dim3(CQKV/128, NROWS/128), 256, SMEM_DYN>>>(
            xh, xl, wqkvh + oQ, bqkv + i*CQKV,
            qkv, nullptr, nullptr, CD, CQKV, 0);

        // attention for q=0 only; compact output rows (2048 x 384)
        attn0_kernel<<<NENT * CH, 128>>>();

        // Wo GEMM compact (M = 2048)
        gemm_mma<<<dim3(CD/128, NENT/128), 256, SMEM_DYN>>>(
            oh, ol, woh + oO, bo + i*CD,
            t_, nullptr, nullptr, CHDK, CD, 0);

        ln1_last_kernel<<<NENT, 256>>>(ln1g + i*CD, ln1b + i*CD);

        // FFN1 compact
        gemm_mma<<<dim3(CDFF/128, NENT/128), 256, SMEM_DYN>>>(
            xch, xcl, wf1h + oF1, bf1 + i*CDFF,
            nullptr, fh, fl, CD, CDFF, 1);

        // FFN2 compact
        gemm_mma<<<dim3(CD/128, NENT/128), 256, SMEM_DYN>>>(
            fh, fl, wf2h + oF2, bf2 + i*CD,
            t_, nullptr, nullptr, CDFF, CD, 0);

        ln2_last_kernel<<<NENT, 256>>>(ln2g + i*CD, ln2b + i*CD);
    }

    dim3 blk(16, 16);
    gemm_bias_kernel<<<dim3((770 + 63) / 64, NENT / 64), blk>>>(ent, W_ea, b_ea, entp, NENT, 770, CD, 0);
    pool_attn_kernel<<<dim3(CTQ, CB), 256>>>(q_enc, hint);
    pool_wa_kernel<<<CB, 256>>>(q_qlen);
    feat_kernel<<<CB, 256>>>(q_enc);
    gemm_bias_kernel<<<dim3(CNH / 64, 1), blk>>>(feat, W1, b1, h_, CB, CNH, 2 * CD, 1);
    head_out_kernel<<<CB, 256>>>(W2, b2, out);
}

// round 11
// speedup vs baseline: 9.2380x; 1.4094x over previous
#include <cuda_runtime.h>
#include <cuda_fp16.h>
#include <math.h>
#include <stdint.h>

// ---------------- problem constants ----------------
#define CB   64
#define CS   512
#define CD   768
#define CE   32
#define CL   16
#define CTQ  128
#define CH   3
#define CDK  128
#define CHDK 384
#define CQKV 1152
#define CDFF 3072
#define CNH  1024
#define CNL  3
#define NROWS (CB*CE*CL)     // 32768
#define NENT  (CB*CE)        // 2048

// ---------------- device scratch ----------------
__device__ float   g_x  [NROWS*CD];
__device__ __half  g_xh [NROWS*CD];
__device__ __half  g_xl [NROWS*CD];
__device__ float   g_qkv[NROWS*CQKV];
__device__ __half  g_oh [NROWS*CHDK];
__device__ __half  g_fh [NROWS*CDFF];
__device__ float   g_t  [NROWS*CD];

// compact (last-layer) buffers: 2048 rows
__device__ float   g_xc [NENT*CD];
__device__ __half  g_xch[NENT*CD];

// fp16 weights
__device__ __half  g_wqkvh[CNL*CQKV*CD];
__device__ __half  g_woh [CNL*CD*CHDK];
__device__ __half  g_wf1h[CNL*CDFF*CD];
__device__ __half  g_wf2h[CNL*CD*CDFF];
__device__ float   g_bqkv[CNL*CQKV];

__device__ float g_ent [NENT*CD];
__device__ float g_entp[NENT*770];
__device__ float g_attnw[CB*CTQ*CE];
__device__ float g_wa  [CB*CD];
__device__ float g_feat[CB*2*CD];
__device__ float g_h   [CB*CNH];

// ---------------- helpers ----------------
__device__ __forceinline__ uint32_t smem_u32(const void* p) {
    uint32_t a;
    asm("{ .reg .u64 t; cvta.to.shared.u64 t, %1; cvt.u32.u64 %0, t; }" : "=r"(a) : "l"(p));
    return a;
}

__device__ __forceinline__ void split_fp16(float v, __half& h, __half& l) {
    h = __float2half_rn(v);
    l = __float2half_rn(v - __half2float(h));
}

__device__ __forceinline__ void ldmatrix_x4(uint32_t* r, uint32_t addr) {
    asm volatile("ldmatrix.sync.aligned.m8n8.x4.shared.b16 {%0,%1,%2,%3}, [%4];"
        : "=r"(r[0]), "=r"(r[1]), "=r"(r[2]), "=r"(r[3]) : "r"(addr));
}

__device__ __forceinline__ void mma16816(float* c, const uint32_t* a,
                                         uint32_t b0, uint32_t b1) {
    asm volatile("mma.sync.aligned.m16n8k16.row.col.f32.f16.f16.f32 "
        "{%0,%1,%2,%3}, {%4,%5,%6,%7}, {%8,%9}, {%0,%1,%2,%3};"
        : "+f"(c[0]), "+f"(c[1]), "+f"(c[2]), "+f"(c[3])
        : "r"(a[0]), "r"(a[1]), "r"(a[2]), "r"(a[3]), "r"(b0), "r"(b1));
}

// ---------------- tensor-core GEMM (mma.sync fp16) ----------
// TERMS=2: C = (Ah+Al) @ Wh^T + bias.  TERMS=1: C = Ah @ Wh^T + bias.
// W stored [N,K] K-major fp16. CTA 128x128, 256 thr (8 warps, 32x64 each).
// 2 CTAs/SM.
#define ROWB    80
#define TTILE   (128*ROWB)          // 10240
#define STAGES  3
#define SMEM_DYN_T(T) (STAGES*((T)+1)*TTILE + 128)

template<int TERMS>
__global__ __launch_bounds__(256, 2) void gemm_mma(
    const __half* __restrict__ Ah, const __half* __restrict__ Al,
    const __half* __restrict__ Wh,
    const float* __restrict__ bias,
    float* __restrict__ Cf,
    __half* __restrict__ Chi, __half* __restrict__ Clo,
    int K, int Nld, int relu)
{
    constexpr int NT = TERMS + 1;            // tiles per stage
    constexpr int STAGE_BYTES = NT * TTILE;

    extern __shared__ char dynsmem[];
    uint32_t sbase = (smem_u32(dynsmem) + 127u) & ~127u;

    int tid  = threadIdx.x;
    int wid  = tid >> 5, lane = tid & 31;
    int wm   = wid & 3, wn = wid >> 2;           // 4 x 2 warp grid
    int m0   = blockIdx.y * 128, n0 = blockIdx.x * 128;

    const int NC = K >> 5;       // 32-elem chunks

    auto load_chunk = [&](int kc, int buf) {
        uint32_t tb = sbase + buf * STAGE_BYTES;
        #pragma unroll
        for (int i = 0; i < NT * 2; i++) {
            int seg = tid + i * 256;             // 0 .. NT*512-1
            int tile = seg >> 9;                 // 0..TERMS
            int row  = (seg & 511) >> 2;
            int c    = seg & 3;
            uint32_t dst = tb + tile * TTILE + row * ROWB + c * 16;
            const __half* src;
            if (tile == 0)                       src = Ah + (size_t)(m0 + row) * K + kc * 32 + c * 8;
            else if (TERMS == 2 && tile == 1)    src = Al + (size_t)(m0 + row) * K + kc * 32 + c * 8;
            else                                 src = Wh + (size_t)(n0 + row) * K + kc * 32 + c * 8;
            asm volatile("cp.async.cg.shared.global [%0], [%1], 16;" :: "r"(dst), "l"(src));
        }
        asm volatile("cp.async.commit_group;" ::: "memory");
    };

    float acc[2][8][4];
    #pragma unroll
    for (int i = 0; i < 2; i++)
        #pragma unroll
        for (int j = 0; j < 8; j++)
            #pragma unroll
            for (int q = 0; q < 4; q++) acc[i][j][q] = 0.f;

    load_chunk(0, 0);
    if (NC > 1) load_chunk(1, 1);

    int lrow = lane & 15;
    int lcol = (lane >> 4) << 4;

    for (int c = 0; c < NC; c++) {
        if (c < NC - 1) asm volatile("cp.async.wait_group 1;" ::: "memory");
        else            asm volatile("cp.async.wait_group 0;" ::: "memory");
        __syncthreads();

        uint32_t sb = sbase + (c % STAGES) * STAGE_BYTES;

        if (c + 2 < NC) load_chunk(c + 2, (c + 2) % STAGES);

        uint32_t aAddr = sb + (uint32_t)(wm * 32 + lrow) * ROWB + lcol;
        uint32_t bAddr = sb + TERMS * TTILE + (uint32_t)(wn * 64 + lrow) * ROWB + lcol;

        #pragma unroll
        for (int ks = 0; ks < 2; ks++) {
            uint32_t ah[2][4], al[2][4], b[4][4];
            #pragma unroll
            for (int i = 0; i < 2; i++) {
                ldmatrix_x4(ah[i], aAddr + i * (16 * ROWB) + ks * 32);
                if (TERMS == 2)
                    ldmatrix_x4(al[i], aAddr + TTILE + i * (16 * ROWB) + ks * 32);
            }
            #pragma unroll
            for (int jj = 0; jj < 4; jj++)
                ldmatrix_x4(b[jj], bAddr + jj * (16 * ROWB) + ks * 32);
            #pragma unroll
            for (int i = 0; i < 2; i++)
                #pragma unroll
                for (int jj = 0; jj < 4; jj++) {
                    mma16816(acc[i][2 * jj],     ah[i], b[jj][0], b[jj][2]);
                    mma16816(acc[i][2 * jj + 1], ah[i], b[jj][1], b[jj][3]);
                }
            if (TERMS == 2) {
                #pragma unroll
                for (int i = 0; i < 2; i++)
                    #pragma unroll
                    for (int jj = 0; jj < 4; jj++) {
                        mma16816(acc[i][2 * jj],     al[i], b[jj][0], b[jj][2]);
                        mma16816(acc[i][2 * jj + 1], al[i], b[jj][1], b[jj][3]);
                    }
            }
        }
    }

    // ---------------- epilogue ----------------
    const float2* bp = (const float2*)(bias + n0 + wn * 64);
    float2 bv[8];
    #pragma unroll
    for (int j = 0; j < 8; j++) bv[j] = bp[j * 4 + (lane & 3)];

    #pragma unroll
    for (int i = 0; i < 2; i++) {
        int m_lo = m0 + wm * 32 + i * 16 + (lane >> 2);
        #pragma unroll
        for (int j = 0; j < 8; j++) {
            int n = n0 + wn * 64 + j * 8 + (lane & 3) * 2;
            float v0 = acc[i][j][0] + bv[j].x;
            float v1 = acc[i][j][1] + bv[j].y;
            float v2 = acc[i][j][2] + bv[j].x;
            float v3 = acc[i][j][3] + bv[j].y;
            if (relu) {
                v0 = fmaxf(v0, 0.f); v1 = fmaxf(v1, 0.f);
                v2 = fmaxf(v2, 0.f); v3 = fmaxf(v3, 0.f);
            }
            if (Cf) {
                *(float2*)(Cf + (size_t)m_lo * Nld + n)        = make_float2(v0, v1);
                *(float2*)(Cf + (size_t)(m_lo + 8) * Nld + n)  = make_float2(v2, v3);
            }
            if (Chi) {
                __half h0, l0, h1, l1;
                split_fp16(v0, h0, l0); split_fp16(v1, h1, l1);
                __half2 ph = __halves2half2(h0, h1);
                *(uint32_t*)(Chi + (size_t)m_lo * Nld + n) = *(uint32_t*)&ph;
                if (Clo) {
                    __half2 pl = __halves2half2(l0, l1);
                    *(uint32_t*)(Clo + (size_t)m_lo * Nld + n) = *(uint32_t*)&pl;
                }
                split_fp16(v2, h0, l0); split_fp16(v3, h1, l1);
                ph = __halves2half2(h0, h1);
                *(uint32_t*)(Chi + (size_t)(m_lo + 8) * Nld + n) = *(uint32_t*)&ph;
                if (Clo) {
                    __half2 pl = __halves2half2(l0, l1);
                    *(uint32_t*)(Clo + (size_t)(m_lo + 8) * Nld + n) = *(uint32_t*)&pl;
                }
            }
        }
    }
}

// ---------------- weight transpose + fp16 convert ----------------
__global__ void wconv_kernel(const float* __restrict__ src,
                             __half* __restrict__ dh,
                             int K, int N, int rowOff, int dstLd) {
    __shared__ float ts[32][33];
    int n0 = blockIdx.x * 32, k0 = blockIdx.y * 32;
    int tx = threadIdx.x, ty = threadIdx.y;  // 32x8
    #pragma unroll
    for (int j = 0; j < 4; j++)
        ts[ty + 8 * j][tx] = src[(size_t)(k0 + ty + 8 * j) * N + n0 + tx];
    __syncthreads();
    #pragma unroll
    for (int j = 0; j < 4; j++) {
        float v = ts[tx][ty + 8 * j];
        size_t di = (size_t)(rowOff + n0 + ty + 8 * j) * dstLd + k0 + tx;
        dh[di] = __float2half_rn(v);
    }
}

__global__ void wconv3_kernel(const float* __restrict__ srcQ,
                              const float* __restrict__ srcK,
                              const float* __restrict__ srcV,
                              __half* __restrict__ dh) {
    __shared__ float ts[32][33];
    int z = blockIdx.z;
    const float* src = (z == 0) ? srcQ : (z == 1) ? srcK : srcV;
    int rowOff = z * CHDK;
    int n0 = blockIdx.x * 32, k0 = blockIdx.y * 32;
    int tx = threadIdx.x, ty = threadIdx.y;
    #pragma unroll
    for (int j = 0; j < 4; j++)
        ts[ty + 8 * j][tx] = src[(size_t)(k0 + ty + 8 * j) * CHDK + n0 + tx];
    __syncthreads();
    #pragma unroll
    for (int j = 0; j < 4; j++) {
        float v = ts[tx][ty + 8 * j];
        size_t di = (size_t)(rowOff + n0 + ty + 8 * j) * CD + k0 + tx;
        dh[di] = __float2half_rn(v);
    }
}

__global__ void bqkv_kernel(const float* __restrict__ bq,
                            const float* __restrict__ bk,
                            const float* __restrict__ bv) {
    int i = blockIdx.x;
    for (int j = threadIdx.x; j < CQKV; j += 256)
        g_bqkv[i * CQKV + j] =
            (j < CHDK) ? bq[i * CHDK + j] :
            (j < 2 * CHDK) ? bk[i * CHDK + j - CHDK] : bv[i * CHDK + j - 2 * CHDK];
}

// ---------------- gather spans into g_x (+ fp16 split) ----------------
__global__ void gather_kernel(const float* __restrict__ q_enc,
                              const int* __restrict__ ranges) {
    int row = blockIdx.x;
    int be = row >> 4, l = row & 15;
    int b = be >> 5, e = be & 31;
    int st = ranges[(b * CE + e) * 2];
    int en = ranges[(b * CE + e) * 2 + 1];
    int src = min(max(st + l, 0), CS - 1);
    bool m = l < (en - st);
    const float* s = q_enc + ((size_t)b * CS + src) * CD;
    size_t base = (size_t)row * CD;
    for (int i = threadIdx.x; i < CD; i += 256) {
        float v = m ? s[i] : 0.f;
        g_x[base + i] = v;
        __half h, lo; split_fp16(v, h, lo);
        g_xh[base + i] = h; g_xl[base + i] = lo;
    }
}

// ---------------- fp32 SIMT GEMM (small tail matrices) ----------------
__global__ void gemm_bias_kernel(const float* __restrict__ A,
                                 const float* __restrict__ W,
                                 const float* __restrict__ bias,
                                 float* __restrict__ C,
                                 int M, int N, int K, int relu) {
    __shared__ float As[16][65];
    __shared__ float Bs[16][68];
    int tx = threadIdx.x, ty = threadIdx.y;
    int tid = ty * 16 + tx;
    int m0 = blockIdx.y * 64, n0 = blockIdx.x * 64;
    int a_row = tid >> 2, a_col = (tid & 3) << 2;
    int b_row = tid >> 4, b_col = (tid & 15) << 2;
    float acc[4][4] = {};
    for (int k0 = 0; k0 < K; k0 += 16) {
        int m = m0 + a_row;
        #pragma unroll
        for (int i = 0; i < 4; i++) {
            float v = 0.f;
            if (m < M) v = A[(size_t)m * K + k0 + a_col + i];
            As[a_col + i][a_row] = v;
        }
        #pragma unroll
        for (int i = 0; i < 4; i++) {
            int n = n0 + b_col + i;
            float v = 0.f;
            if (n < N) v = W[(size_t)(k0 + b_row) * N + n];
            Bs[b_row][b_col + i] = v;
        }
        __syncthreads();
        #pragma unroll
        for (int kk = 0; kk < 16; kk++) {
            float ra[4], rb[4];
            #pragma unroll
            for (int i = 0; i < 4; i++) ra[i] = As[kk][ty * 4 + i];
            #pragma unroll
            for (int j = 0; j < 4; j++) rb[j] = Bs[kk][tx * 4 + j];
            #pragma unroll
            for (int i = 0; i < 4; i++)
                #pragma unroll
                for (int j = 0; j < 4; j++)
                    acc[i][j] += ra[i] * rb[j];
        }
        __syncthreads();
    }
    #pragma unroll
    for (int i = 0; i < 4; i++) {
        int m = m0 + ty * 4 + i;
        if (m >= M) continue;
        #pragma unroll
        for (int j = 0; j < 4; j++) {
            int n = n0 + tx * 4 + j;
            if (n >= N) continue;
            float v = acc[i][j] + bias[n];
            if (relu) v = fmaxf(v, 0.f);
            C[(size_t)m * N + n] = v;
        }
    }
}

// ---------------- per-(span,head) attention (full, layers 0..NL-2) -------
__global__ void attn_kernel() {
    int nh = blockIdx.x;
    int n = nh / CH, h = nh % CH;
    __shared__ float qs[16][129], ks[16][129], vs[16][129];
    __shared__ float sc[16][17];
    int tid = threadIdx.x;  // 128
    for (int idx = tid; idx < 16 * 128; idx += 128) {
        int l = idx >> 7, d = idx & 127;
        size_t base = ((size_t)(n * CL + l)) * CQKV + h * CDK + d;
        qs[l][d] = g_qkv[base];
        ks[l][d] = g_qkv[base + CHDK];
        vs[l][d] = g_qkv[base + 2 * CHDK];
    }
    __syncthreads();
    const float scale = 0.088388347648318447f;
    for (int p = tid; p < 256; p += 128) {
        int qi = p >> 4, ki = p & 15;
        float s = 0.f;
        #pragma unroll
        for (int d = 0; d < 128; d++) s += qs[qi][d] * ks[ki][d];
        sc[qi][ki] = s * scale;
    }
    __syncthreads();
    if (tid < 16) {
        float m = -1e30f;
        #pragma unroll
        for (int k = 0; k < 16; k++) m = fmaxf(m, sc[tid][k]);
        float sum = 0.f;
        #pragma unroll
        for (int k = 0; k < 16; k++) { float e = __expf(sc[tid][k] - m); sc[tid][k] = e; sum += e; }
        float inv = 1.f / sum;
        #pragma unroll
        for (int k = 0; k < 16; k++) sc[tid][k] *= inv;
    }
    __syncthreads();
    int d = tid;
    #pragma unroll
    for (int qi = 0; qi < 16; qi++) {
        float acc = 0.f;
        #pragma unroll
        for (int k = 0; k < 16; k++) acc += sc[qi][k] * vs[k][d];
        g_oh[((size_t)(n * CL + qi)) * CHDK + h * CDK + d] = __float2half_rn(acc);
    }
}

// last layer: only query position 0; writes COMPACT rows (2048).
__global__ void attn0_kernel() {
    int nh = blockIdx.x;
    int n = nh / CH, h = nh % CH;
    __shared__ float ks[16][129], vs[16][129];
    __shared__ float q0[128];
    __shared__ float p[16];
    int tid = threadIdx.x;  // 128
    for (int idx = tid; idx < 16 * 128; idx += 128) {
        int l = idx >> 7, d = idx & 127;
        size_t base = ((size_t)(n * CL + l)) * CQKV + h * CDK + d;
        ks[l][d] = g_qkv[base + CHDK];
        vs[l][d] = g_qkv[base + 2 * CHDK];
    }
    q0[tid] = g_qkv[((size_t)(n * CL)) * CQKV + h * CDK + tid];
    __syncthreads();
    const float scale = 0.088388347648318447f;
    if (tid < 16) {
        float s = 0.f;
        #pragma unroll
        for (int d = 0; d < 128; d++) s += q0[d] * ks[tid][d];
        p[tid] = s * scale;
    }
    __syncthreads();
    if (tid == 0) {
        float m = -1e30f;
        #pragma unroll
        for (int k = 0; k < 16; k++) m = fmaxf(m, p[k]);
        float sum = 0.f;
        #pragma unroll
        for (int k = 0; k < 16; k++) { float e = __expf(p[k] - m); p[k] = e; sum += e; }
        float inv = 1.f / sum;
        #pragma unroll
        for (int k = 0; k < 16; k++) p[k] *= inv;
    }
    __syncthreads();
    float acc = 0.f;
    #pragma unroll
    for (int k = 0; k < 16; k++) acc += p[k] * vs[k][tid];
    g_oh[(size_t)n * CHDK + h * CDK + tid] = __float2half_rn(acc);
}

// ---------------- LayerNorm kernels ----------------
__device__ __forceinline__ float blockReduceSum(float val) {
    __shared__ float sh[32];
    int lane = threadIdx.x & 31, wid = threadIdx.x >> 5;
    #pragma unroll
    for (int o = 16; o > 0; o >>= 1) val += __shfl_xor_sync(0xffffffffu, val, o);
    if (lane == 0) sh[wid] = val;
    __syncthreads();
    int nw = (blockDim.x + 31) >> 5;
    val = (threadIdx.x < nw) ? sh[lane] : 0.f;
    if (wid == 0) {
        #pragma unroll
        for (int o = 16; o > 0; o >>= 1) val += __shfl_xor_sync(0xffffffffu, val, o);
    }
    return val;
}

__global__ void add_ln_kernel(const float* __restrict__ gamma,
                              const float* __restrict__ beta) {
    int row = blockIdx.x;
    int tid = threadIdx.x;
    float v[3];
    float s = 0.f;
    #pragma unroll
    for (int j = 0; j < 3; j++) {
        size_t idx = (size_t)row * CD + tid + j * 256;
        v[j] = g_x[idx] + g_t[idx];
        s += v[j];
    }
    s = blockReduceSum(s);
    __shared__ float mean_s, rstd_s;
    if (tid == 0) mean_s = s * (1.f / CD);
    __syncthreads();
    float m = mean_s;
    float vv = 0.f;
    #pragma unroll
    for (int j = 0; j < 3; j++) { float d = v[j] - m; vv += d * d; }
    vv = blockReduceSum(vv);
    if (tid == 0) rstd_s = rsqrtf(vv * (1.f / CD) + 1e-5f);
    __syncthreads();
    float r = rstd_s;
    #pragma unroll
    for (int j = 0; j < 3; j++) {
        int c = tid + j * 256;
        float o = (v[j] - m) * r * gamma[c] + beta[c];
        size_t idx = (size_t)row * CD + c;
        g_x[idx] = o;
        __half h, l; split_fp16(o, h, l);
        g_xh[idx] = h; g_xl[idx] = l;
    }
}

// last-layer LN1: residual = g_x row (r*16), t = g_t compact row r.
__global__ void ln1_last_kernel(const float* __restrict__ gamma,
                                const float* __restrict__ beta) {
    int r = blockIdx.x;  // 0..2047
    int tid = threadIdx.x;
    float v[3];
    float s = 0.f;
    #pragma unroll
    for (int j = 0; j < 3; j++) {
        int c = tid + j * 256;
        v[j] = g_x[((size_t)r * CL) * CD + c] + g_t[(size_t)r * CD + c];
        s += v[j];
    }
    s = blockReduceSum(s);
    __shared__ float mean_s, rstd_s;
    if (tid == 0) mean_s = s * (1.f / CD);
    __syncthreads();
    float m = mean_s;
    float vv = 0.f;
    #pragma unroll
    for (int j = 0; j < 3; j++) { float d = v[j] - m; vv += d * d; }
    vv = blockReduceSum(vv);
    if (tid == 0) rstd_s = rsqrtf(vv * (1.f / CD) + 1e-5f);
    __syncthreads();
    float rr = rstd_s;
    #pragma unroll
    for (int j = 0; j < 3; j++) {
        int c = tid + j * 256;
        float o = (v[j] - m) * rr * gamma[c] + beta[c];
        size_t idx = (size_t)r * CD + c;
        g_xc[idx] = o;
        g_xch[idx] = __float2half_rn(o);
    }
}

// last-layer LN2: residual = g_xc, t = g_t compact; writes g_ent (fp32).
__global__ void ln2_last_kernel(const float* __restrict__ gamma,
                                const float* __restrict__ beta) {
    int r = blockIdx.x;  // 0..2047
    int tid = threadIdx.x;
    float v[3];
    float s = 0.f;
    #pragma unroll
    for (int j = 0; j < 3; j++) {
        size_t idx = (size_t)r * CD + tid + j * 256;
        v[j] = g_xc[idx] + g_t[idx];
        s += v[j];
    }
    s = blockReduceSum(s);
    __shared__ float mean_s, rstd_s;
    if (tid == 0) mean_s = s * (1.f / CD);
    __syncthreads();
    float m = mean_s;
    float vv = 0.f;
    #pragma unroll
    for (int j = 0; j < 3; j++) { float d = v[j] - m; vv += d * d; }
    vv = blockReduceSum(vv);
    if (tid == 0) rstd_s = rsqrtf(vv * (1.f / CD) + 1e-5f);
    __syncthreads();
    float rr = rstd_s;
    #pragma unroll
    for (int j = 0; j < 3; j++) {
        int c = tid + j * 256;
        g_ent[(size_t)r * CD + c] = (v[j] - m) * rr * gamma[c] + beta[c];
    }
}

// ---------------- tail kernels ----------------
__global__ void pool_attn_kernel(const float* __restrict__ q_enc,
                                 const float* __restrict__ hint) {
    int t = blockIdx.x, b = blockIdx.y;
    __shared__ float qv[770];
    __shared__ float lg[32];
    int tid = threadIdx.x;
    for (int i = tid; i < 770; i += 256)
        qv[i] = (i < CD) ? q_enc[((size_t)b * CS + t) * CD + i]
                         : hint[((size_t)b * CTQ + t) * 2 + (i - CD)];
    __syncthreads();
    int e = tid >> 3, sub = tid & 7;
    const float* ep = g_entp + ((size_t)b * CE + e) * 770;
    float p = 0.f;
    for (int d = sub; d < 770; d += 8) p += qv[d] * ep[d];
    p += __shfl_down_sync(0xffffffffu, p, 4, 8);
    p += __shfl_down_sync(0xffffffffu, p, 2, 8);
    p += __shfl_down_sync(0xffffffffu, p, 1, 8);
    if (sub == 0) lg[e] = p;
    __syncthreads();
    if (tid < 32) {
        float v = lg[tid];
        float m = v;
        #pragma unroll
        for (int o = 16; o > 0; o >>= 1) m = fmaxf(m, __shfl_xor_sync(0xffffffffu, m, o));
        float ex = __expf(v - m);
        float sm = ex;
        #pragma unroll
        for (int o = 16; o > 0; o >>= 1) sm += __shfl_xor_sync(0xffffffffu, sm, o);
        g_attnw[((size_t)b * CTQ + t) * CE + tid] = ex / sm;
    }
}

__global__ void pool_wa_kernel(const int* __restrict__ qlen) {
    int b = blockIdx.x;
    int tid = threadIdx.x;
    __shared__ float A[32];
    int n = qlen[b];
    if (tid < 32) {
        float s = 0.f;
        for (int t = 0; t < n; t++) s += g_attnw[((size_t)b * CTQ + t) * CE + tid];
        A[tid] = s;
    }
    __syncthreads();
    #pragma unroll
    for (int j = 0; j < 3; j++) {
        int d = tid + j * 256;
        float s = 0.f;
        #pragma unroll
        for (int e = 0; e < 32; e++) s += A[e] * g_ent[((size_t)b * CE + e) * CD + d];
        g_wa[(size_t)b * CD + d] = s;
    }
}

__global__ void feat_kernel(const float* __restrict__ q_enc) {
    int b = blockIdx.x;
    for (int i = threadIdx.x; i < 2 * CD; i += 256)
        g_feat[(size_t)b * 2 * CD + i] =
            (i < CD) ? q_enc[(size_t)b * CS * CD + i] : g_wa[(size_t)b * CD + (i - CD)];
}

__global__ void head_out_kernel(const float* __restrict__ W2,
                                const float* __restrict__ b2,
                                float* __restrict__ out) {
    int b = blockIdx.x, tid = threadIdx.x;
    float s = 0.f;
    for (int n = tid; n < CNH; n += 256) s += g_h[(size_t)b * CNH + n] * W2[n];
    s = blockReduceSum(s);
    if (tid == 0) out[b] = s + b2[0];
}

// ---------------- host ----------------
template <typename T>
static T* dsym(const void* symbol) {
    void* p = nullptr;
    cudaGetSymbolAddress(&p, symbol);
    return (T*)p;
}

extern "C" void kernel_launch(void* const* d_in, const int* in_sizes, int n_in,
                              void* d_out, int out_size) {
    const float* q_enc  = (const float*)d_in[0];
    const int*   q_qlen = (const int*)  d_in[1];
    const float* hint   = (const float*)d_in[2];
    const int*   ranges = (const int*)  d_in[3];
    const float* Wq  = (const float*)d_in[4];
    const float* bq  = (const float*)d_in[5];
    const float* Wk  = (const float*)d_in[6];
    const float* bk  = (const float*)d_in[7];
    const float* Wv  = (const float*)d_in[8];
    const float* bv  = (const float*)d_in[9];
    const float* Wo  = (const float*)d_in[10];
    const float* bo  = (const float*)d_in[11];
    const float* ln1g = (const float*)d_in[12];
    const float* ln1b = (const float*)d_in[13];
    const float* Wf1 = (const float*)d_in[14];
    const float* bf1 = (const float*)d_in[15];
    const float* Wf2 = (const float*)d_in[16];
    const float* bf2 = (const float*)d_in[17];
    const float* ln2g = (const float*)d_in[18];
    const float* ln2b = (const float*)d_in[19];
    const float* W_ea = (const float*)d_in[20];
    const float* b_ea = (const float*)d_in[21];
    const float* W1  = (const float*)d_in[22];
    const float* b1  = (const float*)d_in[23];
    const float* W2  = (const float*)d_in[24];
    const float* b2  = (const float*)d_in[25];
    float* out = (float*)d_out;

    cudaFuncSetAttribute(gemm_mma<2>, cudaFuncAttributeMaxDynamicSharedMemorySize, SMEM_DYN_T(2));
    cudaFuncSetAttribute(gemm_mma<1>, cudaFuncAttributeMaxDynamicSharedMemorySize, SMEM_DYN_T(1));

    __half* xh  = dsym<__half>(g_xh);
    __half* xl  = dsym<__half>(g_xl);
    __half* oh  = dsym<__half>(g_oh);
    __half* fh  = dsym<__half>(g_fh);
    __half* xch = dsym<__half>(g_xch);
    float* qkv = dsym<float>(g_qkv);
    float* t_  = dsym<float>(g_t);
    __half* wqkvh = dsym<__half>(g_wqkvh);
    __half* woh   = dsym<__half>(g_woh);
    __half* wf1h  = dsym<__half>(g_wf1h);
    __half* wf2h  = dsym<__half>(g_wf2h);
    float* bqkv = dsym<float>(g_bqkv);
    float* ent  = dsym<float>(g_ent);
    float* entp = dsym<float>(g_entp);
    float* feat = dsym<float>(g_feat);
    float* h_   = dsym<float>(g_h);

    dim3 wblk(32, 8);

    // launch 0: fused layer-0 QKV weight conversion; 1: bias concat; 2: gather
    wconv3_kernel<<<dim3(CHDK/32, CD/32, 3), wblk>>>(Wq, Wk, Wv, wqkvh);
    bqkv_kernel<<<CNL, 256>>>(bq, bk, bv);
    gather_kernel<<<NROWS, 256>>>(q_enc, ranges);

    // launch 3: layer-0 QKV GEMM — ncu window target
    gemm_mma<2><<<dim3(CQKV/128, NROWS/128), 256, SMEM_DYN_T(2)>>>(
        xh, xl, wqkvh, bqkv,
        qkv, nullptr, nullptr, CD, CQKV, 0);

    // remaining weight conversions
    for (int i = 0; i < CNL; i++) {
        if (i > 0) {
            size_t oQ = (size_t)i * CQKV * CD;
            wconv3_kernel<<<dim3(CHDK/32, CD/32, 3), wblk>>>(
                Wq + (size_t)i*CD*CHDK, Wk + (size_t)i*CD*CHDK, Wv + (size_t)i*CD*CHDK,
                wqkvh + oQ);
        }
        size_t oO = (size_t)i * CD * CHDK;
        wconv_kernel<<<dim3(CD/32, CHDK/32), wblk>>>(Wo + (size_t)i*CHDK*CD, woh + oO, CHDK, CD, 0, CHDK);
        size_t oF1 = (size_t)i * CDFF * CD;
        wconv_kernel<<<dim3(CDFF/32, CD/32), wblk>>>(Wf1 + (size_t)i*CD*CDFF, wf1h + oF1, CD, CDFF, 0, CD);
        size_t oF2 = (size_t)i * CD * CDFF;
        wconv_kernel<<<dim3(CD/32, CDFF/32), wblk>>>(Wf2 + (size_t)i*CDFF*CD, wf2h + oF2, CDFF, CD, 0, CDFF);
    }

    // ---- layers 0 .. NL-2: full-width pipeline ----
    for (int i = 0; i < CNL - 1; i++) {
        size_t oQ  = (size_t)i * CQKV * CD;
        size_t oO  = (size_t)i * CD * CHDK;
        size_t oF1 = (size_t)i * CDFF * CD;
        size_t oF2 = (size_t)i * CD * CDFF;

        if (i > 0) {
            gemm_mma<2><<<dim3(CQKV/128, NROWS/128), 256, SMEM_DYN_T(2)>>>(
                xh, xl, wqkvh + oQ, bqkv + i*CQKV,
                qkv, nullptr, nullptr, CD, CQKV, 0);
        }

        attn_kernel<<<NENT * CH, 128>>>();

        gemm_mma<1><<<dim3(CD/128, NROWS/128), 256, SMEM_DYN_T(1)>>>(
            oh, nullptr, woh + oO, bo + i*CD,
            t_, nullptr, nullptr, CHDK, CD, 0);

        add_ln_kernel<<<NROWS, 256>>>(ln1g + i*CD, ln1b + i*CD);

        gemm_mma<1><<<dim3(CDFF/128, NROWS/128), 256, SMEM_DYN_T(1)>>>(
            xh, nullptr, wf1h + oF1, bf1 + i*CDFF,
            nullptr, fh, nullptr, CD, CDFF, 1);

        gemm_mma<1><<<dim3(CD/128, NROWS/128), 256, SMEM_DYN_T(1)>>>(
            fh, nullptr, wf2h + oF2, bf2 + i*CD,
            t_, nullptr, nullptr, CDFF, CD, 0);

        add_ln_kernel<<<NROWS, 256>>>(ln2g + i*CD, ln2b + i*CD);
    }

    // ---- layer NL-1 (last): only span-row 0 needed post-attention ----
    {
        const int i = CNL - 1;
        size_t oQ  = (size_t)i * CQKV * CD;
        size_t oO  = (size_t)i * CD * CHDK;
        size_t oF1 = (size_t)i * CDFF * CD;
        size_t oF2 = (size_t)i * CD * CDFF;

        gemm_mma<2><<<dim3(CQKV/128, NROWS/128), 256, SMEM_DYN_T(2)>>>(
            xh, xl, wqkvh + oQ, bqkv + i*CQKV,
            qkv, nullptr, nullptr, CD, CQKV, 0);

        attn0_kernel<<<NENT * CH, 128>>>();

        gemm_mma<1><<<dim3(CD/128, NENT/128), 256, SMEM_DYN_T(1)>>>(
            oh, nullptr, woh + oO, bo + i*CD,
            t_, nullptr, nullptr, CHDK, CD, 0);

        ln1_last_kernel<<<NENT, 256>>>(ln1g + i*CD, ln1b + i*CD);

        gemm_mma<1><<<dim3(CDFF/128, NENT/128), 256, SMEM_DYN_T(1)>>>(
            xch, nullptr, wf1h + oF1, bf1 + i*CDFF,
            nullptr, fh, nullptr, CD, CDFF, 1);

        gemm_mma<1><<<dim3(CD/128, NENT/128), 256, SMEM_DYN_T(1)>>>(
            fh, nullptr, wf2h + oF2, bf2 + i*CD,
            t_, nullptr, nullptr, CDFF, CD, 0);

        ln2_last_kernel<<<NENT, 256>>>(ln2g + i*CD, ln2b + i*CD);
    }

    dim3 blk(16, 16);
    gemm_bias_kernel<<<dim3((770 + 63) / 64, NENT / 64), blk>>>(ent, W_ea, b_ea, entp, NENT, 770, CD, 0);
    pool_attn_kernel<<<dim3(CTQ, CB), 256>>>(q_enc, hint);
    pool_wa_kernel<<<CB, 256>>>(q_qlen);
    feat_kernel<<<CB, 256>>>(q_enc);
    gemm_bias_kernel<<<dim3(CNH / 64, 1), blk>>>(feat, W1, b1, h_, CB, CNH, 2 * CD, 1);
    head_out_kernel<<<CB, 256>>>(W2, b2, out);
}

// round 12
// speedup vs baseline: 10.4280x; 1.1288x over previous
#include <cuda_runtime.h>
#include <cuda_fp16.h>
#include <math.h>
#include <stdint.h>

// ---------------- problem constants ----------------
#define CB   64
#define CS   512
#define CD   768
#define CE   32
#define CL   16
#define CTQ  128
#define CH   3
#define CDK  128
#define CHDK 384
#define CQKV 1152
#define CDFF 3072
#define CNH  1024
#define CNL  3
#define NROWS (CB*CE*CL)     // 32768
#define NENT  (CB*CE)        // 2048

// ---------------- device scratch ----------------
__device__ float   g_x  [NROWS*CD];
__device__ __half  g_xh [NROWS*CD];
__device__ __half  g_qkvh[NROWS*CQKV];
__device__ __half  g_oh [NROWS*CHDK];
__device__ __half  g_fh [NROWS*CDFF];
__device__ float   g_t  [NROWS*CD];

// compact (last-layer) buffers: 2048 rows
__device__ float   g_xc [NENT*CD];
__device__ __half  g_xch[NENT*CD];

// fp16 weights
__device__ __half  g_wqkvh[CNL*CQKV*CD];
__device__ __half  g_woh [CNL*CD*CHDK];
__device__ __half  g_wf1h[CNL*CDFF*CD];
__device__ __half  g_wf2h[CNL*CD*CDFF];
__device__ float   g_bqkv[CNL*CQKV];

__device__ float g_ent [NENT*CD];
__device__ float g_entp[NENT*770];
__device__ float g_attnw[CB*CTQ*CE];
__device__ float g_wa  [CB*CD];
__device__ float g_feat[CB*2*CD];
__device__ float g_h   [CB*CNH];

// ---------------- helpers ----------------
__device__ __forceinline__ uint32_t smem_u32(const void* p) {
    uint32_t a;
    asm("{ .reg .u64 t; cvta.to.shared.u64 t, %1; cvt.u32.u64 %0, t; }" : "=r"(a) : "l"(p));
    return a;
}

__device__ __forceinline__ void ldmatrix_x4(uint32_t* r, uint32_t addr) {
    asm volatile("ldmatrix.sync.aligned.m8n8.x4.shared.b16 {%0,%1,%2,%3}, [%4];"
        : "=r"(r[0]), "=r"(r[1]), "=r"(r[2]), "=r"(r[3]) : "r"(addr));
}

__device__ __forceinline__ void mma16816(float* c, const uint32_t* a,
                                         uint32_t b0, uint32_t b1) {
    asm volatile("mma.sync.aligned.m16n8k16.row.col.f32.f16.f16.f32 "
        "{%0,%1,%2,%3}, {%4,%5,%6,%7}, {%8,%9}, {%0,%1,%2,%3};"
        : "+f"(c[0]), "+f"(c[1]), "+f"(c[2]), "+f"(c[3])
        : "r"(a[0]), "r"(a[1]), "r"(a[2]), "r"(a[3]), "r"(b0), "r"(b1));
}

// ---------------- tensor-core GEMM (mma.sync fp16, 1-term) ----------
// C = Ah @ Wh^T + bias.  W stored [N,K] K-major fp16.
// CTA 128x128, 256 thr (8 warps, 32x64 each). 2 CTAs/SM.
#define ROWB    80
#define TTILE   (128*ROWB)          // 10240
#define STAGES  3
#define STAGE_BYTES (2*TTILE)       // Ah | Wh
#define SMEM_DYN (STAGES*STAGE_BYTES + 128)

__global__ __launch_bounds__(256, 2) void gemm_mma(
    const __half* __restrict__ Ah,
    const __half* __restrict__ Wh,
    const float* __restrict__ bias,
    float* __restrict__ Cf,
    __half* __restrict__ Chi,
    int K, int Nld, int relu)
{
    extern __shared__ char dynsmem[];
    uint32_t sbase = (smem_u32(dynsmem) + 127u) & ~127u;

    int tid  = threadIdx.x;
    int wid  = tid >> 5, lane = tid & 31;
    int wm   = wid & 3, wn = wid >> 2;           // 4 x 2 warp grid
    int m0   = blockIdx.y * 128, n0 = blockIdx.x * 128;

    const int NC = K >> 5;       // 32-elem chunks

    auto load_chunk = [&](int kc, int buf) {
        uint32_t tb = sbase + buf * STAGE_BYTES;
        #pragma unroll
        for (int i = 0; i < 4; i++) {
            int seg = tid + i * 256;             // 0..1023
            int tile = seg >> 9;                 // 0:Ah 1:Wh
            int row  = (seg & 511) >> 2;
            int c    = seg & 3;
            uint32_t dst = tb + tile * TTILE + row * ROWB + c * 16;
            const __half* src = (tile == 0)
                ? Ah + (size_t)(m0 + row) * K + kc * 32 + c * 8
                : Wh + (size_t)(n0 + row) * K + kc * 32 + c * 8;
            asm volatile("cp.async.cg.shared.global [%0], [%1], 16;" :: "r"(dst), "l"(src));
        }
        asm volatile("cp.async.commit_group;" ::: "memory");
    };

    float acc[2][8][4];
    #pragma unroll
    for (int i = 0; i < 2; i++)
        #pragma unroll
        for (int j = 0; j < 8; j++)
            #pragma unroll
            for (int q = 0; q < 4; q++) acc[i][j][q] = 0.f;

    load_chunk(0, 0);
    if (NC > 1) load_chunk(1, 1);

    int lrow = lane & 15;
    int lcol = (lane >> 4) << 4;

    for (int c = 0; c < NC; c++) {
        if (c < NC - 1) asm volatile("cp.async.wait_group 1;" ::: "memory");
        else            asm volatile("cp.async.wait_group 0;" ::: "memory");
        __syncthreads();

        uint32_t sb = sbase + (c % STAGES) * STAGE_BYTES;

        if (c + 2 < NC) load_chunk(c + 2, (c + 2) % STAGES);

        uint32_t aAddr = sb + (uint32_t)(wm * 32 + lrow) * ROWB + lcol;
        uint32_t bAddr = sb + TTILE + (uint32_t)(wn * 64 + lrow) * ROWB + lcol;

        #pragma unroll
        for (int ks = 0; ks < 2; ks++) {
            uint32_t a[2][4], b[4][4];
            #pragma unroll
            for (int i = 0; i < 2; i++)
                ldmatrix_x4(a[i], aAddr + i * (16 * ROWB) + ks * 32);
            #pragma unroll
            for (int jj = 0; jj < 4; jj++)
                ldmatrix_x4(b[jj], bAddr + jj * (16 * ROWB) + ks * 32);
            #pragma unroll
            for (int i = 0; i < 2; i++)
                #pragma unroll
                for (int jj = 0; jj < 4; jj++) {
                    mma16816(acc[i][2 * jj],     a[i], b[jj][0], b[jj][2]);
                    mma16816(acc[i][2 * jj + 1], a[i], b[jj][1], b[jj][3]);
                }
        }
    }

    // ---------------- epilogue ----------------
    const float2* bp = (const float2*)(bias + n0 + wn * 64);
    float2 bv[8];
    #pragma unroll
    for (int j = 0; j < 8; j++) bv[j] = bp[j * 4 + (lane & 3)];

    #pragma unroll
    for (int i = 0; i < 2; i++) {
        int m_lo = m0 + wm * 32 + i * 16 + (lane >> 2);
        #pragma unroll
        for (int j = 0; j < 8; j++) {
            int n = n0 + wn * 64 + j * 8 + (lane & 3) * 2;
            float v0 = acc[i][j][0] + bv[j].x;
            float v1 = acc[i][j][1] + bv[j].y;
            float v2 = acc[i][j][2] + bv[j].x;
            float v3 = acc[i][j][3] + bv[j].y;
            if (relu) {
                v0 = fmaxf(v0, 0.f); v1 = fmaxf(v1, 0.f);
                v2 = fmaxf(v2, 0.f); v3 = fmaxf(v3, 0.f);
            }
            if (Cf) {
                *(float2*)(Cf + (size_t)m_lo * Nld + n)        = make_float2(v0, v1);
                *(float2*)(Cf + (size_t)(m_lo + 8) * Nld + n)  = make_float2(v2, v3);
            }
            if (Chi) {
                __half2 ph = __halves2half2(__float2half_rn(v0), __float2half_rn(v1));
                *(uint32_t*)(Chi + (size_t)m_lo * Nld + n) = *(uint32_t*)&ph;
                ph = __halves2half2(__float2half_rn(v2), __float2half_rn(v3));
                *(uint32_t*)(Chi + (size_t)(m_lo + 8) * Nld + n) = *(uint32_t*)&ph;
            }
        }
    }
}

// ---------------- weight transpose + fp16 convert ----------------
__global__ void wconv_kernel(const float* __restrict__ src,
                             __half* __restrict__ dh,
                             int K, int N, int rowOff, int dstLd) {
    __shared__ float ts[32][33];
    int n0 = blockIdx.x * 32, k0 = blockIdx.y * 32;
    int tx = threadIdx.x, ty = threadIdx.y;  // 32x8
    #pragma unroll
    for (int j = 0; j < 4; j++)
        ts[ty + 8 * j][tx] = src[(size_t)(k0 + ty + 8 * j) * N + n0 + tx];
    __syncthreads();
    #pragma unroll
    for (int j = 0; j < 4; j++) {
        float v = ts[tx][ty + 8 * j];
        size_t di = (size_t)(rowOff + n0 + ty + 8 * j) * dstLd + k0 + tx;
        dh[di] = __float2half_rn(v);
    }
}

__global__ void wconv3_kernel(const float* __restrict__ srcQ,
                              const float* __restrict__ srcK,
                              const float* __restrict__ srcV,
                              __half* __restrict__ dh) {
    __shared__ float ts[32][33];
    int z = blockIdx.z;
    const float* src = (z == 0) ? srcQ : (z == 1) ? srcK : srcV;
    int rowOff = z * CHDK;
    int n0 = blockIdx.x * 32, k0 = blockIdx.y * 32;
    int tx = threadIdx.x, ty = threadIdx.y;
    #pragma unroll
    for (int j = 0; j < 4; j++)
        ts[ty + 8 * j][tx] = src[(size_t)(k0 + ty + 8 * j) * CHDK + n0 + tx];
    __syncthreads();
    #pragma unroll
    for (int j = 0; j < 4; j++) {
        float v = ts[tx][ty + 8 * j];
        size_t di = (size_t)(rowOff + n0 + ty + 8 * j) * CD + k0 + tx;
        dh[di] = __float2half_rn(v);
    }
}

__global__ void bqkv_kernel(const float* __restrict__ bq,
                            const float* __restrict__ bk,
                            const float* __restrict__ bv) {
    int i = blockIdx.x;
    for (int j = threadIdx.x; j < CQKV; j += 256)
        g_bqkv[i * CQKV + j] =
            (j < CHDK) ? bq[i * CHDK + j] :
            (j < 2 * CHDK) ? bk[i * CHDK + j - CHDK] : bv[i * CHDK + j - 2 * CHDK];
}

// ---------------- gather spans into g_x (+ fp16) ----------------
__global__ void gather_kernel(const float* __restrict__ q_enc,
                              const int* __restrict__ ranges) {
    int row = blockIdx.x;
    int be = row >> 4, l = row & 15;
    int b = be >> 5, e = be & 31;
    int st = ranges[(b * CE + e) * 2];
    int en = ranges[(b * CE + e) * 2 + 1];
    int src = min(max(st + l, 0), CS - 1);
    bool m = l < (en - st);
    const float* s = q_enc + ((size_t)b * CS + src) * CD;
    size_t base = (size_t)row * CD;
    for (int i = threadIdx.x; i < CD; i += 256) {
        float v = m ? s[i] : 0.f;
        g_x[base + i] = v;
        g_xh[base + i] = __float2half_rn(v);
    }
}

// ---------------- fp32 SIMT GEMM (small tail matrices) ----------------
__global__ void gemm_bias_kernel(const float* __restrict__ A,
                                 const float* __restrict__ W,
                                 const float* __restrict__ bias,
                                 float* __restrict__ C,
                                 int M, int N, int K, int relu) {
    __shared__ float As[16][65];
    __shared__ float Bs[16][68];
    int tx = threadIdx.x, ty = threadIdx.y;
    int tid = ty * 16 + tx;
    int m0 = blockIdx.y * 64, n0 = blockIdx.x * 64;
    int a_row = tid >> 2, a_col = (tid & 3) << 2;
    int b_row = tid >> 4, b_col = (tid & 15) << 2;
    float acc[4][4] = {};
    for (int k0 = 0; k0 < K; k0 += 16) {
        int m = m0 + a_row;
        #pragma unroll
        for (int i = 0; i < 4; i++) {
            float v = 0.f;
            if (m < M) v = A[(size_t)m * K + k0 + a_col + i];
            As[a_col + i][a_row] = v;
        }
        #pragma unroll
        for (int i = 0; i < 4; i++) {
            int n = n0 + b_col + i;
            float v = 0.f;
            if (n < N) v = W[(size_t)(k0 + b_row) * N + n];
            Bs[b_row][b_col + i] = v;
        }
        __syncthreads();
        #pragma unroll
        for (int kk = 0; kk < 16; kk++) {
            float ra[4], rb[4];
            #pragma unroll
            for (int i = 0; i < 4; i++) ra[i] = As[kk][ty * 4 + i];
            #pragma unroll
            for (int j = 0; j < 4; j++) rb[j] = Bs[kk][tx * 4 + j];
            #pragma unroll
            for (int i = 0; i < 4; i++)
                #pragma unroll
                for (int j = 0; j < 4; j++)
                    acc[i][j] += ra[i] * rb[j];
        }
        __syncthreads();
    }
    #pragma unroll
    for (int i = 0; i < 4; i++) {
        int m = m0 + ty * 4 + i;
        if (m >= M) continue;
        #pragma unroll
        for (int j = 0; j < 4; j++) {
            int n = n0 + tx * 4 + j;
            if (n >= N) continue;
            float v = acc[i][j] + bias[n];
            if (relu) v = fmaxf(v, 0.f);
            C[(size_t)m * N + n] = v;
        }
    }
}

// ---------------- per-(span,head) attention (full, layers 0..NL-2) -------
__global__ void attn_kernel() {
    int nh = blockIdx.x;
    int n = nh / CH, h = nh % CH;
    __shared__ float qs[16][129], ks[16][129], vs[16][129];
    __shared__ float sc[16][17];
    int tid = threadIdx.x;  // 128
    for (int idx = tid; idx < 16 * 128; idx += 128) {
        int l = idx >> 7, d = idx & 127;
        size_t base = ((size_t)(n * CL + l)) * CQKV + h * CDK + d;
        qs[l][d] = __half2float(g_qkvh[base]);
        ks[l][d] = __half2float(g_qkvh[base + CHDK]);
        vs[l][d] = __half2float(g_qkvh[base + 2 * CHDK]);
    }
    __syncthreads();
    const float scale = 0.088388347648318447f;
    for (int p = tid; p < 256; p += 128) {
        int qi = p >> 4, ki = p & 15;
        float s = 0.f;
        #pragma unroll
        for (int d = 0; d < 128; d++) s += qs[qi][d] * ks[ki][d];
        sc[qi][ki] = s * scale;
    }
    __syncthreads();
    if (tid < 16) {
        float m = -1e30f;
        #pragma unroll
        for (int k = 0; k < 16; k++) m = fmaxf(m, sc[tid][k]);
        float sum = 0.f;
        #pragma unroll
        for (int k = 0; k < 16; k++) { float e = __expf(sc[tid][k] - m); sc[tid][k] = e; sum += e; }
        float inv = 1.f / sum;
        #pragma unroll
        for (int k = 0; k < 16; k++) sc[tid][k] *= inv;
    }
    __syncthreads();
    int d = tid;
    #pragma unroll
    for (int qi = 0; qi < 16; qi++) {
        float acc = 0.f;
        #pragma unroll
        for (int k = 0; k < 16; k++) acc += sc[qi][k] * vs[k][d];
        g_oh[((size_t)(n * CL + qi)) * CHDK + h * CDK + d] = __float2half_rn(acc);
    }
}

// last layer: only query position 0; writes COMPACT rows (2048).
__global__ void attn0_kernel() {
    int nh = blockIdx.x;
    int n = nh / CH, h = nh % CH;
    __shared__ float ks[16][129], vs[16][129];
    __shared__ float q0[128];
    __shared__ float p[16];
    int tid = threadIdx.x;  // 128
    for (int idx = tid; idx < 16 * 128; idx += 128) {
        int l = idx >> 7, d = idx & 127;
        size_t base = ((size_t)(n * CL + l)) * CQKV + h * CDK + d;
        ks[l][d] = __half2float(g_qkvh[base + CHDK]);
        vs[l][d] = __half2float(g_qkvh[base + 2 * CHDK]);
    }
    q0[tid] = __half2float(g_qkvh[((size_t)(n * CL)) * CQKV + h * CDK + tid]);
    __syncthreads();
    const float scale = 0.088388347648318447f;
    if (tid < 16) {
        float s = 0.f;
        #pragma unroll
        for (int d = 0; d < 128; d++) s += q0[d] * ks[tid][d];
        p[tid] = s * scale;
    }
    __syncthreads();
    if (tid == 0) {
        float m = -1e30f;
        #pragma unroll
        for (int k = 0; k < 16; k++) m = fmaxf(m, p[k]);
        float sum = 0.f;
        #pragma unroll
        for (int k = 0; k < 16; k++) { float e = __expf(p[k] - m); p[k] = e; sum += e; }
        float inv = 1.f / sum;
        #pragma unroll
        for (int k = 0; k < 16; k++) p[k] *= inv;
    }
    __syncthreads();
    float acc = 0.f;
    #pragma unroll
    for (int k = 0; k < 16; k++) acc += p[k] * vs[k][tid];
    g_oh[(size_t)n * CHDK + h * CDK + tid] = __float2half_rn(acc);
}

// ---------------- LayerNorm kernels ----------------
__device__ __forceinline__ float blockReduceSum(float val) {
    __shared__ float sh[32];
    int lane = threadIdx.x & 31, wid = threadIdx.x >> 5;
    #pragma unroll
    for (int o = 16; o > 0; o >>= 1) val += __shfl_xor_sync(0xffffffffu, val, o);
    if (lane == 0) sh[wid] = val;
    __syncthreads();
    int nw = (blockDim.x + 31) >> 5;
    val = (threadIdx.x < nw) ? sh[lane] : 0.f;
    if (wid == 0) {
        #pragma unroll
        for (int o = 16; o > 0; o >>= 1) val += __shfl_xor_sync(0xffffffffu, val, o);
    }
    return val;
}

__global__ void add_ln_kernel(const float* __restrict__ gamma,
                              const float* __restrict__ beta) {
    int row = blockIdx.x;
    int tid = threadIdx.x;
    float v[3];
    float s = 0.f;
    #pragma unroll
    for (int j = 0; j < 3; j++) {
        size_t idx = (size_t)row * CD + tid + j * 256;
        v[j] = g_x[idx] + g_t[idx];
        s += v[j];
    }
    s = blockReduceSum(s);
    __shared__ float mean_s, rstd_s;
    if (tid == 0) mean_s = s * (1.f / CD);
    __syncthreads();
    float m = mean_s;
    float vv = 0.f;
    #pragma unroll
    for (int j = 0; j < 3; j++) { float d = v[j] - m; vv += d * d; }
    vv = blockReduceSum(vv);
    if (tid == 0) rstd_s = rsqrtf(vv * (1.f / CD) + 1e-5f);
    __syncthreads();
    float r = rstd_s;
    #pragma unroll
    for (int j = 0; j < 3; j++) {
        int c = tid + j * 256;
        float o = (v[j] - m) * r * gamma[c] + beta[c];
        size_t idx = (size_t)row * CD + c;
        g_x[idx] = o;
        g_xh[idx] = __float2half_rn(o);
    }
}

// last-layer LN1: residual = g_x row (r*16), t = g_t compact row r.
__global__ void ln1_last_kernel(const float* __restrict__ gamma,
                                const float* __restrict__ beta) {
    int r = blockIdx.x;  // 0..2047
    int tid = threadIdx.x;
    float v[3];
    float s = 0.f;
    #pragma unroll
    for (int j = 0; j < 3; j++) {
        int c = tid + j * 256;
        v[j] = g_x[((size_t)r * CL) * CD + c] + g_t[(size_t)r * CD + c];
        s += v[j];
    }
    s = blockReduceSum(s);
    __shared__ float mean_s, rstd_s;
    if (tid == 0) mean_s = s * (1.f / CD);
    __syncthreads();
    float m = mean_s;
    float vv = 0.f;
    #pragma unroll
    for (int j = 0; j < 3; j++) { float d = v[j] - m; vv += d * d; }
    vv = blockReduceSum(vv);
    if (tid == 0) rstd_s = rsqrtf(vv * (1.f / CD) + 1e-5f);
    __syncthreads();
    float rr = rstd_s;
    #pragma unroll
    for (int j = 0; j < 3; j++) {
        int c = tid + j * 256;
        float o = (v[j] - m) * rr * gamma[c] + beta[c];
        size_t idx = (size_t)r * CD + c;
        g_xc[idx] = o;
        g_xch[idx] = __float2half_rn(o);
    }
}

// last-layer LN2: residual = g_xc, t = g_t compact; writes g_ent (fp32).
__global__ void ln2_last_kernel(const float* __restrict__ gamma,
                                const float* __restrict__ beta) {
    int r = blockIdx.x;  // 0..2047
    int tid = threadIdx.x;
    float v[3];
    float s = 0.f;
    #pragma unroll
    for (int j = 0; j < 3; j++) {
        size_t idx = (size_t)r * CD + tid + j * 256;
        v[j] = g_xc[idx] + g_t[idx];
        s += v[j];
    }
    s = blockReduceSum(s);
    __shared__ float mean_s, rstd_s;
    if (tid == 0) mean_s = s * (1.f / CD);
    __syncthreads();
    float m = mean_s;
    float vv = 0.f;
    #pragma unroll
    for (int j = 0; j < 3; j++) { float d = v[j] - m; vv += d * d; }
    vv = blockReduceSum(vv);
    if (tid == 0) rstd_s = rsqrtf(vv * (1.f / CD) + 1e-5f);
    __syncthreads();
    float rr = rstd_s;
    #pragma unroll
    for (int j = 0; j < 3; j++) {
        int c = tid + j * 256;
        g_ent[(size_t)r * CD + c] = (v[j] - m) * rr * gamma[c] + beta[c];
    }
}

// ---------------- tail kernels ----------------
__global__ void pool_attn_kernel(const float* __restrict__ q_enc,
                                 const float* __restrict__ hint) {
    int t = blockIdx.x, b = blockIdx.y;
    __shared__ float qv[770];
    __shared__ float lg[32];
    int tid = threadIdx.x;
    for (int i = tid; i < 770; i += 256)
        qv[i] = (i < CD) ? q_enc[((size_t)b * CS + t) * CD + i]
                         : hint[((size_t)b * CTQ + t) * 2 + (i - CD)];
    __syncthreads();
    int e = tid >> 3, sub = tid & 7;
    const float* ep = g_entp + ((size_t)b * CE + e) * 770;
    float p = 0.f;
    for (int d = sub; d < 770; d += 8) p += qv[d] * ep[d];
    p += __shfl_down_sync(0xffffffffu, p, 4, 8);
    p += __shfl_down_sync(0xffffffffu, p, 2, 8);
    p += __shfl_down_sync(0xffffffffu, p, 1, 8);
    if (sub == 0) lg[e] = p;
    __syncthreads();
    if (tid < 32) {
        float v = lg[tid];
        float m = v;
        #pragma unroll
        for (int o = 16; o > 0; o >>= 1) m = fmaxf(m, __shfl_xor_sync(0xffffffffu, m, o));
        float ex = __expf(v - m);
        float sm = ex;
        #pragma unroll
        for (int o = 16; o > 0; o >>= 1) sm += __shfl_xor_sync(0xffffffffu, sm, o);
        g_attnw[((size_t)b * CTQ + t) * CE + tid] = ex / sm;
    }
}

__global__ void pool_wa_kernel(const int* __restrict__ qlen) {
    int b = blockIdx.x;
    int tid = threadIdx.x;
    __shared__ float A[32];
    int n = qlen[b];
    if (tid < 32) {
        float s = 0.f;
        for (int t = 0; t < n; t++) s += g_attnw[((size_t)b * CTQ + t) * CE + tid];
        A[tid] = s;
    }
    __syncthreads();
    #pragma unroll
    for (int j = 0; j < 3; j++) {
        int d = tid + j * 256;
        float s = 0.f;
        #pragma unroll
        for (int e = 0; e < 32; e++) s += A[e] * g_ent[((size_t)b * CE + e) * CD + d];
        g_wa[(size_t)b * CD + d] = s;
    }
}

__global__ void feat_kernel(const float* __restrict__ q_enc) {
    int b = blockIdx.x;
    for (int i = threadIdx.x; i < 2 * CD; i += 256)
        g_feat[(size_t)b * 2 * CD + i] =
            (i < CD) ? q_enc[(size_t)b * CS * CD + i] : g_wa[(size_t)b * CD + (i - CD)];
}

__global__ void head_out_kernel(const float* __restrict__ W2,
                                const float* __restrict__ b2,
                                float* __restrict__ out) {
    int b = blockIdx.x, tid = threadIdx.x;
    float s = 0.f;
    for (int n = tid; n < CNH; n += 256) s += g_h[(size_t)b * CNH + n] * W2[n];
    s = blockReduceSum(s);
    if (tid == 0) out[b] = s + b2[0];
}

// ---------------- host ----------------
template <typename T>
static T* dsym(const void* symbol) {
    void* p = nullptr;
    cudaGetSymbolAddress(&p, symbol);
    return (T*)p;
}

extern "C" void kernel_launch(void* const* d_in, const int* in_sizes, int n_in,
                              void* d_out, int out_size) {
    const float* q_enc  = (const float*)d_in[0];
    const int*   q_qlen = (const int*)  d_in[1];
    const float* hint   = (const float*)d_in[2];
    const int*   ranges = (const int*)  d_in[3];
    const float* Wq  = (const float*)d_in[4];
    const float* bq  = (const float*)d_in[5];
    const float* Wk  = (const float*)d_in[6];
    const float* bk  = (const float*)d_in[7];
    const float* Wv  = (const float*)d_in[8];
    const float* bv  = (const float*)d_in[9];
    const float* Wo  = (const float*)d_in[10];
    const float* bo  = (const float*)d_in[11];
    const float* ln1g = (const float*)d_in[12];
    const float* ln1b = (const float*)d_in[13];
    const float* Wf1 = (const float*)d_in[14];
    const float* bf1 = (const float*)d_in[15];
    const float* Wf2 = (const float*)d_in[16];
    const float* bf2 = (const float*)d_in[17];
    const float* ln2g = (const float*)d_in[18];
    const float* ln2b = (const float*)d_in[19];
    const float* W_ea = (const float*)d_in[20];
    const float* b_ea = (const float*)d_in[21];
    const float* W1  = (const float*)d_in[22];
    const float* b1  = (const float*)d_in[23];
    const float* W2  = (const float*)d_in[24];
    const float* b2  = (const float*)d_in[25];
    float* out = (float*)d_out;

    cudaFuncSetAttribute(gemm_mma, cudaFuncAttributeMaxDynamicSharedMemorySize, SMEM_DYN);

    __half* xh  = dsym<__half>(g_xh);
    __half* oh  = dsym<__half>(g_oh);
    __half* fh  = dsym<__half>(g_fh);
    __half* xch = dsym<__half>(g_xch);
    __half* qkvh = dsym<__half>(g_qkvh);
    float* t_  = dsym<float>(g_t);
    __half* wqkvh = dsym<__half>(g_wqkvh);
    __half* woh   = dsym<__half>(g_woh);
    __half* wf1h  = dsym<__half>(g_wf1h);
    __half* wf2h  = dsym<__half>(g_wf2h);
    float* bqkv = dsym<float>(g_bqkv);
    float* ent  = dsym<float>(g_ent);
    float* entp = dsym<float>(g_entp);
    float* feat = dsym<float>(g_feat);
    float* h_   = dsym<float>(g_h);

    dim3 wblk(32, 8);

    // launch 0: fused layer-0 QKV weight conversion; 1: bias concat; 2: gather
    wconv3_kernel<<<dim3(CHDK/32, CD/32, 3), wblk>>>(Wq, Wk, Wv, wqkvh);
    bqkv_kernel<<<CNL, 256>>>(bq, bk, bv);
    gather_kernel<<<NROWS, 256>>>(q_enc, ranges);

    // launch 3: layer-0 QKV GEMM — ncu window target
    gemm_mma<<<dim3(CQKV/128, NROWS/128), 256, SMEM_DYN>>>(
        xh, wqkvh, bqkv, nullptr, qkvh, CD, CQKV, 0);

    // remaining weight conversions
    for (int i = 0; i < CNL; i++) {
        if (i > 0) {
            size_t oQ = (size_t)i * CQKV * CD;
            wconv3_kernel<<<dim3(CHDK/32, CD/32, 3), wblk>>>(
                Wq + (size_t)i*CD*CHDK, Wk + (size_t)i*CD*CHDK, Wv + (size_t)i*CD*CHDK,
                wqkvh + oQ);
        }
        size_t oO = (size_t)i * CD * CHDK;
        wconv_kernel<<<dim3(CD/32, CHDK/32), wblk>>>(Wo + (size_t)i*CHDK*CD, woh + oO, CHDK, CD, 0, CHDK);
        size_t oF1 = (size_t)i * CDFF * CD;
        wconv_kernel<<<dim3(CDFF/32, CD/32), wblk>>>(Wf1 + (size_t)i*CD*CDFF, wf1h + oF1, CD, CDFF, 0, CD);
        size_t oF2 = (size_t)i * CD * CDFF;
        wconv_kernel<<<dim3(CD/32, CDFF/32), wblk>>>(Wf2 + (size_t)i*CDFF*CD, wf2h + oF2, CDFF, CD, 0, CDFF);
    }

    // ---- layers 0 .. NL-2: full-width pipeline ----
    for (int i = 0; i < CNL - 1; i++) {
        size_t oQ  = (size_t)i * CQKV * CD;
        size_t oO  = (size_t)i * CD * CHDK;
        size_t oF1 = (size_t)i * CDFF * CD;
        size_t oF2 = (size_t)i * CD * CDFF;

        if (i > 0) {
            gemm_mma<<<dim3(CQKV/128, NROWS/128), 256, SMEM_DYN>>>(
                xh, wqkvh + oQ, bqkv + i*CQKV, nullptr, qkvh, CD, CQKV, 0);
        }

        attn_kernel<<<NENT * CH, 128>>>();

        gemm_mma<<<dim3(CD/128, NROWS/128), 256, SMEM_DYN>>>(
            oh, woh + oO, bo + i*CD, t_, nullptr, CHDK, CD, 0);

        add_ln_kernel<<<NROWS, 256>>>(ln1g + i*CD, ln1b + i*CD);

        gemm_mma<<<dim3(CDFF/128, NROWS/128), 256, SMEM_DYN>>>(
            xh, wf1h + oF1, bf1 + i*CDFF, nullptr, fh, CD, CDFF, 1);

        gemm_mma<<<dim3(CD/128, NROWS/128), 256, SMEM_DYN>>>(
            fh, wf2h + oF2, bf2 + i*CD, t_, nullptr, CDFF, CD, 0);

        add_ln_kernel<<<NROWS, 256>>>(ln2g + i*CD, ln2b + i*CD);
    }

    // ---- layer NL-1 (last): only span-row 0 needed post-attention ----
    {
        const int i = CNL - 1;
        size_t oQ  = (size_t)i * CQKV * CD;
        size_t oO  = (size_t)i * CD * CHDK;
        size_t oF1 = (size_t)i * CDFF * CD;
        size_t oF2 = (size_t)i * CD * CDFF;

        gemm_mma<<<dim3(CQKV/128, NROWS/128), 256, SMEM_DYN>>>(
            xh, wqkvh + oQ, bqkv + i*CQKV, nullptr, qkvh, CD, CQKV, 0);

        attn0_kernel<<<NENT * CH, 128>>>();

        gemm_mma<<<dim3(CD/128, NENT/128), 256, SMEM_DYN>>>(
            oh, woh + oO, bo + i*CD, t_, nullptr, CHDK, CD, 0);

        ln1_last_kernel<<<NENT, 256>>>(ln1g + i*CD, ln1b + i*CD);

        gemm_mma<<<dim3(CDFF/128, NENT/128), 256, SMEM_DYN>>>(
            xch, wf1h + oF1, bf1 + i*CDFF, nullptr, fh, CD, CDFF, 1);

        gemm_mma<<<dim3(CD/128, NENT/128), 256, SMEM_DYN>>>(
            fh, wf2h + oF2, bf2 + i*CD, t_, nullptr, CDFF, CD, 0);

        ln2_last_kernel<<<NENT, 256>>>(ln2g + i*CD, ln2b + i*CD);
    }

    dim3 blk(16, 16);
    gemm_bias_kernel<<<dim3((770 + 63) / 64, NENT / 64), blk>>>(ent, W_ea, b_ea, entp, NENT, 770, CD, 0);
    pool_attn_kernel<<<dim3(CTQ, CB), 256>>>(q_enc, hint);
    pool_wa_kernel<<<CB, 256>>>(q_qlen);
    feat_kernel<<<CB, 256>>>(q_enc);
    gemm_bias_kernel<<<dim3(CNH / 64, 1), blk>>>(feat, W1, b1, h_, CB, CNH, 2 * CD, 1);
    head_out_kernel<<<CB, 256>>>(W2, b2, out);
}

// round 13
// speedup vs baseline: 11.3411x; 1.0876x over previous
#include <cuda_runtime.h>
#include <cuda_fp16.h>
#include <math.h>
#include <stdint.h>

// ---------------- problem constants ----------------
#define CB   64
#define CS   512
#define CD   768
#define CE   32
#define CL   16
#define CTQ  128
#define CH   3
#define CDK  128
#define CHDK 384
#define CQKV 1152
#define CDFF 3072
#define CNH  1024
#define CNL  3
#define NROWS (CB*CE*CL)     // 32768
#define NENT  (CB*CE)        // 2048

// ---------------- device scratch ----------------
__device__ float   g_x  [NROWS*CD];
__device__ __half  g_xh [NROWS*CD];
__device__ __half  g_qkvh[NROWS*CQKV];
__device__ __half  g_oh [NROWS*CHDK];
__device__ __half  g_fh [NROWS*CDFF];
__device__ float   g_t  [NROWS*CD];

// compact (last-layer) buffers: 2048 rows
__device__ float   g_xc [NENT*CD];
__device__ __half  g_xch[NENT*CD];

// fp16 weights
__device__ __half  g_wqkvh[CNL*CQKV*CD];
__device__ __half  g_woh [CNL*CD*CHDK];
__device__ __half  g_wf1h[CNL*CDFF*CD];
__device__ __half  g_wf2h[CNL*CD*CDFF];
__device__ float   g_bqkv[CNL*CQKV];

__device__ float g_ent [NENT*CD];
__device__ float g_entp[NENT*770];
__device__ float g_attnw[CB*CTQ*CE];
__device__ float g_wa  [CB*CD];
__device__ float g_feat[CB*2*CD];
__device__ float g_h   [CB*CNH];

// ---------------- helpers ----------------
__device__ __forceinline__ uint32_t smem_u32(const void* p) {
    uint32_t a;
    asm("{ .reg .u64 t; cvta.to.shared.u64 t, %1; cvt.u32.u64 %0, t; }" : "=r"(a) : "l"(p));
    return a;
}

__device__ __forceinline__ void ldmatrix_x4(uint32_t* r, uint32_t addr) {
    asm volatile("ldmatrix.sync.aligned.m8n8.x4.shared.b16 {%0,%1,%2,%3}, [%4];"
        : "=r"(r[0]), "=r"(r[1]), "=r"(r[2]), "=r"(r[3]) : "r"(addr));
}

__device__ __forceinline__ void mma16816(float* c, const uint32_t* a,
                                         uint32_t b0, uint32_t b1) {
    asm volatile("mma.sync.aligned.m16n8k16.row.col.f32.f16.f16.f32 "
        "{%0,%1,%2,%3}, {%4,%5,%6,%7}, {%8,%9}, {%0,%1,%2,%3};"
        : "+f"(c[0]), "+f"(c[1]), "+f"(c[2]), "+f"(c[3])
        : "r"(a[0]), "r"(a[1]), "r"(a[2]), "r"(a[3]), "r"(b0), "r"(b1));
}

// ---------------- tensor-core GEMM (mma.sync fp16, 1-term, K-chunk 64) ---
// C = Ah @ Wh^T + bias.  W stored [N,K] K-major fp16.
// CTA 128x128, 256 thr (8 warps, 32x64 each). 2 CTAs/SM.
#define ROWB    144                 // 64 fp16 = 128B data, padded to 144B
#define TTILE   (128*ROWB)          // 18432
#define STAGES  3
#define STAGE_BYTES (2*TTILE)       // Ah | Wh = 36864
#define SMEM_DYN (STAGES*STAGE_BYTES + 128)

__global__ __launch_bounds__(256, 2) void gemm_mma(
    const __half* __restrict__ Ah,
    const __half* __restrict__ Wh,
    const float* __restrict__ bias,
    float* __restrict__ Cf,
    __half* __restrict__ Chi,
    int K, int Nld, int relu)
{
    extern __shared__ char dynsmem[];
    uint32_t sbase = (smem_u32(dynsmem) + 127u) & ~127u;

    int tid  = threadIdx.x;
    int wid  = tid >> 5, lane = tid & 31;
    int wm   = wid & 3, wn = wid >> 2;           // 4 x 2 warp grid
    int m0   = blockIdx.y * 128, n0 = blockIdx.x * 128;

    const int NC = K >> 6;       // 64-elem chunks

    auto load_chunk = [&](int kc, int buf) {
        uint32_t tb = sbase + buf * STAGE_BYTES;
        #pragma unroll
        for (int i = 0; i < 8; i++) {
            int seg = tid + i * 256;             // 0..2047
            int tile = seg >> 10;                // 0:Ah 1:Wh
            int row  = (seg & 1023) >> 3;        // 0..127
            int c    = seg & 7;                  // 16B segment in 128B row
            uint32_t dst = tb + tile * TTILE + row * ROWB + c * 16;
            const __half* src = (tile == 0)
                ? Ah + (size_t)(m0 + row) * K + kc * 64 + c * 8
                : Wh + (size_t)(n0 + row) * K + kc * 64 + c * 8;
            asm volatile("cp.async.cg.shared.global [%0], [%1], 16;" :: "r"(dst), "l"(src));
        }
        asm volatile("cp.async.commit_group;" ::: "memory");
    };

    float acc[2][8][4];
    #pragma unroll
    for (int i = 0; i < 2; i++)
        #pragma unroll
        for (int j = 0; j < 8; j++)
            #pragma unroll
            for (int q = 0; q < 4; q++) acc[i][j][q] = 0.f;

    load_chunk(0, 0);
    if (NC > 1) load_chunk(1, 1);

    int lrow = lane & 15;
    int lcol = (lane >> 4) << 4;

    for (int c = 0; c < NC; c++) {
        if (c < NC - 1) asm volatile("cp.async.wait_group 1;" ::: "memory");
        else            asm volatile("cp.async.wait_group 0;" ::: "memory");
        __syncthreads();

        uint32_t sb = sbase + (c % STAGES) * STAGE_BYTES;

        if (c + 2 < NC) load_chunk(c + 2, (c + 2) % STAGES);

        uint32_t aAddr = sb + (uint32_t)(wm * 32 + lrow) * ROWB + lcol;
        uint32_t bAddr = sb + TTILE + (uint32_t)(wn * 64 + lrow) * ROWB + lcol;

        #pragma unroll
        for (int ks = 0; ks < 4; ks++) {
            uint32_t a[2][4], b[4][4];
            #pragma unroll
            for (int i = 0; i < 2; i++)
                ldmatrix_x4(a[i], aAddr + i * (16 * ROWB) + ks * 32);
            #pragma unroll
            for (int jj = 0; jj < 4; jj++)
                ldmatrix_x4(b[jj], bAddr + jj * (16 * ROWB) + ks * 32);
            #pragma unroll
            for (int i = 0; i < 2; i++)
                #pragma unroll
                for (int jj = 0; jj < 4; jj++) {
                    mma16816(acc[i][2 * jj],     a[i], b[jj][0], b[jj][2]);
                    mma16816(acc[i][2 * jj + 1], a[i], b[jj][1], b[jj][3]);
                }
        }
    }

    // ---------------- epilogue ----------------
    const float2* bp = (const float2*)(bias + n0 + wn * 64);
    float2 bv[8];
    #pragma unroll
    for (int j = 0; j < 8; j++) bv[j] = bp[j * 4 + (lane & 3)];

    #pragma unroll
    for (int i = 0; i < 2; i++) {
        int m_lo = m0 + wm * 32 + i * 16 + (lane >> 2);
        #pragma unroll
        for (int j = 0; j < 8; j++) {
            int n = n0 + wn * 64 + j * 8 + (lane & 3) * 2;
            float v0 = acc[i][j][0] + bv[j].x;
            float v1 = acc[i][j][1] + bv[j].y;
            float v2 = acc[i][j][2] + bv[j].x;
            float v3 = acc[i][j][3] + bv[j].y;
            if (relu) {
                v0 = fmaxf(v0, 0.f); v1 = fmaxf(v1, 0.f);
                v2 = fmaxf(v2, 0.f); v3 = fmaxf(v3, 0.f);
            }
            if (Cf) {
                *(float2*)(Cf + (size_t)m_lo * Nld + n)        = make_float2(v0, v1);
                *(float2*)(Cf + (size_t)(m_lo + 8) * Nld + n)  = make_float2(v2, v3);
            }
            if (Chi) {
                __half2 ph = __halves2half2(__float2half_rn(v0), __float2half_rn(v1));
                *(uint32_t*)(Chi + (size_t)m_lo * Nld + n) = *(uint32_t*)&ph;
                ph = __halves2half2(__float2half_rn(v2), __float2half_rn(v3));
                *(uint32_t*)(Chi + (size_t)(m_lo + 8) * Nld + n) = *(uint32_t*)&ph;
            }
        }
    }
}

// ---------------- weight transpose + fp16 convert ----------------
__global__ void wconv_kernel(const float* __restrict__ src,
                             __half* __restrict__ dh,
                             int K, int N, int rowOff, int dstLd) {
    __shared__ float ts[32][33];
    int n0 = blockIdx.x * 32, k0 = blockIdx.y * 32;
    int tx = threadIdx.x, ty = threadIdx.y;  // 32x8
    #pragma unroll
    for (int j = 0; j < 4; j++)
        ts[ty + 8 * j][tx] = src[(size_t)(k0 + ty + 8 * j) * N + n0 + tx];
    __syncthreads();
    #pragma unroll
    for (int j = 0; j < 4; j++) {
        float v = ts[tx][ty + 8 * j];
        size_t di = (size_t)(rowOff + n0 + ty + 8 * j) * dstLd + k0 + tx;
        dh[di] = __float2half_rn(v);
    }
}

__global__ void wconv3_kernel(const float* __restrict__ srcQ,
                              const float* __restrict__ srcK,
                              const float* __restrict__ srcV,
                              __half* __restrict__ dh) {
    __shared__ float ts[32][33];
    int z = blockIdx.z;
    const float* src = (z == 0) ? srcQ : (z == 1) ? srcK : srcV;
    int rowOff = z * CHDK;
    int n0 = blockIdx.x * 32, k0 = blockIdx.y * 32;
    int tx = threadIdx.x, ty = threadIdx.y;
    #pragma unroll
    for (int j = 0; j < 4; j++)
        ts[ty + 8 * j][tx] = src[(size_t)(k0 + ty + 8 * j) * CHDK + n0 + tx];
    __syncthreads();
    #pragma unroll
    for (int j = 0; j < 4; j++) {
        float v = ts[tx][ty + 8 * j];
        size_t di = (size_t)(rowOff + n0 + ty + 8 * j) * CD + k0 + tx;
        dh[di] = __float2half_rn(v);
    }
}

__global__ void bqkv_kernel(const float* __restrict__ bq,
                            const float* __restrict__ bk,
                            const float* __restrict__ bv) {
    int i = blockIdx.x;
    for (int j = threadIdx.x; j < CQKV; j += 256)
        g_bqkv[i * CQKV + j] =
            (j < CHDK) ? bq[i * CHDK + j] :
            (j < 2 * CHDK) ? bk[i * CHDK + j - CHDK] : bv[i * CHDK + j - 2 * CHDK];
}

// ---------------- gather spans into g_x (+ fp16) ----------------
__global__ void gather_kernel(const float* __restrict__ q_enc,
                              const int* __restrict__ ranges) {
    int row = blockIdx.x;
    int be = row >> 4, l = row & 15;
    int b = be >> 5, e = be & 31;
    int st = ranges[(b * CE + e) * 2];
    int en = ranges[(b * CE + e) * 2 + 1];
    int src = min(max(st + l, 0), CS - 1);
    bool m = l < (en - st);
    const float* s = q_enc + ((size_t)b * CS + src) * CD;
    size_t base = (size_t)row * CD;
    for (int i = threadIdx.x; i < CD; i += 256) {
        float v = m ? s[i] : 0.f;
        g_x[base + i] = v;
        g_xh[base + i] = __float2half_rn(v);
    }
}

// ---------------- fp32 SIMT GEMM (small tail matrices) ----------------
__global__ void gemm_bias_kernel(const float* __restrict__ A,
                                 const float* __restrict__ W,
                                 const float* __restrict__ bias,
                                 float* __restrict__ C,
                                 int M, int N, int K, int relu) {
    __shared__ float As[16][65];
    __shared__ float Bs[16][68];
    int tx = threadIdx.x, ty = threadIdx.y;
    int tid = ty * 16 + tx;
    int m0 = blockIdx.y * 64, n0 = blockIdx.x * 64;
    int a_row = tid >> 2, a_col = (tid & 3) << 2;
    int b_row = tid >> 4, b_col = (tid & 15) << 2;
    float acc[4][4] = {};
    for (int k0 = 0; k0 < K; k0 += 16) {
        int m = m0 + a_row;
        #pragma unroll
        for (int i = 0; i < 4; i++) {
            float v = 0.f;
            if (m < M) v = A[(size_t)m * K + k0 + a_col + i];
            As[a_col + i][a_row] = v;
        }
        #pragma unroll
        for (int i = 0; i < 4; i++) {
            int n = n0 + b_col + i;
            float v = 0.f;
            if (n < N) v = W[(size_t)(k0 + b_row) * N + n];
            Bs[b_row][b_col + i] = v;
        }
        __syncthreads();
        #pragma unroll
        for (int kk = 0; kk < 16; kk++) {
            float ra[4], rb[4];
            #pragma unroll
            for (int i = 0; i < 4; i++) ra[i] = As[kk][ty * 4 + i];
            #pragma unroll
            for (int j = 0; j < 4; j++) rb[j] = Bs[kk][tx * 4 + j];
            #pragma unroll
            for (int i = 0; i < 4; i++)
                #pragma unroll
                for (int j = 0; j < 4; j++)
                    acc[i][j] += ra[i] * rb[j];
        }
        __syncthreads();
    }
    #pragma unroll
    for (int i = 0; i < 4; i++) {
        int m = m0 + ty * 4 + i;
        if (m >= M) continue;
        #pragma unroll
        for (int j = 0; j < 4; j++) {
            int n = n0 + tx * 4 + j;
            if (n >= N) continue;
            float v = acc[i][j] + bias[n];
            if (relu) v = fmaxf(v, 0.f);
            C[(size_t)m * N + n] = v;
        }
    }
}

// ---------------- per-(span,head) attention (full, layers 0..NL-2) -------
__global__ void attn_kernel() {
    int nh = blockIdx.x;
    int n = nh / CH, h = nh % CH;
    __shared__ float qs[16][129], ks[16][129], vs[16][129];
    __shared__ float sc[16][17];
    int tid = threadIdx.x;  // 128
    for (int idx = tid; idx < 16 * 128; idx += 128) {
        int l = idx >> 7, d = idx & 127;
        size_t base = ((size_t)(n * CL + l)) * CQKV + h * CDK + d;
        qs[l][d] = __half2float(g_qkvh[base]);
        ks[l][d] = __half2float(g_qkvh[base + CHDK]);
        vs[l][d] = __half2float(g_qkvh[base + 2 * CHDK]);
    }
    __syncthreads();
    const float scale = 0.088388347648318447f;
    for (int p = tid; p < 256; p += 128) {
        int qi = p >> 4, ki = p & 15;
        float s = 0.f;
        #pragma unroll
        for (int d = 0; d < 128; d++) s += qs[qi][d] * ks[ki][d];
        sc[qi][ki] = s * scale;
    }
    __syncthreads();
    if (tid < 16) {
        float m = -1e30f;
        #pragma unroll
        for (int k = 0; k < 16; k++) m = fmaxf(m, sc[tid][k]);
        float sum = 0.f;
        #pragma unroll
        for (int k = 0; k < 16; k++) { float e = __expf(sc[tid][k] - m); sc[tid][k] = e; sum += e; }
        float inv = 1.f / sum;
        #pragma unroll
        for (int k = 0; k < 16; k++) sc[tid][k] *= inv;
    }
    __syncthreads();
    int d = tid;
    #pragma unroll
    for (int qi = 0; qi < 16; qi++) {
        float acc = 0.f;
        #pragma unroll
        for (int k = 0; k < 16; k++) acc += sc[qi][k] * vs[k][d];
        g_oh[((size_t)(n * CL + qi)) * CHDK + h * CDK + d] = __float2half_rn(acc);
    }
}

// last layer: only query position 0; writes COMPACT rows (2048).
__global__ void attn0_kernel() {
    int nh = blockIdx.x;
    int n = nh / CH, h = nh % CH;
    __shared__ float ks[16][129], vs[16][129];
    __shared__ float q0[128];
    __shared__ float p[16];
    int tid = threadIdx.x;  // 128
    for (int idx = tid; idx < 16 * 128; idx += 128) {
        int l = idx >> 7, d = idx & 127;
        size_t base = ((size_t)(n * CL + l)) * CQKV + h * CDK + d;
        ks[l][d] = __half2float(g_qkvh[base + CHDK]);
        vs[l][d] = __half2float(g_qkvh[base + 2 * CHDK]);
    }
    q0[tid] = __half2float(g_qkvh[((size_t)(n * CL)) * CQKV + h * CDK + tid]);
    __syncthreads();
    const float scale = 0.088388347648318447f;
    if (tid < 16) {
        float s = 0.f;
        #pragma unroll
        for (int d = 0; d < 128; d++) s += q0[d] * ks[tid][d];
        p[tid] = s * scale;
    }
    __syncthreads();
    if (tid == 0) {
        float m = -1e30f;
        #pragma unroll
        for (int k = 0; k < 16; k++) m = fmaxf(m, p[k]);
        float sum = 0.f;
        #pragma unroll
        for (int k = 0; k < 16; k++) { float e = __expf(p[k] - m); p[k] = e; sum += e; }
        float inv = 1.f / sum;
        #pragma unroll
        for (int k = 0; k < 16; k++) p[k] *= inv;
    }
    __syncthreads();
    float acc = 0.f;
    #pragma unroll
    for (int k = 0; k < 16; k++) acc += p[k] * vs[k][tid];
    g_oh[(size_t)n * CHDK + h * CDK + tid] = __float2half_rn(acc);
}

// ---------------- LayerNorm kernels ----------------
__device__ __forceinline__ float blockReduceSum(float val) {
    __shared__ float sh[32];
    int lane = threadIdx.x & 31, wid = threadIdx.x >> 5;
    #pragma unroll
    for (int o = 16; o > 0; o >>= 1) val += __shfl_xor_sync(0xffffffffu, val, o);
    if (lane == 0) sh[wid] = val;
    __syncthreads();
    int nw = (blockDim.x + 31) >> 5;
    val = (threadIdx.x < nw) ? sh[lane] : 0.f;
    if (wid == 0) {
        #pragma unroll
        for (int o = 16; o > 0; o >>= 1) val += __shfl_xor_sync(0xffffffffu, val, o);
    }
    return val;
}

__global__ void add_ln_kernel(const float* __restrict__ gamma,
                              const float* __restrict__ beta) {
    int row = blockIdx.x;
    int tid = threadIdx.x;
    float v[3];
    float s = 0.f;
    #pragma unroll
    for (int j = 0; j < 3; j++) {
        size_t idx = (size_t)row * CD + tid + j * 256;
        v[j] = g_x[idx] + g_t[idx];
        s += v[j];
    }
    s = blockReduceSum(s);
    __shared__ float mean_s, rstd_s;
    if (tid == 0) mean_s = s * (1.f / CD);
    __syncthreads();
    float m = mean_s;
    float vv = 0.f;
    #pragma unroll
    for (int j = 0; j < 3; j++) { float d = v[j] - m; vv += d * d; }
    vv = blockReduceSum(vv);
    if (tid == 0) rstd_s = rsqrtf(vv * (1.f / CD) + 1e-5f);
    __syncthreads();
    float r = rstd_s;
    #pragma unroll
    for (int j = 0; j < 3; j++) {
        int c = tid + j * 256;
        float o = (v[j] - m) * r * gamma[c] + beta[c];
        size_t idx = (size_t)row * CD + c;
        g_x[idx] = o;
        g_xh[idx] = __float2half_rn(o);
    }
}

// last-layer LN1: residual = g_x row (r*16), t = g_t compact row r.
__global__ void ln1_last_kernel(const float* __restrict__ gamma,
                                const float* __restrict__ beta) {
    int r = blockIdx.x;  // 0..2047
    int tid = threadIdx.x;
    float v[3];
    float s = 0.f;
    #pragma unroll
    for (int j = 0; j < 3; j++) {
        int c = tid + j * 256;
        v[j] = g_x[((size_t)r * CL) * CD + c] + g_t[(size_t)r * CD + c];
        s += v[j];
    }
    s = blockReduceSum(s);
    __shared__ float mean_s, rstd_s;
    if (tid == 0) mean_s = s * (1.f / CD);
    __syncthreads();
    float m = mean_s;
    float vv = 0.f;
    #pragma unroll
    for (int j = 0; j < 3; j++) { float d = v[j] - m; vv += d * d; }
    vv = blockReduceSum(vv);
    if (tid == 0) rstd_s = rsqrtf(vv * (1.f / CD) + 1e-5f);
    __syncthreads();
    float rr = rstd_s;
    #pragma unroll
    for (int j = 0; j < 3; j++) {
        int c = tid + j * 256;
        float o = (v[j] - m) * rr * gamma[c] + beta[c];
        size_t idx = (size_t)r * CD + c;
        g_xc[idx] = o;
        g_xch[idx] = __float2half_rn(o);
    }
}

// last-layer LN2: residual = g_xc, t = g_t compact; writes g_ent (fp32).
__global__ void ln2_last_kernel(const float* __restrict__ gamma,
                                const float* __restrict__ beta) {
    int r = blockIdx.x;  // 0..2047
    int tid = threadIdx.x;
    float v[3];
    float s = 0.f;
    #pragma unroll
    for (int j = 0; j < 3; j++) {
        size_t idx = (size_t)r * CD + tid + j * 256;
        v[j] = g_xc[idx] + g_t[idx];
        s += v[j];
    }
    s = blockReduceSum(s);
    __shared__ float mean_s, rstd_s;
    if (tid == 0) mean_s = s * (1.f / CD);
    __syncthreads();
    float m = mean_s;
    float vv = 0.f;
    #pragma unroll
    for (int j = 0; j < 3; j++) { float d = v[j] - m; vv += d * d; }
    vv = blockReduceSum(vv);
    if (tid == 0) rstd_s = rsqrtf(vv * (1.f / CD) + 1e-5f);
    __syncthreads();
    float rr = rstd_s;
    #pragma unroll
    for (int j = 0; j < 3; j++) {
        int c = tid + j * 256;
        g_ent[(size_t)r * CD + c] = (v[j] - m) * rr * gamma[c] + beta[c];
    }
}

// ---------------- tail kernels ----------------
__global__ void pool_attn_kernel(const float* __restrict__ q_enc,
                                 const float* __restrict__ hint) {
    int t = blockIdx.x, b = blockIdx.y;
    __shared__ float qv[770];
    __shared__ float lg[32];
    int tid = threadIdx.x;
    for (int i = tid; i < 770; i += 256)
        qv[i] = (i < CD) ? q_enc[((size_t)b * CS + t) * CD + i]
                         : hint[((size_t)b * CTQ + t) * 2 + (i - CD)];
    __syncthreads();
    int e = tid >> 3, sub = tid & 7;
    const float* ep = g_entp + ((size_t)b * CE + e) * 770;
    float p = 0.f;
    for (int d = sub; d < 770; d += 8) p += qv[d] * ep[d];
    p += __shfl_down_sync(0xffffffffu, p, 4, 8);
    p += __shfl_down_sync(0xffffffffu, p, 2, 8);
    p += __shfl_down_sync(0xffffffffu, p, 1, 8);
    if (sub == 0) lg[e] = p;
    __syncthreads();
    if (tid < 32) {
        float v = lg[tid];
        float m = v;
        #pragma unroll
        for (int o = 16; o > 0; o >>= 1) m = fmaxf(m, __shfl_xor_sync(0xffffffffu, m, o));
        float ex = __expf(v - m);
        float sm = ex;
        #pragma unroll
        for (int o = 16; o > 0; o >>= 1) sm += __shfl_xor_sync(0xffffffffu, sm, o);
        g_attnw[((size_t)b * CTQ + t) * CE + tid] = ex / sm;
    }
}

__global__ void pool_wa_kernel(const int* __restrict__ qlen) {
    int b = blockIdx.x;
    int tid = threadIdx.x;
    __shared__ float A[32];
    int n = qlen[b];
    if (tid < 32) {
        float s = 0.f;
        for (int t = 0; t < n; t++) s += g_attnw[((size_t)b * CTQ + t) * CE + tid];
        A[tid] = s;
    }
    __syncthreads();
    #pragma unroll
    for (int j = 0; j < 3; j++) {
        int d = tid + j * 256;
        float s = 0.f;
        #pragma unroll
        for (int e = 0; e < 32; e++) s += A[e] * g_ent[((size_t)b * CE + e) * CD + d];
        g_wa[(size_t)b * CD + d] = s;
    }
}

__global__ void feat_kernel(const float* __restrict__ q_enc) {
    int b = blockIdx.x;
    for (int i = threadIdx.x; i < 2 * CD; i += 256)
        g_feat[(size_t)b * 2 * CD + i] =
            (i < CD) ? q_enc[(size_t)b * CS * CD + i] : g_wa[(size_t)b * CD + (i - CD)];
}

__global__ void head_out_kernel(const float* __restrict__ W2,
                                const float* __restrict__ b2,
                                float* __restrict__ out) {
    int b = blockIdx.x, tid = threadIdx.x;
    float s = 0.f;
    for (int n = tid; n < CNH; n += 256) s += g_h[(size_t)b * CNH + n] * W2[n];
    s = blockReduceSum(s);
    if (tid == 0) out[b] = s + b2[0];
}

// ---------------- host ----------------
template <typename T>
static T* dsym(const void* symbol) {
    void* p = nullptr;
    cudaGetSymbolAddress(&p, symbol);
    return (T*)p;
}

extern "C" void kernel_launch(void* const* d_in, const int* in_sizes, int n_in,
                              void* d_out, int out_size) {
    const float* q_enc  = (const float*)d_in[0];
    const int*   q_qlen = (const int*)  d_in[1];
    const float* hint   = (const float*)d_in[2];
    const int*   ranges = (const int*)  d_in[3];
    const float* Wq  = (const float*)d_in[4];
    const float* bq  = (const float*)d_in[5];
    const float* Wk  = (const float*)d_in[6];
    const float* bk  = (const float*)d_in[7];
    const float* Wv  = (const float*)d_in[8];
    const float* bv  = (const float*)d_in[9];
    const float* Wo  = (const float*)d_in[10];
    const float* bo  = (const float*)d_in[11];
    const float* ln1g = (const float*)d_in[12];
    const float* ln1b = (const float*)d_in[13];
    const float* Wf1 = (const float*)d_in[14];
    const float* bf1 = (const float*)d_in[15];
    const float* Wf2 = (const float*)d_in[16];
    const float* bf2 = (const float*)d_in[17];
    const float* ln2g = (const float*)d_in[18];
    const float* ln2b = (const float*)d_in[19];
    const float* W_ea = (const float*)d_in[20];
    const float* b_ea = (const float*)d_in[21];
    const float* W1  = (const float*)d_in[22];
    const float* b1  = (const float*)d_in[23];
    const float* W2  = (const float*)d_in[24];
    const float* b2  = (const float*)d_in[25];
    float* out = (float*)d_out;

    cudaFuncSetAttribute(gemm_mma, cudaFuncAttributeMaxDynamicSharedMemorySize, SMEM_DYN);

    __half* xh  = dsym<__half>(g_xh);
    __half* oh  = dsym<__half>(g_oh);
    __half* fh  = dsym<__half>(g_fh);
    __half* xch = dsym<__half>(g_xch);
    __half* qkvh = dsym<__half>(g_qkvh);
    float* t_  = dsym<float>(g_t);
    __half* wqkvh = dsym<__half>(g_wqkvh);
    __half* woh   = dsym<__half>(g_woh);
    __half* wf1h  = dsym<__half>(g_wf1h);
    __half* wf2h  = dsym<__half>(g_wf2h);
    float* bqkv = dsym<float>(g_bqkv);
    float* ent  = dsym<float>(g_ent);
    float* entp = dsym<float>(g_entp);
    float* feat = dsym<float>(g_feat);
    float* h_   = dsym<float>(g_h);

    dim3 wblk(32, 8);

    // launch 0: fused layer-0 QKV weight conversion; 1: bias concat; 2: gather
    wconv3_kernel<<<dim3(CHDK/32, CD/32, 3), wblk>>>(Wq, Wk, Wv, wqkvh);
    bqkv_kernel<<<CNL, 256>>>(bq, bk, bv);
    gather_kernel<<<NROWS, 256>>>(q_enc, ranges);

    // launch 3: layer-0 QKV GEMM — ncu window target
    gemm_mma<<<dim3(CQKV/128, NROWS/128), 256, SMEM_DYN>>>(
        xh, wqkvh, bqkv, nullptr, qkvh, CD, CQKV, 0);

    // remaining weight conversions
    for (int i = 0; i < CNL; i++) {
        if (i > 0) {
            size_t oQ = (size_t)i * CQKV * CD;
            wconv3_kernel<<<dim3(CHDK/32, CD/32, 3), wblk>>>(
                Wq + (size_t)i*CD*CHDK, Wk + (size_t)i*CD*CHDK, Wv + (size_t)i*CD*CHDK,
                wqkvh + oQ);
        }
        size_t oO = (size_t)i * CD * CHDK;
        wconv_kernel<<<dim3(CD/32, CHDK/32), wblk>>>(Wo + (size_t)i*CHDK*CD, woh + oO, CHDK, CD, 0, CHDK);
        size_t oF1 = (size_t)i * CDFF * CD;
        wconv_kernel<<<dim3(CDFF/32, CD/32), wblk>>>(Wf1 + (size_t)i*CD*CDFF, wf1h + oF1, CD, CDFF, 0, CD);
        size_t oF2 = (size_t)i * CD * CDFF;
        wconv_kernel<<<dim3(CD/32, CDFF/32), wblk>>>(Wf2 + (size_t)i*CDFF*CD, wf2h + oF2, CDFF, CD, 0, CDFF);
    }

    // ---- layers 0 .. NL-2: full-width pipeline ----
    for (int i = 0; i < CNL - 1; i++) {
        size_t oQ  = (size_t)i * CQKV * CD;
        size_t oO  = (size_t)i * CD * CHDK;
        size_t oF1 = (size_t)i * CDFF * CD;
        size_t oF2 = (size_t)i * CD * CDFF;

        if (i > 0) {
            gemm_mma<<<dim3(CQKV/128, NROWS/128), 256, SMEM_DYN>>>(
                xh, wqkvh + oQ, bqkv + i*CQKV, nullptr, qkvh, CD, CQKV, 0);
        }

        attn_kernel<<<NENT * CH, 128>>>();

        gemm_mma<<<dim3(CD/128, NROWS/128), 256, SMEM_DYN>>>(
            oh, woh + oO, bo + i*CD, t_, nullptr, CHDK, CD, 0);

        add_ln_kernel<<<NROWS, 256>>>(ln1g + i*CD, ln1b + i*CD);

        gemm_mma<<<dim3(CDFF/128, NROWS/128), 256, SMEM_DYN>>>(
            xh, wf1h + oF1, bf1 + i*CDFF, nullptr, fh, CD, CDFF, 1);

        gemm_mma<<<dim3(CD/128, NROWS/128), 256, SMEM_DYN>>>(
            fh, wf2h + oF2, bf2 + i*CD, t_, nullptr, CDFF, CD, 0);

        add_ln_kernel<<<NROWS, 256>>>(ln2g + i*CD, ln2b + i*CD);
    }

    // ---- layer NL-1 (last): only span-row 0 needed post-attention ----
    {
        const int i = CNL - 1;
        size_t oQ  = (size_t)i * CQKV * CD;
        size_t oO  = (size_t)i * CD * CHDK;
        size_t oF1 = (size_t)i * CDFF * CD;
        size_t oF2 = (size_t)i * CD * CDFF;

        gemm_mma<<<dim3(CQKV/128, NROWS/128), 256, SMEM_DYN>>>(
            xh, wqkvh + oQ, bqkv + i*CQKV, nullptr, qkvh, CD, CQKV, 0);

        attn0_kernel<<<NENT * CH, 128>>>();

        gemm_mma<<<dim3(CD/128, NENT/128), 256, SMEM_DYN>>>(
            oh, woh + oO, bo + i*CD, t_, nullptr, CHDK, CD, 0);

        ln1_last_kernel<<<NENT, 256>>>(ln1g + i*CD, ln1b + i*CD);

        gemm_mma<<<dim3(CDFF/128, NENT/128), 256, SMEM_DYN>>>(
            xch, wf1h + oF1, bf1 + i*CDFF, nullptr, fh, CD, CDFF, 1);

        gemm_mma<<<dim3(CD/128, NENT/128), 256, SMEM_DYN>>>(
            fh, wf2h + oF2, bf2 + i*CD, t_, nullptr, CDFF, CD, 0);

        ln2_last_kernel<<<NENT, 256>>>(ln2g + i*CD, ln2b + i*CD);
    }

    dim3 blk(16, 16);
    gemm_bias_kernel<<<dim3((770 + 63) / 64, NENT / 64), blk>>>(ent, W_ea, b_ea, entp, NENT, 770, CD, 0);
    pool_attn_kernel<<<dim3(CTQ, CB), 256>>>(q_enc, hint);
    pool_wa_kernel<<<CB, 256>>>(q_qlen);
    feat_kernel<<<CB, 256>>>(q_enc);
    gemm_bias_kernel<<<dim3(CNH / 64, 1), blk>>>(feat, W1, b1, h_, CB, CNH, 2 * CD, 1);
    head_out_kernel<<<CB, 256>>>(W2, b2, out);
}

// round 14
// speedup vs baseline: 11.8581x; 1.0456x over previous
#include <cuda_runtime.h>
#include <cuda_fp16.h>
#include <math.h>
#include <stdint.h>

// ---------------- problem constants ----------------
#define CB   64
#define CS   512
#define CD   768
#define CE   32
#define CL   16
#define CTQ  128
#define CH   3
#define CDK  128
#define CHDK 384
#define CQKV 1152
#define CDFF 3072
#define CNH  1024
#define CNL  3
#define NROWS (CB*CE*CL)     // 32768
#define NENT  (CB*CE)        // 2048

// ---------------- device scratch ----------------
__device__ float   g_x  [NROWS*CD];
__device__ __half  g_xh [NROWS*CD];
__device__ __half  g_qkvh[NROWS*CQKV];
__device__ __half  g_oh [NROWS*CHDK];
__device__ __half  g_fh [NROWS*CDFF];
__device__ float   g_t  [NROWS*CD];

// compact (last-layer) buffers: 2048 rows
__device__ float   g_xc [NENT*CD];
__device__ __half  g_xch[NENT*CD];

// fp16 weights
__device__ __half  g_wqkvh[CNL*CQKV*CD];
__device__ __half  g_woh [CNL*CD*CHDK];
__device__ __half  g_wf1h[CNL*CDFF*CD];
__device__ __half  g_wf2h[CNL*CD*CDFF];
__device__ float   g_bqkv[CNL*CQKV];

__device__ float g_ent [NENT*CD];
__device__ float g_entp[NENT*770];
__device__ float g_attnw[CB*CTQ*CE];
__device__ float g_wa  [CB*CD];
__device__ float g_feat[CB*2*CD];
__device__ float g_h   [CB*CNH];

// ---------------- helpers ----------------
__device__ __forceinline__ uint32_t smem_u32(const void* p) {
    uint32_t a;
    asm("{ .reg .u64 t; cvta.to.shared.u64 t, %1; cvt.u32.u64 %0, t; }" : "=r"(a) : "l"(p));
    return a;
}

__device__ __forceinline__ void ldmatrix_x4(uint32_t* r, uint32_t addr) {
    asm volatile("ldmatrix.sync.aligned.m8n8.x4.shared.b16 {%0,%1,%2,%3}, [%4];"
        : "=r"(r[0]), "=r"(r[1]), "=r"(r[2]), "=r"(r[3]) : "r"(addr));
}

__device__ __forceinline__ void mma16816(float* c, const uint32_t* a,
                                         uint32_t b0, uint32_t b1) {
    asm volatile("mma.sync.aligned.m16n8k16.row.col.f32.f16.f16.f32 "
        "{%0,%1,%2,%3}, {%4,%5,%6,%7}, {%8,%9}, {%0,%1,%2,%3};"
        : "+f"(c[0]), "+f"(c[1]), "+f"(c[2]), "+f"(c[3])
        : "r"(a[0]), "r"(a[1]), "r"(a[2]), "r"(a[3]), "r"(b0), "r"(b1));
}

// ---------------- tensor-core GEMM (mma.sync fp16, 1-term, K-chunk 64) ---
// C = Ah @ Wh^T + bias.  W stored [N,K] K-major fp16.
// CTA tile 64x128, 128 threads (4 warps = 2m x 2n, warp 32x64).
// 2-stage ring, 4 CTAs/SM (4 independent barrier domains).
// AmS = element stride between A rows; CmS = element stride between C rows.
#define ROWB    144                 // 64 fp16 = 128B data, padded to 144B
#define ATROWS  64
#define WTROWS  128
#define ATILE   (ATROWS*ROWB)       // 9216
#define WTILE   (WTROWS*ROWB)       // 18432
#define STAGE_BYTES (ATILE+WTILE)   // 27648
#define STAGES  2
#define SMEM_DYN (STAGES*STAGE_BYTES + 128)

__global__ __launch_bounds__(128, 4) void gemm_mma(
    const __half* __restrict__ Ah,
    const __half* __restrict__ Wh,
    const float* __restrict__ bias,
    float* __restrict__ Cf,
    __half* __restrict__ Chi,
    int K, int AmS, int CmS, int relu)
{
    extern __shared__ char dynsmem[];
    uint32_t sbase = (smem_u32(dynsmem) + 127u) & ~127u;

    int tid  = threadIdx.x;
    int wid  = tid >> 5, lane = tid & 31;
    int wm   = wid & 1, wn = wid >> 1;           // 2 x 2 warp grid
    int m0   = blockIdx.y * 64, n0 = blockIdx.x * 128;

    const int NC = K >> 6;       // 64-elem chunks

    auto load_chunk = [&](int kc, int buf) {
        uint32_t tb = sbase + buf * STAGE_BYTES;
        #pragma unroll
        for (int i = 0; i < 12; i++) {
            int seg = tid + i * 128;             // 0..1535
            uint32_t dst;
            const __half* src;
            if (seg < 512) {                     // A: 64 rows x 8 segs
                int row = seg >> 3, c = seg & 7;
                dst = tb + row * ROWB + c * 16;
                src = Ah + (size_t)(m0 + row) * AmS + kc * 64 + c * 8;
            } else {                             // W: 128 rows x 8 segs
                int s2 = seg - 512;
                int row = s2 >> 3, c = s2 & 7;
                dst = tb + ATILE + row * ROWB + c * 16;
                src = Wh + (size_t)(n0 + row) * K + kc * 64 + c * 8;
            }
            asm volatile("cp.async.cg.shared.global [%0], [%1], 16;" :: "r"(dst), "l"(src));
        }
        asm volatile("cp.async.commit_group;" ::: "memory");
    };

    float acc[2][8][4];
    #pragma unroll
    for (int i = 0; i < 2; i++)
        #pragma unroll
        for (int j = 0; j < 8; j++)
            #pragma unroll
            for (int q = 0; q < 4; q++) acc[i][j][q] = 0.f;

    load_chunk(0, 0);

    int lrow = lane & 15;
    int lcol = (lane >> 4) << 4;

    for (int c = 0; c < NC; c++) {
        asm volatile("cp.async.wait_group 0;" ::: "memory");
        __syncthreads();

        uint32_t sb = sbase + (c & 1) * STAGE_BYTES;

        if (c + 1 < NC) load_chunk(c + 1, (c + 1) & 1);

        uint32_t aAddr = sb + (uint32_t)(wm * 32 + lrow) * ROWB + lcol;
        uint32_t bAddr = sb + ATILE + (uint32_t)(wn * 64 + lrow) * ROWB + lcol;

        #pragma unroll
        for (int ks = 0; ks < 4; ks++) {
            uint32_t a[2][4], b[4][4];
            #pragma unroll
            for (int i = 0; i < 2; i++)
                ldmatrix_x4(a[i], aAddr + i * (16 * ROWB) + ks * 32);
            #pragma unroll
            for (int jj = 0; jj < 4; jj++)
                ldmatrix_x4(b[jj], bAddr + jj * (16 * ROWB) + ks * 32);
            #pragma unroll
            for (int i = 0; i < 2; i++)
                #pragma unroll
                for (int jj = 0; jj < 4; jj++) {
                    mma16816(acc[i][2 * jj],     a[i], b[jj][0], b[jj][2]);
                    mma16816(acc[i][2 * jj + 1], a[i], b[jj][1], b[jj][3]);
                }
        }
    }

    // ---------------- epilogue ----------------
    const float2* bp = (const float2*)(bias + n0 + wn * 64);
    float2 bv[8];
    #pragma unroll
    for (int j = 0; j < 8; j++) bv[j] = bp[j * 4 + (lane & 3)];

    #pragma unroll
    for (int i = 0; i < 2; i++) {
        int m_lo = m0 + wm * 32 + i * 16 + (lane >> 2);
        #pragma unroll
        for (int j = 0; j < 8; j++) {
            int n = n0 + wn * 64 + j * 8 + (lane & 3) * 2;
            float v0 = acc[i][j][0] + bv[j].x;
            float v1 = acc[i][j][1] + bv[j].y;
            float v2 = acc[i][j][2] + bv[j].x;
            float v3 = acc[i][j][3] + bv[j].y;
            if (relu) {
                v0 = fmaxf(v0, 0.f); v1 = fmaxf(v1, 0.f);
                v2 = fmaxf(v2, 0.f); v3 = fmaxf(v3, 0.f);
            }
            if (Cf) {
                *(float2*)(Cf + (size_t)m_lo * CmS + n)        = make_float2(v0, v1);
                *(float2*)(Cf + (size_t)(m_lo + 8) * CmS + n)  = make_float2(v2, v3);
            }
            if (Chi) {
                __half2 ph = __halves2half2(__float2half_rn(v0), __float2half_rn(v1));
                *(uint32_t*)(Chi + (size_t)m_lo * CmS + n) = *(uint32_t*)&ph;
                ph = __halves2half2(__float2half_rn(v2), __float2half_rn(v3));
                *(uint32_t*)(Chi + (size_t)(m_lo + 8) * CmS + n) = *(uint32_t*)&ph;
            }
        }
    }
}

// ---------------- weight transpose + fp16 convert ----------------
__global__ void wconv_kernel(const float* __restrict__ src,
                             __half* __restrict__ dh,
                             int K, int N, int rowOff, int dstLd) {
    __shared__ float ts[32][33];
    int n0 = blockIdx.x * 32, k0 = blockIdx.y * 32;
    int tx = threadIdx.x, ty = threadIdx.y;  // 32x8
    #pragma unroll
    for (int j = 0; j < 4; j++)
        ts[ty + 8 * j][tx] = src[(size_t)(k0 + ty + 8 * j) * N + n0 + tx];
    __syncthreads();
    #pragma unroll
    for (int j = 0; j < 4; j++) {
        float v = ts[tx][ty + 8 * j];
        size_t di = (size_t)(rowOff + n0 + ty + 8 * j) * dstLd + k0 + tx;
        dh[di] = __float2half_rn(v);
    }
}

__global__ void wconv3_kernel(const float* __restrict__ srcQ,
                              const float* __restrict__ srcK,
                              const float* __restrict__ srcV,
                              __half* __restrict__ dh) {
    __shared__ float ts[32][33];
    int z = blockIdx.z;
    const float* src = (z == 0) ? srcQ : (z == 1) ? srcK : srcV;
    int rowOff = z * CHDK;
    int n0 = blockIdx.x * 32, k0 = blockIdx.y * 32;
    int tx = threadIdx.x, ty = threadIdx.y;
    #pragma unroll
    for (int j = 0; j < 4; j++)
        ts[ty + 8 * j][tx] = src[(size_t)(k0 + ty + 8 * j) * CHDK + n0 + tx];
    __syncthreads();
    #pragma unroll
    for (int j = 0; j < 4; j++) {
        float v = ts[tx][ty + 8 * j];
        size_t di = (size_t)(rowOff + n0 + ty + 8 * j) * CD + k0 + tx;
        dh[di] = __float2half_rn(v);
    }
}

__global__ void bqkv_kernel(const float* __restrict__ bq,
                            const float* __restrict__ bk,
                            const float* __restrict__ bv) {
    int i = blockIdx.x;
    for (int j = threadIdx.x; j < CQKV; j += 256)
        g_bqkv[i * CQKV + j] =
            (j < CHDK) ? bq[i * CHDK + j] :
            (j < 2 * CHDK) ? bk[i * CHDK + j - CHDK] : bv[i * CHDK + j - 2 * CHDK];
}

// ---------------- gather spans into g_x (+ fp16) ----------------
__global__ void gather_kernel(const float* __restrict__ q_enc,
                              const int* __restrict__ ranges) {
    int row = blockIdx.x;
    int be = row >> 4, l = row & 15;
    int b = be >> 5, e = be & 31;
    int st = ranges[(b * CE + e) * 2];
    int en = ranges[(b * CE + e) * 2 + 1];
    int src = min(max(st + l, 0), CS - 1);
    bool m = l < (en - st);
    const float* s = q_enc + ((size_t)b * CS + src) * CD;
    size_t base = (size_t)row * CD;
    for (int i = threadIdx.x; i < CD; i += 256) {
        float v = m ? s[i] : 0.f;
        g_x[base + i] = v;
        g_xh[base + i] = __float2half_rn(v);
    }
}

// ---------------- fp32 SIMT GEMM (small tail matrices) ----------------
__global__ void gemm_bias_kernel(const float* __restrict__ A,
                                 const float* __restrict__ W,
                                 const float* __restrict__ bias,
                                 float* __restrict__ C,
                                 int M, int N, int K, int relu) {
    __shared__ float As[16][65];
    __shared__ float Bs[16][68];
    int tx = threadIdx.x, ty = threadIdx.y;
    int tid = ty * 16 + tx;
    int m0 = blockIdx.y * 64, n0 = blockIdx.x * 64;
    int a_row = tid >> 2, a_col = (tid & 3) << 2;
    int b_row = tid >> 4, b_col = (tid & 15) << 2;
    float acc[4][4] = {};
    for (int k0 = 0; k0 < K; k0 += 16) {
        int m = m0 + a_row;
        #pragma unroll
        for (int i = 0; i < 4; i++) {
            float v = 0.f;
            if (m < M) v = A[(size_t)m * K + k0 + a_col + i];
            As[a_col + i][a_row] = v;
        }
        #pragma unroll
        for (int i = 0; i < 4; i++) {
            int n = n0 + b_col + i;
            float v = 0.f;
            if (n < N) v = W[(size_t)(k0 + b_row) * N + n];
            Bs[b_row][b_col + i] = v;
        }
        __syncthreads();
        #pragma unroll
        for (int kk = 0; kk < 16; kk++) {
            float ra[4], rb[4];
            #pragma unroll
            for (int i = 0; i < 4; i++) ra[i] = As[kk][ty * 4 + i];
            #pragma unroll
            for (int j = 0; j < 4; j++) rb[j] = Bs[kk][tx * 4 + j];
            #pragma unroll
            for (int i = 0; i < 4; i++)
                #pragma unroll
                for (int j = 0; j < 4; j++)
                    acc[i][j] += ra[i] * rb[j];
        }
        __syncthreads();
    }
    #pragma unroll
    for (int i = 0; i < 4; i++) {
        int m = m0 + ty * 4 + i;
        if (m >= M) continue;
        #pragma unroll
        for (int j = 0; j < 4; j++) {
            int n = n0 + tx * 4 + j;
            if (n >= N) continue;
            float v = acc[i][j] + bias[n];
            if (relu) v = fmaxf(v, 0.f);
            C[(size_t)m * N + n] = v;
        }
    }
}

// ---------------- per-(span,head) attention (full, layers 0..NL-2) -------
__global__ void attn_kernel() {
    int nh = blockIdx.x;
    int n = nh / CH, h = nh % CH;
    __shared__ float qs[16][129], ks[16][129], vs[16][129];
    __shared__ float sc[16][17];
    int tid = threadIdx.x;  // 128
    for (int idx = tid; idx < 16 * 128; idx += 128) {
        int l = idx >> 7, d = idx & 127;
        size_t base = ((size_t)(n * CL + l)) * CQKV + h * CDK + d;
        qs[l][d] = __half2float(g_qkvh[base]);
        ks[l][d] = __half2float(g_qkvh[base + CHDK]);
        vs[l][d] = __half2float(g_qkvh[base + 2 * CHDK]);
    }
    __syncthreads();
    const float scale = 0.088388347648318447f;
    for (int p = tid; p < 256; p += 128) {
        int qi = p >> 4, ki = p & 15;
        float s = 0.f;
        #pragma unroll
        for (int d = 0; d < 128; d++) s += qs[qi][d] * ks[ki][d];
        sc[qi][ki] = s * scale;
    }
    __syncthreads();
    if (tid < 16) {
        float m = -1e30f;
        #pragma unroll
        for (int k = 0; k < 16; k++) m = fmaxf(m, sc[tid][k]);
        float sum = 0.f;
        #pragma unroll
        for (int k = 0; k < 16; k++) { float e = __expf(sc[tid][k] - m); sc[tid][k] = e; sum += e; }
        float inv = 1.f / sum;
        #pragma unroll
        for (int k = 0; k < 16; k++) sc[tid][k] *= inv;
    }
    __syncthreads();
    int d = tid;
    #pragma unroll
    for (int qi = 0; qi < 16; qi++) {
        float acc = 0.f;
        #pragma unroll
        for (int k = 0; k < 16; k++) acc += sc[qi][k] * vs[k][d];
        g_oh[((size_t)(n * CL + qi)) * CHDK + h * CDK + d] = __float2half_rn(acc);
    }
}

// last layer: only query position 0; writes COMPACT rows (2048).
__global__ void attn0_kernel() {
    int nh = blockIdx.x;
    int n = nh / CH, h = nh % CH;
    __shared__ float ks[16][129], vs[16][129];
    __shared__ float q0[128];
    __shared__ float p[16];
    int tid = threadIdx.x;  // 128
    for (int idx = tid; idx < 16 * 128; idx += 128) {
        int l = idx >> 7, d = idx & 127;
        size_t base = ((size_t)(n * CL + l)) * CQKV + h * CDK + d;
        ks[l][d] = __half2float(g_qkvh[base + CHDK]);
        vs[l][d] = __half2float(g_qkvh[base + 2 * CHDK]);
    }
    q0[tid] = __half2float(g_qkvh[((size_t)(n * CL)) * CQKV + h * CDK + tid]);
    __syncthreads();
    const float scale = 0.088388347648318447f;
    if (tid < 16) {
        float s = 0.f;
        #pragma unroll
        for (int d = 0; d < 128; d++) s += q0[d] * ks[tid][d];
        p[tid] = s * scale;
    }
    __syncthreads();
    if (tid == 0) {
        float m = -1e30f;
        #pragma unroll
        for (int k = 0; k < 16; k++) m = fmaxf(m, p[k]);
        float sum = 0.f;
        #pragma unroll
        for (int k = 0; k < 16; k++) { float e = __expf(p[k] - m); p[k] = e; sum += e; }
        float inv = 1.f / sum;
        #pragma unroll
        for (int k = 0; k < 16; k++) p[k] *= inv;
    }
    __syncthreads();
    float acc = 0.f;
    #pragma unroll
    for (int k = 0; k < 16; k++) acc += p[k] * vs[k][tid];
    g_oh[(size_t)n * CHDK + h * CDK + tid] = __float2half_rn(acc);
}

// ---------------- LayerNorm kernels ----------------
__device__ __forceinline__ float blockReduceSum(float val) {
    __shared__ float sh[32];
    int lane = threadIdx.x & 31, wid = threadIdx.x >> 5;
    #pragma unroll
    for (int o = 16; o > 0; o >>= 1) val += __shfl_xor_sync(0xffffffffu, val, o);
    if (lane == 0) sh[wid] = val;
    __syncthreads();
    int nw = (blockDim.x + 31) >> 5;
    val = (threadIdx.x < nw) ? sh[lane] : 0.f;
    if (wid == 0) {
        #pragma unroll
        for (int o = 16; o > 0; o >>= 1) val += __shfl_xor_sync(0xffffffffu, val, o);
    }
    return val;
}

__global__ void add_ln_kernel(const float* __restrict__ gamma,
                              const float* __restrict__ beta) {
    int row = blockIdx.x;
    int tid = threadIdx.x;
    float v[3];
    float s = 0.f;
    #pragma unroll
    for (int j = 0; j < 3; j++) {
        size_t idx = (size_t)row * CD + tid + j * 256;
        v[j] = g_x[idx] + g_t[idx];
        s += v[j];
    }
    s = blockReduceSum(s);
    __shared__ float mean_s, rstd_s;
    if (tid == 0) mean_s = s * (1.f / CD);
    __syncthreads();
    float m = mean_s;
    float vv = 0.f;
    #pragma unroll
    for (int j = 0; j < 3; j++) { float d = v[j] - m; vv += d * d; }
    vv = blockReduceSum(vv);
    if (tid == 0) rstd_s = rsqrtf(vv * (1.f / CD) + 1e-5f);
    __syncthreads();
    float r = rstd_s;
    #pragma unroll
    for (int j = 0; j < 3; j++) {
        int c = tid + j * 256;
        float o = (v[j] - m) * r * gamma[c] + beta[c];
        size_t idx = (size_t)row * CD + c;
        g_x[idx] = o;
        g_xh[idx] = __float2half_rn(o);
    }
}

// last-layer LN1: residual = g_x row (r*16), t = g_t compact row r.
__global__ void ln1_last_kernel(const float* __restrict__ gamma,
                                const float* __restrict__ beta) {
    int r = blockIdx.x;  // 0..2047
    int tid = threadIdx.x;
    float v[3];
    float s = 0.f;
    #pragma unroll
    for (int j = 0; j < 3; j++) {
        int c = tid + j * 256;
        v[j] = g_x[((size_t)r * CL) * CD + c] + g_t[(size_t)r * CD + c];
        s += v[j];
    }
    s = blockReduceSum(s);
    __shared__ float mean_s, rstd_s;
    if (tid == 0) mean_s = s * (1.f / CD);
    __syncthreads();
    float m = mean_s;
    float vv = 0.f;
    #pragma unroll
    for (int j = 0; j < 3; j++) { float d = v[j] - m; vv += d * d; }
    vv = blockReduceSum(vv);
    if (tid == 0) rstd_s = rsqrtf(vv * (1.f / CD) + 1e-5f);
    __syncthreads();
    float rr = rstd_s;
    #pragma unroll
    for (int j = 0; j < 3; j++) {
        int c = tid + j * 256;
        float o = (v[j] - m) * rr * gamma[c] + beta[c];
        size_t idx = (size_t)r * CD + c;
        g_xc[idx] = o;
        g_xch[idx] = __float2half_rn(o);
    }
}

// last-layer LN2: residual = g_xc, t = g_t compact; writes g_ent (fp32).
__global__ void ln2_last_kernel(const float* __restrict__ gamma,
                                const float* __restrict__ beta) {
    int r = blockIdx.x;  // 0..2047
    int tid = threadIdx.x;
    float v[3];
    float s = 0.f;
    #pragma unroll
    for (int j = 0; j < 3; j++) {
        size_t idx = (size_t)r * CD + tid + j * 256;
        v[j] = g_xc[idx] + g_t[idx];
        s += v[j];
    }
    s = blockReduceSum(s);
    __shared__ float mean_s, rstd_s;
    if (tid == 0) mean_s = s * (1.f / CD);
    __syncthreads();
    float m = mean_s;
    float vv = 0.f;
    #pragma unroll
    for (int j = 0; j < 3; j++) { float d = v[j] - m; vv += d * d; }
    vv = blockReduceSum(vv);
    if (tid == 0) rstd_s = rsqrtf(vv * (1.f / CD) + 1e-5f);
    __syncthreads();
    float rr = rstd_s;
    #pragma unroll
    for (int j = 0; j < 3; j++) {
        int c = tid + j * 256;
        g_ent[(size_t)r * CD + c] = (v[j] - m) * rr * gamma[c] + beta[c];
    }
}

// ---------------- tail kernels ----------------
__global__ void pool_attn_kernel(const float* __restrict__ q_enc,
                                 const float* __restrict__ hint) {
    int t = blockIdx.x, b = blockIdx.y;
    __shared__ float qv[770];
    __shared__ float lg[32];
    int tid = threadIdx.x;
    for (int i = tid; i < 770; i += 256)
        qv[i] = (i < CD) ? q_enc[((size_t)b * CS + t) * CD + i]
                         : hint[((size_t)b * CTQ + t) * 2 + (i - CD)];
    __syncthreads();
    int e = tid >> 3, sub = tid & 7;
    const float* ep = g_entp + ((size_t)b * CE + e) * 770;
    float p = 0.f;
    for (int d = sub; d < 770; d += 8) p += qv[d] * ep[d];
    p += __shfl_down_sync(0xffffffffu, p, 4, 8);
    p += __shfl_down_sync(0xffffffffu, p, 2, 8);
    p += __shfl_down_sync(0xffffffffu, p, 1, 8);
    if (sub == 0) lg[e] = p;
    __syncthreads();
    if (tid < 32) {
        float v = lg[tid];
        float m = v;
        #pragma unroll
        for (int o = 16; o > 0; o >>= 1) m = fmaxf(m, __shfl_xor_sync(0xffffffffu, m, o));
        float ex = __expf(v - m);
        float sm = ex;
        #pragma unroll
        for (int o = 16; o > 0; o >>= 1) sm += __shfl_xor_sync(0xffffffffu, sm, o);
        g_attnw[((size_t)b * CTQ + t) * CE + tid] = ex / sm;
    }
}

__global__ void pool_wa_kernel(const int* __restrict__ qlen) {
    int b = blockIdx.x;
    int tid = threadIdx.x;
    __shared__ float A[32];
    int n = qlen[b];
    if (tid < 32) {
        float s = 0.f;
        for (int t = 0; t < n; t++) s += g_attnw[((size_t)b * CTQ + t) * CE + tid];
        A[tid] = s;
    }
    __syncthreads();
    #pragma unroll
    for (int j = 0; j < 3; j++) {
        int d = tid + j * 256;
        float s = 0.f;
        #pragma unroll
        for (int e = 0; e < 32; e++) s += A[e] * g_ent[((size_t)b * CE + e) * CD + d];
        g_wa[(size_t)b * CD + d] = s;
    }
}

__global__ void feat_kernel(const float* __restrict__ q_enc) {
    int b = blockIdx.x;
    for (int i = threadIdx.x; i < 2 * CD; i += 256)
        g_feat[(size_t)b * 2 * CD + i] =
            (i < CD) ? q_enc[(size_t)b * CS * CD + i] : g_wa[(size_t)b * CD + (i - CD)];
}

__global__ void head_out_kernel(const float* __restrict__ W2,
                                const float* __restrict__ b2,
                                float* __restrict__ out) {
    int b = blockIdx.x, tid = threadIdx.x;
    float s = 0.f;
    for (int n = tid; n < CNH; n += 256) s += g_h[(size_t)b * CNH + n] * W2[n];
    s = blockReduceSum(s);
    if (tid == 0) out[b] = s + b2[0];
}

// ---------------- host ----------------
template <typename T>
static T* dsym(const void* symbol) {
    void* p = nullptr;
    cudaGetSymbolAddress(&p, symbol);
    return (T*)p;
}

extern "C" void kernel_launch(void* const* d_in, const int* in_sizes, int n_in,
                              void* d_out, int out_size) {
    const float* q_enc  = (const float*)d_in[0];
    const int*   q_qlen = (const int*)  d_in[1];
    const float* hint   = (const float*)d_in[2];
    const int*   ranges = (const int*)  d_in[3];
    const float* Wq  = (const float*)d_in[4];
    const float* bq  = (const float*)d_in[5];
    const float* Wk  = (const float*)d_in[6];
    const float* bk  = (const float*)d_in[7];
    const float* Wv  = (const float*)d_in[8];
    const float* bv  = (const float*)d_in[9];
    const float* Wo  = (const float*)d_in[10];
    const float* bo  = (const float*)d_in[11];
    const float* ln1g = (const float*)d_in[12];
    const float* ln1b = (const float*)d_in[13];
    const float* Wf1 = (const float*)d_in[14];
    const float* bf1 = (const float*)d_in[15];
    const float* Wf2 = (const float*)d_in[16];
    const float* bf2 = (const float*)d_in[17];
    const float* ln2g = (const float*)d_in[18];
    const float* ln2b = (const float*)d_in[19];
    const float* W_ea = (const float*)d_in[20];
    const float* b_ea = (const float*)d_in[21];
    const float* W1  = (const float*)d_in[22];
    const float* b1  = (const float*)d_in[23];
    const float* W2  = (const float*)d_in[24];
    const float* b2  = (const float*)d_in[25];
    float* out = (float*)d_out;

    cudaFuncSetAttribute(gemm_mma, cudaFuncAttributeMaxDynamicSharedMemorySize, SMEM_DYN);

    __half* xh  = dsym<__half>(g_xh);
    __half* oh  = dsym<__half>(g_oh);
    __half* fh  = dsym<__half>(g_fh);
    __half* xch = dsym<__half>(g_xch);
    __half* qkvh = dsym<__half>(g_qkvh);
    float* t_  = dsym<float>(g_t);
    __half* wqkvh = dsym<__half>(g_wqkvh);
    __half* woh   = dsym<__half>(g_woh);
    __half* wf1h  = dsym<__half>(g_wf1h);
    __half* wf2h  = dsym<__half>(g_wf2h);
    float* bqkv = dsym<float>(g_bqkv);
    float* ent  = dsym<float>(g_ent);
    float* entp = dsym<float>(g_entp);
    float* feat = dsym<float>(g_feat);
    float* h_   = dsym<float>(g_h);

    dim3 wblk(32, 8);

    // launch 0: fused layer-0 QKV weight conversion; 1: bias concat; 2: gather
    wconv3_kernel<<<dim3(CHDK/32, CD/32, 3), wblk>>>(Wq, Wk, Wv, wqkvh);
    bqkv_kernel<<<CNL, 256>>>(bq, bk, bv);
    gather_kernel<<<NROWS, 256>>>(q_enc, ranges);

    // launch 3: layer-0 QKV GEMM — ncu window target
    gemm_mma<<<dim3(CQKV/128, NROWS/64), 128, SMEM_DYN>>>(
        xh, wqkvh, bqkv, nullptr, qkvh, CD, CD, CQKV, 0);

    // remaining weight conversions
    for (int i = 0; i < CNL; i++) {
        if (i > 0) {
            size_t oQ = (size_t)i * CQKV * CD;
            wconv3_kernel<<<dim3(CHDK/32, CD/32, 3), wblk>>>(
                Wq + (size_t)i*CD*CHDK, Wk + (size_t)i*CD*CHDK, Wv + (size_t)i*CD*CHDK,
                wqkvh + oQ);
        }
        size_t oO = (size_t)i * CD * CHDK;
        wconv_kernel<<<dim3(CD/32, CHDK/32), wblk>>>(Wo + (size_t)i*CHDK*CD, woh + oO, CHDK, CD, 0, CHDK);
        size_t oF1 = (size_t)i * CDFF * CD;
        wconv_kernel<<<dim3(CDFF/32, CD/32), wblk>>>(Wf1 + (size_t)i*CD*CDFF, wf1h + oF1, CD, CDFF, 0, CD);
        size_t oF2 = (size_t)i * CD * CDFF;
        wconv_kernel<<<dim3(CD/32, CDFF/32), wblk>>>(Wf2 + (size_t)i*CDFF*CD, wf2h + oF2, CDFF, CD, 0, CDFF);
    }

    // ---- layers 0 .. NL-2: full-width pipeline ----
    for (int i = 0; i < CNL - 1; i++) {
        size_t oQ  = (size_t)i * CQKV * CD;
        size_t oO  = (size_t)i * CD * CHDK;
        size_t oF1 = (size_t)i * CDFF * CD;
        size_t oF2 = (size_t)i * CD * CDFF;

        if (i > 0) {
            gemm_mma<<<dim3(CQKV/128, NROWS/64), 128, SMEM_DYN>>>(
                xh, wqkvh + oQ, bqkv + i*CQKV, nullptr, qkvh, CD, CD, CQKV, 0);
        }

        attn_kernel<<<NENT * CH, 128>>>();

        gemm_mma<<<dim3(CD/128, NROWS/64), 128, SMEM_DYN>>>(
            oh, woh + oO, bo + i*CD, t_, nullptr, CHDK, CHDK, CD, 0);

        add_ln_kernel<<<NROWS, 256>>>(ln1g + i*CD, ln1b + i*CD);

        gemm_mma<<<dim3(CDFF/128, NROWS/64), 128, SMEM_DYN>>>(
            xh, wf1h + oF1, bf1 + i*CDFF, nullptr, fh, CD, CD, CDFF, 1);

        gemm_mma<<<dim3(CD/128, NROWS/64), 128, SMEM_DYN>>>(
            fh, wf2h + oF2, bf2 + i*CD, t_, nullptr, CDFF, CDFF, CD, 0);

        add_ln_kernel<<<NROWS, 256>>>(ln2g + i*CD, ln2b + i*CD);
    }

    // ---- layer NL-1 (last): only span-row 0 needed post-attention ----
    {
        const int i = CNL - 1;
        size_t oQ  = (size_t)i * CQKV * CD;
        size_t oO  = (size_t)i * CD * CHDK;
        size_t oF1 = (size_t)i * CDFF * CD;
        size_t oF2 = (size_t)i * CD * CDFF;

        // K/V for ALL rows (N = 768, columns CHDK..CQKV)
        gemm_mma<<<dim3((2*CHDK)/128, NROWS/64), 128, SMEM_DYN>>>(
            xh, wqkvh + oQ + (size_t)CHDK*CD, bqkv + i*CQKV + CHDK,
            nullptr, qkvh + CHDK, CD, CD, CQKV, 0);

        // Q only for span-row 0 (compact M = 2048, strided A rows & C rows)
        gemm_mma<<<dim3(CHDK/128, NENT/64), 128, SMEM_DYN>>>(
            xh, wqkvh + oQ, bqkv + i*CQKV,
            nullptr, qkvh, CD, CL*CD, CL*CQKV, 0);

        attn0_kernel<<<NENT * CH, 128>>>();

        gemm_mma<<<dim3(CD/128, NENT/64), 128, SMEM_DYN>>>(
            oh, woh + oO, bo + i*CD, t_, nullptr, CHDK, CHDK, CD, 0);

        ln1_last_kernel<<<NENT, 256>>>(ln1g + i*CD, ln1b + i*CD);

        gemm_mma<<<dim3(CDFF/128, NENT/64), 128, SMEM_DYN>>>(
            xch, wf1h + oF1, bf1 + i*CDFF, nullptr, fh, CD, CD, CDFF, 1);

        gemm_mma<<<dim3(CD/128, NENT/64), 128, SMEM_DYN>>>(
            fh, wf2h + oF2, bf2 + i*CD, t_, nullptr, CDFF, CDFF, CD, 0);

        ln2_last_kernel<<<NENT, 256>>>(ln2g + i*CD, ln2b + i*CD);
    }

    dim3 blk(16, 16);
    gemm_bias_kernel<<<dim3((770 + 63) / 64, NENT / 64), blk>>>(ent, W_ea, b_ea, entp, NENT, 770, CD, 0);
    pool_attn_kernel<<<dim3(CTQ, CB), 256>>>(q_enc, hint);
    pool_wa_kernel<<<CB, 256>>>(q_qlen);
    feat_kernel<<<CB, 256>>>(q_enc);
    gemm_bias_kernel<<<dim3(CNH / 64, 1), blk>>>(feat, W1, b1, h_, CB, CNH, 2 * CD, 1);
    head_out_kernel<<<CB, 256>>>(W2, b2, out);
}

// round 15
// speedup vs baseline: 12.5426x; 1.0577x over previous
#include <cuda_runtime.h>
#include <cuda_fp16.h>
#include <math.h>
#include <stdint.h>

// ---------------- problem constants ----------------
#define CB   64
#define CS   512
#define CD   768
#define CE   32
#define CL   16
#define CTQ  128
#define CH   3
#define CDK  128
#define CHDK 384
#define CQKV 1152
#define CDFF 3072
#define CNH  1024
#define CNL  3
#define NROWS (CB*CE*CL)     // 32768
#define NENT  (CB*CE)        // 2048
#define CEAP  896            // ent_proj padded N (770 -> 896 = 7*128)

// ---------------- device scratch ----------------
__device__ float   g_x  [NROWS*CD];
__device__ __half  g_xh [NROWS*CD];
__device__ __half  g_qkvh[NROWS*CQKV];
__device__ __half  g_oh [NROWS*CHDK];
__device__ __half  g_fh [NROWS*CDFF];
__device__ float   g_t  [NROWS*CD];

// compact (last-layer) buffers: 2048 rows
__device__ float   g_xc [NENT*CD];
__device__ __half  g_xch[NENT*CD];

// fp16 weights
__device__ __half  g_wqkvh[CNL*CQKV*CD];
__device__ __half  g_woh [CNL*CD*CHDK];
__device__ __half  g_wf1h[CNL*CDFF*CD];
__device__ __half  g_wf2h[CNL*CD*CDFF];
__device__ float   g_bqkv[CNL*CQKV];

// tail tensorization buffers
__device__ __half  g_weah[CEAP*CD];      // W_ea^T fp16, rows 770..895 stay zero (.bss)
__device__ float   g_bea [CEAP];         // padded bias (zeros beyond 770)
__device__ __half  g_enth[NENT*CD];      // enc_ent fp16
__device__ __half  g_feath[CB*2*CD];     // feat fp16
__device__ __half  g_w1h [CNH*2*CD];     // W1^T fp16 [1024,1536]

__device__ float g_ent [NENT*CD];
__device__ float g_entp[NENT*CEAP];      // row stride 896
__device__ float g_attnw[CB*CTQ*CE];
__device__ float g_wa  [CB*CD];
__device__ float g_h   [CB*CNH];

// ---------------- helpers ----------------
__device__ __forceinline__ uint32_t smem_u32(const void* p) {
    uint32_t a;
    asm("{ .reg .u64 t; cvta.to.shared.u64 t, %1; cvt.u32.u64 %0, t; }" : "=r"(a) : "l"(p));
    return a;
}

__device__ __forceinline__ void ldmatrix_x4(uint32_t* r, uint32_t addr) {
    asm volatile("ldmatrix.sync.aligned.m8n8.x4.shared.b16 {%0,%1,%2,%3}, [%4];"
        : "=r"(r[0]), "=r"(r[1]), "=r"(r[2]), "=r"(r[3]) : "r"(addr));
}

__device__ __forceinline__ void mma16816(float* c, const uint32_t* a,
                                         uint32_t b0, uint32_t b1) {
    asm volatile("mma.sync.aligned.m16n8k16.row.col.f32.f16.f16.f32 "
        "{%0,%1,%2,%3}, {%4,%5,%6,%7}, {%8,%9}, {%0,%1,%2,%3};"
        : "+f"(c[0]), "+f"(c[1]), "+f"(c[2]), "+f"(c[3])
        : "r"(a[0]), "r"(a[1]), "r"(a[2]), "r"(a[3]), "r"(b0), "r"(b1));
}

// ---------------- tensor-core GEMM (mma.sync fp16, 1-term, K-chunk 64) ---
// C = Ah @ Wh^T + bias.  W stored [N,K] K-major fp16.
// CTA tile 64x128, 128 threads (4 warps = 2m x 2n, warp 32x64).
// 2-stage ring, 4 CTAs/SM. AmS/CmS = element strides between A/C rows.
#define ROWB    144                 // 64 fp16 = 128B data, padded to 144B
#define ATROWS  64
#define WTROWS  128
#define ATILE   (ATROWS*ROWB)       // 9216
#define WTILE   (WTROWS*ROWB)       // 18432
#define STAGE_BYTES (ATILE+WTILE)   // 27648
#define STAGES  2
#define SMEM_DYN (STAGES*STAGE_BYTES + 128)

__global__ __launch_bounds__(128, 4) void gemm_mma(
    const __half* __restrict__ Ah,
    const __half* __restrict__ Wh,
    const float* __restrict__ bias,
    float* __restrict__ Cf,
    __half* __restrict__ Chi,
    int K, int AmS, int CmS, int relu)
{
    extern __shared__ char dynsmem[];
    uint32_t sbase = (smem_u32(dynsmem) + 127u) & ~127u;

    int tid  = threadIdx.x;
    int wid  = tid >> 5, lane = tid & 31;
    int wm   = wid & 1, wn = wid >> 1;           // 2 x 2 warp grid
    int m0   = blockIdx.y * 64, n0 = blockIdx.x * 128;

    const int NC = K >> 6;       // 64-elem chunks

    auto load_chunk = [&](int kc, int buf) {
        uint32_t tb = sbase + buf * STAGE_BYTES;
        #pragma unroll
        for (int i = 0; i < 12; i++) {
            int seg = tid + i * 128;             // 0..1535
            uint32_t dst;
            const __half* src;
            if (seg < 512) {                     // A: 64 rows x 8 segs
                int row = seg >> 3, c = seg & 7;
                dst = tb + row * ROWB + c * 16;
                src = Ah + (size_t)(m0 + row) * AmS + kc * 64 + c * 8;
            } else {                             // W: 128 rows x 8 segs
                int s2 = seg - 512;
                int row = s2 >> 3, c = s2 & 7;
                dst = tb + ATILE + row * ROWB + c * 16;
                src = Wh + (size_t)(n0 + row) * K + kc * 64 + c * 8;
            }
            asm volatile("cp.async.cg.shared.global [%0], [%1], 16;" :: "r"(dst), "l"(src));
        }
        asm volatile("cp.async.commit_group;" ::: "memory");
    };

    float acc[2][8][4];
    #pragma unroll
    for (int i = 0; i < 2; i++)
        #pragma unroll
        for (int j = 0; j < 8; j++)
            #pragma unroll
            for (int q = 0; q < 4; q++) acc[i][j][q] = 0.f;

    load_chunk(0, 0);

    int lrow = lane & 15;
    int lcol = (lane >> 4) << 4;

    for (int c = 0; c < NC; c++) {
        asm volatile("cp.async.wait_group 0;" ::: "memory");
        __syncthreads();

        uint32_t sb = sbase + (c & 1) * STAGE_BYTES;

        if (c + 1 < NC) load_chunk(c + 1, (c + 1) & 1);

        uint32_t aAddr = sb + (uint32_t)(wm * 32 + lrow) * ROWB + lcol;
        uint32_t bAddr = sb + ATILE + (uint32_t)(wn * 64 + lrow) * ROWB + lcol;

        #pragma unroll
        for (int ks = 0; ks < 4; ks++) {
            uint32_t a[2][4], b[4][4];
            #pragma unroll
            for (int i = 0; i < 2; i++)
                ldmatrix_x4(a[i], aAddr + i * (16 * ROWB) + ks * 32);
            #pragma unroll
            for (int jj = 0; jj < 4; jj++)
                ldmatrix_x4(b[jj], bAddr + jj * (16 * ROWB) + ks * 32);
            #pragma unroll
            for (int i = 0; i < 2; i++)
                #pragma unroll
                for (int jj = 0; jj < 4; jj++) {
                    mma16816(acc[i][2 * jj],     a[i], b[jj][0], b[jj][2]);
                    mma16816(acc[i][2 * jj + 1], a[i], b[jj][1], b[jj][3]);
                }
        }
    }

    // ---------------- epilogue ----------------
    const float2* bp = (const float2*)(bias + n0 + wn * 64);
    float2 bv[8];
    #pragma unroll
    for (int j = 0; j < 8; j++) bv[j] = bp[j * 4 + (lane & 3)];

    #pragma unroll
    for (int i = 0; i < 2; i++) {
        int m_lo = m0 + wm * 32 + i * 16 + (lane >> 2);
        #pragma unroll
        for (int j = 0; j < 8; j++) {
            int n = n0 + wn * 64 + j * 8 + (lane & 3) * 2;
            float v0 = acc[i][j][0] + bv[j].x;
            float v1 = acc[i][j][1] + bv[j].y;
            float v2 = acc[i][j][2] + bv[j].x;
            float v3 = acc[i][j][3] + bv[j].y;
            if (relu) {
                v0 = fmaxf(v0, 0.f); v1 = fmaxf(v1, 0.f);
                v2 = fmaxf(v2, 0.f); v3 = fmaxf(v3, 0.f);
            }
            if (Cf) {
                *(float2*)(Cf + (size_t)m_lo * CmS + n)        = make_float2(v0, v1);
                *(float2*)(Cf + (size_t)(m_lo + 8) * CmS + n)  = make_float2(v2, v3);
            }
            if (Chi) {
                __half2 ph = __halves2half2(__float2half_rn(v0), __float2half_rn(v1));
                *(uint32_t*)(Chi + (size_t)m_lo * CmS + n) = *(uint32_t*)&ph;
                ph = __halves2half2(__float2half_rn(v2), __float2half_rn(v3));
                *(uint32_t*)(Chi + (size_t)(m_lo + 8) * CmS + n) = *(uint32_t*)&ph;
            }
        }
    }
}

// ---------------- weight transpose + fp16 convert ----------------
__global__ void wconv_kernel(const float* __restrict__ src,
                             __half* __restrict__ dh,
                             int K, int N, int rowOff, int dstLd) {
    __shared__ float ts[32][33];
    int n0 = blockIdx.x * 32, k0 = blockIdx.y * 32;
    int tx = threadIdx.x, ty = threadIdx.y;  // 32x8
    #pragma unroll
    for (int j = 0; j < 4; j++)
        ts[ty + 8 * j][tx] = src[(size_t)(k0 + ty + 8 * j) * N + n0 + tx];
    __syncthreads();
    #pragma unroll
    for (int j = 0; j < 4; j++) {
        float v = ts[tx][ty + 8 * j];
        size_t di = (size_t)(rowOff + n0 + ty + 8 * j) * dstLd + k0 + tx;
        dh[di] = __float2half_rn(v);
    }
}

// guarded transpose for W_ea: src [CD, 770] -> dst [770(pad CEAP), CD] fp16
__global__ void wconv_ea_kernel(const float* __restrict__ src) {
    __shared__ float ts[32][33];
    int n0 = blockIdx.x * 32, k0 = blockIdx.y * 32;
    int tx = threadIdx.x, ty = threadIdx.y;  // 32x8
    #pragma unroll
    for (int j = 0; j < 4; j++) {
        int n = n0 + tx;
        ts[ty + 8 * j][tx] = (n < 770) ? src[(size_t)(k0 + ty + 8 * j) * 770 + n] : 0.f;
    }
    __syncthreads();
    #pragma unroll
    for (int j = 0; j < 4; j++) {
        int n = n0 + ty + 8 * j;
        if (n < 770)
            g_weah[(size_t)n * CD + k0 + tx] = __float2half_rn(ts[tx][ty + 8 * j]);
    }
}

__global__ void wconv3_kernel(const float* __restrict__ srcQ,
                              const float* __restrict__ srcK,
                              const float* __restrict__ srcV,
                              __half* __restrict__ dh) {
    __shared__ float ts[32][33];
    int z = blockIdx.z;
    const float* src = (z == 0) ? srcQ : (z == 1) ? srcK : srcV;
    int rowOff = z * CHDK;
    int n0 = blockIdx.x * 32, k0 = blockIdx.y * 32;
    int tx = threadIdx.x, ty = threadIdx.y;
    #pragma unroll
    for (int j = 0; j < 4; j++)
        ts[ty + 8 * j][tx] = src[(size_t)(k0 + ty + 8 * j) * CHDK + n0 + tx];
    __syncthreads();
    #pragma unroll
    for (int j = 0; j < 4; j++) {
        float v = ts[tx][ty + 8 * j];
        size_t di = (size_t)(rowOff + n0 + ty + 8 * j) * CD + k0 + tx;
        dh[di] = __float2half_rn(v);
    }
}

__global__ void bqkv_kernel(const float* __restrict__ bq,
                            const float* __restrict__ bk,
                            const float* __restrict__ bv,
                            const float* __restrict__ b_ea) {
    int i = blockIdx.x;
    for (int j = threadIdx.x; j < CQKV; j += 256)
        g_bqkv[i * CQKV + j] =
            (j < CHDK) ? bq[i * CHDK + j] :
            (j < 2 * CHDK) ? bk[i * CHDK + j - CHDK] : bv[i * CHDK + j - 2 * CHDK];
    if (i == 0)
        for (int j = threadIdx.x; j < CEAP; j += 256)
            g_bea[j] = (j < 770) ? b_ea[j] : 0.f;
}

// ---------------- gather spans into g_x (+ fp16) ----------------
__global__ void gather_kernel(const float* __restrict__ q_enc,
                              const int* __restrict__ ranges) {
    int row = blockIdx.x;
    int be = row >> 4, l = row & 15;
    int b = be >> 5, e = be & 31;
    int st = ranges[(b * CE + e) * 2];
    int en = ranges[(b * CE + e) * 2 + 1];
    int src = min(max(st + l, 0), CS - 1);
    bool m = l < (en - st);
    const float* s = q_enc + ((size_t)b * CS + src) * CD;
    size_t base = (size_t)row * CD;
    for (int i = threadIdx.x; i < CD; i += 256) {
        float v = m ? s[i] : 0.f;
        g_x[base + i] = v;
        g_xh[base + i] = __float2half_rn(v);
    }
}

// ---------------- per-(span,head) attention (full, layers 0..NL-2) -------
__global__ void attn_kernel() {
    int nh = blockIdx.x;
    int n = nh / CH, h = nh % CH;
    __shared__ float qs[16][129], ks[16][129], vs[16][129];
    __shared__ float sc[16][17];
    int tid = threadIdx.x;  // 128
    for (int idx = tid; idx < 16 * 128; idx += 128) {
        int l = idx >> 7, d = idx & 127;
        size_t base = ((size_t)(n * CL + l)) * CQKV + h * CDK + d;
        qs[l][d] = __half2float(g_qkvh[base]);
        ks[l][d] = __half2float(g_qkvh[base + CHDK]);
        vs[l][d] = __half2float(g_qkvh[base + 2 * CHDK]);
    }
    __syncthreads();
    const float scale = 0.088388347648318447f;
    for (int p = tid; p < 256; p += 128) {
        int qi = p >> 4, ki = p & 15;
        float s = 0.f;
        #pragma unroll
        for (int d = 0; d < 128; d++) s += qs[qi][d] * ks[ki][d];
        sc[qi][ki] = s * scale;
    }
    __syncthreads();
    if (tid < 16) {
        float m = -1e30f;
        #pragma unroll
        for (int k = 0; k < 16; k++) m = fmaxf(m, sc[tid][k]);
        float sum = 0.f;
        #pragma unroll
        for (int k = 0; k < 16; k++) { float e = __expf(sc[tid][k] - m); sc[tid][k] = e; sum += e; }
        float inv = 1.f / sum;
        #pragma unroll
        for (int k = 0; k < 16; k++) sc[tid][k] *= inv;
    }
    __syncthreads();
    int d = tid;
    #pragma unroll
    for (int qi = 0; qi < 16; qi++) {
        float acc = 0.f;
        #pragma unroll
        for (int k = 0; k < 16; k++) acc += sc[qi][k] * vs[k][d];
        g_oh[((size_t)(n * CL + qi)) * CHDK + h * CDK + d] = __float2half_rn(acc);
    }
}

// last layer: only query position 0; writes COMPACT rows (2048).
__global__ void attn0_kernel() {
    int nh = blockIdx.x;
    int n = nh / CH, h = nh % CH;
    __shared__ float ks[16][129], vs[16][129];
    __shared__ float q0[128];
    __shared__ float p[16];
    int tid = threadIdx.x;  // 128
    for (int idx = tid; idx < 16 * 128; idx += 128) {
        int l = idx >> 7, d = idx & 127;
        size_t base = ((size_t)(n * CL + l)) * CQKV + h * CDK + d;
        ks[l][d] = __half2float(g_qkvh[base + CHDK]);
        vs[l][d] = __half2float(g_qkvh[base + 2 * CHDK]);
    }
    q0[tid] = __half2float(g_qkvh[((size_t)(n * CL)) * CQKV + h * CDK + tid]);
    __syncthreads();
    const float scale = 0.088388347648318447f;
    if (tid < 16) {
        float s = 0.f;
        #pragma unroll
        for (int d = 0; d < 128; d++) s += q0[d] * ks[tid][d];
        p[tid] = s * scale;
    }
    __syncthreads();
    if (tid == 0) {
        float m = -1e30f;
        #pragma unroll
        for (int k = 0; k < 16; k++) m = fmaxf(m, p[k]);
        float sum = 0.f;
        #pragma unroll
        for (int k = 0; k < 16; k++) { float e = __expf(p[k] - m); p[k] = e; sum += e; }
        float inv = 1.f / sum;
        #pragma unroll
        for (int k = 0; k < 16; k++) p[k] *= inv;
    }
    __syncthreads();
    float acc = 0.f;
    #pragma unroll
    for (int k = 0; k < 16; k++) acc += p[k] * vs[k][tid];
    g_oh[(size_t)n * CHDK + h * CDK + tid] = __float2half_rn(acc);
}

// ---------------- LayerNorm kernels ----------------
__device__ __forceinline__ float blockReduceSum(float val) {
    __shared__ float sh[32];
    int lane = threadIdx.x & 31, wid = threadIdx.x >> 5;
    #pragma unroll
    for (int o = 16; o > 0; o >>= 1) val += __shfl_xor_sync(0xffffffffu, val, o);
    if (lane == 0) sh[wid] = val;
    __syncthreads();
    int nw = (blockDim.x + 31) >> 5;
    val = (threadIdx.x < nw) ? sh[lane] : 0.f;
    if (wid == 0) {
        #pragma unroll
        for (int o = 16; o > 0; o >>= 1) val += __shfl_xor_sync(0xffffffffu, val, o);
    }
    return val;
}

__global__ void add_ln_kernel(const float* __restrict__ gamma,
                              const float* __restrict__ beta) {
    int row = blockIdx.x;
    int tid = threadIdx.x;
    float v[3];
    float s = 0.f;
    #pragma unroll
    for (int j = 0; j < 3; j++) {
        size_t idx = (size_t)row * CD + tid + j * 256;
        v[j] = g_x[idx] + g_t[idx];
        s += v[j];
    }
    s = blockReduceSum(s);
    __shared__ float mean_s, rstd_s;
    if (tid == 0) mean_s = s * (1.f / CD);
    __syncthreads();
    float m = mean_s;
    float vv = 0.f;
    #pragma unroll
    for (int j = 0; j < 3; j++) { float d = v[j] - m; vv += d * d; }
    vv = blockReduceSum(vv);
    if (tid == 0) rstd_s = rsqrtf(vv * (1.f / CD) + 1e-5f);
    __syncthreads();
    float r = rstd_s;
    #pragma unroll
    for (int j = 0; j < 3; j++) {
        int c = tid + j * 256;
        float o = (v[j] - m) * r * gamma[c] + beta[c];
        size_t idx = (size_t)row * CD + c;
        g_x[idx] = o;
        g_xh[idx] = __float2half_rn(o);
    }
}

// last-layer LN1: residual = g_x row (r*16), t = g_t compact row r.
__global__ void ln1_last_kernel(const float* __restrict__ gamma,
                                const float* __restrict__ beta) {
    int r = blockIdx.x;  // 0..2047
    int tid = threadIdx.x;
    float v[3];
    float s = 0.f;
    #pragma unroll
    for (int j = 0; j < 3; j++) {
        int c = tid + j * 256;
        v[j] = g_x[((size_t)r * CL) * CD + c] + g_t[(size_t)r * CD + c];
        s += v[j];
    }
    s = blockReduceSum(s);
    __shared__ float mean_s, rstd_s;
    if (tid == 0) mean_s = s * (1.f / CD);
    __syncthreads();
    float m = mean_s;
    float vv = 0.f;
    #pragma unroll
    for (int j = 0; j < 3; j++) { float d = v[j] - m; vv += d * d; }
    vv = blockReduceSum(vv);
    if (tid == 0) rstd_s = rsqrtf(vv * (1.f / CD) + 1e-5f);
    __syncthreads();
    float rr = rstd_s;
    #pragma unroll
    for (int j = 0; j < 3; j++) {
        int c = tid + j * 256;
        float o = (v[j] - m) * rr * gamma[c] + beta[c];
        size_t idx = (size_t)r * CD + c;
        g_xc[idx] = o;
        g_xch[idx] = __float2half_rn(o);
    }
}

// last-layer LN2: residual = g_xc, t = g_t compact; writes g_ent + g_enth.
__global__ void ln2_last_kernel(const float* __restrict__ gamma,
                                const float* __restrict__ beta) {
    int r = blockIdx.x;  // 0..2047
    int tid = threadIdx.x;
    float v[3];
    float s = 0.f;
    #pragma unroll
    for (int j = 0; j < 3; j++) {
        size_t idx = (size_t)r * CD + tid + j * 256;
        v[j] = g_xc[idx] + g_t[idx];
        s += v[j];
    }
    s = blockReduceSum(s);
    __shared__ float mean_s, rstd_s;
    if (tid == 0) mean_s = s * (1.f / CD);
    __syncthreads();
    float m = mean_s;
    float vv = 0.f;
    #pragma unroll
    for (int j = 0; j < 3; j++) { float d = v[j] - m; vv += d * d; }
    vv = blockReduceSum(vv);
    if (tid == 0) rstd_s = rsqrtf(vv * (1.f / CD) + 1e-5f);
    __syncthreads();
    float rr = rstd_s;
    #pragma unroll
    for (int j = 0; j < 3; j++) {
        int c = tid + j * 256;
        float o = (v[j] - m) * rr * gamma[c] + beta[c];
        size_t idx = (size_t)r * CD + c;
        g_ent[idx] = o;
        g_enth[idx] = __float2half_rn(o);
    }
}

// ---------------- tail kernels ----------------
__global__ void pool_attn_kernel(const float* __restrict__ q_enc,
                                 const float* __restrict__ hint) {
    int t = blockIdx.x, b = blockIdx.y;
    __shared__ float qv[770];
    __shared__ float lg[32];
    int tid = threadIdx.x;
    for (int i = tid; i < 770; i += 256)
        qv[i] = (i < CD) ? q_enc[((size_t)b * CS + t) * CD + i]
                         : hint[((size_t)b * CTQ + t) * 2 + (i - CD)];
    __syncthreads();
    int e = tid >> 3, sub = tid & 7;
    const float* ep = g_entp + ((size_t)b * CE + e) * CEAP;
    float p = 0.f;
    for (int d = sub; d < 770; d += 8) p += qv[d] * ep[d];
    p += __shfl_down_sync(0xffffffffu, p, 4, 8);
    p += __shfl_down_sync(0xffffffffu, p, 2, 8);
    p += __shfl_down_sync(0xffffffffu, p, 1, 8);
    if (sub == 0) lg[e] = p;
    __syncthreads();
    if (tid < 32) {
        float v = lg[tid];
        float m = v;
        #pragma unroll
        for (int o = 16; o > 0; o >>= 1) m = fmaxf(m, __shfl_xor_sync(0xffffffffu, m, o));
        float ex = __expf(v - m);
        float sm = ex;
        #pragma unroll
        for (int o = 16; o > 0; o >>= 1) sm += __shfl_xor_sync(0xffffffffu, sm, o);
        g_attnw[((size_t)b * CTQ + t) * CE + tid] = ex / sm;
    }
}

__global__ void pool_wa_kernel(const int* __restrict__ qlen) {
    int b = blockIdx.x;
    int tid = threadIdx.x;
    __shared__ float A[32];
    int n = qlen[b];
    if (tid < 32) {
        float s = 0.f;
        for (int t = 0; t < n; t++) s += g_attnw[((size_t)b * CTQ + t) * CE + tid];
        A[tid] = s;
    }
    __syncthreads();
    #pragma unroll
    for (int j = 0; j < 3; j++) {
        int d = tid + j * 256;
        float s = 0.f;
        #pragma unroll
        for (int e = 0; e < 32; e++) s += A[e] * g_ent[((size_t)b * CE + e) * CD + d];
        g_wa[(size_t)b * CD + d] = s;
    }
}

// feat (fp16) = [q_enc[b,0,:], wa[b,:]]
__global__ void feat_kernel(const float* __restrict__ q_enc) {
    int b = blockIdx.x;
    for (int i = threadIdx.x; i < 2 * CD; i += 256)
        g_feath[(size_t)b * 2 * CD + i] = __float2half_rn(
            (i < CD) ? q_enc[(size_t)b * CS * CD + i] : g_wa[(size_t)b * CD + (i - CD)]);
}

__global__ void head_out_kernel(const float* __restrict__ W2,
                                const float* __restrict__ b2,
                                float* __restrict__ out) {
    int b = blockIdx.x, tid = threadIdx.x;
    float s = 0.f;
    for (int n = tid; n < CNH; n += 256) s += g_h[(size_t)b * CNH + n] * W2[n];
    s = blockReduceSum(s);
    if (tid == 0) out[b] = s + b2[0];
}

// ---------------- host ----------------
template <typename T>
static T* dsym(const void* symbol) {
    void* p = nullptr;
    cudaGetSymbolAddress(&p, symbol);
    return (T*)p;
}

extern "C" void kernel_launch(void* const* d_in, const int* in_sizes, int n_in,
                              void* d_out, int out_size) {
    const float* q_enc  = (const float*)d_in[0];
    const int*   q_qlen = (const int*)  d_in[1];
    const float* hint   = (const float*)d_in[2];
    const int*   ranges = (const int*)  d_in[3];
    const float* Wq  = (const float*)d_in[4];
    const float* bq  = (const float*)d_in[5];
    const float* Wk  = (const float*)d_in[6];
    const float* bk  = (const float*)d_in[7];
    const float* Wv  = (const float*)d_in[8];
    const float* bv  = (const float*)d_in[9];
    const float* Wo  = (const float*)d_in[10];
    const float* bo  = (const float*)d_in[11];
    const float* ln1g = (const float*)d_in[12];
    const float* ln1b = (const float*)d_in[13];
    const float* Wf1 = (const float*)d_in[14];
    const float* bf1 = (const float*)d_in[15];
    const float* Wf2 = (const float*)d_in[16];
    const float* bf2 = (const float*)d_in[17];
    const float* ln2g = (const float*)d_in[18];
    const float* ln2b = (const float*)d_in[19];
    const float* W_ea = (const float*)d_in[20];
    const float* b_ea = (const float*)d_in[21];
    const float* W1  = (const float*)d_in[22];
    const float* b1  = (const float*)d_in[23];
    const float* W2  = (const float*)d_in[24];
    const float* b2  = (const float*)d_in[25];
    float* out = (float*)d_out;

    cudaFuncSetAttribute(gemm_mma, cudaFuncAttributeMaxDynamicSharedMemorySize, SMEM_DYN);

    __half* xh  = dsym<__half>(g_xh);
    __half* oh  = dsym<__half>(g_oh);
    __half* fh  = dsym<__half>(g_fh);
    __half* xch = dsym<__half>(g_xch);
    __half* qkvh = dsym<__half>(g_qkvh);
    float* t_  = dsym<float>(g_t);
    __half* wqkvh = dsym<__half>(g_wqkvh);
    __half* woh   = dsym<__half>(g_woh);
    __half* wf1h  = dsym<__half>(g_wf1h);
    __half* wf2h  = dsym<__half>(g_wf2h);
    __half* weah  = dsym<__half>(g_weah);
    __half* enth  = dsym<__half>(g_enth);
    __half* feath = dsym<__half>(g_feath);
    __half* w1h   = dsym<__half>(g_w1h);
    float* bqkv = dsym<float>(g_bqkv);
    float* bea  = dsym<float>(g_bea);
    float* entp = dsym<float>(g_entp);
    float* h_   = dsym<float>(g_h);

    dim3 wblk(32, 8);

    // launch 0: fused layer-0 QKV weight conversion; 1: bias concat; 2: gather
    wconv3_kernel<<<dim3(CHDK/32, CD/32, 3), wblk>>>(Wq, Wk, Wv, wqkvh);
    bqkv_kernel<<<CNL, 256>>>(bq, bk, bv, b_ea);
    gather_kernel<<<NROWS, 256>>>(q_enc, ranges);

    // launch 3: layer-0 QKV GEMM — ncu window target
    gemm_mma<<<dim3(CQKV/128, NROWS/64), 128, SMEM_DYN>>>(
        xh, wqkvh, bqkv, nullptr, qkvh, CD, CD, CQKV, 0);

    // remaining weight conversions
    for (int i = 0; i < CNL; i++) {
        if (i > 0) {
            size_t oQ = (size_t)i * CQKV * CD;
            wconv3_kernel<<<dim3(CHDK/32, CD/32, 3), wblk>>>(
                Wq + (size_t)i*CD*CHDK, Wk + (size_t)i*CD*CHDK, Wv + (size_t)i*CD*CHDK,
                wqkvh + oQ);
        }
        size_t oO = (size_t)i * CD * CHDK;
        wconv_kernel<<<dim3(CD/32, CHDK/32), wblk>>>(Wo + (size_t)i*CHDK*CD, woh + oO, CHDK, CD, 0, CHDK);
        size_t oF1 = (size_t)i * CDFF * CD;
        wconv_kernel<<<dim3(CDFF/32, CD/32), wblk>>>(Wf1 + (size_t)i*CD*CDFF, wf1h + oF1, CD, CDFF, 0, CD);
        size_t oF2 = (size_t)i * CD * CDFF;
        wconv_kernel<<<dim3(CD/32, CDFF/32), wblk>>>(Wf2 + (size_t)i*CDFF*CD, wf2h + oF2, CDFF, CD, 0, CDFF);
    }
    // tail weight conversions
    wconv_ea_kernel<<<dim3((770 + 31)/32, CD/32), wblk>>>(W_ea);
    wconv_kernel<<<dim3(CNH/32, (2*CD)/32), wblk>>>(W1, w1h, 2*CD, CNH, 0, 2*CD);

    // ---- layers 0 .. NL-2: full-width pipeline ----
    for (int i = 0; i < CNL - 1; i++) {
        size_t oQ  = (size_t)i * CQKV * CD;
        size_t oO  = (size_t)i * CD * CHDK;
        size_t oF1 = (size_t)i * CDFF * CD;
        size_t oF2 = (size_t)i * CD * CDFF;

        if (i > 0) {
            gemm_mma<<<dim3(CQKV/128, NROWS/64), 128, SMEM_DYN>>>(
                xh, wqkvh + oQ, bqkv + i*CQKV, nullptr, qkvh, CD, CD, CQKV, 0);
        }

        attn_kernel<<<NENT * CH, 128>>>();

        gemm_mma<<<dim3(CD/128, NROWS/64), 128, SMEM_DYN>>>(
            oh, woh + oO, bo + i*CD, t_, nullptr, CHDK, CHDK, CD, 0);

        add_ln_kernel<<<NROWS, 256>>>(ln1g + i*CD, ln1b + i*CD);

        gemm_mma<<<dim3(CDFF/128, NROWS/64), 128, SMEM_DYN>>>(
            xh, wf1h + oF1, bf1 + i*CDFF, nullptr, fh, CD, CD, CDFF, 1);

        gemm_mma<<<dim3(CD/128, NROWS/64), 128, SMEM_DYN>>>(
            fh, wf2h + oF2, bf2 + i*CD, t_, nullptr, CDFF, CDFF, CD, 0);

        add_ln_kernel<<<NROWS, 256>>>(ln2g + i*CD, ln2b + i*CD);
    }

    // ---- layer NL-1 (last): only span-row 0 needed post-attention ----
    {
        const int i = CNL - 1;
        size_t oQ  = (size_t)i * CQKV * CD;
        size_t oO  = (size_t)i * CD * CHDK;
        size_t oF1 = (size_t)i * CDFF * CD;
        size_t oF2 = (size_t)i * CD * CDFF;

        // K/V for ALL rows (N = 768, columns CHDK..CQKV)
        gemm_mma<<<dim3((2*CHDK)/128, NROWS/64), 128, SMEM_DYN>>>(
            xh, wqkvh + oQ + (size_t)CHDK*CD, bqkv + i*CQKV + CHDK,
            nullptr, qkvh + CHDK, CD, CD, CQKV, 0);

        // Q only for span-row 0 (compact M = 2048, strided A rows & C rows)
        gemm_mma<<<dim3(CHDK/128, NENT/64), 128, SMEM_DYN>>>(
            xh, wqkvh + oQ, bqkv + i*CQKV,
            nullptr, qkvh, CD, CL*CD, CL*CQKV, 0);

        attn0_kernel<<<NENT * CH, 128>>>();

        gemm_mma<<<dim3(CD/128, NENT/64), 128, SMEM_DYN>>>(
            oh, woh + oO, bo + i*CD, t_, nullptr, CHDK, CHDK, CD, 0);

        ln1_last_kernel<<<NENT, 256>>>(ln1g + i*CD, ln1b + i*CD);

        gemm_mma<<<dim3(CDFF/128, NENT/64), 128, SMEM_DYN>>>(
            xch, wf1h + oF1, bf1 + i*CDFF, nullptr, fh, CD, CD, CDFF, 1);

        gemm_mma<<<dim3(CD/128, NENT/64), 128, SMEM_DYN>>>(
            fh, wf2h + oF2, bf2 + i*CD, t_, nullptr, CDFF, CDFF, CD, 0);

        ln2_last_kernel<<<NENT, 256>>>(ln2g + i*CD, ln2b + i*CD);
    }

    // ---- tail: ent_proj + pooling + head (tensorized) ----
    gemm_mma<<<dim3(CEAP/128, NENT/64), 128, SMEM_DYN>>>(
        enth, weah, bea, entp, nullptr, CD, CD, CEAP, 0);

    pool_attn_kernel<<<dim3(CTQ, CB), 256>>>(q_enc, hint);
    pool_wa_kernel<<<CB, 256>>>(q_qlen);
    feat_kernel<<<CB, 256>>>(q_enc);

    gemm_mma<<<dim3(CNH/128, CB/64), 128, SMEM_DYN>>>(
        feath, w1h, b1, h_, nullptr, 2*CD, 2*CD, CNH, 1);

    head_out_kernel<<<CB, 256>>>(W2, b2, out);
}